// round 1
// baseline (speedup 1.0000x reference)
#include <cuda_runtime.h>
#include <math.h>

// Problem constants
#define B_      4
#define S_      2048
#define D_      1024
#define H_      16
#define HD_     64
#define L_      6
#define SEQDIM_ 128
#define ROWS_   (B_ * S_)   // 8192

// ---------------------------------------------------------------------------
// Device scratch (allocation-free: __device__ globals)
// ---------------------------------------------------------------------------
__device__ float g_xe[ROWS_ * SEQDIM_];
__device__ float g_x [ROWS_ * D_];
__device__ float g_q [ROWS_ * D_];
__device__ float g_k [ROWS_ * D_];
__device__ float g_v [ROWS_ * D_];
__device__ float g_ao[ROWS_ * D_];
__device__ float g_t [ROWS_ * D_];

// ---------------------------------------------------------------------------
// Embedding gather: xe[row][c] = emb[seq[row]][c]
// ---------------------------------------------------------------------------
__global__ void gather_emb(const int* __restrict__ seq,
                           const float* __restrict__ emb,
                           float* __restrict__ xe) {
    int idx = blockIdx.x * blockDim.x + threadIdx.x;
    if (idx >= ROWS_ * SEQDIM_) return;
    int row = idx >> 7;          // /128
    int c   = idx & 127;
    xe[idx] = emb[seq[row] * SEQDIM_ + c];
}

// ---------------------------------------------------------------------------
// Tiled SGEMM + bias: C[M,N] = A[M,K] @ B[K,N] + bias[N]
// BM=BN=128, BK=8, 256 threads, 8x8 register tile per thread.
// M,N multiples of 128; K multiple of 8 (here 128 or 1024).
// ---------------------------------------------------------------------------
__global__ __launch_bounds__(256)
void gemm_bias(const float* __restrict__ A, const float* __restrict__ Bm,
               const float* __restrict__ bias, float* __restrict__ C,
               int M, int N, int K) {
    __shared__ float As[8][128];
    __shared__ float Bs[8][128];

    const int tid  = threadIdx.x;
    const int brow = blockIdx.y * 128;
    const int bcol = blockIdx.x * 128;

    const int arow = tid >> 1;            // 0..127
    const int acol = (tid & 1) * 4;       // 0 or 4
    const int brw  = tid >> 5;            // 0..7
    const int bcl  = (tid & 31) * 4;      // 0..124

    const int ty = tid >> 4, tx = tid & 15;

    float acc[8][8];
    #pragma unroll
    for (int i = 0; i < 8; i++)
        #pragma unroll
        for (int j = 0; j < 8; j++) acc[i][j] = 0.f;

    const float* Ap = A  + (size_t)brow * K;
    const float* Bp = Bm + bcol;

    for (int k0 = 0; k0 < K; k0 += 8) {
        float4 av = *(const float4*)(Ap + (size_t)arow * K + k0 + acol);
        As[acol + 0][arow] = av.x;
        As[acol + 1][arow] = av.y;
        As[acol + 2][arow] = av.z;
        As[acol + 3][arow] = av.w;
        float4 bv = *(const float4*)(Bp + (size_t)(k0 + brw) * N + bcl);
        *(float4*)&Bs[brw][bcl] = bv;
        __syncthreads();

        #pragma unroll
        for (int kk = 0; kk < 8; kk++) {
            float ar[8], br[8];
            #pragma unroll
            for (int i = 0; i < 8; i++) ar[i] = As[kk][ty * 8 + i];
            #pragma unroll
            for (int j = 0; j < 8; j++) br[j] = Bs[kk][tx * 8 + j];
            #pragma unroll
            for (int i = 0; i < 8; i++)
                #pragma unroll
                for (int j = 0; j < 8; j++)
                    acc[i][j] = fmaf(ar[i], br[j], acc[i][j]);
        }
        __syncthreads();
    }

    #pragma unroll
    for (int i = 0; i < 8; i++) {
        int r = brow + ty * 8 + i;
        #pragma unroll
        for (int j = 0; j < 8; j += 4) {
            int c = bcol + tx * 8 + j;
            float4 o;
            o.x = acc[i][j + 0] + bias[c + 0];
            o.y = acc[i][j + 1] + bias[c + 1];
            o.z = acc[i][j + 2] + bias[c + 2];
            o.w = acc[i][j + 3] + bias[c + 3];
            *(float4*)(C + (size_t)r * N + c) = o;
        }
    }
}

// ---------------------------------------------------------------------------
// Fused flash attention (per (b,h), 64-query blocks, 64-key tiles, online
// softmax). Q/K/V laid out as [B*S, D] with head h at cols [h*64, h*64+64).
// ---------------------------------------------------------------------------
__global__ __launch_bounds__(256)
void flash_attn(const float* __restrict__ Q, const float* __restrict__ Kt,
                const float* __restrict__ Vt, const int* __restrict__ mask,
                float* __restrict__ O) {
    extern __shared__ float sm[];
    float* Qs = sm;               // 64 x 65
    float* Ks = sm + 4160;        // 64 x 65
    float* Vs = sm + 8320;        // 64 x 65
    float* Ps = sm + 12480;       // 64 x 65
    int*   smask = (int*)(sm + 16640);  // 64

    const int tid = threadIdx.x;
    const int q0  = blockIdx.x * 64;
    const int b   = blockIdx.y >> 4;
    const int h   = blockIdx.y & 15;
    const float scale = 0.125f;   // 1/sqrt(64)

    // Load Q tile, pre-scaled
    #pragma unroll
    for (int i = 0; i < 4; i++) {
        int f4 = tid + i * 256;            // float4 index, 0..1023
        int q  = f4 >> 4;
        int d4 = (f4 & 15) << 2;
        float4 qv = *(const float4*)(Q + ((size_t)(b * S_ + q0 + q)) * D_ + h * HD_ + d4);
        float* dst = Qs + q * 65 + d4;
        dst[0] = qv.x * scale; dst[1] = qv.y * scale;
        dst[2] = qv.z * scale; dst[3] = qv.w * scale;
    }

    const int ty = tid >> 4, tx = tid & 15;
    float o[4][4];
    #pragma unroll
    for (int r = 0; r < 4; r++)
        #pragma unroll
        for (int c = 0; c < 4; c++) o[r][c] = 0.f;
    float m[4] = {-1e30f, -1e30f, -1e30f, -1e30f};
    float l[4] = {0.f, 0.f, 0.f, 0.f};

    for (int kt = 0; kt < S_; kt += 64) {
        // Load K,V tiles + mask
        #pragma unroll
        for (int i = 0; i < 4; i++) {
            int f4 = tid + i * 256;
            int r  = f4 >> 4;
            int d4 = (f4 & 15) << 2;
            size_t gk = ((size_t)(b * S_ + kt + r)) * D_ + h * HD_ + d4;
            float4 kv = *(const float4*)(Kt + gk);
            float* kd = Ks + r * 65 + d4;
            kd[0] = kv.x; kd[1] = kv.y; kd[2] = kv.z; kd[3] = kv.w;
            float4 vv = *(const float4*)(Vt + gk);
            float* vd = Vs + r * 65 + d4;
            vd[0] = vv.x; vd[1] = vv.y; vd[2] = vv.z; vd[3] = vv.w;
        }
        if (tid < 64) smask[tid] = mask[b * S_ + kt + tid];
        __syncthreads();

        // Scores S = Qs @ Ks^T
        float s[4][4];
        #pragma unroll
        for (int r = 0; r < 4; r++)
            #pragma unroll
            for (int c = 0; c < 4; c++) s[r][c] = 0.f;
        #pragma unroll 8
        for (int d = 0; d < 64; d++) {
            float qv[4], kv[4];
            #pragma unroll
            for (int r = 0; r < 4; r++) qv[r] = Qs[(ty * 4 + r) * 65 + d];
            #pragma unroll
            for (int c = 0; c < 4; c++) kv[c] = Ks[(tx * 4 + c) * 65 + d];
            #pragma unroll
            for (int r = 0; r < 4; r++)
                #pragma unroll
                for (int c = 0; c < 4; c++)
                    s[r][c] = fmaf(qv[r], kv[c], s[r][c]);
        }
        // key mask
        #pragma unroll
        for (int c = 0; c < 4; c++) {
            if (smask[tx * 4 + c] == 0) {
                #pragma unroll
                for (int r = 0; r < 4; r++) s[r][c] = -1e9f;
            }
        }

        // Online softmax (row reduce across tx lanes via shuffle, width 16)
        #pragma unroll
        for (int r = 0; r < 4; r++) {
            float mx = fmaxf(fmaxf(s[r][0], s[r][1]), fmaxf(s[r][2], s[r][3]));
            #pragma unroll
            for (int off = 8; off; off >>= 1)
                mx = fmaxf(mx, __shfl_xor_sync(0xffffffffu, mx, off, 16));
            float mn = fmaxf(m[r], mx);
            float sum = 0.f;
            #pragma unroll
            for (int c = 0; c < 4; c++) {
                float p = __expf(s[r][c] - mn);
                s[r][c] = p;
                sum += p;
            }
            #pragma unroll
            for (int off = 8; off; off >>= 1)
                sum += __shfl_xor_sync(0xffffffffu, sum, off, 16);
            float corr = __expf(m[r] - mn);
            l[r] = l[r] * corr + sum;
            m[r] = mn;
            #pragma unroll
            for (int c = 0; c < 4; c++) o[r][c] *= corr;
        }

        // Publish P
        #pragma unroll
        for (int r = 0; r < 4; r++)
            #pragma unroll
            for (int c = 0; c < 4; c++)
                Ps[(ty * 4 + r) * 65 + tx * 4 + c] = s[r][c];
        __syncthreads();

        // O += P @ V
        #pragma unroll 8
        for (int k = 0; k < 64; k++) {
            float pr[4], vv[4];
            #pragma unroll
            for (int r = 0; r < 4; r++) pr[r] = Ps[(ty * 4 + r) * 65 + k];
            #pragma unroll
            for (int c = 0; c < 4; c++) vv[c] = Vs[k * 65 + tx * 4 + c];
            #pragma unroll
            for (int r = 0; r < 4; r++)
                #pragma unroll
                for (int c = 0; c < 4; c++)
                    o[r][c] = fmaf(pr[r], vv[c], o[r][c]);
        }
        __syncthreads();
    }

    // Write normalized output
    #pragma unroll
    for (int r = 0; r < 4; r++) {
        float inv = 1.0f / l[r];
        int q = q0 + ty * 4 + r;
        #pragma unroll
        for (int c = 0; c < 4; c++)
            O[((size_t)(b * S_ + q)) * D_ + h * HD_ + tx * 4 + c] = o[r][c] * inv;
    }
}

// ---------------------------------------------------------------------------
// Fused residual add + LayerNorm: out = LN(x + y) * g + b   (row = 1024)
// ---------------------------------------------------------------------------
__global__ __launch_bounds__(256)
void add_ln(const float* __restrict__ x, const float* __restrict__ y,
            const float* __restrict__ g, const float* __restrict__ bta,
            float* __restrict__ out) {
    __shared__ float red[256];
    int row = blockIdx.x, tid = threadIdx.x;
    const float* xr = x + (size_t)row * D_;
    const float* yr = y + (size_t)row * D_;

    float v[4];
    float sum = 0.f;
    #pragma unroll
    for (int i = 0; i < 4; i++) {
        int c = tid + i * 256;
        v[i] = xr[c] + yr[c];
        sum += v[i];
    }
    red[tid] = sum; __syncthreads();
    for (int s = 128; s; s >>= 1) { if (tid < s) red[tid] += red[tid + s]; __syncthreads(); }
    float mu = red[0] * (1.0f / 1024.0f);
    __syncthreads();

    float sq = 0.f;
    #pragma unroll
    for (int i = 0; i < 4; i++) { float d = v[i] - mu; sq += d * d; }
    red[tid] = sq; __syncthreads();
    for (int s = 128; s; s >>= 1) { if (tid < s) red[tid] += red[tid + s]; __syncthreads(); }
    float var  = red[0] * (1.0f / 1024.0f);
    float rstd = rsqrtf(var + 1e-5f);

    #pragma unroll
    for (int i = 0; i < 4; i++) {
        int c = tid + i * 256;
        out[(size_t)row * D_ + c] = (v[i] - mu) * rstd * g[c] + bta[c];
    }
}

// ---------------------------------------------------------------------------
// Launch
// ---------------------------------------------------------------------------
extern "C" void kernel_launch(void* const* d_in, const int* in_sizes, int n_in,
                              void* d_out, int out_size) {
    const int*   seq    = (const int*)  d_in[0];
    const int*   mask   = (const int*)  d_in[1];
    const float* emb    = (const float*)d_in[2];
    const float* proj_w = (const float*)d_in[3];
    const float* proj_b = (const float*)d_in[4];
    const float* qw     = (const float*)d_in[5];
    const float* qb     = (const float*)d_in[6];
    const float* kw     = (const float*)d_in[7];
    const float* kb     = (const float*)d_in[8];
    const float* vw     = (const float*)d_in[9];
    const float* vb     = (const float*)d_in[10];
    const float* ow     = (const float*)d_in[11];
    const float* ob     = (const float*)d_in[12];
    const float* lng    = (const float*)d_in[13];
    const float* lnb    = (const float*)d_in[14];
    float* out = (float*)d_out;

    float *xe, *x, *q, *k, *v, *ao, *t;
    cudaGetSymbolAddress((void**)&xe, g_xe);
    cudaGetSymbolAddress((void**)&x,  g_x);
    cudaGetSymbolAddress((void**)&q,  g_q);
    cudaGetSymbolAddress((void**)&k,  g_k);
    cudaGetSymbolAddress((void**)&v,  g_v);
    cudaGetSymbolAddress((void**)&ao, g_ao);
    cudaGetSymbolAddress((void**)&t,  g_t);

    // Opt-in to >48KB dynamic smem for flash_attn (idempotent, capture-safe)
    size_t shb = (size_t)(4 * 64 * 65) * sizeof(float) + 64 * sizeof(int);
    cudaFuncSetAttribute(flash_attn, cudaFuncAttributeMaxDynamicSharedMemorySize, (int)(shb + 256));

    // 1. embed gather + input projection
    gather_emb<<<(ROWS_ * SEQDIM_ + 255) / 256, 256>>>(seq, emb, xe);
    dim3 gp(D_ / 128, ROWS_ / 128);
    gemm_bias<<<gp, 256>>>(xe, proj_w, proj_b, x, ROWS_, D_, SEQDIM_);

    dim3 ga(S_ / 64, B_ * H_);
    for (int l = 0; l < L_; l++) {
        const float* qwl = qw + (size_t)l * D_ * D_;
        const float* kwl = kw + (size_t)l * D_ * D_;
        const float* vwl = vw + (size_t)l * D_ * D_;
        const float* owl = ow + (size_t)l * D_ * D_;

        gemm_bias<<<gp, 256>>>(x,  qwl, qb + l * D_, q, ROWS_, D_, D_);
        gemm_bias<<<gp, 256>>>(x,  kwl, kb + l * D_, k, ROWS_, D_, D_);
        gemm_bias<<<gp, 256>>>(x,  vwl, vb + l * D_, v, ROWS_, D_, D_);
        flash_attn<<<ga, 256, shb>>>(q, k, v, mask, ao);
        gemm_bias<<<gp, 256>>>(ao, owl, ob + l * D_, t, ROWS_, D_, D_);
        add_ln<<<ROWS_, 256>>>(x, t, lng + l * D_, lnb + l * D_,
                               (l == L_ - 1) ? out : x);
    }
}

// round 3
// speedup vs baseline: 1.3658x; 1.3658x over previous
#include <cuda_runtime.h>
#include <cuda_bf16.h>
#include <math.h>
#include <stdint.h>

// Problem constants
#define B_      4
#define S_      2048
#define D_      1024
#define H_      16
#define HD_     64
#define L_      6
#define SEQDIM_ 128
#define ROWS_   (B_ * S_)   // 8192

#define WT_PROJ_ELEMS (D_ * SEQDIM_)
#define WT_MAT_ELEMS  (D_ * D_)
#define WT_ELEMS      (WT_PROJ_ELEMS + 24 * WT_MAT_ELEMS)

// ---------------------------------------------------------------------------
// Device scratch
// ---------------------------------------------------------------------------
__device__ float g_xe[ROWS_ * SEQDIM_];
__device__ float g_x [ROWS_ * D_];
__device__ float g_q [ROWS_ * D_];
__device__ float g_k [ROWS_ * D_];
__device__ float g_v [ROWS_ * D_];
__device__ float g_ao[ROWS_ * D_];
__device__ float g_t [ROWS_ * D_];
__device__ __nv_bfloat16 g_ah[ROWS_ * D_];
__device__ __nv_bfloat16 g_al[ROWS_ * D_];
__device__ __nv_bfloat16 g_wth[WT_ELEMS];
__device__ __nv_bfloat16 g_wtl[WT_ELEMS];

// ---------------------------------------------------------------------------
// Helpers
// ---------------------------------------------------------------------------
__device__ __forceinline__ uint32_t smem_u32(const void* p) {
    uint32_t a;
    asm("{ .reg .u64 t; cvta.to.shared.u64 t, %1; cvt.u32.u64 %0, t; }"
        : "=r"(a) : "l"(p));
    return a;
}

__device__ __forceinline__ void ldm_x4(uint32_t* r, uint32_t addr) {
    asm volatile("ldmatrix.sync.aligned.m8n8.x4.shared.b16 {%0,%1,%2,%3}, [%4];"
                 : "=r"(r[0]), "=r"(r[1]), "=r"(r[2]), "=r"(r[3]) : "r"(addr));
}

__device__ __forceinline__ void mma16816(float* c, const uint32_t* a,
                                         uint32_t b0, uint32_t b1) {
    asm volatile(
        "mma.sync.aligned.m16n8k16.row.col.f32.bf16.bf16.f32 "
        "{%0,%1,%2,%3}, {%4,%5,%6,%7}, {%8,%9}, {%0,%1,%2,%3};"
        : "+f"(c[0]), "+f"(c[1]), "+f"(c[2]), "+f"(c[3])
        : "r"(a[0]), "r"(a[1]), "r"(a[2]), "r"(a[3]), "r"(b0), "r"(b1));
}

#define CP_ASYNC16(dst, src) \
    asm volatile("cp.async.cg.shared.global [%0], [%1], 16;" :: "r"(dst), "l"(src))
#define CP_COMMIT() asm volatile("cp.async.commit_group;" ::: "memory")
#define CP_WAIT(n)  asm volatile("cp.async.wait_group %0;" :: "n"(n) : "memory")

// ---------------------------------------------------------------------------
// Embedding gather
// ---------------------------------------------------------------------------
__global__ void gather_emb(const int* __restrict__ seq,
                           const float* __restrict__ emb,
                           float* __restrict__ xe) {
    int idx = blockIdx.x * blockDim.x + threadIdx.x;
    if (idx >= ROWS_ * SEQDIM_) return;
    int row = idx >> 7;
    int c   = idx & 127;
    xe[idx] = emb[seq[row] * SEQDIM_ + c];
}

// ---------------------------------------------------------------------------
// fp32 -> bf16 hi/lo split
// ---------------------------------------------------------------------------
__global__ void split_bf16(const float* __restrict__ x,
                           __nv_bfloat16* __restrict__ hi,
                           __nv_bfloat16* __restrict__ lo, int n4) {
    int i = blockIdx.x * blockDim.x + threadIdx.x;
    if (i >= n4) return;
    float4 v = ((const float4*)x)[i];
    __nv_bfloat16 h0 = __float2bfloat16(v.x);
    __nv_bfloat16 h1 = __float2bfloat16(v.y);
    __nv_bfloat16 h2 = __float2bfloat16(v.z);
    __nv_bfloat16 h3 = __float2bfloat16(v.w);
    __nv_bfloat162 hp0; hp0.x = h0; hp0.y = h1;
    __nv_bfloat162 hp1; hp1.x = h2; hp1.y = h3;
    ((__nv_bfloat162*)hi)[i * 2 + 0] = hp0;
    ((__nv_bfloat162*)hi)[i * 2 + 1] = hp1;
    __nv_bfloat162 lp0, lp1;
    lp0.x = __float2bfloat16(v.x - __bfloat162float(h0));
    lp0.y = __float2bfloat16(v.y - __bfloat162float(h1));
    lp1.x = __float2bfloat16(v.z - __bfloat162float(h2));
    lp1.y = __float2bfloat16(v.w - __bfloat162float(h3));
    ((__nv_bfloat162*)lo)[i * 2 + 0] = lp0;
    ((__nv_bfloat162*)lo)[i * 2 + 1] = lp1;
}

// ---------------------------------------------------------------------------
// Weight transpose + split: W[K,N] fp32 -> Wt[N,K] bf16 hi/lo
// ---------------------------------------------------------------------------
__global__ void tsplit_w(const float* __restrict__ W,
                         __nv_bfloat16* __restrict__ th,
                         __nv_bfloat16* __restrict__ tl, int K, int N) {
    __shared__ float t[32][33];
    int bx = blockIdx.x * 32;  // n
    int by = blockIdx.y * 32;  // k
    #pragma unroll
    for (int i = 0; i < 32; i += 8)
        t[threadIdx.y + i][threadIdx.x] =
            W[(size_t)(by + threadIdx.y + i) * N + bx + threadIdx.x];
    __syncthreads();
    #pragma unroll
    for (int i = 0; i < 32; i += 8) {
        float v = t[threadIdx.x][threadIdx.y + i];
        int n = bx + threadIdx.y + i;
        int k = by + threadIdx.x;
        __nv_bfloat16 h = __float2bfloat16(v);
        th[(size_t)n * K + k] = h;
        tl[(size_t)n * K + k] = __float2bfloat16(v - __bfloat162float(h));
    }
}

// ---------------------------------------------------------------------------
// mma.sync GEMM: C[M,N] = (Ah+Al)[M,K] @ (Wh+Wl)[N,K]^T + bias  (3-pass split)
// 128x128 tile, BK=32, 8 warps (64x32 each), 3-stage cp.async pipeline.
// SMEM tiles: 128 rows x 80B (32 bf16 data + 16B pad) -> conflict-free ldmatrix.
// ---------------------------------------------------------------------------
#define TILEB  10240            // 128 * 80
#define CHUNKB (4 * TILEB)      // Ah, Al, Wh, Wl
#define GEMM_SMEM (3 * CHUNKB)  // 122880

__global__ __launch_bounds__(256, 1)
void gemm_mma(const __nv_bfloat16* __restrict__ Ah,
              const __nv_bfloat16* __restrict__ Al,
              const __nv_bfloat16* __restrict__ Wh,
              const __nv_bfloat16* __restrict__ Wl,
              const float* __restrict__ bias,
              float* __restrict__ C, int M, int N, int K) {
    extern __shared__ char smem[];
    const uint32_t sb = smem_u32(smem);
    const int tid  = threadIdx.x;
    const int wid  = tid >> 5;
    const int lane = tid & 31;
    const int brow = blockIdx.y * 128;
    const int bcol = blockIdx.x * 128;
    const int wm = wid & 1;       // 0..1  (64-row group)
    const int wn = wid >> 1;      // 0..3  (32-col group)

    const __nv_bfloat16* s0 = Ah + (size_t)brow * K;
    const __nv_bfloat16* s1 = Al + (size_t)brow * K;
    const __nv_bfloat16* s2 = Wh + (size_t)bcol * K;
    const __nv_bfloat16* s3 = Wl + (size_t)bcol * K;

    const int nk = K >> 5;        // chunks of 32

    // ---- async loader for one chunk into stage buffer ----
    auto load_chunk = [&](int c, int stage) {
        const int k0 = c << 5;
        uint32_t buf = sb + stage * CHUNKB;
        #pragma unroll
        for (int i = 0; i < 2; i++) {
            int t = tid + i * 256;            // 0..511
            int row = t >> 2;
            int seg = t & 3;
            uint32_t dst = buf + row * 80 + seg * 16;
            size_t so = (size_t)row * K + k0 + seg * 8;
            CP_ASYNC16(dst,              (const char*)(s0 + so));
            CP_ASYNC16(dst + TILEB,      (const char*)(s1 + so));
            CP_ASYNC16(dst + 2 * TILEB,  (const char*)(s2 + so));
            CP_ASYNC16(dst + 3 * TILEB,  (const char*)(s3 + so));
        }
        CP_COMMIT();
    };

    float acc[4][4][4];
    #pragma unroll
    for (int mi = 0; mi < 4; mi++)
        #pragma unroll
        for (int nb = 0; nb < 4; nb++)
            #pragma unroll
            for (int j = 0; j < 4; j++) acc[mi][nb][j] = 0.f;

    // Precomputed intra-tile ldmatrix address offsets
    const int l16 = lane & 15;
    const uint32_t a_off = (uint32_t)((wm * 64 + l16) * 80 + (lane >> 4) * 16);
    const uint32_t b_off = (uint32_t)((wn * 32 + ((lane >> 4) & 1) * 8 + (lane & 7)) * 80
                                      + ((lane >> 3) & 1) * 16);

    // Prefetch stages 0,1
    load_chunk(0, 0);
    if (nk > 1) load_chunk(1, 1);

    for (int c = 0; c < nk; c++) {
        if (c + 2 < nk) {
            load_chunk(c + 2, (c + 2) % 3);
            CP_WAIT(2);
        } else if (c + 1 < nk) {
            CP_WAIT(1);
        } else {
            CP_WAIT(0);
        }
        __syncthreads();

        uint32_t buf = sb + (c % 3) * CHUNKB;
        #pragma unroll
        for (int s = 0; s < 2; s++) {
            uint32_t ah[4][4], al[4][4], wh[2][4], wl[2][4];
            #pragma unroll
            for (int g = 0; g < 4; g++) {
                uint32_t ao = buf + a_off + (uint32_t)(g * 16 * 80 + s * 32);
                ldm_x4(ah[g], ao);
                ldm_x4(al[g], ao + TILEB);
            }
            #pragma unroll
            for (int h = 0; h < 2; h++) {
                uint32_t bo = buf + 2 * TILEB + b_off + (uint32_t)(h * 16 * 80 + s * 32);
                ldm_x4(wh[h], bo);
                ldm_x4(wl[h], bo + TILEB);
            }
            #pragma unroll
            for (int mi = 0; mi < 4; mi++) {
                #pragma unroll
                for (int nb = 0; nb < 4; nb++) {
                    const int h = nb >> 1, j = nb & 1;
                    mma16816(acc[mi][nb], ah[mi], wh[h][2 * j], wh[h][2 * j + 1]);
                    mma16816(acc[mi][nb], ah[mi], wl[h][2 * j], wl[h][2 * j + 1]);
                    mma16816(acc[mi][nb], al[mi], wh[h][2 * j], wh[h][2 * j + 1]);
                }
            }
        }
        __syncthreads();
    }

    // Epilogue: write C + bias
    #pragma unroll
    for (int mi = 0; mi < 4; mi++) {
        int row = brow + wm * 64 + mi * 16 + (lane >> 2);
        #pragma unroll
        for (int nb = 0; nb < 4; nb++) {
            int col = bcol + wn * 32 + nb * 8 + (lane & 3) * 2;
            float b0 = bias[col], b1 = bias[col + 1];
            float2 v0 = make_float2(acc[mi][nb][0] + b0, acc[mi][nb][1] + b1);
            float2 v1 = make_float2(acc[mi][nb][2] + b0, acc[mi][nb][3] + b1);
            *(float2*)(C + (size_t)row * N + col)       = v0;
            *(float2*)(C + (size_t)(row + 8) * N + col) = v1;
        }
    }
}

// ---------------------------------------------------------------------------
// Fused flash attention (fp32 SIMT)
// ---------------------------------------------------------------------------
__global__ __launch_bounds__(256)
void flash_attn(const float* __restrict__ Q, const float* __restrict__ Kt,
                const float* __restrict__ Vt, const int* __restrict__ mask,
                float* __restrict__ O) {
    extern __shared__ float sm[];
    float* Qs = sm;
    float* Ks = sm + 4160;
    float* Vs = sm + 8320;
    float* Ps = sm + 12480;
    int*   smask = (int*)(sm + 16640);

    const int tid = threadIdx.x;
    const int q0  = blockIdx.x * 64;
    const int b   = blockIdx.y >> 4;
    const int h   = blockIdx.y & 15;
    const float scale = 0.125f;

    #pragma unroll
    for (int i = 0; i < 4; i++) {
        int f4 = tid + i * 256;
        int q  = f4 >> 4;
        int d4 = (f4 & 15) << 2;
        float4 qv = *(const float4*)(Q + ((size_t)(b * S_ + q0 + q)) * D_ + h * HD_ + d4);
        float* dst = Qs + q * 65 + d4;
        dst[0] = qv.x * scale; dst[1] = qv.y * scale;
        dst[2] = qv.z * scale; dst[3] = qv.w * scale;
    }

    const int ty = tid >> 4, tx = tid & 15;
    float o[4][4];
    #pragma unroll
    for (int r = 0; r < 4; r++)
        #pragma unroll
        for (int c = 0; c < 4; c++) o[r][c] = 0.f;
    float m[4] = {-1e30f, -1e30f, -1e30f, -1e30f};
    float l[4] = {0.f, 0.f, 0.f, 0.f};

    for (int kt = 0; kt < S_; kt += 64) {
        #pragma unroll
        for (int i = 0; i < 4; i++) {
            int f4 = tid + i * 256;
            int r  = f4 >> 4;
            int d4 = (f4 & 15) << 2;
            size_t gk = ((size_t)(b * S_ + kt + r)) * D_ + h * HD_ + d4;
            float4 kv = *(const float4*)(Kt + gk);
            float* kd = Ks + r * 65 + d4;
            kd[0] = kv.x; kd[1] = kv.y; kd[2] = kv.z; kd[3] = kv.w;
            float4 vv = *(const float4*)(Vt + gk);
            float* vd = Vs + r * 65 + d4;
            vd[0] = vv.x; vd[1] = vv.y; vd[2] = vv.z; vd[3] = vv.w;
        }
        if (tid < 64) smask[tid] = mask[b * S_ + kt + tid];
        __syncthreads();

        float s[4][4];
        #pragma unroll
        for (int r = 0; r < 4; r++)
            #pragma unroll
            for (int c = 0; c < 4; c++) s[r][c] = 0.f;
        #pragma unroll 8
        for (int d = 0; d < 64; d++) {
            float qv[4], kv[4];
            #pragma unroll
            for (int r = 0; r < 4; r++) qv[r] = Qs[(ty * 4 + r) * 65 + d];
            #pragma unroll
            for (int c = 0; c < 4; c++) kv[c] = Ks[(tx * 4 + c) * 65 + d];
            #pragma unroll
            for (int r = 0; r < 4; r++)
                #pragma unroll
                for (int c = 0; c < 4; c++)
                    s[r][c] = fmaf(qv[r], kv[c], s[r][c]);
        }
        #pragma unroll
        for (int c = 0; c < 4; c++) {
            if (smask[tx * 4 + c] == 0) {
                #pragma unroll
                for (int r = 0; r < 4; r++) s[r][c] = -1e9f;
            }
        }

        #pragma unroll
        for (int r = 0; r < 4; r++) {
            float mx = fmaxf(fmaxf(s[r][0], s[r][1]), fmaxf(s[r][2], s[r][3]));
            #pragma unroll
            for (int off = 8; off; off >>= 1)
                mx = fmaxf(mx, __shfl_xor_sync(0xffffffffu, mx, off, 16));
            float mn = fmaxf(m[r], mx);
            float sum = 0.f;
            #pragma unroll
            for (int c = 0; c < 4; c++) {
                float p = __expf(s[r][c] - mn);
                s[r][c] = p;
                sum += p;
            }
            #pragma unroll
            for (int off = 8; off; off >>= 1)
                sum += __shfl_xor_sync(0xffffffffu, sum, off, 16);
            float corr = __expf(m[r] - mn);
            l[r] = l[r] * corr + sum;
            m[r] = mn;
            #pragma unroll
            for (int c = 0; c < 4; c++) o[r][c] *= corr;
        }

        #pragma unroll
        for (int r = 0; r < 4; r++)
            #pragma unroll
            for (int c = 0; c < 4; c++)
                Ps[(ty * 4 + r) * 65 + tx * 4 + c] = s[r][c];
        __syncthreads();

        #pragma unroll 8
        for (int k = 0; k < 64; k++) {
            float pr[4], vv[4];
            #pragma unroll
            for (int r = 0; r < 4; r++) pr[r] = Ps[(ty * 4 + r) * 65 + k];
            #pragma unroll
            for (int c = 0; c < 4; c++) vv[c] = Vs[k * 65 + tx * 4 + c];
            #pragma unroll
            for (int r = 0; r < 4; r++)
                #pragma unroll
                for (int c = 0; c < 4; c++)
                    o[r][c] = fmaf(pr[r], vv[c], o[r][c]);
        }
        __syncthreads();
    }

    #pragma unroll
    for (int r = 0; r < 4; r++) {
        float inv = 1.0f / l[r];
        int q = q0 + ty * 4 + r;
        #pragma unroll
        for (int c = 0; c < 4; c++)
            O[((size_t)(b * S_ + q)) * D_ + h * HD_ + tx * 4 + c] = o[r][c] * inv;
    }
}

// ---------------------------------------------------------------------------
// Fused residual add + LayerNorm
// ---------------------------------------------------------------------------
__global__ __launch_bounds__(256)
void add_ln(const float* __restrict__ x, const float* __restrict__ y,
            const float* __restrict__ g, const float* __restrict__ bta,
            float* __restrict__ out) {
    __shared__ float red[256];
    int row = blockIdx.x, tid = threadIdx.x;
    const float* xr = x + (size_t)row * D_;
    const float* yr = y + (size_t)row * D_;

    float v[4];
    float sum = 0.f;
    #pragma unroll
    for (int i = 0; i < 4; i++) {
        int c = tid + i * 256;
        v[i] = xr[c] + yr[c];
        sum += v[i];
    }
    red[tid] = sum; __syncthreads();
    for (int s = 128; s; s >>= 1) { if (tid < s) red[tid] += red[tid + s]; __syncthreads(); }
    float mu = red[0] * (1.0f / 1024.0f);
    __syncthreads();

    float sq = 0.f;
    #pragma unroll
    for (int i = 0; i < 4; i++) { float d = v[i] - mu; sq += d * d; }
    red[tid] = sq; __syncthreads();
    for (int s = 128; s; s >>= 1) { if (tid < s) red[tid] += red[tid + s]; __syncthreads(); }
    float var  = red[0] * (1.0f / 1024.0f);
    float rstd = rsqrtf(var + 1e-5f);

    #pragma unroll
    for (int i = 0; i < 4; i++) {
        int c = tid + i * 256;
        out[(size_t)row * D_ + c] = (v[i] - mu) * rstd * g[c] + bta[c];
    }
}

// ---------------------------------------------------------------------------
// Launch
// ---------------------------------------------------------------------------
extern "C" void kernel_launch(void* const* d_in, const int* in_sizes, int n_in,
                              void* d_out, int out_size) {
    const int*   seq    = (const int*)  d_in[0];
    const int*   mask   = (const int*)  d_in[1];
    const float* emb    = (const float*)d_in[2];
    const float* proj_w = (const float*)d_in[3];
    const float* proj_b = (const float*)d_in[4];
    const float* qw     = (const float*)d_in[5];
    const float* qb     = (const float*)d_in[6];
    const float* kw     = (const float*)d_in[7];
    const float* kb     = (const float*)d_in[8];
    const float* vw     = (const float*)d_in[9];
    const float* vb     = (const float*)d_in[10];
    const float* ow     = (const float*)d_in[11];
    const float* ob     = (const float*)d_in[12];
    const float* lng    = (const float*)d_in[13];
    const float* lnb    = (const float*)d_in[14];
    float* out = (float*)d_out;

    float *xe, *x, *q, *k, *v, *ao, *t;
    __nv_bfloat16 *ah, *al, *wth, *wtl;
    cudaGetSymbolAddress((void**)&xe,  g_xe);
    cudaGetSymbolAddress((void**)&x,   g_x);
    cudaGetSymbolAddress((void**)&q,   g_q);
    cudaGetSymbolAddress((void**)&k,   g_k);
    cudaGetSymbolAddress((void**)&v,   g_v);
    cudaGetSymbolAddress((void**)&ao,  g_ao);
    cudaGetSymbolAddress((void**)&t,   g_t);
    cudaGetSymbolAddress((void**)&ah,  g_ah);
    cudaGetSymbolAddress((void**)&al,  g_al);
    cudaGetSymbolAddress((void**)&wth, g_wth);
    cudaGetSymbolAddress((void**)&wtl, g_wtl);

    size_t shb = (size_t)(4 * 64 * 65) * sizeof(float) + 64 * sizeof(int);
    cudaFuncSetAttribute(flash_attn, cudaFuncAttributeMaxDynamicSharedMemorySize, (int)(shb + 256));
    cudaFuncSetAttribute(gemm_mma, cudaFuncAttributeMaxDynamicSharedMemorySize, GEMM_SMEM);

    // ---- weight transpose+split ----
    {
        dim3 tb(32, 8);
        tsplit_w<<<dim3(D_ / 32, SEQDIM_ / 32), tb>>>(proj_w, wth, wtl, SEQDIM_, D_);
        dim3 tg(D_ / 32, D_ / 32);
        for (int l = 0; l < L_; l++) {
            size_t off = WT_PROJ_ELEMS + (size_t)(l * 4) * WT_MAT_ELEMS;
            tsplit_w<<<tg, tb>>>(qw + (size_t)l * D_ * D_, wth + off,                    wtl + off,                    D_, D_);
            tsplit_w<<<tg, tb>>>(kw + (size_t)l * D_ * D_, wth + off + WT_MAT_ELEMS,     wtl + off + WT_MAT_ELEMS,     D_, D_);
            tsplit_w<<<tg, tb>>>(vw + (size_t)l * D_ * D_, wth + off + 2 * WT_MAT_ELEMS, wtl + off + 2 * WT_MAT_ELEMS, D_, D_);
            tsplit_w<<<tg, tb>>>(ow + (size_t)l * D_ * D_, wth + off + 3 * WT_MAT_ELEMS, wtl + off + 3 * WT_MAT_ELEMS, D_, D_);
        }
    }

    // ---- embedding + input projection ----
    gather_emb<<<(ROWS_ * SEQDIM_ + 255) / 256, 256>>>(seq, emb, xe);
    split_bf16<<<(ROWS_ * SEQDIM_ / 4 + 255) / 256, 256>>>(xe, ah, al, ROWS_ * SEQDIM_ / 4);
    dim3 gp(D_ / 128, ROWS_ / 128);
    gemm_mma<<<gp, 256, GEMM_SMEM>>>(ah, al, wth, wtl, proj_b, x, ROWS_, D_, SEQDIM_);

    dim3 ga(S_ / 64, B_ * H_);
    const int n4 = ROWS_ * D_ / 4;
    for (int l = 0; l < L_; l++) {
        size_t off = WT_PROJ_ELEMS + (size_t)(l * 4) * WT_MAT_ELEMS;
        const __nv_bfloat16* qwh = wth + off;
        const __nv_bfloat16* qwl = wtl + off;
        const __nv_bfloat16* kwh = wth + off + WT_MAT_ELEMS;
        const __nv_bfloat16* kwl = wtl + off + WT_MAT_ELEMS;
        const __nv_bfloat16* vwh = wth + off + 2 * WT_MAT_ELEMS;
        const __nv_bfloat16* vwl = wtl + off + 2 * WT_MAT_ELEMS;
        const __nv_bfloat16* owh = wth + off + 3 * WT_MAT_ELEMS;
        const __nv_bfloat16* owl = wtl + off + 3 * WT_MAT_ELEMS;

        split_bf16<<<(n4 + 255) / 256, 256>>>(x, ah, al, n4);
        gemm_mma<<<gp, 256, GEMM_SMEM>>>(ah, al, qwh, qwl, qb + l * D_, q, ROWS_, D_, D_);
        gemm_mma<<<gp, 256, GEMM_SMEM>>>(ah, al, kwh, kwl, kb + l * D_, k, ROWS_, D_, D_);
        gemm_mma<<<gp, 256, GEMM_SMEM>>>(ah, al, vwh, vwl, vb + l * D_, v, ROWS_, D_, D_);
        flash_attn<<<ga, 256, shb>>>(q, k, v, mask, ao);
        split_bf16<<<(n4 + 255) / 256, 256>>>(ao, ah, al, n4);
        gemm_mma<<<gp, 256, GEMM_SMEM>>>(ah, al, owh, owl, ob + l * D_, t, ROWS_, D_, D_);
        add_ln<<<ROWS_, 256>>>(x, t, lng + l * D_, lnb + l * D_,
                               (l == L_ - 1) ? out : x);
    }
}

// round 4
// speedup vs baseline: 2.7957x; 2.0470x over previous
#include <cuda_runtime.h>
#include <cuda_bf16.h>
#include <math.h>
#include <stdint.h>

// Problem constants
#define B_      4
#define S_      2048
#define D_      1024
#define H_      16
#define HD_     64
#define L_      6
#define SEQDIM_ 128
#define ROWS_   (B_ * S_)   // 8192

#define WT_PROJ_ELEMS (D_ * SEQDIM_)
#define WT_MAT_ELEMS  (D_ * D_)
#define WT_ELEMS      (WT_PROJ_ELEMS + 24 * WT_MAT_ELEMS)

// ---------------------------------------------------------------------------
// Device scratch
// ---------------------------------------------------------------------------
__device__ float g_xe[ROWS_ * SEQDIM_];
__device__ float g_x [ROWS_ * D_];
__device__ float g_q [ROWS_ * D_];
__device__ float g_k [ROWS_ * D_];
__device__ float g_v [ROWS_ * D_];
__device__ float g_ao[ROWS_ * D_];
__device__ float g_t [ROWS_ * D_];
__device__ __nv_bfloat16 g_ah[ROWS_ * D_];
__device__ __nv_bfloat16 g_al[ROWS_ * D_];
__device__ __nv_bfloat16 g_wth[WT_ELEMS];
__device__ __nv_bfloat16 g_wtl[WT_ELEMS];
// attention operands
__device__ __nv_bfloat16 g_qh[ROWS_ * D_];
__device__ __nv_bfloat16 g_ql[ROWS_ * D_];
__device__ __nv_bfloat16 g_kh[ROWS_ * D_];
__device__ __nv_bfloat16 g_kl[ROWS_ * D_];
__device__ __nv_bfloat16 g_vth[ROWS_ * D_];   // [bh][64][S]
__device__ __nv_bfloat16 g_vtl[ROWS_ * D_];

// ---------------------------------------------------------------------------
// Helpers
// ---------------------------------------------------------------------------
__device__ __forceinline__ uint32_t smem_u32(const void* p) {
    uint32_t a;
    asm("{ .reg .u64 t; cvta.to.shared.u64 t, %1; cvt.u32.u64 %0, t; }"
        : "=r"(a) : "l"(p));
    return a;
}

__device__ __forceinline__ void ldm_x4(uint32_t* r, uint32_t addr) {
    asm volatile("ldmatrix.sync.aligned.m8n8.x4.shared.b16 {%0,%1,%2,%3}, [%4];"
                 : "=r"(r[0]), "=r"(r[1]), "=r"(r[2]), "=r"(r[3]) : "r"(addr));
}

__device__ __forceinline__ void mma16816(float* c, const uint32_t* a,
                                         uint32_t b0, uint32_t b1) {
    asm volatile(
        "mma.sync.aligned.m16n8k16.row.col.f32.bf16.bf16.f32 "
        "{%0,%1,%2,%3}, {%4,%5,%6,%7}, {%8,%9}, {%0,%1,%2,%3};"
        : "+f"(c[0]), "+f"(c[1]), "+f"(c[2]), "+f"(c[3])
        : "r"(a[0]), "r"(a[1]), "r"(a[2]), "r"(a[3]), "r"(b0), "r"(b1));
}

__device__ __forceinline__ uint32_t pk_bf16(float lo, float hi) {
    uint32_t r;
    asm("cvt.rn.bf16x2.f32 %0, %1, %2;" : "=r"(r) : "f"(hi), "f"(lo));
    return r;
}

#define CP_ASYNC16(dst, src) \
    asm volatile("cp.async.cg.shared.global [%0], [%1], 16;" :: "r"(dst), "l"(src))
#define CP_COMMIT() asm volatile("cp.async.commit_group;" ::: "memory")
#define CP_WAIT(n)  asm volatile("cp.async.wait_group %0;" :: "n"(n) : "memory")

// ---------------------------------------------------------------------------
// Embedding gather
// ---------------------------------------------------------------------------
__global__ void gather_emb(const int* __restrict__ seq,
                           const float* __restrict__ emb,
                           float* __restrict__ xe) {
    int idx = blockIdx.x * blockDim.x + threadIdx.x;
    if (idx >= ROWS_ * SEQDIM_) return;
    int row = idx >> 7;
    int c   = idx & 127;
    xe[idx] = emb[seq[row] * SEQDIM_ + c];
}

// ---------------------------------------------------------------------------
// fp32 -> bf16 hi/lo split, optional exact power-of-two scale
// ---------------------------------------------------------------------------
__global__ void split_bf16(const float* __restrict__ x,
                           __nv_bfloat16* __restrict__ hi,
                           __nv_bfloat16* __restrict__ lo, int n4, float sc) {
    int i = blockIdx.x * blockDim.x + threadIdx.x;
    if (i >= n4) return;
    float4 v = ((const float4*)x)[i];
    v.x *= sc; v.y *= sc; v.z *= sc; v.w *= sc;
    __nv_bfloat16 h0 = __float2bfloat16(v.x);
    __nv_bfloat16 h1 = __float2bfloat16(v.y);
    __nv_bfloat16 h2 = __float2bfloat16(v.z);
    __nv_bfloat16 h3 = __float2bfloat16(v.w);
    __nv_bfloat162 hp0; hp0.x = h0; hp0.y = h1;
    __nv_bfloat162 hp1; hp1.x = h2; hp1.y = h3;
    ((__nv_bfloat162*)hi)[i * 2 + 0] = hp0;
    ((__nv_bfloat162*)hi)[i * 2 + 1] = hp1;
    __nv_bfloat162 lp0, lp1;
    lp0.x = __float2bfloat16(v.x - __bfloat162float(h0));
    lp0.y = __float2bfloat16(v.y - __bfloat162float(h1));
    lp1.x = __float2bfloat16(v.z - __bfloat162float(h2));
    lp1.y = __float2bfloat16(v.w - __bfloat162float(h3));
    ((__nv_bfloat162*)lo)[i * 2 + 0] = lp0;
    ((__nv_bfloat162*)lo)[i * 2 + 1] = lp1;
}

// ---------------------------------------------------------------------------
// Weight transpose + split: W[K,N] fp32 -> Wt[N,K] bf16 hi/lo
// ---------------------------------------------------------------------------
__global__ void tsplit_w(const float* __restrict__ W,
                         __nv_bfloat16* __restrict__ th,
                         __nv_bfloat16* __restrict__ tl, int K, int N) {
    __shared__ float t[32][33];
    int bx = blockIdx.x * 32;  // n
    int by = blockIdx.y * 32;  // k
    #pragma unroll
    for (int i = 0; i < 32; i += 8)
        t[threadIdx.y + i][threadIdx.x] =
            W[(size_t)(by + threadIdx.y + i) * N + bx + threadIdx.x];
    __syncthreads();
    #pragma unroll
    for (int i = 0; i < 32; i += 8) {
        float v = t[threadIdx.x][threadIdx.y + i];
        int n = bx + threadIdx.y + i;
        int k = by + threadIdx.x;
        __nv_bfloat16 h = __float2bfloat16(v);
        th[(size_t)n * K + k] = h;
        tl[(size_t)n * K + k] = __float2bfloat16(v - __bfloat162float(h));
    }
}

// ---------------------------------------------------------------------------
// V transpose + split per head: v[b*S+s][h*64+d] -> vt[bh][d][s] bf16 hi/lo
// ---------------------------------------------------------------------------
__global__ void vtsplit(const float* __restrict__ v,
                        __nv_bfloat16* __restrict__ th,
                        __nv_bfloat16* __restrict__ tl) {
    __shared__ float t[32][33];
    int s0 = blockIdx.x * 32;
    int bh = blockIdx.y;
    int b  = bh >> 4, h = bh & 15;
    for (int dh = 0; dh < HD_; dh += 32) {
        #pragma unroll
        for (int i = 0; i < 32; i += 8)
            t[threadIdx.y + i][threadIdx.x] =
                v[(size_t)(b * S_ + s0 + threadIdx.y + i) * D_ + h * HD_ + dh + threadIdx.x];
        __syncthreads();
        #pragma unroll
        for (int i = 0; i < 32; i += 8) {
            float val = t[threadIdx.x][threadIdx.y + i];
            int d = dh + threadIdx.y + i;
            int s = s0 + threadIdx.x;
            __nv_bfloat16 hh = __float2bfloat16(val);
            th[((size_t)bh * HD_ + d) * S_ + s] = hh;
            tl[((size_t)bh * HD_ + d) * S_ + s] = __float2bfloat16(val - __bfloat162float(hh));
        }
        __syncthreads();
    }
}

// ---------------------------------------------------------------------------
// mma.sync GEMM (unchanged from R3)
// ---------------------------------------------------------------------------
#define TILEB  10240
#define CHUNKB (4 * TILEB)
#define GEMM_SMEM (3 * CHUNKB)

__global__ __launch_bounds__(256, 1)
void gemm_mma(const __nv_bfloat16* __restrict__ Ah,
              const __nv_bfloat16* __restrict__ Al,
              const __nv_bfloat16* __restrict__ Wh,
              const __nv_bfloat16* __restrict__ Wl,
              const float* __restrict__ bias,
              float* __restrict__ C, int M, int N, int K) {
    extern __shared__ char smem[];
    const uint32_t sb = smem_u32(smem);
    const int tid  = threadIdx.x;
    const int wid  = tid >> 5;
    const int lane = tid & 31;
    const int brow = blockIdx.y * 128;
    const int bcol = blockIdx.x * 128;
    const int wm = wid & 1;
    const int wn = wid >> 1;

    const __nv_bfloat16* s0 = Ah + (size_t)brow * K;
    const __nv_bfloat16* s1 = Al + (size_t)brow * K;
    const __nv_bfloat16* s2 = Wh + (size_t)bcol * K;
    const __nv_bfloat16* s3 = Wl + (size_t)bcol * K;

    const int nk = K >> 5;

    auto load_chunk = [&](int c, int stage) {
        const int k0 = c << 5;
        uint32_t buf = sb + stage * CHUNKB;
        #pragma unroll
        for (int i = 0; i < 2; i++) {
            int t = tid + i * 256;
            int row = t >> 2;
            int seg = t & 3;
            uint32_t dst = buf + row * 80 + seg * 16;
            size_t so = (size_t)row * K + k0 + seg * 8;
            CP_ASYNC16(dst,              (const char*)(s0 + so));
            CP_ASYNC16(dst + TILEB,      (const char*)(s1 + so));
            CP_ASYNC16(dst + 2 * TILEB,  (const char*)(s2 + so));
            CP_ASYNC16(dst + 3 * TILEB,  (const char*)(s3 + so));
        }
        CP_COMMIT();
    };

    float acc[4][4][4];
    #pragma unroll
    for (int mi = 0; mi < 4; mi++)
        #pragma unroll
        for (int nb = 0; nb < 4; nb++)
            #pragma unroll
            for (int j = 0; j < 4; j++) acc[mi][nb][j] = 0.f;

    const int l16 = lane & 15;
    const uint32_t a_off = (uint32_t)((wm * 64 + l16) * 80 + (lane >> 4) * 16);
    const uint32_t b_off = (uint32_t)((wn * 32 + ((lane >> 4) & 1) * 8 + (lane & 7)) * 80
                                      + ((lane >> 3) & 1) * 16);

    load_chunk(0, 0);
    if (nk > 1) load_chunk(1, 1);

    for (int c = 0; c < nk; c++) {
        if (c + 2 < nk) {
            load_chunk(c + 2, (c + 2) % 3);
            CP_WAIT(2);
        } else if (c + 1 < nk) {
            CP_WAIT(1);
        } else {
            CP_WAIT(0);
        }
        __syncthreads();

        uint32_t buf = sb + (c % 3) * CHUNKB;
        #pragma unroll
        for (int s = 0; s < 2; s++) {
            uint32_t ah[4][4], al[4][4], wh[2][4], wl[2][4];
            #pragma unroll
            for (int g = 0; g < 4; g++) {
                uint32_t ao = buf + a_off + (uint32_t)(g * 16 * 80 + s * 32);
                ldm_x4(ah[g], ao);
                ldm_x4(al[g], ao + TILEB);
            }
            #pragma unroll
            for (int h = 0; h < 2; h++) {
                uint32_t bo = buf + 2 * TILEB + b_off + (uint32_t)(h * 16 * 80 + s * 32);
                ldm_x4(wh[h], bo);
                ldm_x4(wl[h], bo + TILEB);
            }
            #pragma unroll
            for (int mi = 0; mi < 4; mi++) {
                #pragma unroll
                for (int nb = 0; nb < 4; nb++) {
                    const int h = nb >> 1, j = nb & 1;
                    mma16816(acc[mi][nb], ah[mi], wh[h][2 * j], wh[h][2 * j + 1]);
                    mma16816(acc[mi][nb], ah[mi], wl[h][2 * j], wl[h][2 * j + 1]);
                    mma16816(acc[mi][nb], al[mi], wh[h][2 * j], wh[h][2 * j + 1]);
                }
            }
        }
        __syncthreads();
    }

    #pragma unroll
    for (int mi = 0; mi < 4; mi++) {
        int row = brow + wm * 64 + mi * 16 + (lane >> 2);
        #pragma unroll
        for (int nb = 0; nb < 4; nb++) {
            int col = bcol + wn * 32 + nb * 8 + (lane & 3) * 2;
            float b0 = bias[col], b1 = bias[col + 1];
            float2 v0 = make_float2(acc[mi][nb][0] + b0, acc[mi][nb][1] + b1);
            float2 v1 = make_float2(acc[mi][nb][2] + b0, acc[mi][nb][3] + b1);
            *(float2*)(C + (size_t)row * N + col)       = v0;
            *(float2*)(C + (size_t)(row + 8) * N + col) = v1;
        }
    }
}

// ---------------------------------------------------------------------------
// Tensor-core flash attention.
// Grid (S/128, B*H). Block 256 (8 warps, 16 queries each).
// K tiles of 64 keys, 3-stage cp.async pipeline.
// Stage layout (stride 144B rows, 64 rows each): Kh | Kl | Vth | Vtl
// ---------------------------------------------------------------------------
#define AST      36864                // bytes per stage
#define AKL      9216                 // one 64x144 tile
#define AMASK    (3 * AST)            // 110592
#define ATT_SMEM (AMASK + 3 * 256)    // 111360

__global__ __launch_bounds__(256, 1)
void attn_mma(const __nv_bfloat16* __restrict__ qh, const __nv_bfloat16* __restrict__ ql,
              const __nv_bfloat16* __restrict__ kh, const __nv_bfloat16* __restrict__ kl,
              const __nv_bfloat16* __restrict__ vth, const __nv_bfloat16* __restrict__ vtl,
              const int* __restrict__ mask, float* __restrict__ O) {
    extern __shared__ char smem[];
    const uint32_t sb = smem_u32(smem);
    const int tid = threadIdx.x, wid = tid >> 5, lane = tid & 31;
    const int q0 = blockIdx.x * 128;
    const int bh = blockIdx.y;
    const int b = bh >> 4, h = bh & 15;
    const size_t rowbase = (size_t)b * S_;

    // ---- Q tile (hi/lo) -> smem -> persistent register fragments ----
    #pragma unroll
    for (int i = 0; i < 4; i++) {
        int t = tid + i * 256;           // 0..1023
        int row = t >> 3, seg = t & 7;
        uint32_t dst = sb + row * 144 + seg * 16;
        size_t so = (rowbase + q0 + row) * D_ + h * HD_ + seg * 8;
        CP_ASYNC16(dst,         (const char*)(qh + so));
        CP_ASYNC16(dst + 18432, (const char*)(ql + so));
    }
    CP_COMMIT(); CP_WAIT(0);
    __syncthreads();

    uint32_t qhf[4][4], qlf[4][4];
    #pragma unroll
    for (int s = 0; s < 4; s++) {
        uint32_t a = sb + (uint32_t)((wid * 16 + (lane & 15)) * 144 + (lane >> 4) * 16 + s * 32);
        ldm_x4(qhf[s], a);
        ldm_x4(qlf[s], a + 18432);
    }
    __syncthreads();

    auto load_kv = [&](int kt, int st) {
        uint32_t buf = sb + st * AST;
        int key0 = kt * 64;
        #pragma unroll
        for (int i = 0; i < 2; i++) {
            int t = tid + i * 256;       // 0..511
            int row = t >> 3, seg = t & 7;
            uint32_t dst = buf + row * 144 + seg * 16;
            size_t sk = (rowbase + key0 + row) * D_ + h * HD_ + seg * 8;
            CP_ASYNC16(dst,           (const char*)(kh + sk));
            CP_ASYNC16(dst + AKL,     (const char*)(kl + sk));
            size_t sv = ((size_t)bh * HD_ + row) * S_ + key0 + seg * 8;
            CP_ASYNC16(dst + 2 * AKL, (const char*)(vth + sv));
            CP_ASYNC16(dst + 3 * AKL, (const char*)(vtl + sv));
        }
        if (tid < 16)
            CP_ASYNC16(sb + AMASK + st * 256 + tid * 16,
                       (const char*)(mask + b * S_ + key0 + tid * 4));
        CP_COMMIT();
    };

    float oacc[8][4];
    #pragma unroll
    for (int nb = 0; nb < 8; nb++)
        #pragma unroll
        for (int j = 0; j < 4; j++) oacc[nb][j] = 0.f;
    float mrow0 = -1e30f, mrow1 = -1e30f, lrow0 = 0.f, lrow1 = 0.f;

    const uint32_t bfrag_off = (uint32_t)((((lane >> 4) & 1) * 8 + (lane & 7)) * 144
                                          + ((lane >> 3) & 1) * 16);

    load_kv(0, 0);
    load_kv(1, 1);

    const int NKT = S_ / 64;  // 32
    for (int kt = 0; kt < NKT; kt++) {
        if (kt + 2 < NKT)      { load_kv(kt + 2, (kt + 2) % 3); CP_WAIT(2); }
        else if (kt + 1 < NKT) { CP_WAIT(1); }
        else                   { CP_WAIT(0); }
        __syncthreads();

        uint32_t buf = sb + (kt % 3) * AST;

        // ---- S = Q @ K^T (3-pass split) ----
        float sacc[8][4];
        #pragma unroll
        for (int nb = 0; nb < 8; nb++)
            #pragma unroll
            for (int j = 0; j < 4; j++) sacc[nb][j] = 0.f;

        #pragma unroll
        for (int s = 0; s < 4; s++) {
            uint32_t khf[4][4], klf[4][4];
            #pragma unroll
            for (int g = 0; g < 4; g++) {
                uint32_t a = buf + bfrag_off + (uint32_t)(g * 16 * 144 + s * 32);
                ldm_x4(khf[g], a);
                ldm_x4(klf[g], a + AKL);
            }
            #pragma unroll
            for (int g = 0; g < 4; g++) {
                #pragma unroll
                for (int j = 0; j < 2; j++) {
                    int nb = g * 2 + j;
                    mma16816(sacc[nb], qhf[s], khf[g][2 * j], khf[g][2 * j + 1]);
                    mma16816(sacc[nb], qhf[s], klf[g][2 * j], klf[g][2 * j + 1]);
                    mma16816(sacc[nb], qlf[s], khf[g][2 * j], khf[g][2 * j + 1]);
                }
            }
        }

        // ---- mask ----
        {
            const int* smk = (const int*)(smem + AMASK + (kt % 3) * 256);
            int cb = 2 * (lane & 3);
            #pragma unroll
            for (int nb = 0; nb < 8; nb++) {
                if (smk[nb * 8 + cb] == 0)     { sacc[nb][0] = -1e9f; sacc[nb][2] = -1e9f; }
                if (smk[nb * 8 + cb + 1] == 0) { sacc[nb][1] = -1e9f; sacc[nb][3] = -1e9f; }
            }
        }

        // ---- online softmax ----
        float mx0 = -1e30f, mx1 = -1e30f;
        #pragma unroll
        for (int nb = 0; nb < 8; nb++) {
            mx0 = fmaxf(mx0, fmaxf(sacc[nb][0], sacc[nb][1]));
            mx1 = fmaxf(mx1, fmaxf(sacc[nb][2], sacc[nb][3]));
        }
        mx0 = fmaxf(mx0, __shfl_xor_sync(0xffffffffu, mx0, 1));
        mx0 = fmaxf(mx0, __shfl_xor_sync(0xffffffffu, mx0, 2));
        mx1 = fmaxf(mx1, __shfl_xor_sync(0xffffffffu, mx1, 1));
        mx1 = fmaxf(mx1, __shfl_xor_sync(0xffffffffu, mx1, 2));
        float mn0 = fmaxf(mrow0, mx0), mn1 = fmaxf(mrow1, mx1);
        float corr0 = __expf(mrow0 - mn0), corr1 = __expf(mrow1 - mn1);
        float sum0 = 0.f, sum1 = 0.f;
        #pragma unroll
        for (int nb = 0; nb < 8; nb++) {
            sacc[nb][0] = __expf(sacc[nb][0] - mn0);
            sacc[nb][1] = __expf(sacc[nb][1] - mn0);
            sacc[nb][2] = __expf(sacc[nb][2] - mn1);
            sacc[nb][3] = __expf(sacc[nb][3] - mn1);
            sum0 += sacc[nb][0] + sacc[nb][1];
            sum1 += sacc[nb][2] + sacc[nb][3];
        }
        sum0 += __shfl_xor_sync(0xffffffffu, sum0, 1);
        sum0 += __shfl_xor_sync(0xffffffffu, sum0, 2);
        sum1 += __shfl_xor_sync(0xffffffffu, sum1, 1);
        sum1 += __shfl_xor_sync(0xffffffffu, sum1, 2);
        lrow0 = lrow0 * corr0 + sum0;
        lrow1 = lrow1 * corr1 + sum1;
        mrow0 = mn0; mrow1 = mn1;
        #pragma unroll
        for (int nb = 0; nb < 8; nb++) {
            oacc[nb][0] *= corr0; oacc[nb][1] *= corr0;
            oacc[nb][2] *= corr1; oacc[nb][3] *= corr1;
        }

        // ---- O += P @ V (3-pass: PhVh + PhVl + PlVh) ----
        #pragma unroll
        for (int c = 0; c < 4; c++) {
            uint32_t pha[4], pla[4];
            #pragma unroll
            for (int half = 0; half < 2; half++) {
                int nb = 2 * c + half;
                __nv_bfloat16 b0 = __float2bfloat16(sacc[nb][0]);
                __nv_bfloat16 b1 = __float2bfloat16(sacc[nb][1]);
                __nv_bfloat16 b2 = __float2bfloat16(sacc[nb][2]);
                __nv_bfloat16 b3 = __float2bfloat16(sacc[nb][3]);
                __nv_bfloat162 t01; t01.x = b0; t01.y = b1;
                __nv_bfloat162 t23; t23.x = b2; t23.y = b3;
                pha[half * 2 + 0] = *(uint32_t*)&t01;
                pha[half * 2 + 1] = *(uint32_t*)&t23;
                pla[half * 2 + 0] = pk_bf16(sacc[nb][0] - __bfloat162float(b0),
                                            sacc[nb][1] - __bfloat162float(b1));
                pla[half * 2 + 1] = pk_bf16(sacc[nb][2] - __bfloat162float(b2),
                                            sacc[nb][3] - __bfloat162float(b3));
            }
            uint32_t vhf[4][4], vlf[4][4];
            #pragma unroll
            for (int g = 0; g < 4; g++) {
                uint32_t a = buf + 2 * AKL + bfrag_off + (uint32_t)(g * 16 * 144 + c * 32);
                ldm_x4(vhf[g], a);
                ldm_x4(vlf[g], a + AKL);
            }
            #pragma unroll
            for (int g = 0; g < 4; g++) {
                #pragma unroll
                for (int j = 0; j < 2; j++) {
                    int nb = g * 2 + j;
                    mma16816(oacc[nb], pha, vhf[g][2 * j], vhf[g][2 * j + 1]);
                    mma16816(oacc[nb], pha, vlf[g][2 * j], vlf[g][2 * j + 1]);
                    mma16816(oacc[nb], pla, vhf[g][2 * j], vhf[g][2 * j + 1]);
                }
            }
        }
        __syncthreads();
    }

    // ---- epilogue ----
    float inv0 = 1.0f / lrow0, inv1 = 1.0f / lrow1;
    int r0 = q0 + wid * 16 + (lane >> 2);
    #pragma unroll
    for (int nb = 0; nb < 8; nb++) {
        int col = h * HD_ + nb * 8 + 2 * (lane & 3);
        float2 v0 = make_float2(oacc[nb][0] * inv0, oacc[nb][1] * inv0);
        float2 v1 = make_float2(oacc[nb][2] * inv1, oacc[nb][3] * inv1);
        *(float2*)(O + (rowbase + r0) * D_ + col)     = v0;
        *(float2*)(O + (rowbase + r0 + 8) * D_ + col) = v1;
    }
}

// ---------------------------------------------------------------------------
// Fused residual add + LayerNorm
// ---------------------------------------------------------------------------
__global__ __launch_bounds__(256)
void add_ln(const float* __restrict__ x, const float* __restrict__ y,
            const float* __restrict__ g, const float* __restrict__ bta,
            float* __restrict__ out) {
    __shared__ float red[256];
    int row = blockIdx.x, tid = threadIdx.x;
    const float* xr = x + (size_t)row * D_;
    const float* yr = y + (size_t)row * D_;

    float v[4];
    float sum = 0.f;
    #pragma unroll
    for (int i = 0; i < 4; i++) {
        int c = tid + i * 256;
        v[i] = xr[c] + yr[c];
        sum += v[i];
    }
    red[tid] = sum; __syncthreads();
    for (int s = 128; s; s >>= 1) { if (tid < s) red[tid] += red[tid + s]; __syncthreads(); }
    float mu = red[0] * (1.0f / 1024.0f);
    __syncthreads();

    float sq = 0.f;
    #pragma unroll
    for (int i = 0; i < 4; i++) { float d = v[i] - mu; sq += d * d; }
    red[tid] = sq; __syncthreads();
    for (int s = 128; s; s >>= 1) { if (tid < s) red[tid] += red[tid + s]; __syncthreads(); }
    float var  = red[0] * (1.0f / 1024.0f);
    float rstd = rsqrtf(var + 1e-5f);

    #pragma unroll
    for (int i = 0; i < 4; i++) {
        int c = tid + i * 256;
        out[(size_t)row * D_ + c] = (v[i] - mu) * rstd * g[c] + bta[c];
    }
}

// ---------------------------------------------------------------------------
// Launch
// ---------------------------------------------------------------------------
extern "C" void kernel_launch(void* const* d_in, const int* in_sizes, int n_in,
                              void* d_out, int out_size) {
    const int*   seq    = (const int*)  d_in[0];
    const int*   mask   = (const int*)  d_in[1];
    const float* emb    = (const float*)d_in[2];
    const float* proj_w = (const float*)d_in[3];
    const float* proj_b = (const float*)d_in[4];
    const float* qw     = (const float*)d_in[5];
    const float* qb     = (const float*)d_in[6];
    const float* kw     = (const float*)d_in[7];
    const float* kb     = (const float*)d_in[8];
    const float* vw     = (const float*)d_in[9];
    const float* vb     = (const float*)d_in[10];
    const float* ow     = (const float*)d_in[11];
    const float* ob     = (const float*)d_in[12];
    const float* lng    = (const float*)d_in[13];
    const float* lnb    = (const float*)d_in[14];
    float* out = (float*)d_out;

    float *xe, *x, *q, *k, *v, *ao, *t;
    __nv_bfloat16 *ah, *al, *wth, *wtl, *qhp, *qlp, *khp, *klp, *vthp, *vtlp;
    cudaGetSymbolAddress((void**)&xe,   g_xe);
    cudaGetSymbolAddress((void**)&x,    g_x);
    cudaGetSymbolAddress((void**)&q,    g_q);
    cudaGetSymbolAddress((void**)&k,    g_k);
    cudaGetSymbolAddress((void**)&v,    g_v);
    cudaGetSymbolAddress((void**)&ao,   g_ao);
    cudaGetSymbolAddress((void**)&t,    g_t);
    cudaGetSymbolAddress((void**)&ah,   g_ah);
    cudaGetSymbolAddress((void**)&al,   g_al);
    cudaGetSymbolAddress((void**)&wth,  g_wth);
    cudaGetSymbolAddress((void**)&wtl,  g_wtl);
    cudaGetSymbolAddress((void**)&qhp,  g_qh);
    cudaGetSymbolAddress((void**)&qlp,  g_ql);
    cudaGetSymbolAddress((void**)&khp,  g_kh);
    cudaGetSymbolAddress((void**)&klp,  g_kl);
    cudaGetSymbolAddress((void**)&vthp, g_vth);
    cudaGetSymbolAddress((void**)&vtlp, g_vtl);

    cudaFuncSetAttribute(gemm_mma, cudaFuncAttributeMaxDynamicSharedMemorySize, GEMM_SMEM);
    cudaFuncSetAttribute(attn_mma, cudaFuncAttributeMaxDynamicSharedMemorySize, ATT_SMEM);

    // ---- weight transpose+split ----
    {
        dim3 tb(32, 8);
        tsplit_w<<<dim3(D_ / 32, SEQDIM_ / 32), tb>>>(proj_w, wth, wtl, SEQDIM_, D_);
        dim3 tg(D_ / 32, D_ / 32);
        for (int l = 0; l < L_; l++) {
            size_t off = WT_PROJ_ELEMS + (size_t)(l * 4) * WT_MAT_ELEMS;
            tsplit_w<<<tg, tb>>>(qw + (size_t)l * D_ * D_, wth + off,                    wtl + off,                    D_, D_);
            tsplit_w<<<tg, tb>>>(kw + (size_t)l * D_ * D_, wth + off + WT_MAT_ELEMS,     wtl + off + WT_MAT_ELEMS,     D_, D_);
            tsplit_w<<<tg, tb>>>(vw + (size_t)l * D_ * D_, wth + off + 2 * WT_MAT_ELEMS, wtl + off + 2 * WT_MAT_ELEMS, D_, D_);
            tsplit_w<<<tg, tb>>>(ow + (size_t)l * D_ * D_, wth + off + 3 * WT_MAT_ELEMS, wtl + off + 3 * WT_MAT_ELEMS, D_, D_);
        }
    }

    // ---- embedding + input projection ----
    gather_emb<<<(ROWS_ * SEQDIM_ + 255) / 256, 256>>>(seq, emb, xe);
    split_bf16<<<(ROWS_ * SEQDIM_ / 4 + 255) / 256, 256>>>(xe, ah, al, ROWS_ * SEQDIM_ / 4, 1.0f);
    dim3 gp(D_ / 128, ROWS_ / 128);
    gemm_mma<<<gp, 256, GEMM_SMEM>>>(ah, al, wth, wtl, proj_b, x, ROWS_, D_, SEQDIM_);

    dim3 ga(ROWS_ / 128 / B_, B_ * H_);          // (16, 64)
    dim3 vg(S_ / 32, B_ * H_);
    dim3 vb8(32, 8);
    const int n4 = ROWS_ * D_ / 4;
    for (int l = 0; l < L_; l++) {
        size_t off = WT_PROJ_ELEMS + (size_t)(l * 4) * WT_MAT_ELEMS;
        const __nv_bfloat16* qwh = wth + off;
        const __nv_bfloat16* qwl = wtl + off;
        const __nv_bfloat16* kwh = wth + off + WT_MAT_ELEMS;
        const __nv_bfloat16* kwl = wtl + off + WT_MAT_ELEMS;
        const __nv_bfloat16* vwh = wth + off + 2 * WT_MAT_ELEMS;
        const __nv_bfloat16* vwl = wtl + off + 2 * WT_MAT_ELEMS;
        const __nv_bfloat16* owh = wth + off + 3 * WT_MAT_ELEMS;
        const __nv_bfloat16* owl = wtl + off + 3 * WT_MAT_ELEMS;

        split_bf16<<<(n4 + 255) / 256, 256>>>(x, ah, al, n4, 1.0f);
        gemm_mma<<<gp, 256, GEMM_SMEM>>>(ah, al, qwh, qwl, qb + l * D_, q, ROWS_, D_, D_);
        gemm_mma<<<gp, 256, GEMM_SMEM>>>(ah, al, kwh, kwl, kb + l * D_, k, ROWS_, D_, D_);
        gemm_mma<<<gp, 256, GEMM_SMEM>>>(ah, al, vwh, vwl, vb + l * D_, v, ROWS_, D_, D_);

        // attention operand prep: scaled Q split, K split, V transpose-split
        split_bf16<<<(n4 + 255) / 256, 256>>>(q, qhp, qlp, n4, 0.125f);
        split_bf16<<<(n4 + 255) / 256, 256>>>(k, khp, klp, n4, 1.0f);
        vtsplit<<<vg, vb8>>>(v, vthp, vtlp);

        attn_mma<<<ga, 256, ATT_SMEM>>>(qhp, qlp, khp, klp, vthp, vtlp, mask, ao);

        split_bf16<<<(n4 + 255) / 256, 256>>>(ao, ah, al, n4, 1.0f);
        gemm_mma<<<gp, 256, GEMM_SMEM>>>(ah, al, owh, owl, ob + l * D_, t, ROWS_, D_, D_);
        add_ln<<<ROWS_, 256>>>(x, t, lng + l * D_, lnb + l * D_,
                               (l == L_ - 1) ? out : x);
    }
}

// round 5
// speedup vs baseline: 2.9462x; 1.0538x over previous
#include <cuda_runtime.h>
#include <cuda_bf16.h>
#include <math.h>
#include <stdint.h>

// Problem constants
#define B_      4
#define S_      2048
#define D_      1024
#define H_      16
#define HD_     64
#define L_      6
#define SEQDIM_ 128
#define ROWS_   (B_ * S_)   // 8192

#define WT_PROJ_ELEMS (D_ * SEQDIM_)
#define WT_MAT_ELEMS  (D_ * D_)
#define WT_ELEMS      (WT_PROJ_ELEMS + 24 * WT_MAT_ELEMS)

// ---------------------------------------------------------------------------
// Device scratch
// ---------------------------------------------------------------------------
__device__ float g_xe[ROWS_ * SEQDIM_];
__device__ float g_x [ROWS_ * D_];
__device__ float g_v [ROWS_ * D_];
__device__ float g_t [ROWS_ * D_];
__device__ float g_bqkv[L_ * 3 * D_];
__device__ __nv_bfloat16 g_ah[ROWS_ * D_];
__device__ __nv_bfloat16 g_al[ROWS_ * D_];
__device__ __nv_bfloat16 g_wth[WT_ELEMS];
__device__ __nv_bfloat16 g_wtl[WT_ELEMS];
__device__ __nv_bfloat16 g_qh[ROWS_ * D_];
__device__ __nv_bfloat16 g_ql[ROWS_ * D_];
__device__ __nv_bfloat16 g_kh[ROWS_ * D_];
__device__ __nv_bfloat16 g_kl[ROWS_ * D_];
__device__ __nv_bfloat16 g_vth[ROWS_ * D_];   // [bh][64][S]
__device__ __nv_bfloat16 g_vtl[ROWS_ * D_];

// ---------------------------------------------------------------------------
// Helpers
// ---------------------------------------------------------------------------
__device__ __forceinline__ uint32_t smem_u32(const void* p) {
    uint32_t a;
    asm("{ .reg .u64 t; cvta.to.shared.u64 t, %1; cvt.u32.u64 %0, t; }"
        : "=r"(a) : "l"(p));
    return a;
}

__device__ __forceinline__ void ldm_x4(uint32_t* r, uint32_t addr) {
    asm volatile("ldmatrix.sync.aligned.m8n8.x4.shared.b16 {%0,%1,%2,%3}, [%4];"
                 : "=r"(r[0]), "=r"(r[1]), "=r"(r[2]), "=r"(r[3]) : "r"(addr));
}

__device__ __forceinline__ void mma16816(float* c, const uint32_t* a,
                                         uint32_t b0, uint32_t b1) {
    asm volatile(
        "mma.sync.aligned.m16n8k16.row.col.f32.bf16.bf16.f32 "
        "{%0,%1,%2,%3}, {%4,%5,%6,%7}, {%8,%9}, {%0,%1,%2,%3};"
        : "+f"(c[0]), "+f"(c[1]), "+f"(c[2]), "+f"(c[3])
        : "r"(a[0]), "r"(a[1]), "r"(a[2]), "r"(a[3]), "r"(b0), "r"(b1));
}

// packs: low half = first arg, high half = second arg
__device__ __forceinline__ uint32_t pk_bf16(float lo, float hi) {
    uint32_t r;
    asm("cvt.rn.bf16x2.f32 %0, %1, %2;" : "=r"(r) : "f"(hi), "f"(lo));
    return r;
}

// split two fp32 into hi/lo bf16x2 words
__device__ __forceinline__ void split2(float c0, float c1, uint32_t& hw, uint32_t& lw) {
    __nv_bfloat16 h0 = __float2bfloat16(c0);
    __nv_bfloat16 h1 = __float2bfloat16(c1);
    __nv_bfloat162 hp; hp.x = h0; hp.y = h1;
    hw = *(uint32_t*)&hp;
    lw = pk_bf16(c0 - __bfloat162float(h0), c1 - __bfloat162float(h1));
}

#define CP_ASYNC16(dst, src) \
    asm volatile("cp.async.cg.shared.global [%0], [%1], 16;" :: "r"(dst), "l"(src))
#define CP_COMMIT() asm volatile("cp.async.commit_group;" ::: "memory")
#define CP_WAIT(n)  asm volatile("cp.async.wait_group %0;" :: "n"(n) : "memory")

// ---------------------------------------------------------------------------
// Embedding gather
// ---------------------------------------------------------------------------
__global__ void gather_emb(const int* __restrict__ seq,
                           const float* __restrict__ emb,
                           float* __restrict__ xe) {
    int idx = blockIdx.x * blockDim.x + threadIdx.x;
    if (idx >= ROWS_ * SEQDIM_) return;
    int row = idx >> 7;
    int c   = idx & 127;
    xe[idx] = emb[seq[row] * SEQDIM_ + c];
}

// ---------------------------------------------------------------------------
// bias concat: [qb|kb|vb] per layer -> g_bqkv[L][3072]
// ---------------------------------------------------------------------------
__global__ void bias_concat(const float* __restrict__ qb, const float* __restrict__ kb,
                            const float* __restrict__ vb, float* __restrict__ o) {
    int idx = blockIdx.x * blockDim.x + threadIdx.x;
    if (idx >= L_ * 3 * D_) return;
    int l = idx / (3 * D_);
    int c = idx % (3 * D_);
    float v;
    if (c < D_)           v = qb[l * D_ + c];
    else if (c < 2 * D_)  v = kb[l * D_ + c - D_];
    else                  v = vb[l * D_ + c - 2 * D_];
    o[idx] = v;
}

// ---------------------------------------------------------------------------
// fp32 -> bf16 hi/lo split
// ---------------------------------------------------------------------------
__global__ void split_bf16(const float* __restrict__ x,
                           __nv_bfloat16* __restrict__ hi,
                           __nv_bfloat16* __restrict__ lo, int n4) {
    int i = blockIdx.x * blockDim.x + threadIdx.x;
    if (i >= n4) return;
    float4 v = ((const float4*)x)[i];
    uint32_t h0, l0, h1, l1;
    split2(v.x, v.y, h0, l0);
    split2(v.z, v.w, h1, l1);
    ((uint32_t*)hi)[i * 2 + 0] = h0;
    ((uint32_t*)hi)[i * 2 + 1] = h1;
    ((uint32_t*)lo)[i * 2 + 0] = l0;
    ((uint32_t*)lo)[i * 2 + 1] = l1;
}

// ---------------------------------------------------------------------------
// Weight transpose + split: W[K,N] fp32 -> Wt[N,K] bf16 hi/lo
// ---------------------------------------------------------------------------
__global__ void tsplit_w(const float* __restrict__ W,
                         __nv_bfloat16* __restrict__ th,
                         __nv_bfloat16* __restrict__ tl, int K, int N) {
    __shared__ float t[32][33];
    int bx = blockIdx.x * 32;
    int by = blockIdx.y * 32;
    #pragma unroll
    for (int i = 0; i < 32; i += 8)
        t[threadIdx.y + i][threadIdx.x] =
            W[(size_t)(by + threadIdx.y + i) * N + bx + threadIdx.x];
    __syncthreads();
    #pragma unroll
    for (int i = 0; i < 32; i += 8) {
        float v = t[threadIdx.x][threadIdx.y + i];
        int n = bx + threadIdx.y + i;
        int k = by + threadIdx.x;
        __nv_bfloat16 h = __float2bfloat16(v);
        th[(size_t)n * K + k] = h;
        tl[(size_t)n * K + k] = __float2bfloat16(v - __bfloat162float(h));
    }
}

// ---------------------------------------------------------------------------
// V transpose + split per head: v[b*S+s][h*64+d] -> vt[bh][d][s]
// ---------------------------------------------------------------------------
__global__ void vtsplit(const float* __restrict__ v,
                        __nv_bfloat16* __restrict__ th,
                        __nv_bfloat16* __restrict__ tl) {
    __shared__ float t[32][33];
    int s0 = blockIdx.x * 32;
    int bh = blockIdx.y;
    int b  = bh >> 4, h = bh & 15;
    for (int dh = 0; dh < HD_; dh += 32) {
        #pragma unroll
        for (int i = 0; i < 32; i += 8)
            t[threadIdx.y + i][threadIdx.x] =
                v[(size_t)(b * S_ + s0 + threadIdx.y + i) * D_ + h * HD_ + dh + threadIdx.x];
        __syncthreads();
        #pragma unroll
        for (int i = 0; i < 32; i += 8) {
            float val = t[threadIdx.x][threadIdx.y + i];
            int d = dh + threadIdx.y + i;
            int s = s0 + threadIdx.x;
            __nv_bfloat16 hh = __float2bfloat16(val);
            th[((size_t)bh * HD_ + d) * S_ + s] = hh;
            tl[((size_t)bh * HD_ + d) * S_ + s] = __float2bfloat16(val - __bfloat162float(hh));
        }
        __syncthreads();
    }
}

// ---------------------------------------------------------------------------
// Shared GEMM mainloop core (macro-free via inline): computes acc for one
// 128x128 tile of C = (Ah+Al)(Wh+Wl)^T, 3-pass. Used by gemm_mma & gemm_qkv.
// ---------------------------------------------------------------------------
#define TILEB  10240
#define CHUNKB (4 * TILEB)
#define GEMM_SMEM (3 * CHUNKB)

template <typename EPI>
__device__ __forceinline__
void gemm_core(const __nv_bfloat16* s0, const __nv_bfloat16* s1,
               const __nv_bfloat16* s2, const __nv_bfloat16* s3,
               int K, char* smem, EPI epilogue) {
    const uint32_t sb = smem_u32(smem);
    const int tid  = threadIdx.x;
    const int lane = tid & 31;
    const int wid  = tid >> 5;
    const int wm = wid & 1;
    const int wn = wid >> 1;

    const int nk = K >> 5;

    auto load_chunk = [&](int c, int stage) {
        const int k0 = c << 5;
        uint32_t buf = sb + stage * CHUNKB;
        #pragma unroll
        for (int i = 0; i < 2; i++) {
            int t = tid + i * 256;
            int row = t >> 2;
            int seg = t & 3;
            uint32_t dst = buf + row * 80 + seg * 16;
            size_t so = (size_t)row * K + k0 + seg * 8;
            CP_ASYNC16(dst,              (const char*)(s0 + so));
            CP_ASYNC16(dst + TILEB,      (const char*)(s1 + so));
            CP_ASYNC16(dst + 2 * TILEB,  (const char*)(s2 + so));
            CP_ASYNC16(dst + 3 * TILEB,  (const char*)(s3 + so));
        }
        CP_COMMIT();
    };

    float acc[4][4][4];
    #pragma unroll
    for (int mi = 0; mi < 4; mi++)
        #pragma unroll
        for (int nb = 0; nb < 4; nb++)
            #pragma unroll
            for (int j = 0; j < 4; j++) acc[mi][nb][j] = 0.f;

    const int l16 = lane & 15;
    const uint32_t a_off = (uint32_t)((wm * 64 + l16) * 80 + (lane >> 4) * 16);
    const uint32_t b_off = (uint32_t)((wn * 32 + ((lane >> 4) & 1) * 8 + (lane & 7)) * 80
                                      + ((lane >> 3) & 1) * 16);

    load_chunk(0, 0);
    if (nk > 1) load_chunk(1, 1);

    for (int c = 0; c < nk; c++) {
        if (c + 2 < nk)      { load_chunk(c + 2, (c + 2) % 3); CP_WAIT(2); }
        else if (c + 1 < nk) { CP_WAIT(1); }
        else                 { CP_WAIT(0); }
        __syncthreads();

        uint32_t buf = sb + (c % 3) * CHUNKB;
        #pragma unroll
        for (int s = 0; s < 2; s++) {
            uint32_t ah[4][4], al[4][4], wh[2][4], wl[2][4];
            #pragma unroll
            for (int g = 0; g < 4; g++) {
                uint32_t ao = buf + a_off + (uint32_t)(g * 16 * 80 + s * 32);
                ldm_x4(ah[g], ao);
                ldm_x4(al[g], ao + TILEB);
            }
            #pragma unroll
            for (int h = 0; h < 2; h++) {
                uint32_t bo = buf + 2 * TILEB + b_off + (uint32_t)(h * 16 * 80 + s * 32);
                ldm_x4(wh[h], bo);
                ldm_x4(wl[h], bo + TILEB);
            }
            #pragma unroll
            for (int mi = 0; mi < 4; mi++) {
                #pragma unroll
                for (int nb = 0; nb < 4; nb++) {
                    const int h = nb >> 1, j = nb & 1;
                    mma16816(acc[mi][nb], ah[mi], wh[h][2 * j], wh[h][2 * j + 1]);
                    mma16816(acc[mi][nb], ah[mi], wl[h][2 * j], wl[h][2 * j + 1]);
                    mma16816(acc[mi][nb], al[mi], wh[h][2 * j], wh[h][2 * j + 1]);
                }
            }
        }
        __syncthreads();
    }

    epilogue(acc, wm, wn, lane);
}

// ---------------------------------------------------------------------------
// Generic GEMM + bias -> fp32 C
// ---------------------------------------------------------------------------
__global__ __launch_bounds__(256, 1)
void gemm_mma(const __nv_bfloat16* __restrict__ Ah,
              const __nv_bfloat16* __restrict__ Al,
              const __nv_bfloat16* __restrict__ Wh,
              const __nv_bfloat16* __restrict__ Wl,
              const float* __restrict__ bias,
              float* __restrict__ C, int N, int K) {
    extern __shared__ char smem[];
    const int brow = blockIdx.y * 128;
    const int bcol = blockIdx.x * 128;
    gemm_core(Ah + (size_t)brow * K, Al + (size_t)brow * K,
              Wh + (size_t)bcol * K, Wl + (size_t)bcol * K, K, smem,
        [&](float acc[4][4][4], int wm, int wn, int lane) {
            #pragma unroll
            for (int mi = 0; mi < 4; mi++) {
                int row = brow + wm * 64 + mi * 16 + (lane >> 2);
                #pragma unroll
                for (int nb = 0; nb < 4; nb++) {
                    int col = bcol + wn * 32 + nb * 8 + (lane & 3) * 2;
                    float b0 = bias[col], b1 = bias[col + 1];
                    float2 v0 = make_float2(acc[mi][nb][0] + b0, acc[mi][nb][1] + b1);
                    float2 v1 = make_float2(acc[mi][nb][2] + b0, acc[mi][nb][3] + b1);
                    *(float2*)(C + (size_t)row * N + col)       = v0;
                    *(float2*)(C + (size_t)(row + 8) * N + col) = v1;
                }
            }
        });
}

// ---------------------------------------------------------------------------
// Fused QKV GEMM: N=3072 (weights contiguous [3N, K]); writes
//   cols [0,1024):    qh/ql bf16 split, scaled by 0.125
//   cols [1024,2048): kh/kl bf16 split
//   cols [2048,3072): v fp32
// ---------------------------------------------------------------------------
__global__ __launch_bounds__(256, 1)
void gemm_qkv(const __nv_bfloat16* __restrict__ Ah,
              const __nv_bfloat16* __restrict__ Al,
              const __nv_bfloat16* __restrict__ Wh,
              const __nv_bfloat16* __restrict__ Wl,
              const float* __restrict__ bias,   // [3072]
              __nv_bfloat16* __restrict__ qh, __nv_bfloat16* __restrict__ ql,
              __nv_bfloat16* __restrict__ kh, __nv_bfloat16* __restrict__ kl,
              float* __restrict__ vout) {
    extern __shared__ char smem[];
    const int K = D_;
    const int brow = blockIdx.y * 128;
    const int bcol = blockIdx.x * 128;
    const int mat = bcol >> 10;            // 0=q 1=k 2=v
    const int colb = bcol & 1023;
    gemm_core(Ah + (size_t)brow * K, Al + (size_t)brow * K,
              Wh + (size_t)bcol * K, Wl + (size_t)bcol * K, K, smem,
        [&](float acc[4][4][4], int wm, int wn, int lane) {
            #pragma unroll
            for (int mi = 0; mi < 4; mi++) {
                int row = brow + wm * 64 + mi * 16 + (lane >> 2);
                #pragma unroll
                for (int nb = 0; nb < 4; nb++) {
                    int col = colb + wn * 32 + nb * 8 + (lane & 3) * 2;
                    float b0 = bias[(mat << 10) + col], b1 = bias[(mat << 10) + col + 1];
                    float c00 = acc[mi][nb][0] + b0, c01 = acc[mi][nb][1] + b1;
                    float c10 = acc[mi][nb][2] + b0, c11 = acc[mi][nb][3] + b1;
                    size_t i0 = (size_t)row * D_ + col;
                    size_t i1 = (size_t)(row + 8) * D_ + col;
                    if (mat == 2) {
                        *(float2*)(vout + i0) = make_float2(c00, c01);
                        *(float2*)(vout + i1) = make_float2(c10, c11);
                    } else {
                        __nv_bfloat16* hB = (mat == 0) ? qh : kh;
                        __nv_bfloat16* lB = (mat == 0) ? ql : kl;
                        if (mat == 0) { c00 *= 0.125f; c01 *= 0.125f; c10 *= 0.125f; c11 *= 0.125f; }
                        uint32_t hw, lw;
                        split2(c00, c01, hw, lw);
                        *(uint32_t*)(hB + i0) = hw; *(uint32_t*)(lB + i0) = lw;
                        split2(c10, c11, hw, lw);
                        *(uint32_t*)(hB + i1) = hw; *(uint32_t*)(lB + i1) = lw;
                    }
                }
            }
        });
}

// ---------------------------------------------------------------------------
// Tensor-core flash attention; output written as bf16 hi/lo split (feeds O-proj)
// ---------------------------------------------------------------------------
#define AST      36864
#define AKL      9216
#define AMASK    (3 * AST)
#define ATT_SMEM (AMASK + 3 * 256)

__global__ __launch_bounds__(256, 1)
void attn_mma(const __nv_bfloat16* __restrict__ qh, const __nv_bfloat16* __restrict__ ql,
              const __nv_bfloat16* __restrict__ kh, const __nv_bfloat16* __restrict__ kl,
              const __nv_bfloat16* __restrict__ vth, const __nv_bfloat16* __restrict__ vtl,
              const int* __restrict__ mask,
              __nv_bfloat16* __restrict__ oh, __nv_bfloat16* __restrict__ ol) {
    extern __shared__ char smem[];
    const uint32_t sb = smem_u32(smem);
    const int tid = threadIdx.x, wid = tid >> 5, lane = tid & 31;
    const int q0 = blockIdx.x * 128;
    const int bh = blockIdx.y;
    const int b = bh >> 4, h = bh & 15;
    const size_t rowbase = (size_t)b * S_;

    #pragma unroll
    for (int i = 0; i < 4; i++) {
        int t = tid + i * 256;
        int row = t >> 3, seg = t & 7;
        uint32_t dst = sb + row * 144 + seg * 16;
        size_t so = (rowbase + q0 + row) * D_ + h * HD_ + seg * 8;
        CP_ASYNC16(dst,         (const char*)(qh + so));
        CP_ASYNC16(dst + 18432, (const char*)(ql + so));
    }
    CP_COMMIT(); CP_WAIT(0);
    __syncthreads();

    uint32_t qhf[4][4], qlf[4][4];
    #pragma unroll
    for (int s = 0; s < 4; s++) {
        uint32_t a = sb + (uint32_t)((wid * 16 + (lane & 15)) * 144 + (lane >> 4) * 16 + s * 32);
        ldm_x4(qhf[s], a);
        ldm_x4(qlf[s], a + 18432);
    }
    __syncthreads();

    auto load_kv = [&](int kt, int st) {
        uint32_t buf = sb + st * AST;
        int key0 = kt * 64;
        #pragma unroll
        for (int i = 0; i < 2; i++) {
            int t = tid + i * 256;
            int row = t >> 3, seg = t & 7;
            uint32_t dst = buf + row * 144 + seg * 16;
            size_t sk = (rowbase + key0 + row) * D_ + h * HD_ + seg * 8;
            CP_ASYNC16(dst,           (const char*)(kh + sk));
            CP_ASYNC16(dst + AKL,     (const char*)(kl + sk));
            size_t sv = ((size_t)bh * HD_ + row) * S_ + key0 + seg * 8;
            CP_ASYNC16(dst + 2 * AKL, (const char*)(vth + sv));
            CP_ASYNC16(dst + 3 * AKL, (const char*)(vtl + sv));
        }
        if (tid < 16)
            CP_ASYNC16(sb + AMASK + st * 256 + tid * 16,
                       (const char*)(mask + b * S_ + key0 + tid * 4));
        CP_COMMIT();
    };

    float oacc[8][4];
    #pragma unroll
    for (int nb = 0; nb < 8; nb++)
        #pragma unroll
        for (int j = 0; j < 4; j++) oacc[nb][j] = 0.f;
    float mrow0 = -1e30f, mrow1 = -1e30f, lrow0 = 0.f, lrow1 = 0.f;

    const uint32_t bfrag_off = (uint32_t)((((lane >> 4) & 1) * 8 + (lane & 7)) * 144
                                          + ((lane >> 3) & 1) * 16);

    load_kv(0, 0);
    load_kv(1, 1);

    const int NKT = S_ / 64;
    for (int kt = 0; kt < NKT; kt++) {
        if (kt + 2 < NKT)      { load_kv(kt + 2, (kt + 2) % 3); CP_WAIT(2); }
        else if (kt + 1 < NKT) { CP_WAIT(1); }
        else                   { CP_WAIT(0); }
        __syncthreads();

        uint32_t buf = sb + (kt % 3) * AST;

        float sacc[8][4];
        #pragma unroll
        for (int nb = 0; nb < 8; nb++)
            #pragma unroll
            for (int j = 0; j < 4; j++) sacc[nb][j] = 0.f;

        #pragma unroll
        for (int s = 0; s < 4; s++) {
            uint32_t khf[4][4], klf[4][4];
            #pragma unroll
            for (int g = 0; g < 4; g++) {
                uint32_t a = buf + bfrag_off + (uint32_t)(g * 16 * 144 + s * 32);
                ldm_x4(khf[g], a);
                ldm_x4(klf[g], a + AKL);
            }
            #pragma unroll
            for (int g = 0; g < 4; g++) {
                #pragma unroll
                for (int j = 0; j < 2; j++) {
                    int nb = g * 2 + j;
                    mma16816(sacc[nb], qhf[s], khf[g][2 * j], khf[g][2 * j + 1]);
                    mma16816(sacc[nb], qhf[s], klf[g][2 * j], klf[g][2 * j + 1]);
                    mma16816(sacc[nb], qlf[s], khf[g][2 * j], khf[g][2 * j + 1]);
                }
            }
        }

        {
            const int* smk = (const int*)(smem + AMASK + (kt % 3) * 256);
            int cb = 2 * (lane & 3);
            #pragma unroll
            for (int nb = 0; nb < 8; nb++) {
                if (smk[nb * 8 + cb] == 0)     { sacc[nb][0] = -1e9f; sacc[nb][2] = -1e9f; }
                if (smk[nb * 8 + cb + 1] == 0) { sacc[nb][1] = -1e9f; sacc[nb][3] = -1e9f; }
            }
        }

        float mx0 = -1e30f, mx1 = -1e30f;
        #pragma unroll
        for (int nb = 0; nb < 8; nb++) {
            mx0 = fmaxf(mx0, fmaxf(sacc[nb][0], sacc[nb][1]));
            mx1 = fmaxf(mx1, fmaxf(sacc[nb][2], sacc[nb][3]));
        }
        mx0 = fmaxf(mx0, __shfl_xor_sync(0xffffffffu, mx0, 1));
        mx0 = fmaxf(mx0, __shfl_xor_sync(0xffffffffu, mx0, 2));
        mx1 = fmaxf(mx1, __shfl_xor_sync(0xffffffffu, mx1, 1));
        mx1 = fmaxf(mx1, __shfl_xor_sync(0xffffffffu, mx1, 2));
        float mn0 = fmaxf(mrow0, mx0), mn1 = fmaxf(mrow1, mx1);
        float corr0 = __expf(mrow0 - mn0), corr1 = __expf(mrow1 - mn1);
        float sum0 = 0.f, sum1 = 0.f;
        #pragma unroll
        for (int nb = 0; nb < 8; nb++) {
            sacc[nb][0] = __expf(sacc[nb][0] - mn0);
            sacc[nb][1] = __expf(sacc[nb][1] - mn0);
            sacc[nb][2] = __expf(sacc[nb][2] - mn1);
            sacc[nb][3] = __expf(sacc[nb][3] - mn1);
            sum0 += sacc[nb][0] + sacc[nb][1];
            sum1 += sacc[nb][2] + sacc[nb][3];
        }
        sum0 += __shfl_xor_sync(0xffffffffu, sum0, 1);
        sum0 += __shfl_xor_sync(0xffffffffu, sum0, 2);
        sum1 += __shfl_xor_sync(0xffffffffu, sum1, 1);
        sum1 += __shfl_xor_sync(0xffffffffu, sum1, 2);
        lrow0 = lrow0 * corr0 + sum0;
        lrow1 = lrow1 * corr1 + sum1;
        mrow0 = mn0; mrow1 = mn1;
        #pragma unroll
        for (int nb = 0; nb < 8; nb++) {
            oacc[nb][0] *= corr0; oacc[nb][1] *= corr0;
            oacc[nb][2] *= corr1; oacc[nb][3] *= corr1;
        }

        #pragma unroll
        for (int c = 0; c < 4; c++) {
            uint32_t pha[4], pla[4];
            #pragma unroll
            for (int half = 0; half < 2; half++) {
                int nb = 2 * c + half;
                __nv_bfloat16 b0 = __float2bfloat16(sacc[nb][0]);
                __nv_bfloat16 b1 = __float2bfloat16(sacc[nb][1]);
                __nv_bfloat16 b2 = __float2bfloat16(sacc[nb][2]);
                __nv_bfloat16 b3 = __float2bfloat16(sacc[nb][3]);
                __nv_bfloat162 t01; t01.x = b0; t01.y = b1;
                __nv_bfloat162 t23; t23.x = b2; t23.y = b3;
                pha[half * 2 + 0] = *(uint32_t*)&t01;
                pha[half * 2 + 1] = *(uint32_t*)&t23;
                pla[half * 2 + 0] = pk_bf16(sacc[nb][0] - __bfloat162float(b0),
                                            sacc[nb][1] - __bfloat162float(b1));
                pla[half * 2 + 1] = pk_bf16(sacc[nb][2] - __bfloat162float(b2),
                                            sacc[nb][3] - __bfloat162float(b3));
            }
            uint32_t vhf[4][4], vlf[4][4];
            #pragma unroll
            for (int g = 0; g < 4; g++) {
                uint32_t a = buf + 2 * AKL + bfrag_off + (uint32_t)(g * 16 * 144 + c * 32);
                ldm_x4(vhf[g], a);
                ldm_x4(vlf[g], a + AKL);
            }
            #pragma unroll
            for (int g = 0; g < 4; g++) {
                #pragma unroll
                for (int j = 0; j < 2; j++) {
                    int nb = g * 2 + j;
                    mma16816(oacc[nb], pha, vhf[g][2 * j], vhf[g][2 * j + 1]);
                    mma16816(oacc[nb], pha, vlf[g][2 * j], vlf[g][2 * j + 1]);
                    mma16816(oacc[nb], pla, vhf[g][2 * j], vhf[g][2 * j + 1]);
                }
            }
        }
        __syncthreads();
    }

    // epilogue: normalized output -> bf16 hi/lo split
    float inv0 = 1.0f / lrow0, inv1 = 1.0f / lrow1;
    int r0 = q0 + wid * 16 + (lane >> 2);
    #pragma unroll
    for (int nb = 0; nb < 8; nb++) {
        int col = h * HD_ + nb * 8 + 2 * (lane & 3);
        size_t i0 = (rowbase + r0) * D_ + col;
        size_t i1 = (rowbase + r0 + 8) * D_ + col;
        uint32_t hw, lw;
        split2(oacc[nb][0] * inv0, oacc[nb][1] * inv0, hw, lw);
        *(uint32_t*)(oh + i0) = hw; *(uint32_t*)(ol + i0) = lw;
        split2(oacc[nb][2] * inv1, oacc[nb][3] * inv1, hw, lw);
        *(uint32_t*)(oh + i1) = hw; *(uint32_t*)(ol + i1) = lw;
    }
}

// ---------------------------------------------------------------------------
// Fused residual add + LayerNorm; optionally also emit bf16 hi/lo split
// ---------------------------------------------------------------------------
template <bool SPLIT>
__global__ __launch_bounds__(256)
void add_ln(const float* __restrict__ x, const float* __restrict__ y,
            const float* __restrict__ g, const float* __restrict__ bta,
            float* __restrict__ out,
            __nv_bfloat16* __restrict__ oh, __nv_bfloat16* __restrict__ ol) {
    __shared__ float red[256];
    int row = blockIdx.x, tid = threadIdx.x;
    const float* xr = x + (size_t)row * D_;
    const float* yr = y + (size_t)row * D_;

    float v[4];
    float sum = 0.f;
    #pragma unroll
    for (int i = 0; i < 4; i++) {
        int c = tid + i * 256;
        v[i] = xr[c] + yr[c];
        sum += v[i];
    }
    red[tid] = sum; __syncthreads();
    for (int s = 128; s; s >>= 1) { if (tid < s) red[tid] += red[tid + s]; __syncthreads(); }
    float mu = red[0] * (1.0f / 1024.0f);
    __syncthreads();

    float sq = 0.f;
    #pragma unroll
    for (int i = 0; i < 4; i++) { float d = v[i] - mu; sq += d * d; }
    red[tid] = sq; __syncthreads();
    for (int s = 128; s; s >>= 1) { if (tid < s) red[tid] += red[tid + s]; __syncthreads(); }
    float var  = red[0] * (1.0f / 1024.0f);
    float rstd = rsqrtf(var + 1e-5f);

    #pragma unroll
    for (int i = 0; i < 4; i++) {
        int c = tid + i * 256;
        float o = (v[i] - mu) * rstd * g[c] + bta[c];
        out[(size_t)row * D_ + c] = o;
        if (SPLIT) {
            __nv_bfloat16 h = __float2bfloat16(o);
            oh[(size_t)row * D_ + c] = h;
            ol[(size_t)row * D_ + c] = __float2bfloat16(o - __bfloat162float(h));
        }
    }
}

// ---------------------------------------------------------------------------
// Launch
// ---------------------------------------------------------------------------
extern "C" void kernel_launch(void* const* d_in, const int* in_sizes, int n_in,
                              void* d_out, int out_size) {
    const int*   seq    = (const int*)  d_in[0];
    const int*   mask   = (const int*)  d_in[1];
    const float* emb    = (const float*)d_in[2];
    const float* proj_w = (const float*)d_in[3];
    const float* proj_b = (const float*)d_in[4];
    const float* qw     = (const float*)d_in[5];
    const float* qb     = (const float*)d_in[6];
    const float* kw     = (const float*)d_in[7];
    const float* kb     = (const float*)d_in[8];
    const float* vw     = (const float*)d_in[9];
    const float* vb     = (const float*)d_in[10];
    const float* ow     = (const float*)d_in[11];
    const float* ob     = (const float*)d_in[12];
    const float* lng    = (const float*)d_in[13];
    const float* lnb    = (const float*)d_in[14];
    float* out = (float*)d_out;

    float *xe, *x, *v, *t, *bqkv;
    __nv_bfloat16 *ah, *al, *wth, *wtl, *qhp, *qlp, *khp, *klp, *vthp, *vtlp;
    cudaGetSymbolAddress((void**)&xe,   g_xe);
    cudaGetSymbolAddress((void**)&x,    g_x);
    cudaGetSymbolAddress((void**)&v,    g_v);
    cudaGetSymbolAddress((void**)&t,    g_t);
    cudaGetSymbolAddress((void**)&bqkv, g_bqkv);
    cudaGetSymbolAddress((void**)&ah,   g_ah);
    cudaGetSymbolAddress((void**)&al,   g_al);
    cudaGetSymbolAddress((void**)&wth,  g_wth);
    cudaGetSymbolAddress((void**)&wtl,  g_wtl);
    cudaGetSymbolAddress((void**)&qhp,  g_qh);
    cudaGetSymbolAddress((void**)&qlp,  g_ql);
    cudaGetSymbolAddress((void**)&khp,  g_kh);
    cudaGetSymbolAddress((void**)&klp,  g_kl);
    cudaGetSymbolAddress((void**)&vthp, g_vth);
    cudaGetSymbolAddress((void**)&vtlp, g_vtl);

    cudaFuncSetAttribute(gemm_mma, cudaFuncAttributeMaxDynamicSharedMemorySize, GEMM_SMEM);
    cudaFuncSetAttribute(gemm_qkv, cudaFuncAttributeMaxDynamicSharedMemorySize, GEMM_SMEM);
    cudaFuncSetAttribute(attn_mma, cudaFuncAttributeMaxDynamicSharedMemorySize, ATT_SMEM);

    // ---- weight transpose+split + bias concat ----
    {
        dim3 tb(32, 8);
        tsplit_w<<<dim3(D_ / 32, SEQDIM_ / 32), tb>>>(proj_w, wth, wtl, SEQDIM_, D_);
        dim3 tg(D_ / 32, D_ / 32);
        for (int l = 0; l < L_; l++) {
            size_t off = WT_PROJ_ELEMS + (size_t)(l * 4) * WT_MAT_ELEMS;
            tsplit_w<<<tg, tb>>>(qw + (size_t)l * D_ * D_, wth + off,                    wtl + off,                    D_, D_);
            tsplit_w<<<tg, tb>>>(kw + (size_t)l * D_ * D_, wth + off + WT_MAT_ELEMS,     wtl + off + WT_MAT_ELEMS,     D_, D_);
            tsplit_w<<<tg, tb>>>(vw + (size_t)l * D_ * D_, wth + off + 2 * WT_MAT_ELEMS, wtl + off + 2 * WT_MAT_ELEMS, D_, D_);
            tsplit_w<<<tg, tb>>>(ow + (size_t)l * D_ * D_, wth + off + 3 * WT_MAT_ELEMS, wtl + off + 3 * WT_MAT_ELEMS, D_, D_);
        }
        bias_concat<<<(L_ * 3 * D_ + 255) / 256, 256>>>(qb, kb, vb, bqkv);
    }

    // ---- embedding + input projection ----
    gather_emb<<<(ROWS_ * SEQDIM_ + 255) / 256, 256>>>(seq, emb, xe);
    split_bf16<<<(ROWS_ * SEQDIM_ / 4 + 255) / 256, 256>>>(xe, ah, al, ROWS_ * SEQDIM_ / 4);
    dim3 gp(D_ / 128, ROWS_ / 128);
    gemm_mma<<<gp, 256, GEMM_SMEM>>>(ah, al, wth, wtl, proj_b, x, D_, SEQDIM_);
    split_bf16<<<(ROWS_ * D_ / 4 + 255) / 256, 256>>>(x, ah, al, ROWS_ * D_ / 4);

    dim3 gqkv(3 * D_ / 128, ROWS_ / 128);        // (24, 64)
    dim3 ga(S_ / 128, B_ * H_);                  // (16, 64)
    dim3 vg(S_ / 32, B_ * H_);
    dim3 vb8(32, 8);
    for (int l = 0; l < L_; l++) {
        size_t off = WT_PROJ_ELEMS + (size_t)(l * 4) * WT_MAT_ELEMS;
        const __nv_bfloat16* owh = wth + off + 3 * WT_MAT_ELEMS;
        const __nv_bfloat16* owl = wtl + off + 3 * WT_MAT_ELEMS;

        gemm_qkv<<<gqkv, 256, GEMM_SMEM>>>(ah, al, wth + off, wtl + off,
                                           bqkv + l * 3 * D_,
                                           qhp, qlp, khp, klp, v);
        vtsplit<<<vg, vb8>>>(v, vthp, vtlp);
        attn_mma<<<ga, 256, ATT_SMEM>>>(qhp, qlp, khp, klp, vthp, vtlp, mask, ah, al);
        gemm_mma<<<gp, 256, GEMM_SMEM>>>(ah, al, owh, owl, ob + l * D_, t, D_, D_);
        if (l == L_ - 1)
            add_ln<false><<<ROWS_, 256>>>(x, t, lng + l * D_, lnb + l * D_, out, nullptr, nullptr);
        else
            add_ln<true><<<ROWS_, 256>>>(x, t, lng + l * D_, lnb + l * D_, x, ah, al);
    }
}

// round 6
// speedup vs baseline: 3.1813x; 1.0798x over previous
#include <cuda_runtime.h>
#include <cuda_bf16.h>
#include <math.h>
#include <stdint.h>

// Problem constants
#define B_      4
#define S_      2048
#define D_      1024
#define H_      16
#define HD_     64
#define L_      6
#define SEQDIM_ 128
#define ROWS_   (B_ * S_)   // 8192

#define WT_PROJ_ELEMS (D_ * SEQDIM_)
#define WT_MAT_ELEMS  (D_ * D_)
#define WT_ELEMS      (WT_PROJ_ELEMS + 24 * WT_MAT_ELEMS)

// ---------------------------------------------------------------------------
// Device scratch
// ---------------------------------------------------------------------------
__device__ float g_x [ROWS_ * D_];
__device__ float g_v [ROWS_ * D_];
__device__ float g_t [ROWS_ * D_];
__device__ float g_bqkv[L_ * 3 * D_];
__device__ __nv_bfloat16 g_ah[ROWS_ * D_];
__device__ __nv_bfloat16 g_al[ROWS_ * D_];
__device__ __nv_bfloat16 g_wth[WT_ELEMS];
__device__ __nv_bfloat16 g_wtl[WT_ELEMS];
__device__ __nv_bfloat16 g_qh[ROWS_ * D_];
__device__ __nv_bfloat16 g_ql[ROWS_ * D_];
__device__ __nv_bfloat16 g_kh[ROWS_ * D_];
__device__ __nv_bfloat16 g_kl[ROWS_ * D_];
__device__ __nv_bfloat16 g_vth[ROWS_ * D_];   // [bh][64][S]
__device__ __nv_bfloat16 g_vtl[ROWS_ * D_];

// ---------------------------------------------------------------------------
// Helpers
// ---------------------------------------------------------------------------
__device__ __forceinline__ uint32_t smem_u32(const void* p) {
    uint32_t a;
    asm("{ .reg .u64 t; cvta.to.shared.u64 t, %1; cvt.u32.u64 %0, t; }"
        : "=r"(a) : "l"(p));
    return a;
}

__device__ __forceinline__ void ldm_x4(uint32_t* r, uint32_t addr) {
    asm volatile("ldmatrix.sync.aligned.m8n8.x4.shared.b16 {%0,%1,%2,%3}, [%4];"
                 : "=r"(r[0]), "=r"(r[1]), "=r"(r[2]), "=r"(r[3]) : "r"(addr));
}

__device__ __forceinline__ void mma16816(float* c, const uint32_t* a,
                                         uint32_t b0, uint32_t b1) {
    asm volatile(
        "mma.sync.aligned.m16n8k16.row.col.f32.bf16.bf16.f32 "
        "{%0,%1,%2,%3}, {%4,%5,%6,%7}, {%8,%9}, {%0,%1,%2,%3};"
        : "+f"(c[0]), "+f"(c[1]), "+f"(c[2]), "+f"(c[3])
        : "r"(a[0]), "r"(a[1]), "r"(a[2]), "r"(a[3]), "r"(b0), "r"(b1));
}

__device__ __forceinline__ uint32_t pk_bf16(float lo, float hi) {
    uint32_t r;
    asm("cvt.rn.bf16x2.f32 %0, %1, %2;" : "=r"(r) : "f"(hi), "f"(lo));
    return r;
}

__device__ __forceinline__ void split2(float c0, float c1, uint32_t& hw, uint32_t& lw) {
    __nv_bfloat16 h0 = __float2bfloat16(c0);
    __nv_bfloat16 h1 = __float2bfloat16(c1);
    __nv_bfloat162 hp; hp.x = h0; hp.y = h1;
    hw = *(uint32_t*)&hp;
    lw = pk_bf16(c0 - __bfloat162float(h0), c1 - __bfloat162float(h1));
}

#define CP_ASYNC16(dst, src) \
    asm volatile("cp.async.cg.shared.global [%0], [%1], 16;" :: "r"(dst), "l"(src))
#define CP_COMMIT() asm volatile("cp.async.commit_group;" ::: "memory")
#define CP_WAIT(n)  asm volatile("cp.async.wait_group %0;" :: "n"(n) : "memory")

// ---------------------------------------------------------------------------
// Embedding gather -> direct bf16 hi/lo split of x_embed (128 cols)
// ---------------------------------------------------------------------------
__global__ void gather_emb(const int* __restrict__ seq,
                           const float* __restrict__ emb,
                           __nv_bfloat16* __restrict__ xh,
                           __nv_bfloat16* __restrict__ xl) {
    int i = blockIdx.x * blockDim.x + threadIdx.x;   // pair index
    if (i >= ROWS_ * SEQDIM_ / 2) return;
    int row = i >> 6;
    int c2  = (i & 63) * 2;
    const float* e = emb + seq[row] * SEQDIM_ + c2;
    uint32_t hw, lw;
    split2(e[0], e[1], hw, lw);
    ((uint32_t*)xh)[i] = hw;
    ((uint32_t*)xl)[i] = lw;
}

// ---------------------------------------------------------------------------
// bias concat: [qb|kb|vb] per layer
// ---------------------------------------------------------------------------
__global__ void bias_concat(const float* __restrict__ qb, const float* __restrict__ kb,
                            const float* __restrict__ vb, float* __restrict__ o) {
    int idx = blockIdx.x * blockDim.x + threadIdx.x;
    if (idx >= L_ * 3 * D_) return;
    int l = idx / (3 * D_);
    int c = idx % (3 * D_);
    float v;
    if (c < D_)           v = qb[l * D_ + c];
    else if (c < 2 * D_)  v = kb[l * D_ + c - D_];
    else                  v = vb[l * D_ + c - 2 * D_];
    o[idx] = v;
}

// ---------------------------------------------------------------------------
// Weight transpose + split: proj_w only (K=SEQDIM_)
// ---------------------------------------------------------------------------
__global__ void tsplit_w(const float* __restrict__ W,
                         __nv_bfloat16* __restrict__ th,
                         __nv_bfloat16* __restrict__ tl, int K, int N) {
    __shared__ float t[32][33];
    int bx = blockIdx.x * 32;
    int by = blockIdx.y * 32;
    #pragma unroll
    for (int i = 0; i < 32; i += 8)
        t[threadIdx.y + i][threadIdx.x] =
            W[(size_t)(by + threadIdx.y + i) * N + bx + threadIdx.x];
    __syncthreads();
    #pragma unroll
    for (int i = 0; i < 32; i += 8) {
        float v = t[threadIdx.x][threadIdx.y + i];
        int n = bx + threadIdx.y + i;
        int k = by + threadIdx.x;
        __nv_bfloat16 h = __float2bfloat16(v);
        th[(size_t)n * K + k] = h;
        tl[(size_t)n * K + k] = __float2bfloat16(v - __bfloat162float(h));
    }
}

// ---------------------------------------------------------------------------
// Batched weight transpose + split for all 24 layer matrices (z = l*4+m)
// ---------------------------------------------------------------------------
__global__ void tsplit_all(const float* __restrict__ qw, const float* __restrict__ kw,
                           const float* __restrict__ vw, const float* __restrict__ ow,
                           __nv_bfloat16* __restrict__ th,
                           __nv_bfloat16* __restrict__ tl) {
    __shared__ float t[32][33];
    int z = blockIdx.z;
    int l = z >> 2, m = z & 3;
    const float* W = (m == 0 ? qw : m == 1 ? kw : m == 2 ? vw : ow) + (size_t)l * D_ * D_;
    size_t dof = WT_PROJ_ELEMS + (size_t)z * WT_MAT_ELEMS;
    int bx = blockIdx.x * 32;
    int by = blockIdx.y * 32;
    #pragma unroll
    for (int i = 0; i < 32; i += 8)
        t[threadIdx.y + i][threadIdx.x] =
            W[(size_t)(by + threadIdx.y + i) * D_ + bx + threadIdx.x];
    __syncthreads();
    #pragma unroll
    for (int i = 0; i < 32; i += 8) {
        float v = t[threadIdx.x][threadIdx.y + i];
        int n = bx + threadIdx.y + i;
        int k = by + threadIdx.x;
        __nv_bfloat16 h = __float2bfloat16(v);
        th[dof + (size_t)n * D_ + k] = h;
        tl[dof + (size_t)n * D_ + k] = __float2bfloat16(v - __bfloat162float(h));
    }
}

// ---------------------------------------------------------------------------
// V transpose + split per head
// ---------------------------------------------------------------------------
__global__ void vtsplit(const float* __restrict__ v,
                        __nv_bfloat16* __restrict__ th,
                        __nv_bfloat16* __restrict__ tl) {
    __shared__ float t[32][33];
    int s0 = blockIdx.x * 32;
    int bh = blockIdx.y;
    int b  = bh >> 4, h = bh & 15;
    for (int dh = 0; dh < HD_; dh += 32) {
        #pragma unroll
        for (int i = 0; i < 32; i += 8)
            t[threadIdx.y + i][threadIdx.x] =
                v[(size_t)(b * S_ + s0 + threadIdx.y + i) * D_ + h * HD_ + dh + threadIdx.x];
        __syncthreads();
        #pragma unroll
        for (int i = 0; i < 32; i += 8) {
            float val = t[threadIdx.x][threadIdx.y + i];
            int d = dh + threadIdx.y + i;
            int s = s0 + threadIdx.x;
            __nv_bfloat16 hh = __float2bfloat16(val);
            th[((size_t)bh * HD_ + d) * S_ + s] = hh;
            tl[((size_t)bh * HD_ + d) * S_ + s] = __float2bfloat16(val - __bfloat162float(hh));
        }
        __syncthreads();
    }
}

// ---------------------------------------------------------------------------
// GEMM core: BK=64, 2-stage cp.async pipeline, 3-pass bf16 split, 128x128 tile.
// SMEM rows: 144B stride (128B data + 16B pad) -> conflict-free ldmatrix.
// ---------------------------------------------------------------------------
#define TILEB  18432            // 128 * 144
#define CHUNKB (4 * TILEB)      // 73728
#define GEMM_SMEM (2 * CHUNKB)  // 147456

template <typename EPI>
__device__ __forceinline__
void gemm_core(const __nv_bfloat16* s0, const __nv_bfloat16* s1,
               const __nv_bfloat16* s2, const __nv_bfloat16* s3,
               int K, char* smem, EPI epilogue) {
    const uint32_t sb = smem_u32(smem);
    const int tid  = threadIdx.x;
    const int lane = tid & 31;
    const int wid  = tid >> 5;
    const int wm = wid & 1;
    const int wn = wid >> 1;

    const int nk = K >> 6;            // chunks of 64

    auto load_chunk = [&](int c, int stage) {
        const int k0 = c << 6;
        uint32_t buf = sb + stage * CHUNKB;
        #pragma unroll
        for (int i = 0; i < 4; i++) {
            int t = tid + i * 256;            // 0..1023
            int row = t >> 3;
            int seg = t & 7;
            uint32_t dst = buf + row * 144 + seg * 16;
            size_t so = (size_t)row * K + k0 + seg * 8;
            CP_ASYNC16(dst,              (const char*)(s0 + so));
            CP_ASYNC16(dst + TILEB,      (const char*)(s1 + so));
            CP_ASYNC16(dst + 2 * TILEB,  (const char*)(s2 + so));
            CP_ASYNC16(dst + 3 * TILEB,  (const char*)(s3 + so));
        }
        CP_COMMIT();
    };

    float acc[4][4][4];
    #pragma unroll
    for (int mi = 0; mi < 4; mi++)
        #pragma unroll
        for (int nb = 0; nb < 4; nb++)
            #pragma unroll
            for (int j = 0; j < 4; j++) acc[mi][nb][j] = 0.f;

    const uint32_t a_off = (uint32_t)((wm * 64 + (lane & 15)) * 144 + (lane >> 4) * 16);
    const uint32_t b_off = (uint32_t)((wn * 32 + ((lane >> 4) & 1) * 8 + (lane & 7)) * 144
                                      + ((lane >> 3) & 1) * 16);

    load_chunk(0, 0);

    for (int c = 0; c < nk; c++) {
        if (c + 1 < nk) { load_chunk(c + 1, (c + 1) & 1); CP_WAIT(1); }
        else            { CP_WAIT(0); }
        __syncthreads();

        uint32_t buf = sb + (c & 1) * CHUNKB;
        #pragma unroll
        for (int s = 0; s < 4; s++) {
            uint32_t ah[4][4], al[4][4], wh[2][4], wl[2][4];
            #pragma unroll
            for (int g = 0; g < 4; g++) {
                uint32_t ao = buf + a_off + (uint32_t)(g * 16 * 144 + s * 32);
                ldm_x4(ah[g], ao);
                ldm_x4(al[g], ao + TILEB);
            }
            #pragma unroll
            for (int h = 0; h < 2; h++) {
                uint32_t bo = buf + 2 * TILEB + b_off + (uint32_t)(h * 16 * 144 + s * 32);
                ldm_x4(wh[h], bo);
                ldm_x4(wl[h], bo + TILEB);
            }
            #pragma unroll
            for (int mi = 0; mi < 4; mi++) {
                #pragma unroll
                for (int nb = 0; nb < 4; nb++) {
                    const int h = nb >> 1, j = nb & 1;
                    mma16816(acc[mi][nb], ah[mi], wh[h][2 * j], wh[h][2 * j + 1]);
                    mma16816(acc[mi][nb], ah[mi], wl[h][2 * j], wl[h][2 * j + 1]);
                    mma16816(acc[mi][nb], al[mi], wh[h][2 * j], wh[h][2 * j + 1]);
                }
            }
        }
        __syncthreads();
    }

    epilogue(acc, wm, wn, lane);
}

// ---------------------------------------------------------------------------
// Generic GEMM + bias -> fp32 C (optionally also emit bf16 hi/lo split)
// ---------------------------------------------------------------------------
template <bool SPLIT>
__global__ __launch_bounds__(256, 1)
void gemm_mma(const __nv_bfloat16* __restrict__ Ah,
              const __nv_bfloat16* __restrict__ Al,
              const __nv_bfloat16* __restrict__ Wh,
              const __nv_bfloat16* __restrict__ Wl,
              const float* __restrict__ bias,
              float* __restrict__ C, int N, int K,
              __nv_bfloat16* __restrict__ oh, __nv_bfloat16* __restrict__ ol) {
    extern __shared__ char smem[];
    const int brow = blockIdx.y * 128;
    const int bcol = blockIdx.x * 128;
    gemm_core(Ah + (size_t)brow * K, Al + (size_t)brow * K,
              Wh + (size_t)bcol * K, Wl + (size_t)bcol * K, K, smem,
        [&](float acc[4][4][4], int wm, int wn, int lane) {
            #pragma unroll
            for (int mi = 0; mi < 4; mi++) {
                int row = brow + wm * 64 + mi * 16 + (lane >> 2);
                #pragma unroll
                for (int nb = 0; nb < 4; nb++) {
                    int col = bcol + wn * 32 + nb * 8 + (lane & 3) * 2;
                    float b0 = bias[col], b1 = bias[col + 1];
                    float c00 = acc[mi][nb][0] + b0, c01 = acc[mi][nb][1] + b1;
                    float c10 = acc[mi][nb][2] + b0, c11 = acc[mi][nb][3] + b1;
                    size_t i0 = (size_t)row * N + col;
                    size_t i1 = (size_t)(row + 8) * N + col;
                    *(float2*)(C + i0) = make_float2(c00, c01);
                    *(float2*)(C + i1) = make_float2(c10, c11);
                    if (SPLIT) {
                        uint32_t hw, lw;
                        split2(c00, c01, hw, lw);
                        *(uint32_t*)(oh + i0) = hw; *(uint32_t*)(ol + i0) = lw;
                        split2(c10, c11, hw, lw);
                        *(uint32_t*)(oh + i1) = hw; *(uint32_t*)(ol + i1) = lw;
                    }
                }
            }
        });
}

// ---------------------------------------------------------------------------
// Fused QKV GEMM (N=3072, weights contiguous)
// ---------------------------------------------------------------------------
__global__ __launch_bounds__(256, 1)
void gemm_qkv(const __nv_bfloat16* __restrict__ Ah,
              const __nv_bfloat16* __restrict__ Al,
              const __nv_bfloat16* __restrict__ Wh,
              const __nv_bfloat16* __restrict__ Wl,
              const float* __restrict__ bias,   // [3072]
              __nv_bfloat16* __restrict__ qh, __nv_bfloat16* __restrict__ ql,
              __nv_bfloat16* __restrict__ kh, __nv_bfloat16* __restrict__ kl,
              float* __restrict__ vout) {
    extern __shared__ char smem[];
    const int K = D_;
    const int brow = blockIdx.y * 128;
    const int bcol = blockIdx.x * 128;
    const int mat = bcol >> 10;            // 0=q 1=k 2=v
    const int colb = bcol & 1023;
    gemm_core(Ah + (size_t)brow * K, Al + (size_t)brow * K,
              Wh + (size_t)bcol * K, Wl + (size_t)bcol * K, K, smem,
        [&](float acc[4][4][4], int wm, int wn, int lane) {
            #pragma unroll
            for (int mi = 0; mi < 4; mi++) {
                int row = brow + wm * 64 + mi * 16 + (lane >> 2);
                #pragma unroll
                for (int nb = 0; nb < 4; nb++) {
                    int col = colb + wn * 32 + nb * 8 + (lane & 3) * 2;
                    float b0 = bias[(mat << 10) + col], b1 = bias[(mat << 10) + col + 1];
                    float c00 = acc[mi][nb][0] + b0, c01 = acc[mi][nb][1] + b1;
                    float c10 = acc[mi][nb][2] + b0, c11 = acc[mi][nb][3] + b1;
                    size_t i0 = (size_t)row * D_ + col;
                    size_t i1 = (size_t)(row + 8) * D_ + col;
                    if (mat == 2) {
                        *(float2*)(vout + i0) = make_float2(c00, c01);
                        *(float2*)(vout + i1) = make_float2(c10, c11);
                    } else {
                        __nv_bfloat16* hB = (mat == 0) ? qh : kh;
                        __nv_bfloat16* lB = (mat == 0) ? ql : kl;
                        if (mat == 0) { c00 *= 0.125f; c01 *= 0.125f; c10 *= 0.125f; c11 *= 0.125f; }
                        uint32_t hw, lw;
                        split2(c00, c01, hw, lw);
                        *(uint32_t*)(hB + i0) = hw; *(uint32_t*)(lB + i0) = lw;
                        split2(c10, c11, hw, lw);
                        *(uint32_t*)(hB + i1) = hw; *(uint32_t*)(lB + i1) = lw;
                    }
                }
            }
        });
}

// ---------------------------------------------------------------------------
// Tensor-core flash attention; output as bf16 hi/lo split
// ---------------------------------------------------------------------------
#define AST      36864
#define AKL      9216
#define AMASK    (3 * AST)
#define ATT_SMEM (AMASK + 3 * 256)

__global__ __launch_bounds__(256, 1)
void attn_mma(const __nv_bfloat16* __restrict__ qh, const __nv_bfloat16* __restrict__ ql,
              const __nv_bfloat16* __restrict__ kh, const __nv_bfloat16* __restrict__ kl,
              const __nv_bfloat16* __restrict__ vth, const __nv_bfloat16* __restrict__ vtl,
              const int* __restrict__ mask,
              __nv_bfloat16* __restrict__ oh, __nv_bfloat16* __restrict__ ol) {
    extern __shared__ char smem[];
    const uint32_t sb = smem_u32(smem);
    const int tid = threadIdx.x, wid = tid >> 5, lane = tid & 31;
    const int q0 = blockIdx.x * 128;
    const int bh = blockIdx.y;
    const int b = bh >> 4, h = bh & 15;
    const size_t rowbase = (size_t)b * S_;

    #pragma unroll
    for (int i = 0; i < 4; i++) {
        int t = tid + i * 256;
        int row = t >> 3, seg = t & 7;
        uint32_t dst = sb + row * 144 + seg * 16;
        size_t so = (rowbase + q0 + row) * D_ + h * HD_ + seg * 8;
        CP_ASYNC16(dst,         (const char*)(qh + so));
        CP_ASYNC16(dst + 18432, (const char*)(ql + so));
    }
    CP_COMMIT(); CP_WAIT(0);
    __syncthreads();

    uint32_t qhf[4][4], qlf[4][4];
    #pragma unroll
    for (int s = 0; s < 4; s++) {
        uint32_t a = sb + (uint32_t)((wid * 16 + (lane & 15)) * 144 + (lane >> 4) * 16 + s * 32);
        ldm_x4(qhf[s], a);
        ldm_x4(qlf[s], a + 18432);
    }
    __syncthreads();

    auto load_kv = [&](int kt, int st) {
        uint32_t buf = sb + st * AST;
        int key0 = kt * 64;
        #pragma unroll
        for (int i = 0; i < 2; i++) {
            int t = tid + i * 256;
            int row = t >> 3, seg = t & 7;
            uint32_t dst = buf + row * 144 + seg * 16;
            size_t sk = (rowbase + key0 + row) * D_ + h * HD_ + seg * 8;
            CP_ASYNC16(dst,           (const char*)(kh + sk));
            CP_ASYNC16(dst + AKL,     (const char*)(kl + sk));
            size_t sv = ((size_t)bh * HD_ + row) * S_ + key0 + seg * 8;
            CP_ASYNC16(dst + 2 * AKL, (const char*)(vth + sv));
            CP_ASYNC16(dst + 3 * AKL, (const char*)(vtl + sv));
        }
        if (tid < 16)
            CP_ASYNC16(sb + AMASK + st * 256 + tid * 16,
                       (const char*)(mask + b * S_ + key0 + tid * 4));
        CP_COMMIT();
    };

    float oacc[8][4];
    #pragma unroll
    for (int nb = 0; nb < 8; nb++)
        #pragma unroll
        for (int j = 0; j < 4; j++) oacc[nb][j] = 0.f;
    float mrow0 = -1e30f, mrow1 = -1e30f, lrow0 = 0.f, lrow1 = 0.f;

    const uint32_t bfrag_off = (uint32_t)((((lane >> 4) & 1) * 8 + (lane & 7)) * 144
                                          + ((lane >> 3) & 1) * 16);

    load_kv(0, 0);
    load_kv(1, 1);

    const int NKT = S_ / 64;
    for (int kt = 0; kt < NKT; kt++) {
        if (kt + 2 < NKT)      { load_kv(kt + 2, (kt + 2) % 3); CP_WAIT(2); }
        else if (kt + 1 < NKT) { CP_WAIT(1); }
        else                   { CP_WAIT(0); }
        __syncthreads();

        uint32_t buf = sb + (kt % 3) * AST;

        float sacc[8][4];
        #pragma unroll
        for (int nb = 0; nb < 8; nb++)
            #pragma unroll
            for (int j = 0; j < 4; j++) sacc[nb][j] = 0.f;

        #pragma unroll
        for (int s = 0; s < 4; s++) {
            uint32_t khf[4][4], klf[4][4];
            #pragma unroll
            for (int g = 0; g < 4; g++) {
                uint32_t a = buf + bfrag_off + (uint32_t)(g * 16 * 144 + s * 32);
                ldm_x4(khf[g], a);
                ldm_x4(klf[g], a + AKL);
            }
            #pragma unroll
            for (int g = 0; g < 4; g++) {
                #pragma unroll
                for (int j = 0; j < 2; j++) {
                    int nb = g * 2 + j;
                    mma16816(sacc[nb], qhf[s], khf[g][2 * j], khf[g][2 * j + 1]);
                    mma16816(sacc[nb], qhf[s], klf[g][2 * j], klf[g][2 * j + 1]);
                    mma16816(sacc[nb], qlf[s], khf[g][2 * j], khf[g][2 * j + 1]);
                }
            }
        }

        {
            const int* smk = (const int*)(smem + AMASK + (kt % 3) * 256);
            int cb = 2 * (lane & 3);
            #pragma unroll
            for (int nb = 0; nb < 8; nb++) {
                if (smk[nb * 8 + cb] == 0)     { sacc[nb][0] = -1e9f; sacc[nb][2] = -1e9f; }
                if (smk[nb * 8 + cb + 1] == 0) { sacc[nb][1] = -1e9f; sacc[nb][3] = -1e9f; }
            }
        }

        float mx0 = -1e30f, mx1 = -1e30f;
        #pragma unroll
        for (int nb = 0; nb < 8; nb++) {
            mx0 = fmaxf(mx0, fmaxf(sacc[nb][0], sacc[nb][1]));
            mx1 = fmaxf(mx1, fmaxf(sacc[nb][2], sacc[nb][3]));
        }
        mx0 = fmaxf(mx0, __shfl_xor_sync(0xffffffffu, mx0, 1));
        mx0 = fmaxf(mx0, __shfl_xor_sync(0xffffffffu, mx0, 2));
        mx1 = fmaxf(mx1, __shfl_xor_sync(0xffffffffu, mx1, 1));
        mx1 = fmaxf(mx1, __shfl_xor_sync(0xffffffffu, mx1, 2));
        float mn0 = fmaxf(mrow0, mx0), mn1 = fmaxf(mrow1, mx1);
        float corr0 = __expf(mrow0 - mn0), corr1 = __expf(mrow1 - mn1);
        float sum0 = 0.f, sum1 = 0.f;
        #pragma unroll
        for (int nb = 0; nb < 8; nb++) {
            sacc[nb][0] = __expf(sacc[nb][0] - mn0);
            sacc[nb][1] = __expf(sacc[nb][1] - mn0);
            sacc[nb][2] = __expf(sacc[nb][2] - mn1);
            sacc[nb][3] = __expf(sacc[nb][3] - mn1);
            sum0 += sacc[nb][0] + sacc[nb][1];
            sum1 += sacc[nb][2] + sacc[nb][3];
        }
        sum0 += __shfl_xor_sync(0xffffffffu, sum0, 1);
        sum0 += __shfl_xor_sync(0xffffffffu, sum0, 2);
        sum1 += __shfl_xor_sync(0xffffffffu, sum1, 1);
        sum1 += __shfl_xor_sync(0xffffffffu, sum1, 2);
        lrow0 = lrow0 * corr0 + sum0;
        lrow1 = lrow1 * corr1 + sum1;
        mrow0 = mn0; mrow1 = mn1;
        #pragma unroll
        for (int nb = 0; nb < 8; nb++) {
            oacc[nb][0] *= corr0; oacc[nb][1] *= corr0;
            oacc[nb][2] *= corr1; oacc[nb][3] *= corr1;
        }

        #pragma unroll
        for (int c = 0; c < 4; c++) {
            uint32_t pha[4], pla[4];
            #pragma unroll
            for (int half = 0; half < 2; half++) {
                int nb = 2 * c + half;
                __nv_bfloat16 b0 = __float2bfloat16(sacc[nb][0]);
                __nv_bfloat16 b1 = __float2bfloat16(sacc[nb][1]);
                __nv_bfloat16 b2 = __float2bfloat16(sacc[nb][2]);
                __nv_bfloat16 b3 = __float2bfloat16(sacc[nb][3]);
                __nv_bfloat162 t01; t01.x = b0; t01.y = b1;
                __nv_bfloat162 t23; t23.x = b2; t23.y = b3;
                pha[half * 2 + 0] = *(uint32_t*)&t01;
                pha[half * 2 + 1] = *(uint32_t*)&t23;
                pla[half * 2 + 0] = pk_bf16(sacc[nb][0] - __bfloat162float(b0),
                                            sacc[nb][1] - __bfloat162float(b1));
                pla[half * 2 + 1] = pk_bf16(sacc[nb][2] - __bfloat162float(b2),
                                            sacc[nb][3] - __bfloat162float(b3));
            }
            uint32_t vhf[4][4], vlf[4][4];
            #pragma unroll
            for (int g = 0; g < 4; g++) {
                uint32_t a = buf + 2 * AKL + bfrag_off + (uint32_t)(g * 16 * 144 + c * 32);
                ldm_x4(vhf[g], a);
                ldm_x4(vlf[g], a + AKL);
            }
            #pragma unroll
            for (int g = 0; g < 4; g++) {
                #pragma unroll
                for (int j = 0; j < 2; j++) {
                    int nb = g * 2 + j;
                    mma16816(oacc[nb], pha, vhf[g][2 * j], vhf[g][2 * j + 1]);
                    mma16816(oacc[nb], pha, vlf[g][2 * j], vlf[g][2 * j + 1]);
                    mma16816(oacc[nb], pla, vhf[g][2 * j], vhf[g][2 * j + 1]);
                }
            }
        }
        __syncthreads();
    }

    float inv0 = 1.0f / lrow0, inv1 = 1.0f / lrow1;
    int r0 = q0 + wid * 16 + (lane >> 2);
    #pragma unroll
    for (int nb = 0; nb < 8; nb++) {
        int col = h * HD_ + nb * 8 + 2 * (lane & 3);
        size_t i0 = (rowbase + r0) * D_ + col;
        size_t i1 = (rowbase + r0 + 8) * D_ + col;
        uint32_t hw, lw;
        split2(oacc[nb][0] * inv0, oacc[nb][1] * inv0, hw, lw);
        *(uint32_t*)(oh + i0) = hw; *(uint32_t*)(ol + i0) = lw;
        split2(oacc[nb][2] * inv1, oacc[nb][3] * inv1, hw, lw);
        *(uint32_t*)(oh + i1) = hw; *(uint32_t*)(ol + i1) = lw;
    }
}

// ---------------------------------------------------------------------------
// Fused residual add + LayerNorm
// ---------------------------------------------------------------------------
template <bool SPLIT>
__global__ __launch_bounds__(256)
void add_ln(const float* __restrict__ x, const float* __restrict__ y,
            const float* __restrict__ g, const float* __restrict__ bta,
            float* __restrict__ out,
            __nv_bfloat16* __restrict__ oh, __nv_bfloat16* __restrict__ ol) {
    __shared__ float red[256];
    int row = blockIdx.x, tid = threadIdx.x;
    const float* xr = x + (size_t)row * D_;
    const float* yr = y + (size_t)row * D_;

    float v[4];
    float sum = 0.f;
    #pragma unroll
    for (int i = 0; i < 4; i++) {
        int c = tid + i * 256;
        v[i] = xr[c] + yr[c];
        sum += v[i];
    }
    red[tid] = sum; __syncthreads();
    for (int s = 128; s; s >>= 1) { if (tid < s) red[tid] += red[tid + s]; __syncthreads(); }
    float mu = red[0] * (1.0f / 1024.0f);
    __syncthreads();

    float sq = 0.f;
    #pragma unroll
    for (int i = 0; i < 4; i++) { float d = v[i] - mu; sq += d * d; }
    red[tid] = sq; __syncthreads();
    for (int s = 128; s; s >>= 1) { if (tid < s) red[tid] += red[tid + s]; __syncthreads(); }
    float var  = red[0] * (1.0f / 1024.0f);
    float rstd = rsqrtf(var + 1e-5f);

    #pragma unroll
    for (int i = 0; i < 4; i++) {
        int c = tid + i * 256;
        float o = (v[i] - mu) * rstd * g[c] + bta[c];
        out[(size_t)row * D_ + c] = o;
        if (SPLIT) {
            __nv_bfloat16 h = __float2bfloat16(o);
            oh[(size_t)row * D_ + c] = h;
            ol[(size_t)row * D_ + c] = __float2bfloat16(o - __bfloat162float(h));
        }
    }
}

// ---------------------------------------------------------------------------
// Launch
// ---------------------------------------------------------------------------
extern "C" void kernel_launch(void* const* d_in, const int* in_sizes, int n_in,
                              void* d_out, int out_size) {
    const int*   seq    = (const int*)  d_in[0];
    const int*   mask   = (const int*)  d_in[1];
    const float* emb    = (const float*)d_in[2];
    const float* proj_w = (const float*)d_in[3];
    const float* proj_b = (const float*)d_in[4];
    const float* qw     = (const float*)d_in[5];
    const float* qb     = (const float*)d_in[6];
    const float* kw     = (const float*)d_in[7];
    const float* kb     = (const float*)d_in[8];
    const float* vw     = (const float*)d_in[9];
    const float* vb     = (const float*)d_in[10];
    const float* ow     = (const float*)d_in[11];
    const float* ob     = (const float*)d_in[12];
    const float* lng    = (const float*)d_in[13];
    const float* lnb    = (const float*)d_in[14];
    float* out = (float*)d_out;

    float *x, *v, *t, *bqkv;
    __nv_bfloat16 *ah, *al, *wth, *wtl, *qhp, *qlp, *khp, *klp, *vthp, *vtlp;
    cudaGetSymbolAddress((void**)&x,    g_x);
    cudaGetSymbolAddress((void**)&v,    g_v);
    cudaGetSymbolAddress((void**)&t,    g_t);
    cudaGetSymbolAddress((void**)&bqkv, g_bqkv);
    cudaGetSymbolAddress((void**)&ah,   g_ah);
    cudaGetSymbolAddress((void**)&al,   g_al);
    cudaGetSymbolAddress((void**)&wth,  g_wth);
    cudaGetSymbolAddress((void**)&wtl,  g_wtl);
    cudaGetSymbolAddress((void**)&qhp,  g_qh);
    cudaGetSymbolAddress((void**)&qlp,  g_ql);
    cudaGetSymbolAddress((void**)&khp,  g_kh);
    cudaGetSymbolAddress((void**)&klp,  g_kl);
    cudaGetSymbolAddress((void**)&vthp, g_vth);
    cudaGetSymbolAddress((void**)&vtlp, g_vtl);

    cudaFuncSetAttribute(gemm_mma<false>, cudaFuncAttributeMaxDynamicSharedMemorySize, GEMM_SMEM);
    cudaFuncSetAttribute(gemm_mma<true>,  cudaFuncAttributeMaxDynamicSharedMemorySize, GEMM_SMEM);
    cudaFuncSetAttribute(gemm_qkv, cudaFuncAttributeMaxDynamicSharedMemorySize, GEMM_SMEM);
    cudaFuncSetAttribute(attn_mma, cudaFuncAttributeMaxDynamicSharedMemorySize, ATT_SMEM);

    // ---- weight prep ----
    {
        dim3 tb(32, 8);
        tsplit_w<<<dim3(D_ / 32, SEQDIM_ / 32), tb>>>(proj_w, wth, wtl, SEQDIM_, D_);
        tsplit_all<<<dim3(D_ / 32, D_ / 32, 24), tb>>>(qw, kw, vw, ow, wth, wtl);
        bias_concat<<<(L_ * 3 * D_ + 255) / 256, 256>>>(qb, kb, vb, bqkv);
    }

    // ---- embedding (direct split into q-scratch) + input projection ----
    gather_emb<<<(ROWS_ * SEQDIM_ / 2 + 255) / 256, 256>>>(seq, emb, qhp, qlp);
    dim3 gp(D_ / 128, ROWS_ / 128);
    gemm_mma<true><<<gp, 256, GEMM_SMEM>>>(qhp, qlp, wth, wtl, proj_b, x, D_, SEQDIM_, ah, al);

    dim3 gqkv(3 * D_ / 128, ROWS_ / 128);        // (24, 64)
    dim3 ga(S_ / 128, B_ * H_);                  // (16, 64)
    dim3 vg(S_ / 32, B_ * H_);
    dim3 vb8(32, 8);
    for (int l = 0; l < L_; l++) {
        size_t off = WT_PROJ_ELEMS + (size_t)(l * 4) * WT_MAT_ELEMS;
        const __nv_bfloat16* owh = wth + off + 3 * WT_MAT_ELEMS;
        const __nv_bfloat16* owl = wtl + off + 3 * WT_MAT_ELEMS;

        gemm_qkv<<<gqkv, 256, GEMM_SMEM>>>(ah, al, wth + off, wtl + off,
                                           bqkv + l * 3 * D_,
                                           qhp, qlp, khp, klp, v);
        vtsplit<<<vg, vb8>>>(v, vthp, vtlp);
        attn_mma<<<ga, 256, ATT_SMEM>>>(qhp, qlp, khp, klp, vthp, vtlp, mask, ah, al);
        gemm_mma<false><<<gp, 256, GEMM_SMEM>>>(ah, al, owh, owl, ob + l * D_, t, D_, D_,
                                                nullptr, nullptr);
        if (l == L_ - 1)
            add_ln<false><<<ROWS_, 256>>>(x, t, lng + l * D_, lnb + l * D_, out, nullptr, nullptr);
        else
            add_ln<true><<<ROWS_, 256>>>(x, t, lng + l * D_, lnb + l * D_, x, ah, al);
    }
}

// round 7
// speedup vs baseline: 3.2013x; 1.0063x over previous
#include <cuda_runtime.h>
#include <cuda_bf16.h>
#include <math.h>
#include <stdint.h>

// Problem constants
#define B_      4
#define S_      2048
#define D_      1024
#define H_      16
#define HD_     64
#define L_      6
#define SEQDIM_ 128
#define ROWS_   (B_ * S_)   // 8192

#define WT_PROJ_ELEMS (D_ * SEQDIM_)
#define WT_MAT_ELEMS  (D_ * D_)
#define WT_ELEMS      (WT_PROJ_ELEMS + 24 * WT_MAT_ELEMS)

// ---------------------------------------------------------------------------
// Device scratch
// ---------------------------------------------------------------------------
__device__ float g_x [ROWS_ * D_];
__device__ float g_v [ROWS_ * D_];
__device__ float g_t [ROWS_ * D_];
__device__ float g_bqkv[L_ * 3 * D_];
__device__ __nv_bfloat16 g_ah[ROWS_ * D_];
__device__ __nv_bfloat16 g_al[ROWS_ * D_];
__device__ __nv_bfloat16 g_wth[WT_ELEMS];
__device__ __nv_bfloat16 g_wtl[WT_ELEMS];
__device__ __nv_bfloat16 g_qh[ROWS_ * D_];
__device__ __nv_bfloat16 g_ql[ROWS_ * D_];
__device__ __nv_bfloat16 g_kh[ROWS_ * D_];
__device__ __nv_bfloat16 g_kl[ROWS_ * D_];
__device__ __nv_bfloat16 g_vth[ROWS_ * D_];   // [bh][64][S]
__device__ __nv_bfloat16 g_vtl[ROWS_ * D_];

// ---------------------------------------------------------------------------
// Helpers
// ---------------------------------------------------------------------------
__device__ __forceinline__ uint32_t smem_u32(const void* p) {
    uint32_t a;
    asm("{ .reg .u64 t; cvta.to.shared.u64 t, %1; cvt.u32.u64 %0, t; }"
        : "=r"(a) : "l"(p));
    return a;
}

__device__ __forceinline__ void ldm_x4(uint32_t* r, uint32_t addr) {
    asm volatile("ldmatrix.sync.aligned.m8n8.x4.shared.b16 {%0,%1,%2,%3}, [%4];"
                 : "=r"(r[0]), "=r"(r[1]), "=r"(r[2]), "=r"(r[3]) : "r"(addr));
}

__device__ __forceinline__ void mma16816(float* c, const uint32_t* a,
                                         uint32_t b0, uint32_t b1) {
    asm volatile(
        "mma.sync.aligned.m16n8k16.row.col.f32.bf16.bf16.f32 "
        "{%0,%1,%2,%3}, {%4,%5,%6,%7}, {%8,%9}, {%0,%1,%2,%3};"
        : "+f"(c[0]), "+f"(c[1]), "+f"(c[2]), "+f"(c[3])
        : "r"(a[0]), "r"(a[1]), "r"(a[2]), "r"(a[3]), "r"(b0), "r"(b1));
}

__device__ __forceinline__ uint32_t pk_bf16(float lo, float hi) {
    uint32_t r;
    asm("cvt.rn.bf16x2.f32 %0, %1, %2;" : "=r"(r) : "f"(hi), "f"(lo));
    return r;
}

__device__ __forceinline__ void split2(float c0, float c1, uint32_t& hw, uint32_t& lw) {
    __nv_bfloat16 h0 = __float2bfloat16(c0);
    __nv_bfloat16 h1 = __float2bfloat16(c1);
    __nv_bfloat162 hp; hp.x = h0; hp.y = h1;
    hw = *(uint32_t*)&hp;
    lw = pk_bf16(c0 - __bfloat162float(h0), c1 - __bfloat162float(h1));
}

#define CP_ASYNC16(dst, src) \
    asm volatile("cp.async.cg.shared.global [%0], [%1], 16;" :: "r"(dst), "l"(src))
#define CP_COMMIT() asm volatile("cp.async.commit_group;" ::: "memory")
#define CP_WAIT(n)  asm volatile("cp.async.wait_group %0;" :: "n"(n) : "memory")

// ---------------------------------------------------------------------------
// Embedding gather -> direct bf16 hi/lo split
// ---------------------------------------------------------------------------
__global__ void gather_emb(const int* __restrict__ seq,
                           const float* __restrict__ emb,
                           __nv_bfloat16* __restrict__ xh,
                           __nv_bfloat16* __restrict__ xl) {
    int i = blockIdx.x * blockDim.x + threadIdx.x;
    if (i >= ROWS_ * SEQDIM_ / 2) return;
    int row = i >> 6;
    int c2  = (i & 63) * 2;
    const float* e = emb + seq[row] * SEQDIM_ + c2;
    uint32_t hw, lw;
    split2(e[0], e[1], hw, lw);
    ((uint32_t*)xh)[i] = hw;
    ((uint32_t*)xl)[i] = lw;
}

// ---------------------------------------------------------------------------
// bias concat
// ---------------------------------------------------------------------------
__global__ void bias_concat(const float* __restrict__ qb, const float* __restrict__ kb,
                            const float* __restrict__ vb, float* __restrict__ o) {
    int idx = blockIdx.x * blockDim.x + threadIdx.x;
    if (idx >= L_ * 3 * D_) return;
    int l = idx / (3 * D_);
    int c = idx % (3 * D_);
    float v;
    if (c < D_)           v = qb[l * D_ + c];
    else if (c < 2 * D_)  v = kb[l * D_ + c - D_];
    else                  v = vb[l * D_ + c - 2 * D_];
    o[idx] = v;
}

// ---------------------------------------------------------------------------
// Weight transpose + split: proj_w only
// ---------------------------------------------------------------------------
__global__ void tsplit_w(const float* __restrict__ W,
                         __nv_bfloat16* __restrict__ th,
                         __nv_bfloat16* __restrict__ tl, int K, int N) {
    __shared__ float t[32][33];
    int bx = blockIdx.x * 32;
    int by = blockIdx.y * 32;
    #pragma unroll
    for (int i = 0; i < 32; i += 8)
        t[threadIdx.y + i][threadIdx.x] =
            W[(size_t)(by + threadIdx.y + i) * N + bx + threadIdx.x];
    __syncthreads();
    #pragma unroll
    for (int i = 0; i < 32; i += 8) {
        float v = t[threadIdx.x][threadIdx.y + i];
        int n = bx + threadIdx.y + i;
        int k = by + threadIdx.x;
        __nv_bfloat16 h = __float2bfloat16(v);
        th[(size_t)n * K + k] = h;
        tl[(size_t)n * K + k] = __float2bfloat16(v - __bfloat162float(h));
    }
}

// ---------------------------------------------------------------------------
// Batched weight transpose + split for 24 layer matrices
// ---------------------------------------------------------------------------
__global__ void tsplit_all(const float* __restrict__ qw, const float* __restrict__ kw,
                           const float* __restrict__ vw, const float* __restrict__ ow,
                           __nv_bfloat16* __restrict__ th,
                           __nv_bfloat16* __restrict__ tl) {
    __shared__ float t[32][33];
    int z = blockIdx.z;
    int l = z >> 2, m = z & 3;
    const float* W = (m == 0 ? qw : m == 1 ? kw : m == 2 ? vw : ow) + (size_t)l * D_ * D_;
    size_t dof = WT_PROJ_ELEMS + (size_t)z * WT_MAT_ELEMS;
    int bx = blockIdx.x * 32;
    int by = blockIdx.y * 32;
    #pragma unroll
    for (int i = 0; i < 32; i += 8)
        t[threadIdx.y + i][threadIdx.x] =
            W[(size_t)(by + threadIdx.y + i) * D_ + bx + threadIdx.x];
    __syncthreads();
    #pragma unroll
    for (int i = 0; i < 32; i += 8) {
        float v = t[threadIdx.x][threadIdx.y + i];
        int n = bx + threadIdx.y + i;
        int k = by + threadIdx.x;
        __nv_bfloat16 h = __float2bfloat16(v);
        th[dof + (size_t)n * D_ + k] = h;
        tl[dof + (size_t)n * D_ + k] = __float2bfloat16(v - __bfloat162float(h));
    }
}

// ---------------------------------------------------------------------------
// V transpose + split per head
// ---------------------------------------------------------------------------
__global__ void vtsplit(const float* __restrict__ v,
                        __nv_bfloat16* __restrict__ th,
                        __nv_bfloat16* __restrict__ tl) {
    __shared__ float t[32][33];
    int s0 = blockIdx.x * 32;
    int bh = blockIdx.y;
    int b  = bh >> 4, h = bh & 15;
    for (int dh = 0; dh < HD_; dh += 32) {
        #pragma unroll
        for (int i = 0; i < 32; i += 8)
            t[threadIdx.y + i][threadIdx.x] =
                v[(size_t)(b * S_ + s0 + threadIdx.y + i) * D_ + h * HD_ + dh + threadIdx.x];
        __syncthreads();
        #pragma unroll
        for (int i = 0; i < 32; i += 8) {
            float val = t[threadIdx.x][threadIdx.y + i];
            int d = dh + threadIdx.y + i;
            int s = s0 + threadIdx.x;
            __nv_bfloat16 hh = __float2bfloat16(val);
            th[((size_t)bh * HD_ + d) * S_ + s] = hh;
            tl[((size_t)bh * HD_ + d) * S_ + s] = __float2bfloat16(val - __bfloat162float(hh));
        }
        __syncthreads();
    }
}

// ---------------------------------------------------------------------------
// GEMM core: 256x128 block tile, 8 warps of 64x64, BK=64, 2-stage cp.async,
// 3-pass bf16 split. SMEM rows 144B stride (conflict-free ldmatrix).
// ---------------------------------------------------------------------------
#define ATILE  36864            // 256 * 144
#define WTILE  18432            // 128 * 144
#define CHUNKB (2 * ATILE + 2 * WTILE)   // 110592
#define GEMM_SMEM (2 * CHUNKB)           // 221184

template <typename EPI>
__device__ __forceinline__
void gemm_core(const __nv_bfloat16* s0, const __nv_bfloat16* s1,
               const __nv_bfloat16* s2, const __nv_bfloat16* s3,
               int K, char* smem, EPI epilogue) {
    const uint32_t sb = smem_u32(smem);
    const int tid  = threadIdx.x;
    const int lane = tid & 31;
    const int wid  = tid >> 5;
    const int wm = wid & 3;       // 0..3 (64-row group)
    const int wn = wid >> 2;      // 0..1 (64-col group)

    const int nk = K >> 6;

    auto load_chunk = [&](int c, int stage) {
        const int k0 = c << 6;
        uint32_t buf = sb + stage * CHUNKB;
        #pragma unroll
        for (int i = 0; i < 8; i++) {
            int t = tid + i * 256;            // 0..2047
            int row = t >> 3;
            int seg = t & 7;
            uint32_t dst = buf + row * 144 + seg * 16;
            size_t so = (size_t)row * K + k0 + seg * 8;
            CP_ASYNC16(dst,         (const char*)(s0 + so));
            CP_ASYNC16(dst + ATILE, (const char*)(s1 + so));
        }
        #pragma unroll
        for (int i = 0; i < 4; i++) {
            int t = tid + i * 256;            // 0..1023
            int row = t >> 3;
            int seg = t & 7;
            uint32_t dst = buf + 2 * ATILE + row * 144 + seg * 16;
            size_t so = (size_t)row * K + k0 + seg * 8;
            CP_ASYNC16(dst,         (const char*)(s2 + so));
            CP_ASYNC16(dst + WTILE, (const char*)(s3 + so));
        }
        CP_COMMIT();
    };

    float acc[4][8][4];
    #pragma unroll
    for (int mi = 0; mi < 4; mi++)
        #pragma unroll
        for (int nb = 0; nb < 8; nb++)
            #pragma unroll
            for (int j = 0; j < 4; j++) acc[mi][nb][j] = 0.f;

    const uint32_t a_off = (uint32_t)((wm * 64 + (lane & 15)) * 144 + (lane >> 4) * 16);
    const uint32_t b_off = (uint32_t)((wn * 64 + ((lane >> 4) & 1) * 8 + (lane & 7)) * 144
                                      + ((lane >> 3) & 1) * 16);

    load_chunk(0, 0);

    for (int c = 0; c < nk; c++) {
        if (c + 1 < nk) { load_chunk(c + 1, (c + 1) & 1); CP_WAIT(1); }
        else            { CP_WAIT(0); }
        __syncthreads();

        uint32_t buf = sb + (c & 1) * CHUNKB;
        #pragma unroll
        for (int s = 0; s < 4; s++) {
            uint32_t ah[4][4], al[4][4];
            #pragma unroll
            for (int mi = 0; mi < 4; mi++) {
                uint32_t ao = buf + a_off + (uint32_t)(mi * 16 * 144 + s * 32);
                ldm_x4(ah[mi], ao);
                ldm_x4(al[mi], ao + ATILE);
            }
            #pragma unroll
            for (int g = 0; g < 4; g++) {
                uint32_t wh[4], wl[4];
                uint32_t bo = buf + 2 * ATILE + b_off + (uint32_t)(g * 16 * 144 + s * 32);
                ldm_x4(wh, bo);
                ldm_x4(wl, bo + WTILE);
                #pragma unroll
                for (int mi = 0; mi < 4; mi++) {
                    #pragma unroll
                    for (int j = 0; j < 2; j++) {
                        int nb = g * 2 + j;
                        mma16816(acc[mi][nb], ah[mi], wh[2 * j], wh[2 * j + 1]);
                        mma16816(acc[mi][nb], ah[mi], wl[2 * j], wl[2 * j + 1]);
                        mma16816(acc[mi][nb], al[mi], wh[2 * j], wh[2 * j + 1]);
                    }
                }
            }
        }
        __syncthreads();
    }

    epilogue(acc, wm, wn, lane);
}

// ---------------------------------------------------------------------------
// Generic GEMM + bias -> fp32 C (optionally also emit bf16 hi/lo split)
// Block tile 256 rows x 128 cols.
// ---------------------------------------------------------------------------
template <bool SPLIT>
__global__ __launch_bounds__(256, 1)
void gemm_mma(const __nv_bfloat16* __restrict__ Ah,
              const __nv_bfloat16* __restrict__ Al,
              const __nv_bfloat16* __restrict__ Wh,
              const __nv_bfloat16* __restrict__ Wl,
              const float* __restrict__ bias,
              float* __restrict__ C, int N, int K,
              __nv_bfloat16* __restrict__ oh, __nv_bfloat16* __restrict__ ol) {
    extern __shared__ char smem[];
    const int brow = blockIdx.y * 256;
    const int bcol = blockIdx.x * 128;
    gemm_core(Ah + (size_t)brow * K, Al + (size_t)brow * K,
              Wh + (size_t)bcol * K, Wl + (size_t)bcol * K, K, smem,
        [&](float acc[4][8][4], int wm, int wn, int lane) {
            #pragma unroll
            for (int mi = 0; mi < 4; mi++) {
                int row = brow + wm * 64 + mi * 16 + (lane >> 2);
                #pragma unroll
                for (int nb = 0; nb < 8; nb++) {
                    int col = bcol + wn * 64 + nb * 8 + (lane & 3) * 2;
                    float b0 = bias[col], b1 = bias[col + 1];
                    float c00 = acc[mi][nb][0] + b0, c01 = acc[mi][nb][1] + b1;
                    float c10 = acc[mi][nb][2] + b0, c11 = acc[mi][nb][3] + b1;
                    size_t i0 = (size_t)row * N + col;
                    size_t i1 = (size_t)(row + 8) * N + col;
                    *(float2*)(C + i0) = make_float2(c00, c01);
                    *(float2*)(C + i1) = make_float2(c10, c11);
                    if (SPLIT) {
                        uint32_t hw, lw;
                        split2(c00, c01, hw, lw);
                        *(uint32_t*)(oh + i0) = hw; *(uint32_t*)(ol + i0) = lw;
                        split2(c10, c11, hw, lw);
                        *(uint32_t*)(oh + i1) = hw; *(uint32_t*)(ol + i1) = lw;
                    }
                }
            }
        });
}

// ---------------------------------------------------------------------------
// Fused QKV GEMM (N=3072, weights contiguous); block tile 256x128
// ---------------------------------------------------------------------------
__global__ __launch_bounds__(256, 1)
void gemm_qkv(const __nv_bfloat16* __restrict__ Ah,
              const __nv_bfloat16* __restrict__ Al,
              const __nv_bfloat16* __restrict__ Wh,
              const __nv_bfloat16* __restrict__ Wl,
              const float* __restrict__ bias,   // [3072]
              __nv_bfloat16* __restrict__ qh, __nv_bfloat16* __restrict__ ql,
              __nv_bfloat16* __restrict__ kh, __nv_bfloat16* __restrict__ kl,
              float* __restrict__ vout) {
    extern __shared__ char smem[];
    const int K = D_;
    const int brow = blockIdx.y * 256;
    const int bcol = blockIdx.x * 128;
    const int mat = bcol >> 10;            // 0=q 1=k 2=v
    const int colb = bcol & 1023;
    gemm_core(Ah + (size_t)brow * K, Al + (size_t)brow * K,
              Wh + (size_t)bcol * K, Wl + (size_t)bcol * K, K, smem,
        [&](float acc[4][8][4], int wm, int wn, int lane) {
            #pragma unroll
            for (int mi = 0; mi < 4; mi++) {
                int row = brow + wm * 64 + mi * 16 + (lane >> 2);
                #pragma unroll
                for (int nb = 0; nb < 8; nb++) {
                    int col = colb + wn * 64 + nb * 8 + (lane & 3) * 2;
                    float b0 = bias[(mat << 10) + col], b1 = bias[(mat << 10) + col + 1];
                    float c00 = acc[mi][nb][0] + b0, c01 = acc[mi][nb][1] + b1;
                    float c10 = acc[mi][nb][2] + b0, c11 = acc[mi][nb][3] + b1;
                    size_t i0 = (size_t)row * D_ + col;
                    size_t i1 = (size_t)(row + 8) * D_ + col;
                    if (mat == 2) {
                        *(float2*)(vout + i0) = make_float2(c00, c01);
                        *(float2*)(vout + i1) = make_float2(c10, c11);
                    } else {
                        __nv_bfloat16* hB = (mat == 0) ? qh : kh;
                        __nv_bfloat16* lB = (mat == 0) ? ql : kl;
                        if (mat == 0) { c00 *= 0.125f; c01 *= 0.125f; c10 *= 0.125f; c11 *= 0.125f; }
                        uint32_t hw, lw;
                        split2(c00, c01, hw, lw);
                        *(uint32_t*)(hB + i0) = hw; *(uint32_t*)(lB + i0) = lw;
                        split2(c10, c11, hw, lw);
                        *(uint32_t*)(hB + i1) = hw; *(uint32_t*)(lB + i1) = lw;
                    }
                }
            }
        });
}

// ---------------------------------------------------------------------------
// Tensor-core flash attention; output as bf16 hi/lo split
// ---------------------------------------------------------------------------
#define AST      36864
#define AKL      9216
#define AMASK    (3 * AST)
#define ATT_SMEM (AMASK + 3 * 256)

__global__ __launch_bounds__(256, 1)
void attn_mma(const __nv_bfloat16* __restrict__ qh, const __nv_bfloat16* __restrict__ ql,
              const __nv_bfloat16* __restrict__ kh, const __nv_bfloat16* __restrict__ kl,
              const __nv_bfloat16* __restrict__ vth, const __nv_bfloat16* __restrict__ vtl,
              const int* __restrict__ mask,
              __nv_bfloat16* __restrict__ oh, __nv_bfloat16* __restrict__ ol) {
    extern __shared__ char smem[];
    const uint32_t sb = smem_u32(smem);
    const int tid = threadIdx.x, wid = tid >> 5, lane = tid & 31;
    const int q0 = blockIdx.x * 128;
    const int bh = blockIdx.y;
    const int b = bh >> 4, h = bh & 15;
    const size_t rowbase = (size_t)b * S_;

    #pragma unroll
    for (int i = 0; i < 4; i++) {
        int t = tid + i * 256;
        int row = t >> 3, seg = t & 7;
        uint32_t dst = sb + row * 144 + seg * 16;
        size_t so = (rowbase + q0 + row) * D_ + h * HD_ + seg * 8;
        CP_ASYNC16(dst,         (const char*)(qh + so));
        CP_ASYNC16(dst + 18432, (const char*)(ql + so));
    }
    CP_COMMIT(); CP_WAIT(0);
    __syncthreads();

    uint32_t qhf[4][4], qlf[4][4];
    #pragma unroll
    for (int s = 0; s < 4; s++) {
        uint32_t a = sb + (uint32_t)((wid * 16 + (lane & 15)) * 144 + (lane >> 4) * 16 + s * 32);
        ldm_x4(qhf[s], a);
        ldm_x4(qlf[s], a + 18432);
    }
    __syncthreads();

    auto load_kv = [&](int kt, int st) {
        uint32_t buf = sb + st * AST;
        int key0 = kt * 64;
        #pragma unroll
        for (int i = 0; i < 2; i++) {
            int t = tid + i * 256;
            int row = t >> 3, seg = t & 7;
            uint32_t dst = buf + row * 144 + seg * 16;
            size_t sk = (rowbase + key0 + row) * D_ + h * HD_ + seg * 8;
            CP_ASYNC16(dst,           (const char*)(kh + sk));
            CP_ASYNC16(dst + AKL,     (const char*)(kl + sk));
            size_t sv = ((size_t)bh * HD_ + row) * S_ + key0 + seg * 8;
            CP_ASYNC16(dst + 2 * AKL, (const char*)(vth + sv));
            CP_ASYNC16(dst + 3 * AKL, (const char*)(vtl + sv));
        }
        if (tid < 16)
            CP_ASYNC16(sb + AMASK + st * 256 + tid * 16,
                       (const char*)(mask + b * S_ + key0 + tid * 4));
        CP_COMMIT();
    };

    float oacc[8][4];
    #pragma unroll
    for (int nb = 0; nb < 8; nb++)
        #pragma unroll
        for (int j = 0; j < 4; j++) oacc[nb][j] = 0.f;
    float mrow0 = -1e30f, mrow1 = -1e30f, lrow0 = 0.f, lrow1 = 0.f;

    const uint32_t bfrag_off = (uint32_t)((((lane >> 4) & 1) * 8 + (lane & 7)) * 144
                                          + ((lane >> 3) & 1) * 16);

    load_kv(0, 0);
    load_kv(1, 1);

    const int NKT = S_ / 64;
    for (int kt = 0; kt < NKT; kt++) {
        if (kt + 2 < NKT)      { load_kv(kt + 2, (kt + 2) % 3); CP_WAIT(2); }
        else if (kt + 1 < NKT) { CP_WAIT(1); }
        else                   { CP_WAIT(0); }
        __syncthreads();

        uint32_t buf = sb + (kt % 3) * AST;

        float sacc[8][4];
        #pragma unroll
        for (int nb = 0; nb < 8; nb++)
            #pragma unroll
            for (int j = 0; j < 4; j++) sacc[nb][j] = 0.f;

        #pragma unroll
        for (int s = 0; s < 4; s++) {
            uint32_t khf[4][4], klf[4][4];
            #pragma unroll
            for (int g = 0; g < 4; g++) {
                uint32_t a = buf + bfrag_off + (uint32_t)(g * 16 * 144 + s * 32);
                ldm_x4(khf[g], a);
                ldm_x4(klf[g], a + AKL);
            }
            #pragma unroll
            for (int g = 0; g < 4; g++) {
                #pragma unroll
                for (int j = 0; j < 2; j++) {
                    int nb = g * 2 + j;
                    mma16816(sacc[nb], qhf[s], khf[g][2 * j], khf[g][2 * j + 1]);
                    mma16816(sacc[nb], qhf[s], klf[g][2 * j], klf[g][2 * j + 1]);
                    mma16816(sacc[nb], qlf[s], khf[g][2 * j], khf[g][2 * j + 1]);
                }
            }
        }

        {
            const int* smk = (const int*)(smem + AMASK + (kt % 3) * 256);
            int cb = 2 * (lane & 3);
            #pragma unroll
            for (int nb = 0; nb < 8; nb++) {
                if (smk[nb * 8 + cb] == 0)     { sacc[nb][0] = -1e9f; sacc[nb][2] = -1e9f; }
                if (smk[nb * 8 + cb + 1] == 0) { sacc[nb][1] = -1e9f; sacc[nb][3] = -1e9f; }
            }
        }

        float mx0 = -1e30f, mx1 = -1e30f;
        #pragma unroll
        for (int nb = 0; nb < 8; nb++) {
            mx0 = fmaxf(mx0, fmaxf(sacc[nb][0], sacc[nb][1]));
            mx1 = fmaxf(mx1, fmaxf(sacc[nb][2], sacc[nb][3]));
        }
        mx0 = fmaxf(mx0, __shfl_xor_sync(0xffffffffu, mx0, 1));
        mx0 = fmaxf(mx0, __shfl_xor_sync(0xffffffffu, mx0, 2));
        mx1 = fmaxf(mx1, __shfl_xor_sync(0xffffffffu, mx1, 1));
        mx1 = fmaxf(mx1, __shfl_xor_sync(0xffffffffu, mx1, 2));
        float mn0 = fmaxf(mrow0, mx0), mn1 = fmaxf(mrow1, mx1);
        float corr0 = __expf(mrow0 - mn0), corr1 = __expf(mrow1 - mn1);
        float sum0 = 0.f, sum1 = 0.f;
        #pragma unroll
        for (int nb = 0; nb < 8; nb++) {
            sacc[nb][0] = __expf(sacc[nb][0] - mn0);
            sacc[nb][1] = __expf(sacc[nb][1] - mn0);
            sacc[nb][2] = __expf(sacc[nb][2] - mn1);
            sacc[nb][3] = __expf(sacc[nb][3] - mn1);
            sum0 += sacc[nb][0] + sacc[nb][1];
            sum1 += sacc[nb][2] + sacc[nb][3];
        }
        sum0 += __shfl_xor_sync(0xffffffffu, sum0, 1);
        sum0 += __shfl_xor_sync(0xffffffffu, sum0, 2);
        sum1 += __shfl_xor_sync(0xffffffffu, sum1, 1);
        sum1 += __shfl_xor_sync(0xffffffffu, sum1, 2);
        lrow0 = lrow0 * corr0 + sum0;
        lrow1 = lrow1 * corr1 + sum1;
        mrow0 = mn0; mrow1 = mn1;
        #pragma unroll
        for (int nb = 0; nb < 8; nb++) {
            oacc[nb][0] *= corr0; oacc[nb][1] *= corr0;
            oacc[nb][2] *= corr1; oacc[nb][3] *= corr1;
        }

        #pragma unroll
        for (int c = 0; c < 4; c++) {
            uint32_t pha[4], pla[4];
            #pragma unroll
            for (int half = 0; half < 2; half++) {
                int nb = 2 * c + half;
                __nv_bfloat16 b0 = __float2bfloat16(sacc[nb][0]);
                __nv_bfloat16 b1 = __float2bfloat16(sacc[nb][1]);
                __nv_bfloat16 b2 = __float2bfloat16(sacc[nb][2]);
                __nv_bfloat16 b3 = __float2bfloat16(sacc[nb][3]);
                __nv_bfloat162 t01; t01.x = b0; t01.y = b1;
                __nv_bfloat162 t23; t23.x = b2; t23.y = b3;
                pha[half * 2 + 0] = *(uint32_t*)&t01;
                pha[half * 2 + 1] = *(uint32_t*)&t23;
                pla[half * 2 + 0] = pk_bf16(sacc[nb][0] - __bfloat162float(b0),
                                            sacc[nb][1] - __bfloat162float(b1));
                pla[half * 2 + 1] = pk_bf16(sacc[nb][2] - __bfloat162float(b2),
                                            sacc[nb][3] - __bfloat162float(b3));
            }
            uint32_t vhf[4][4], vlf[4][4];
            #pragma unroll
            for (int g = 0; g < 4; g++) {
                uint32_t a = buf + 2 * AKL + bfrag_off + (uint32_t)(g * 16 * 144 + c * 32);
                ldm_x4(vhf[g], a);
                ldm_x4(vlf[g], a + AKL);
            }
            #pragma unroll
            for (int g = 0; g < 4; g++) {
                #pragma unroll
                for (int j = 0; j < 2; j++) {
                    int nb = g * 2 + j;
                    mma16816(oacc[nb], pha, vhf[g][2 * j], vhf[g][2 * j + 1]);
                    mma16816(oacc[nb], pha, vlf[g][2 * j], vlf[g][2 * j + 1]);
                    mma16816(oacc[nb], pla, vhf[g][2 * j], vhf[g][2 * j + 1]);
                }
            }
        }
        __syncthreads();
    }

    float inv0 = 1.0f / lrow0, inv1 = 1.0f / lrow1;
    int r0 = q0 + wid * 16 + (lane >> 2);
    #pragma unroll
    for (int nb = 0; nb < 8; nb++) {
        int col = h * HD_ + nb * 8 + 2 * (lane & 3);
        size_t i0 = (rowbase + r0) * D_ + col;
        size_t i1 = (rowbase + r0 + 8) * D_ + col;
        uint32_t hw, lw;
        split2(oacc[nb][0] * inv0, oacc[nb][1] * inv0, hw, lw);
        *(uint32_t*)(oh + i0) = hw; *(uint32_t*)(ol + i0) = lw;
        split2(oacc[nb][2] * inv1, oacc[nb][3] * inv1, hw, lw);
        *(uint32_t*)(oh + i1) = hw; *(uint32_t*)(ol + i1) = lw;
    }
}

// ---------------------------------------------------------------------------
// Fused residual add + LayerNorm
// ---------------------------------------------------------------------------
template <bool SPLIT>
__global__ __launch_bounds__(256)
void add_ln(const float* __restrict__ x, const float* __restrict__ y,
            const float* __restrict__ g, const float* __restrict__ bta,
            float* __restrict__ out,
            __nv_bfloat16* __restrict__ oh, __nv_bfloat16* __restrict__ ol) {
    __shared__ float red[256];
    int row = blockIdx.x, tid = threadIdx.x;
    const float* xr = x + (size_t)row * D_;
    const float* yr = y + (size_t)row * D_;

    float v[4];
    float sum = 0.f;
    #pragma unroll
    for (int i = 0; i < 4; i++) {
        int c = tid + i * 256;
        v[i] = xr[c] + yr[c];
        sum += v[i];
    }
    red[tid] = sum; __syncthreads();
    for (int s = 128; s; s >>= 1) { if (tid < s) red[tid] += red[tid + s]; __syncthreads(); }
    float mu = red[0] * (1.0f / 1024.0f);
    __syncthreads();

    float sq = 0.f;
    #pragma unroll
    for (int i = 0; i < 4; i++) { float d = v[i] - mu; sq += d * d; }
    red[tid] = sq; __syncthreads();
    for (int s = 128; s; s >>= 1) { if (tid < s) red[tid] += red[tid + s]; __syncthreads(); }
    float var  = red[0] * (1.0f / 1024.0f);
    float rstd = rsqrtf(var + 1e-5f);

    #pragma unroll
    for (int i = 0; i < 4; i++) {
        int c = tid + i * 256;
        float o = (v[i] - mu) * rstd * g[c] + bta[c];
        out[(size_t)row * D_ + c] = o;
        if (SPLIT) {
            __nv_bfloat16 h = __float2bfloat16(o);
            oh[(size_t)row * D_ + c] = h;
            ol[(size_t)row * D_ + c] = __float2bfloat16(o - __bfloat162float(h));
        }
    }
}

// ---------------------------------------------------------------------------
// Launch
// ---------------------------------------------------------------------------
extern "C" void kernel_launch(void* const* d_in, const int* in_sizes, int n_in,
                              void* d_out, int out_size) {
    const int*   seq    = (const int*)  d_in[0];
    const int*   mask   = (const int*)  d_in[1];
    const float* emb    = (const float*)d_in[2];
    const float* proj_w = (const float*)d_in[3];
    const float* proj_b = (const float*)d_in[4];
    const float* qw     = (const float*)d_in[5];
    const float* qb     = (const float*)d_in[6];
    const float* kw     = (const float*)d_in[7];
    const float* kb     = (const float*)d_in[8];
    const float* vw     = (const float*)d_in[9];
    const float* vb     = (const float*)d_in[10];
    const float* ow     = (const float*)d_in[11];
    const float* ob     = (const float*)d_in[12];
    const float* lng    = (const float*)d_in[13];
    const float* lnb    = (const float*)d_in[14];
    float* out = (float*)d_out;

    float *x, *v, *t, *bqkv;
    __nv_bfloat16 *ah, *al, *wth, *wtl, *qhp, *qlp, *khp, *klp, *vthp, *vtlp;
    cudaGetSymbolAddress((void**)&x,    g_x);
    cudaGetSymbolAddress((void**)&v,    g_v);
    cudaGetSymbolAddress((void**)&t,    g_t);
    cudaGetSymbolAddress((void**)&bqkv, g_bqkv);
    cudaGetSymbolAddress((void**)&ah,   g_ah);
    cudaGetSymbolAddress((void**)&al,   g_al);
    cudaGetSymbolAddress((void**)&wth,  g_wth);
    cudaGetSymbolAddress((void**)&wtl,  g_wtl);
    cudaGetSymbolAddress((void**)&qhp,  g_qh);
    cudaGetSymbolAddress((void**)&qlp,  g_ql);
    cudaGetSymbolAddress((void**)&khp,  g_kh);
    cudaGetSymbolAddress((void**)&klp,  g_kl);
    cudaGetSymbolAddress((void**)&vthp, g_vth);
    cudaGetSymbolAddress((void**)&vtlp, g_vtl);

    cudaFuncSetAttribute(gemm_mma<false>, cudaFuncAttributeMaxDynamicSharedMemorySize, GEMM_SMEM);
    cudaFuncSetAttribute(gemm_mma<true>,  cudaFuncAttributeMaxDynamicSharedMemorySize, GEMM_SMEM);
    cudaFuncSetAttribute(gemm_qkv, cudaFuncAttributeMaxDynamicSharedMemorySize, GEMM_SMEM);
    cudaFuncSetAttribute(attn_mma, cudaFuncAttributeMaxDynamicSharedMemorySize, ATT_SMEM);

    // ---- weight prep ----
    {
        dim3 tb(32, 8);
        tsplit_w<<<dim3(D_ / 32, SEQDIM_ / 32), tb>>>(proj_w, wth, wtl, SEQDIM_, D_);
        tsplit_all<<<dim3(D_ / 32, D_ / 32, 24), tb>>>(qw, kw, vw, ow, wth, wtl);
        bias_concat<<<(L_ * 3 * D_ + 255) / 256, 256>>>(qb, kb, vb, bqkv);
    }

    // ---- embedding (split staged in q-scratch) + input projection ----
    gather_emb<<<(ROWS_ * SEQDIM_ / 2 + 255) / 256, 256>>>(seq, emb, qhp, qlp);
    dim3 gp(D_ / 128, ROWS_ / 256);              // (8, 32)
    gemm_mma<true><<<gp, 256, GEMM_SMEM>>>(qhp, qlp, wth, wtl, proj_b, x, D_, SEQDIM_, ah, al);

    dim3 gqkv(3 * D_ / 128, ROWS_ / 256);        // (24, 32)
    dim3 ga(S_ / 128, B_ * H_);                  // (16, 64)
    dim3 vg(S_ / 32, B_ * H_);
    dim3 vb8(32, 8);
    for (int l = 0; l < L_; l++) {
        size_t off = WT_PROJ_ELEMS + (size_t)(l * 4) * WT_MAT_ELEMS;
        const __nv_bfloat16* owh = wth + off + 3 * WT_MAT_ELEMS;
        const __nv_bfloat16* owl = wtl + off + 3 * WT_MAT_ELEMS;

        gemm_qkv<<<gqkv, 256, GEMM_SMEM>>>(ah, al, wth + off, wtl + off,
                                           bqkv + l * 3 * D_,
                                           qhp, qlp, khp, klp, v);
        vtsplit<<<vg, vb8>>>(v, vthp, vtlp);
        attn_mma<<<ga, 256, ATT_SMEM>>>(qhp, qlp, khp, klp, vthp, vtlp, mask, ah, al);
        gemm_mma<false><<<gp, 256, GEMM_SMEM>>>(ah, al, owh, owl, ob + l * D_, t, D_, D_,
                                                nullptr, nullptr);
        if (l == L_ - 1)
            add_ln<false><<<ROWS_, 256>>>(x, t, lng + l * D_, lnb + l * D_, out, nullptr, nullptr);
        else
            add_ln<true><<<ROWS_, 256>>>(x, t, lng + l * D_, lnb + l * D_, x, ah, al);
    }
}

// round 8
// speedup vs baseline: 3.2115x; 1.0032x over previous
#include <cuda_runtime.h>
#include <cuda_bf16.h>
#include <math.h>
#include <stdint.h>

// Problem constants
#define B_      4
#define S_      2048
#define D_      1024
#define H_      16
#define HD_     64
#define L_      6
#define SEQDIM_ 128
#define ROWS_   (B_ * S_)   // 8192

#define WT_PROJ_ELEMS (D_ * SEQDIM_)
#define WT_MAT_ELEMS  (D_ * D_)
#define WT_ELEMS      (WT_PROJ_ELEMS + 24 * WT_MAT_ELEMS)

// ---------------------------------------------------------------------------
// Device scratch
// ---------------------------------------------------------------------------
__device__ float g_x [ROWS_ * D_];
__device__ float g_v [ROWS_ * D_];
__device__ float g_t [ROWS_ * D_];
__device__ float g_bqkv[L_ * 3 * D_];
__device__ __nv_bfloat16 g_ah[ROWS_ * D_];
__device__ __nv_bfloat16 g_al[ROWS_ * D_];
__device__ __nv_bfloat16 g_wth[WT_ELEMS];
__device__ __nv_bfloat16 g_wtl[WT_ELEMS];
__device__ __nv_bfloat16 g_qh[ROWS_ * D_];
__device__ __nv_bfloat16 g_ql[ROWS_ * D_];
__device__ __nv_bfloat16 g_kh[ROWS_ * D_];
__device__ __nv_bfloat16 g_kl[ROWS_ * D_];
__device__ __nv_bfloat16 g_vth[ROWS_ * D_];   // [bh][64][S]
__device__ __nv_bfloat16 g_vtl[ROWS_ * D_];

// ---------------------------------------------------------------------------
// Helpers
// ---------------------------------------------------------------------------
__device__ __forceinline__ uint32_t smem_u32(const void* p) {
    uint32_t a;
    asm("{ .reg .u64 t; cvta.to.shared.u64 t, %1; cvt.u32.u64 %0, t; }"
        : "=r"(a) : "l"(p));
    return a;
}

__device__ __forceinline__ void ldm_x4(uint32_t* r, uint32_t addr) {
    asm volatile("ldmatrix.sync.aligned.m8n8.x4.shared.b16 {%0,%1,%2,%3}, [%4];"
                 : "=r"(r[0]), "=r"(r[1]), "=r"(r[2]), "=r"(r[3]) : "r"(addr));
}

__device__ __forceinline__ void mma16816(float* c, const uint32_t* a,
                                         uint32_t b0, uint32_t b1) {
    asm volatile(
        "mma.sync.aligned.m16n8k16.row.col.f32.bf16.bf16.f32 "
        "{%0,%1,%2,%3}, {%4,%5,%6,%7}, {%8,%9}, {%0,%1,%2,%3};"
        : "+f"(c[0]), "+f"(c[1]), "+f"(c[2]), "+f"(c[3])
        : "r"(a[0]), "r"(a[1]), "r"(a[2]), "r"(a[3]), "r"(b0), "r"(b1));
}

__device__ __forceinline__ uint32_t pk_bf16(float lo, float hi) {
    uint32_t r;
    asm("cvt.rn.bf16x2.f32 %0, %1, %2;" : "=r"(r) : "f"(hi), "f"(lo));
    return r;
}

__device__ __forceinline__ void split2(float c0, float c1, uint32_t& hw, uint32_t& lw) {
    __nv_bfloat16 h0 = __float2bfloat16(c0);
    __nv_bfloat16 h1 = __float2bfloat16(c1);
    __nv_bfloat162 hp; hp.x = h0; hp.y = h1;
    hw = *(uint32_t*)&hp;
    lw = pk_bf16(c0 - __bfloat162float(h0), c1 - __bfloat162float(h1));
}

#define CP_ASYNC16(dst, src) \
    asm volatile("cp.async.cg.shared.global [%0], [%1], 16;" :: "r"(dst), "l"(src))
#define CP_COMMIT() asm volatile("cp.async.commit_group;" ::: "memory")
#define CP_WAIT(n)  asm volatile("cp.async.wait_group %0;" :: "n"(n) : "memory")

// ---------------------------------------------------------------------------
// Embedding gather -> direct bf16 hi/lo split
// ---------------------------------------------------------------------------
__global__ void gather_emb(const int* __restrict__ seq,
                           const float* __restrict__ emb,
                           __nv_bfloat16* __restrict__ xh,
                           __nv_bfloat16* __restrict__ xl) {
    int i = blockIdx.x * blockDim.x + threadIdx.x;
    if (i >= ROWS_ * SEQDIM_ / 2) return;
    int row = i >> 6;
    int c2  = (i & 63) * 2;
    const float* e = emb + seq[row] * SEQDIM_ + c2;
    uint32_t hw, lw;
    split2(e[0], e[1], hw, lw);
    ((uint32_t*)xh)[i] = hw;
    ((uint32_t*)xl)[i] = lw;
}

// ---------------------------------------------------------------------------
// bias concat
// ---------------------------------------------------------------------------
__global__ void bias_concat(const float* __restrict__ qb, const float* __restrict__ kb,
                            const float* __restrict__ vb, float* __restrict__ o) {
    int idx = blockIdx.x * blockDim.x + threadIdx.x;
    if (idx >= L_ * 3 * D_) return;
    int l = idx / (3 * D_);
    int c = idx % (3 * D_);
    float v;
    if (c < D_)           v = qb[l * D_ + c];
    else if (c < 2 * D_)  v = kb[l * D_ + c - D_];
    else                  v = vb[l * D_ + c - 2 * D_];
    o[idx] = v;
}

// ---------------------------------------------------------------------------
// Weight transpose + split: proj_w only
// ---------------------------------------------------------------------------
__global__ void tsplit_w(const float* __restrict__ W,
                         __nv_bfloat16* __restrict__ th,
                         __nv_bfloat16* __restrict__ tl, int K, int N) {
    __shared__ float t[32][33];
    int bx = blockIdx.x * 32;
    int by = blockIdx.y * 32;
    #pragma unroll
    for (int i = 0; i < 32; i += 8)
        t[threadIdx.y + i][threadIdx.x] =
            W[(size_t)(by + threadIdx.y + i) * N + bx + threadIdx.x];
    __syncthreads();
    #pragma unroll
    for (int i = 0; i < 32; i += 8) {
        float v = t[threadIdx.x][threadIdx.y + i];
        int n = bx + threadIdx.y + i;
        int k = by + threadIdx.x;
        __nv_bfloat16 h = __float2bfloat16(v);
        th[(size_t)n * K + k] = h;
        tl[(size_t)n * K + k] = __float2bfloat16(v - __bfloat162float(h));
    }
}

// ---------------------------------------------------------------------------
// Batched weight transpose + split for 24 layer matrices
// ---------------------------------------------------------------------------
__global__ void tsplit_all(const float* __restrict__ qw, const float* __restrict__ kw,
                           const float* __restrict__ vw, const float* __restrict__ ow,
                           __nv_bfloat16* __restrict__ th,
                           __nv_bfloat16* __restrict__ tl) {
    __shared__ float t[32][33];
    int z = blockIdx.z;
    int l = z >> 2, m = z & 3;
    const float* W = (m == 0 ? qw : m == 1 ? kw : m == 2 ? vw : ow) + (size_t)l * D_ * D_;
    size_t dof = WT_PROJ_ELEMS + (size_t)z * WT_MAT_ELEMS;
    int bx = blockIdx.x * 32;
    int by = blockIdx.y * 32;
    #pragma unroll
    for (int i = 0; i < 32; i += 8)
        t[threadIdx.y + i][threadIdx.x] =
            W[(size_t)(by + threadIdx.y + i) * D_ + bx + threadIdx.x];
    __syncthreads();
    #pragma unroll
    for (int i = 0; i < 32; i += 8) {
        float v = t[threadIdx.x][threadIdx.y + i];
        int n = bx + threadIdx.y + i;
        int k = by + threadIdx.x;
        __nv_bfloat16 h = __float2bfloat16(v);
        th[dof + (size_t)n * D_ + k] = h;
        tl[dof + (size_t)n * D_ + k] = __float2bfloat16(v - __bfloat162float(h));
    }
}

// ---------------------------------------------------------------------------
// V transpose + split per head
// ---------------------------------------------------------------------------
__global__ void vtsplit(const float* __restrict__ v,
                        __nv_bfloat16* __restrict__ th,
                        __nv_bfloat16* __restrict__ tl) {
    __shared__ float t[32][33];
    int s0 = blockIdx.x * 32;
    int bh = blockIdx.y;
    int b  = bh >> 4, h = bh & 15;
    for (int dh = 0; dh < HD_; dh += 32) {
        #pragma unroll
        for (int i = 0; i < 32; i += 8)
            t[threadIdx.y + i][threadIdx.x] =
                v[(size_t)(b * S_ + s0 + threadIdx.y + i) * D_ + h * HD_ + dh + threadIdx.x];
        __syncthreads();
        #pragma unroll
        for (int i = 0; i < 32; i += 8) {
            float val = t[threadIdx.x][threadIdx.y + i];
            int d = dh + threadIdx.y + i;
            int s = s0 + threadIdx.x;
            __nv_bfloat16 hh = __float2bfloat16(val);
            th[((size_t)bh * HD_ + d) * S_ + s] = hh;
            tl[((size_t)bh * HD_ + d) * S_ + s] = __float2bfloat16(val - __bfloat162float(hh));
        }
        __syncthreads();
    }
}

// ---------------------------------------------------------------------------
// GEMM core: 128x128 block tile, 8 warps of 64x32, BK=32, 2-stage cp.async,
// 3-pass bf16 split. 80B-stride rows (conflict-free). 2 CTAs per SM.
// ---------------------------------------------------------------------------
#define TILEB  10240            // 128 * 80
#define CHUNKB (4 * TILEB)      // 40960
#define GEMM_SMEM (2 * CHUNKB)  // 81920 -> 2 CTAs/SM

template <typename EPI>
__device__ __forceinline__
void gemm_core(const __nv_bfloat16* s0, const __nv_bfloat16* s1,
               const __nv_bfloat16* s2, const __nv_bfloat16* s3,
               int K, char* smem, EPI epilogue) {
    const uint32_t sb = smem_u32(smem);
    const int tid  = threadIdx.x;
    const int lane = tid & 31;
    const int wid  = tid >> 5;
    const int wm = wid & 1;       // 0..1 (64-row group)
    const int wn = wid >> 1;      // 0..3 (32-col group)

    const int nk = K >> 5;        // chunks of 32

    auto load_chunk = [&](int c, int stage) {
        const int k0 = c << 5;
        uint32_t buf = sb + stage * CHUNKB;
        #pragma unroll
        for (int i = 0; i < 2; i++) {
            int t = tid + i * 256;            // 0..511
            int row = t >> 2;
            int seg = t & 3;
            uint32_t dst = buf + row * 80 + seg * 16;
            size_t so = (size_t)row * K + k0 + seg * 8;
            CP_ASYNC16(dst,              (const char*)(s0 + so));
            CP_ASYNC16(dst + TILEB,      (const char*)(s1 + so));
            CP_ASYNC16(dst + 2 * TILEB,  (const char*)(s2 + so));
            CP_ASYNC16(dst + 3 * TILEB,  (const char*)(s3 + so));
        }
        CP_COMMIT();
    };

    float acc[4][4][4];
    #pragma unroll
    for (int mi = 0; mi < 4; mi++)
        #pragma unroll
        for (int nb = 0; nb < 4; nb++)
            #pragma unroll
            for (int j = 0; j < 4; j++) acc[mi][nb][j] = 0.f;

    const uint32_t a_off = (uint32_t)((wm * 64 + (lane & 15)) * 80 + (lane >> 4) * 16);
    const uint32_t b_off = (uint32_t)((wn * 32 + ((lane >> 4) & 1) * 8 + (lane & 7)) * 80
                                      + ((lane >> 3) & 1) * 16);

    load_chunk(0, 0);

    for (int c = 0; c < nk; c++) {
        if (c + 1 < nk) { load_chunk(c + 1, (c + 1) & 1); CP_WAIT(1); }
        else            { CP_WAIT(0); }
        __syncthreads();

        uint32_t buf = sb + (c & 1) * CHUNKB;
        #pragma unroll
        for (int s = 0; s < 2; s++) {
            uint32_t ah[4][4], al[4][4], wh[2][4], wl[2][4];
            #pragma unroll
            for (int g = 0; g < 4; g++) {
                uint32_t ao = buf + a_off + (uint32_t)(g * 16 * 80 + s * 32);
                ldm_x4(ah[g], ao);
                ldm_x4(al[g], ao + TILEB);
            }
            #pragma unroll
            for (int h = 0; h < 2; h++) {
                uint32_t bo = buf + 2 * TILEB + b_off + (uint32_t)(h * 16 * 80 + s * 32);
                ldm_x4(wh[h], bo);
                ldm_x4(wl[h], bo + TILEB);
            }
            #pragma unroll
            for (int mi = 0; mi < 4; mi++) {
                #pragma unroll
                for (int nb = 0; nb < 4; nb++) {
                    const int h = nb >> 1, j = nb & 1;
                    mma16816(acc[mi][nb], ah[mi], wh[h][2 * j], wh[h][2 * j + 1]);
                    mma16816(acc[mi][nb], ah[mi], wl[h][2 * j], wl[h][2 * j + 1]);
                    mma16816(acc[mi][nb], al[mi], wh[h][2 * j], wh[h][2 * j + 1]);
                }
            }
        }
        __syncthreads();
    }

    epilogue(acc, wm, wn, lane);
}

// ---------------------------------------------------------------------------
// Generic GEMM + bias -> fp32 C (optionally also emit bf16 hi/lo split)
// ---------------------------------------------------------------------------
template <bool SPLIT>
__global__ __launch_bounds__(256, 2)
void gemm_mma(const __nv_bfloat16* __restrict__ Ah,
              const __nv_bfloat16* __restrict__ Al,
              const __nv_bfloat16* __restrict__ Wh,
              const __nv_bfloat16* __restrict__ Wl,
              const float* __restrict__ bias,
              float* __restrict__ C, int N, int K,
              __nv_bfloat16* __restrict__ oh, __nv_bfloat16* __restrict__ ol) {
    extern __shared__ char smem[];
    const int brow = blockIdx.y * 128;
    const int bcol = blockIdx.x * 128;
    gemm_core(Ah + (size_t)brow * K, Al + (size_t)brow * K,
              Wh + (size_t)bcol * K, Wl + (size_t)bcol * K, K, smem,
        [&](float acc[4][4][4], int wm, int wn, int lane) {
            #pragma unroll
            for (int mi = 0; mi < 4; mi++) {
                int row = brow + wm * 64 + mi * 16 + (lane >> 2);
                #pragma unroll
                for (int nb = 0; nb < 4; nb++) {
                    int col = bcol + wn * 32 + nb * 8 + (lane & 3) * 2;
                    float b0 = bias[col], b1 = bias[col + 1];
                    float c00 = acc[mi][nb][0] + b0, c01 = acc[mi][nb][1] + b1;
                    float c10 = acc[mi][nb][2] + b0, c11 = acc[mi][nb][3] + b1;
                    size_t i0 = (size_t)row * N + col;
                    size_t i1 = (size_t)(row + 8) * N + col;
                    *(float2*)(C + i0) = make_float2(c00, c01);
                    *(float2*)(C + i1) = make_float2(c10, c11);
                    if (SPLIT) {
                        uint32_t hw, lw;
                        split2(c00, c01, hw, lw);
                        *(uint32_t*)(oh + i0) = hw; *(uint32_t*)(ol + i0) = lw;
                        split2(c10, c11, hw, lw);
                        *(uint32_t*)(oh + i1) = hw; *(uint32_t*)(ol + i1) = lw;
                    }
                }
            }
        });
}

// ---------------------------------------------------------------------------
// Fused QKV GEMM (N=3072, weights contiguous)
// ---------------------------------------------------------------------------
__global__ __launch_bounds__(256, 2)
void gemm_qkv(const __nv_bfloat16* __restrict__ Ah,
              const __nv_bfloat16* __restrict__ Al,
              const __nv_bfloat16* __restrict__ Wh,
              const __nv_bfloat16* __restrict__ Wl,
              const float* __restrict__ bias,   // [3072]
              __nv_bfloat16* __restrict__ qh, __nv_bfloat16* __restrict__ ql,
              __nv_bfloat16* __restrict__ kh, __nv_bfloat16* __restrict__ kl,
              float* __restrict__ vout) {
    extern __shared__ char smem[];
    const int K = D_;
    const int brow = blockIdx.y * 128;
    const int bcol = blockIdx.x * 128;
    const int mat = bcol >> 10;            // 0=q 1=k 2=v
    const int colb = bcol & 1023;
    gemm_core(Ah + (size_t)brow * K, Al + (size_t)brow * K,
              Wh + (size_t)bcol * K, Wl + (size_t)bcol * K, K, smem,
        [&](float acc[4][4][4], int wm, int wn, int lane) {
            #pragma unroll
            for (int mi = 0; mi < 4; mi++) {
                int row = brow + wm * 64 + mi * 16 + (lane >> 2);
                #pragma unroll
                for (int nb = 0; nb < 4; nb++) {
                    int col = colb + wn * 32 + nb * 8 + (lane & 3) * 2;
                    float b0 = bias[(mat << 10) + col], b1 = bias[(mat << 10) + col + 1];
                    float c00 = acc[mi][nb][0] + b0, c01 = acc[mi][nb][1] + b1;
                    float c10 = acc[mi][nb][2] + b0, c11 = acc[mi][nb][3] + b1;
                    size_t i0 = (size_t)row * D_ + col;
                    size_t i1 = (size_t)(row + 8) * D_ + col;
                    if (mat == 2) {
                        *(float2*)(vout + i0) = make_float2(c00, c01);
                        *(float2*)(vout + i1) = make_float2(c10, c11);
                    } else {
                        __nv_bfloat16* hB = (mat == 0) ? qh : kh;
                        __nv_bfloat16* lB = (mat == 0) ? ql : kl;
                        if (mat == 0) { c00 *= 0.125f; c01 *= 0.125f; c10 *= 0.125f; c11 *= 0.125f; }
                        uint32_t hw, lw;
                        split2(c00, c01, hw, lw);
                        *(uint32_t*)(hB + i0) = hw; *(uint32_t*)(lB + i0) = lw;
                        split2(c10, c11, hw, lw);
                        *(uint32_t*)(hB + i1) = hw; *(uint32_t*)(lB + i1) = lw;
                    }
                }
            }
        });
}

// ---------------------------------------------------------------------------
// Tensor-core flash attention; output as bf16 hi/lo split (unchanged)
// ---------------------------------------------------------------------------
#define AST      36864
#define AKL      9216
#define AMASK    (3 * AST)
#define ATT_SMEM (AMASK + 3 * 256)

__global__ __launch_bounds__(256, 1)
void attn_mma(const __nv_bfloat16* __restrict__ qh, const __nv_bfloat16* __restrict__ ql,
              const __nv_bfloat16* __restrict__ kh, const __nv_bfloat16* __restrict__ kl,
              const __nv_bfloat16* __restrict__ vth, const __nv_bfloat16* __restrict__ vtl,
              const int* __restrict__ mask,
              __nv_bfloat16* __restrict__ oh, __nv_bfloat16* __restrict__ ol) {
    extern __shared__ char smem[];
    const uint32_t sb = smem_u32(smem);
    const int tid = threadIdx.x, wid = tid >> 5, lane = tid & 31;
    const int q0 = blockIdx.x * 128;
    const int bh = blockIdx.y;
    const int b = bh >> 4, h = bh & 15;
    const size_t rowbase = (size_t)b * S_;

    #pragma unroll
    for (int i = 0; i < 4; i++) {
        int t = tid + i * 256;
        int row = t >> 3, seg = t & 7;
        uint32_t dst = sb + row * 144 + seg * 16;
        size_t so = (rowbase + q0 + row) * D_ + h * HD_ + seg * 8;
        CP_ASYNC16(dst,         (const char*)(qh + so));
        CP_ASYNC16(dst + 18432, (const char*)(ql + so));
    }
    CP_COMMIT(); CP_WAIT(0);
    __syncthreads();

    uint32_t qhf[4][4], qlf[4][4];
    #pragma unroll
    for (int s = 0; s < 4; s++) {
        uint32_t a = sb + (uint32_t)((wid * 16 + (lane & 15)) * 144 + (lane >> 4) * 16 + s * 32);
        ldm_x4(qhf[s], a);
        ldm_x4(qlf[s], a + 18432);
    }
    __syncthreads();

    auto load_kv = [&](int kt, int st) {
        uint32_t buf = sb + st * AST;
        int key0 = kt * 64;
        #pragma unroll
        for (int i = 0; i < 2; i++) {
            int t = tid + i * 256;
            int row = t >> 3, seg = t & 7;
            uint32_t dst = buf + row * 144 + seg * 16;
            size_t sk = (rowbase + key0 + row) * D_ + h * HD_ + seg * 8;
            CP_ASYNC16(dst,           (const char*)(kh + sk));
            CP_ASYNC16(dst + AKL,     (const char*)(kl + sk));
            size_t sv = ((size_t)bh * HD_ + row) * S_ + key0 + seg * 8;
            CP_ASYNC16(dst + 2 * AKL, (const char*)(vth + sv));
            CP_ASYNC16(dst + 3 * AKL, (const char*)(vtl + sv));
        }
        if (tid < 16)
            CP_ASYNC16(sb + AMASK + st * 256 + tid * 16,
                       (const char*)(mask + b * S_ + key0 + tid * 4));
        CP_COMMIT();
    };

    float oacc[8][4];
    #pragma unroll
    for (int nb = 0; nb < 8; nb++)
        #pragma unroll
        for (int j = 0; j < 4; j++) oacc[nb][j] = 0.f;
    float mrow0 = -1e30f, mrow1 = -1e30f, lrow0 = 0.f, lrow1 = 0.f;

    const uint32_t bfrag_off = (uint32_t)((((lane >> 4) & 1) * 8 + (lane & 7)) * 144
                                          + ((lane >> 3) & 1) * 16);

    load_kv(0, 0);
    load_kv(1, 1);

    const int NKT = S_ / 64;
    for (int kt = 0; kt < NKT; kt++) {
        if (kt + 2 < NKT)      { load_kv(kt + 2, (kt + 2) % 3); CP_WAIT(2); }
        else if (kt + 1 < NKT) { CP_WAIT(1); }
        else                   { CP_WAIT(0); }
        __syncthreads();

        uint32_t buf = sb + (kt % 3) * AST;

        float sacc[8][4];
        #pragma unroll
        for (int nb = 0; nb < 8; nb++)
            #pragma unroll
            for (int j = 0; j < 4; j++) sacc[nb][j] = 0.f;

        #pragma unroll
        for (int s = 0; s < 4; s++) {
            uint32_t khf[4][4], klf[4][4];
            #pragma unroll
            for (int g = 0; g < 4; g++) {
                uint32_t a = buf + bfrag_off + (uint32_t)(g * 16 * 144 + s * 32);
                ldm_x4(khf[g], a);
                ldm_x4(klf[g], a + AKL);
            }
            #pragma unroll
            for (int g = 0; g < 4; g++) {
                #pragma unroll
                for (int j = 0; j < 2; j++) {
                    int nb = g * 2 + j;
                    mma16816(sacc[nb], qhf[s], khf[g][2 * j], khf[g][2 * j + 1]);
                    mma16816(sacc[nb], qhf[s], klf[g][2 * j], klf[g][2 * j + 1]);
                    mma16816(sacc[nb], qlf[s], khf[g][2 * j], khf[g][2 * j + 1]);
                }
            }
        }

        {
            const int* smk = (const int*)(smem + AMASK + (kt % 3) * 256);
            int cb = 2 * (lane & 3);
            #pragma unroll
            for (int nb = 0; nb < 8; nb++) {
                if (smk[nb * 8 + cb] == 0)     { sacc[nb][0] = -1e9f; sacc[nb][2] = -1e9f; }
                if (smk[nb * 8 + cb + 1] == 0) { sacc[nb][1] = -1e9f; sacc[nb][3] = -1e9f; }
            }
        }

        float mx0 = -1e30f, mx1 = -1e30f;
        #pragma unroll
        for (int nb = 0; nb < 8; nb++) {
            mx0 = fmaxf(mx0, fmaxf(sacc[nb][0], sacc[nb][1]));
            mx1 = fmaxf(mx1, fmaxf(sacc[nb][2], sacc[nb][3]));
        }
        mx0 = fmaxf(mx0, __shfl_xor_sync(0xffffffffu, mx0, 1));
        mx0 = fmaxf(mx0, __shfl_xor_sync(0xffffffffu, mx0, 2));
        mx1 = fmaxf(mx1, __shfl_xor_sync(0xffffffffu, mx1, 1));
        mx1 = fmaxf(mx1, __shfl_xor_sync(0xffffffffu, mx1, 2));
        float mn0 = fmaxf(mrow0, mx0), mn1 = fmaxf(mrow1, mx1);
        float corr0 = __expf(mrow0 - mn0), corr1 = __expf(mrow1 - mn1);
        float sum0 = 0.f, sum1 = 0.f;
        #pragma unroll
        for (int nb = 0; nb < 8; nb++) {
            sacc[nb][0] = __expf(sacc[nb][0] - mn0);
            sacc[nb][1] = __expf(sacc[nb][1] - mn0);
            sacc[nb][2] = __expf(sacc[nb][2] - mn1);
            sacc[nb][3] = __expf(sacc[nb][3] - mn1);
            sum0 += sacc[nb][0] + sacc[nb][1];
            sum1 += sacc[nb][2] + sacc[nb][3];
        }
        sum0 += __shfl_xor_sync(0xffffffffu, sum0, 1);
        sum0 += __shfl_xor_sync(0xffffffffu, sum0, 2);
        sum1 += __shfl_xor_sync(0xffffffffu, sum1, 1);
        sum1 += __shfl_xor_sync(0xffffffffu, sum1, 2);
        lrow0 = lrow0 * corr0 + sum0;
        lrow1 = lrow1 * corr1 + sum1;
        mrow0 = mn0; mrow1 = mn1;
        #pragma unroll
        for (int nb = 0; nb < 8; nb++) {
            oacc[nb][0] *= corr0; oacc[nb][1] *= corr0;
            oacc[nb][2] *= corr1; oacc[nb][3] *= corr1;
        }

        #pragma unroll
        for (int c = 0; c < 4; c++) {
            uint32_t pha[4], pla[4];
            #pragma unroll
            for (int half = 0; half < 2; half++) {
                int nb = 2 * c + half;
                __nv_bfloat16 b0 = __float2bfloat16(sacc[nb][0]);
                __nv_bfloat16 b1 = __float2bfloat16(sacc[nb][1]);
                __nv_bfloat16 b2 = __float2bfloat16(sacc[nb][2]);
                __nv_bfloat16 b3 = __float2bfloat16(sacc[nb][3]);
                __nv_bfloat162 t01; t01.x = b0; t01.y = b1;
                __nv_bfloat162 t23; t23.x = b2; t23.y = b3;
                pha[half * 2 + 0] = *(uint32_t*)&t01;
                pha[half * 2 + 1] = *(uint32_t*)&t23;
                pla[half * 2 + 0] = pk_bf16(sacc[nb][0] - __bfloat162float(b0),
                                            sacc[nb][1] - __bfloat162float(b1));
                pla[half * 2 + 1] = pk_bf16(sacc[nb][2] - __bfloat162float(b2),
                                            sacc[nb][3] - __bfloat162float(b3));
            }
            uint32_t vhf[4][4], vlf[4][4];
            #pragma unroll
            for (int g = 0; g < 4; g++) {
                uint32_t a = buf + 2 * AKL + bfrag_off + (uint32_t)(g * 16 * 144 + c * 32);
                ldm_x4(vhf[g], a);
                ldm_x4(vlf[g], a + AKL);
            }
            #pragma unroll
            for (int g = 0; g < 4; g++) {
                #pragma unroll
                for (int j = 0; j < 2; j++) {
                    int nb = g * 2 + j;
                    mma16816(oacc[nb], pha, vhf[g][2 * j], vhf[g][2 * j + 1]);
                    mma16816(oacc[nb], pha, vlf[g][2 * j], vlf[g][2 * j + 1]);
                    mma16816(oacc[nb], pla, vhf[g][2 * j], vhf[g][2 * j + 1]);
                }
            }
        }
        __syncthreads();
    }

    float inv0 = 1.0f / lrow0, inv1 = 1.0f / lrow1;
    int r0 = q0 + wid * 16 + (lane >> 2);
    #pragma unroll
    for (int nb = 0; nb < 8; nb++) {
        int col = h * HD_ + nb * 8 + 2 * (lane & 3);
        size_t i0 = (rowbase + r0) * D_ + col;
        size_t i1 = (rowbase + r0 + 8) * D_ + col;
        uint32_t hw, lw;
        split2(oacc[nb][0] * inv0, oacc[nb][1] * inv0, hw, lw);
        *(uint32_t*)(oh + i0) = hw; *(uint32_t*)(ol + i0) = lw;
        split2(oacc[nb][2] * inv1, oacc[nb][3] * inv1, hw, lw);
        *(uint32_t*)(oh + i1) = hw; *(uint32_t*)(ol + i1) = lw;
    }
}

// ---------------------------------------------------------------------------
// Fused residual add + LayerNorm
// ---------------------------------------------------------------------------
template <bool SPLIT>
__global__ __launch_bounds__(256)
void add_ln(const float* __restrict__ x, const float* __restrict__ y,
            const float* __restrict__ g, const float* __restrict__ bta,
            float* __restrict__ out,
            __nv_bfloat16* __restrict__ oh, __nv_bfloat16* __restrict__ ol) {
    __shared__ float red[256];
    int row = blockIdx.x, tid = threadIdx.x;
    const float* xr = x + (size_t)row * D_;
    const float* yr = y + (size_t)row * D_;

    float v[4];
    float sum = 0.f;
    #pragma unroll
    for (int i = 0; i < 4; i++) {
        int c = tid + i * 256;
        v[i] = xr[c] + yr[c];
        sum += v[i];
    }
    red[tid] = sum; __syncthreads();
    for (int s = 128; s; s >>= 1) { if (tid < s) red[tid] += red[tid + s]; __syncthreads(); }
    float mu = red[0] * (1.0f / 1024.0f);
    __syncthreads();

    float sq = 0.f;
    #pragma unroll
    for (int i = 0; i < 4; i++) { float d = v[i] - mu; sq += d * d; }
    red[tid] = sq; __syncthreads();
    for (int s = 128; s; s >>= 1) { if (tid < s) red[tid] += red[tid + s]; __syncthreads(); }
    float var  = red[0] * (1.0f / 1024.0f);
    float rstd = rsqrtf(var + 1e-5f);

    #pragma unroll
    for (int i = 0; i < 4; i++) {
        int c = tid + i * 256;
        float o = (v[i] - mu) * rstd * g[c] + bta[c];
        out[(size_t)row * D_ + c] = o;
        if (SPLIT) {
            __nv_bfloat16 h = __float2bfloat16(o);
            oh[(size_t)row * D_ + c] = h;
            ol[(size_t)row * D_ + c] = __float2bfloat16(o - __bfloat162float(h));
        }
    }
}

// ---------------------------------------------------------------------------
// Launch
// ---------------------------------------------------------------------------
extern "C" void kernel_launch(void* const* d_in, const int* in_sizes, int n_in,
                              void* d_out, int out_size) {
    const int*   seq    = (const int*)  d_in[0];
    const int*   mask   = (const int*)  d_in[1];
    const float* emb    = (const float*)d_in[2];
    const float* proj_w = (const float*)d_in[3];
    const float* proj_b = (const float*)d_in[4];
    const float* qw     = (const float*)d_in[5];
    const float* qb     = (const float*)d_in[6];
    const float* kw     = (const float*)d_in[7];
    const float* kb     = (const float*)d_in[8];
    const float* vw     = (const float*)d_in[9];
    const float* vb     = (const float*)d_in[10];
    const float* ow     = (const float*)d_in[11];
    const float* ob     = (const float*)d_in[12];
    const float* lng    = (const float*)d_in[13];
    const float* lnb    = (const float*)d_in[14];
    float* out = (float*)d_out;

    float *x, *v, *t, *bqkv;
    __nv_bfloat16 *ah, *al, *wth, *wtl, *qhp, *qlp, *khp, *klp, *vthp, *vtlp;
    cudaGetSymbolAddress((void**)&x,    g_x);
    cudaGetSymbolAddress((void**)&v,    g_v);
    cudaGetSymbolAddress((void**)&t,    g_t);
    cudaGetSymbolAddress((void**)&bqkv, g_bqkv);
    cudaGetSymbolAddress((void**)&ah,   g_ah);
    cudaGetSymbolAddress((void**)&al,   g_al);
    cudaGetSymbolAddress((void**)&wth,  g_wth);
    cudaGetSymbolAddress((void**)&wtl,  g_wtl);
    cudaGetSymbolAddress((void**)&qhp,  g_qh);
    cudaGetSymbolAddress((void**)&qlp,  g_ql);
    cudaGetSymbolAddress((void**)&khp,  g_kh);
    cudaGetSymbolAddress((void**)&klp,  g_kl);
    cudaGetSymbolAddress((void**)&vthp, g_vth);
    cudaGetSymbolAddress((void**)&vtlp, g_vtl);

    cudaFuncSetAttribute(gemm_mma<false>, cudaFuncAttributeMaxDynamicSharedMemorySize, GEMM_SMEM);
    cudaFuncSetAttribute(gemm_mma<true>,  cudaFuncAttributeMaxDynamicSharedMemorySize, GEMM_SMEM);
    cudaFuncSetAttribute(gemm_qkv, cudaFuncAttributeMaxDynamicSharedMemorySize, GEMM_SMEM);
    cudaFuncSetAttribute(attn_mma, cudaFuncAttributeMaxDynamicSharedMemorySize, ATT_SMEM);

    // ---- weight prep ----
    {
        dim3 tb(32, 8);
        tsplit_w<<<dim3(D_ / 32, SEQDIM_ / 32), tb>>>(proj_w, wth, wtl, SEQDIM_, D_);
        tsplit_all<<<dim3(D_ / 32, D_ / 32, 24), tb>>>(qw, kw, vw, ow, wth, wtl);
        bias_concat<<<(L_ * 3 * D_ + 255) / 256, 256>>>(qb, kb, vb, bqkv);
    }

    // ---- embedding (split staged in q-scratch) + input projection ----
    gather_emb<<<(ROWS_ * SEQDIM_ / 2 + 255) / 256, 256>>>(seq, emb, qhp, qlp);
    dim3 gp(D_ / 128, ROWS_ / 128);              // (8, 64)
    gemm_mma<true><<<gp, 256, GEMM_SMEM>>>(qhp, qlp, wth, wtl, proj_b, x, D_, SEQDIM_, ah, al);

    dim3 gqkv(3 * D_ / 128, ROWS_ / 128);        // (24, 64)
    dim3 ga(S_ / 128, B_ * H_);                  // (16, 64)
    dim3 vg(S_ / 32, B_ * H_);
    dim3 vb8(32, 8);
    for (int l = 0; l < L_; l++) {
        size_t off = WT_PROJ_ELEMS + (size_t)(l * 4) * WT_MAT_ELEMS;
        const __nv_bfloat16* owh = wth + off + 3 * WT_MAT_ELEMS;
        const __nv_bfloat16* owl = wtl + off + 3 * WT_MAT_ELEMS;

        gemm_qkv<<<gqkv, 256, GEMM_SMEM>>>(ah, al, wth + off, wtl + off,
                                           bqkv + l * 3 * D_,
                                           qhp, qlp, khp, klp, v);
        vtsplit<<<vg, vb8>>>(v, vthp, vtlp);
        attn_mma<<<ga, 256, ATT_SMEM>>>(qhp, qlp, khp, klp, vthp, vtlp, mask, ah, al);
        gemm_mma<false><<<gp, 256, GEMM_SMEM>>>(ah, al, owh, owl, ob + l * D_, t, D_, D_,
                                                nullptr, nullptr);
        if (l == L_ - 1)
            add_ln<false><<<ROWS_, 256>>>(x, t, lng + l * D_, lnb + l * D_, out, nullptr, nullptr);
        else
            add_ln<true><<<ROWS_, 256>>>(x, t, lng + l * D_, lnb + l * D_, x, ah, al);
    }
}

// round 9
// speedup vs baseline: 3.2189x; 1.0023x over previous
#include <cuda_runtime.h>
#include <cuda_bf16.h>
#include <math.h>
#include <stdint.h>

// Problem constants
#define B_      4
#define S_      2048
#define D_      1024
#define H_      16
#define HD_     64
#define L_      6
#define SEQDIM_ 128
#define ROWS_   (B_ * S_)   // 8192

#define WT_PROJ_ELEMS (D_ * SEQDIM_)
#define WT_MAT_ELEMS  (D_ * D_)
#define WT_ELEMS      (WT_PROJ_ELEMS + 24 * WT_MAT_ELEMS)

// ---------------------------------------------------------------------------
// Device scratch
// ---------------------------------------------------------------------------
__device__ float g_x [ROWS_ * D_];
__device__ float g_v [ROWS_ * D_];
__device__ float g_t [ROWS_ * D_];
__device__ float g_bqkv[L_ * 3 * D_];
__device__ __nv_bfloat16 g_ah[ROWS_ * D_];
__device__ __nv_bfloat16 g_al[ROWS_ * D_];
__device__ __nv_bfloat16 g_wth[WT_ELEMS];
__device__ __nv_bfloat16 g_wtl[WT_ELEMS];
__device__ __nv_bfloat16 g_qh[ROWS_ * D_];
__device__ __nv_bfloat16 g_ql[ROWS_ * D_];
__device__ __nv_bfloat16 g_kh[ROWS_ * D_];
__device__ __nv_bfloat16 g_kl[ROWS_ * D_];
__device__ __nv_bfloat16 g_vth[ROWS_ * D_];   // [bh][64][S]
__device__ __nv_bfloat16 g_vtl[ROWS_ * D_];

// ---------------------------------------------------------------------------
// Helpers
// ---------------------------------------------------------------------------
__device__ __forceinline__ uint32_t smem_u32(const void* p) {
    uint32_t a;
    asm("{ .reg .u64 t; cvta.to.shared.u64 t, %1; cvt.u32.u64 %0, t; }"
        : "=r"(a) : "l"(p));
    return a;
}

__device__ __forceinline__ void ldm_x4(uint32_t* r, uint32_t addr) {
    asm volatile("ldmatrix.sync.aligned.m8n8.x4.shared.b16 {%0,%1,%2,%3}, [%4];"
                 : "=r"(r[0]), "=r"(r[1]), "=r"(r[2]), "=r"(r[3]) : "r"(addr));
}

// NOTE: non-volatile — data deps via "+f" keep correctness; lets ptxas schedule.
__device__ __forceinline__ void mma16816(float* c, const uint32_t* a,
                                         uint32_t b0, uint32_t b1) {
    asm("mma.sync.aligned.m16n8k16.row.col.f32.bf16.bf16.f32 "
        "{%0,%1,%2,%3}, {%4,%5,%6,%7}, {%8,%9}, {%0,%1,%2,%3};"
        : "+f"(c[0]), "+f"(c[1]), "+f"(c[2]), "+f"(c[3])
        : "r"(a[0]), "r"(a[1]), "r"(a[2]), "r"(a[3]), "r"(b0), "r"(b1));
}

__device__ __forceinline__ uint32_t pk_bf16(float lo, float hi) {
    uint32_t r;
    asm("cvt.rn.bf16x2.f32 %0, %1, %2;" : "=r"(r) : "f"(hi), "f"(lo));
    return r;
}

__device__ __forceinline__ void split2(float c0, float c1, uint32_t& hw, uint32_t& lw) {
    __nv_bfloat16 h0 = __float2bfloat16(c0);
    __nv_bfloat16 h1 = __float2bfloat16(c1);
    __nv_bfloat162 hp; hp.x = h0; hp.y = h1;
    hw = *(uint32_t*)&hp;
    lw = pk_bf16(c0 - __bfloat162float(h0), c1 - __bfloat162float(h1));
}

#define CP_ASYNC16(dst, src) \
    asm volatile("cp.async.cg.shared.global [%0], [%1], 16;" :: "r"(dst), "l"(src))
#define CP_COMMIT() asm volatile("cp.async.commit_group;" ::: "memory")
#define CP_WAIT(n)  asm volatile("cp.async.wait_group %0;" :: "n"(n) : "memory")

// ---------------------------------------------------------------------------
// Embedding gather -> direct bf16 hi/lo split
// ---------------------------------------------------------------------------
__global__ void gather_emb(const int* __restrict__ seq,
                           const float* __restrict__ emb,
                           __nv_bfloat16* __restrict__ xh,
                           __nv_bfloat16* __restrict__ xl) {
    int i = blockIdx.x * blockDim.x + threadIdx.x;
    if (i >= ROWS_ * SEQDIM_ / 2) return;
    int row = i >> 6;
    int c2  = (i & 63) * 2;
    const float* e = emb + seq[row] * SEQDIM_ + c2;
    uint32_t hw, lw;
    split2(e[0], e[1], hw, lw);
    ((uint32_t*)xh)[i] = hw;
    ((uint32_t*)xl)[i] = lw;
}

// ---------------------------------------------------------------------------
// bias concat
// ---------------------------------------------------------------------------
__global__ void bias_concat(const float* __restrict__ qb, const float* __restrict__ kb,
                            const float* __restrict__ vb, float* __restrict__ o) {
    int idx = blockIdx.x * blockDim.x + threadIdx.x;
    if (idx >= L_ * 3 * D_) return;
    int l = idx / (3 * D_);
    int c = idx % (3 * D_);
    float v;
    if (c < D_)           v = qb[l * D_ + c];
    else if (c < 2 * D_)  v = kb[l * D_ + c - D_];
    else                  v = vb[l * D_ + c - 2 * D_];
    o[idx] = v;
}

// ---------------------------------------------------------------------------
// Weight transpose + split: proj_w only
// ---------------------------------------------------------------------------
__global__ void tsplit_w(const float* __restrict__ W,
                         __nv_bfloat16* __restrict__ th,
                         __nv_bfloat16* __restrict__ tl, int K, int N) {
    __shared__ float t[32][33];
    int bx = blockIdx.x * 32;
    int by = blockIdx.y * 32;
    #pragma unroll
    for (int i = 0; i < 32; i += 8)
        t[threadIdx.y + i][threadIdx.x] =
            W[(size_t)(by + threadIdx.y + i) * N + bx + threadIdx.x];
    __syncthreads();
    #pragma unroll
    for (int i = 0; i < 32; i += 8) {
        float v = t[threadIdx.x][threadIdx.y + i];
        int n = bx + threadIdx.y + i;
        int k = by + threadIdx.x;
        __nv_bfloat16 h = __float2bfloat16(v);
        th[(size_t)n * K + k] = h;
        tl[(size_t)n * K + k] = __float2bfloat16(v - __bfloat162float(h));
    }
}

// ---------------------------------------------------------------------------
// Batched weight transpose + split for 24 layer matrices
// ---------------------------------------------------------------------------
__global__ void tsplit_all(const float* __restrict__ qw, const float* __restrict__ kw,
                           const float* __restrict__ vw, const float* __restrict__ ow,
                           __nv_bfloat16* __restrict__ th,
                           __nv_bfloat16* __restrict__ tl) {
    __shared__ float t[32][33];
    int z = blockIdx.z;
    int l = z >> 2, m = z & 3;
    const float* W = (m == 0 ? qw : m == 1 ? kw : m == 2 ? vw : ow) + (size_t)l * D_ * D_;
    size_t dof = WT_PROJ_ELEMS + (size_t)z * WT_MAT_ELEMS;
    int bx = blockIdx.x * 32;
    int by = blockIdx.y * 32;
    #pragma unroll
    for (int i = 0; i < 32; i += 8)
        t[threadIdx.y + i][threadIdx.x] =
            W[(size_t)(by + threadIdx.y + i) * D_ + bx + threadIdx.x];
    __syncthreads();
    #pragma unroll
    for (int i = 0; i < 32; i += 8) {
        float v = t[threadIdx.x][threadIdx.y + i];
        int n = bx + threadIdx.y + i;
        int k = by + threadIdx.x;
        __nv_bfloat16 h = __float2bfloat16(v);
        th[dof + (size_t)n * D_ + k] = h;
        tl[dof + (size_t)n * D_ + k] = __float2bfloat16(v - __bfloat162float(h));
    }
}

// ---------------------------------------------------------------------------
// V transpose + split per head
// ---------------------------------------------------------------------------
__global__ void vtsplit(const float* __restrict__ v,
                        __nv_bfloat16* __restrict__ th,
                        __nv_bfloat16* __restrict__ tl) {
    __shared__ float t[32][33];
    int s0 = blockIdx.x * 32;
    int bh = blockIdx.y;
    int b  = bh >> 4, h = bh & 15;
    for (int dh = 0; dh < HD_; dh += 32) {
        #pragma unroll
        for (int i = 0; i < 32; i += 8)
            t[threadIdx.y + i][threadIdx.x] =
                v[(size_t)(b * S_ + s0 + threadIdx.y + i) * D_ + h * HD_ + dh + threadIdx.x];
        __syncthreads();
        #pragma unroll
        for (int i = 0; i < 32; i += 8) {
            float val = t[threadIdx.x][threadIdx.y + i];
            int d = dh + threadIdx.y + i;
            int s = s0 + threadIdx.x;
            __nv_bfloat16 hh = __float2bfloat16(val);
            th[((size_t)bh * HD_ + d) * S_ + s] = hh;
            tl[((size_t)bh * HD_ + d) * S_ + s] = __float2bfloat16(val - __bfloat162float(hh));
        }
        __syncthreads();
    }
}

// ---------------------------------------------------------------------------
// GEMM core: 128x128 block tile, 8 warps of 64x32, BK=32, 2-stage cp.async,
// 3-pass bf16 split issued PASS-MAJOR (no back-to-back same-acc HMMA).
// ---------------------------------------------------------------------------
#define TILEB  10240            // 128 * 80
#define CHUNKB (4 * TILEB)      // 40960
#define GEMM_SMEM (2 * CHUNKB)  // 81920 -> 2 CTAs/SM

template <typename EPI>
__device__ __forceinline__
void gemm_core(const __nv_bfloat16* s0, const __nv_bfloat16* s1,
               const __nv_bfloat16* s2, const __nv_bfloat16* s3,
               int K, char* smem, EPI epilogue) {
    const uint32_t sb = smem_u32(smem);
    const int tid  = threadIdx.x;
    const int lane = tid & 31;
    const int wid  = tid >> 5;
    const int wm = wid & 1;       // 0..1 (64-row group)
    const int wn = wid >> 1;      // 0..3 (32-col group)

    const int nk = K >> 5;        // chunks of 32

    auto load_chunk = [&](int c, int stage) {
        const int k0 = c << 5;
        uint32_t buf = sb + stage * CHUNKB;
        #pragma unroll
        for (int i = 0; i < 2; i++) {
            int t = tid + i * 256;            // 0..511
            int row = t >> 2;
            int seg = t & 3;
            uint32_t dst = buf + row * 80 + seg * 16;
            size_t so = (size_t)row * K + k0 + seg * 8;
            CP_ASYNC16(dst,              (const char*)(s0 + so));
            CP_ASYNC16(dst + TILEB,      (const char*)(s1 + so));
            CP_ASYNC16(dst + 2 * TILEB,  (const char*)(s2 + so));
            CP_ASYNC16(dst + 3 * TILEB,  (const char*)(s3 + so));
        }
        CP_COMMIT();
    };

    float acc[4][4][4];
    #pragma unroll
    for (int mi = 0; mi < 4; mi++)
        #pragma unroll
        for (int nb = 0; nb < 4; nb++)
            #pragma unroll
            for (int j = 0; j < 4; j++) acc[mi][nb][j] = 0.f;

    const uint32_t a_off = (uint32_t)((wm * 64 + (lane & 15)) * 80 + (lane >> 4) * 16);
    const uint32_t b_off = (uint32_t)((wn * 32 + ((lane >> 4) & 1) * 8 + (lane & 7)) * 80
                                      + ((lane >> 3) & 1) * 16);

    load_chunk(0, 0);

    for (int c = 0; c < nk; c++) {
        if (c + 1 < nk) { load_chunk(c + 1, (c + 1) & 1); CP_WAIT(1); }
        else            { CP_WAIT(0); }
        __syncthreads();

        uint32_t buf = sb + (c & 1) * CHUNKB;
        #pragma unroll
        for (int s = 0; s < 2; s++) {
            uint32_t ah[4][4], al[4][4], wh[2][4], wl[2][4];
            #pragma unroll
            for (int g = 0; g < 4; g++) {
                uint32_t ao = buf + a_off + (uint32_t)(g * 16 * 80 + s * 32);
                ldm_x4(ah[g], ao);
                ldm_x4(al[g], ao + TILEB);
            }
            #pragma unroll
            for (int h = 0; h < 2; h++) {
                uint32_t bo = buf + 2 * TILEB + b_off + (uint32_t)(h * 16 * 80 + s * 32);
                ldm_x4(wh[h], bo);
                ldm_x4(wl[h], bo + TILEB);
            }
            // Pass 1: Ah*Wh over all 16 accumulators (independent)
            #pragma unroll
            for (int mi = 0; mi < 4; mi++)
                #pragma unroll
                for (int nb = 0; nb < 4; nb++) {
                    const int h = nb >> 1, j = nb & 1;
                    mma16816(acc[mi][nb], ah[mi], wh[h][2 * j], wh[h][2 * j + 1]);
                }
            // Pass 2: Ah*Wl
            #pragma unroll
            for (int mi = 0; mi < 4; mi++)
                #pragma unroll
                for (int nb = 0; nb < 4; nb++) {
                    const int h = nb >> 1, j = nb & 1;
                    mma16816(acc[mi][nb], ah[mi], wl[h][2 * j], wl[h][2 * j + 1]);
                }
            // Pass 3: Al*Wh
            #pragma unroll
            for (int mi = 0; mi < 4; mi++)
                #pragma unroll
                for (int nb = 0; nb < 4; nb++) {
                    const int h = nb >> 1, j = nb & 1;
                    mma16816(acc[mi][nb], al[mi], wh[h][2 * j], wh[h][2 * j + 1]);
                }
        }
        __syncthreads();
    }

    epilogue(acc, wm, wn, lane);
}

// ---------------------------------------------------------------------------
// Generic GEMM + bias -> fp32 C (optionally also emit bf16 hi/lo split)
// ---------------------------------------------------------------------------
template <bool SPLIT>
__global__ __launch_bounds__(256, 2)
void gemm_mma(const __nv_bfloat16* __restrict__ Ah,
              const __nv_bfloat16* __restrict__ Al,
              const __nv_bfloat16* __restrict__ Wh,
              const __nv_bfloat16* __restrict__ Wl,
              const float* __restrict__ bias,
              float* __restrict__ C, int N, int K,
              __nv_bfloat16* __restrict__ oh, __nv_bfloat16* __restrict__ ol) {
    extern __shared__ char smem[];
    const int brow = blockIdx.y * 128;
    const int bcol = blockIdx.x * 128;
    gemm_core(Ah + (size_t)brow * K, Al + (size_t)brow * K,
              Wh + (size_t)bcol * K, Wl + (size_t)bcol * K, K, smem,
        [&](float acc[4][4][4], int wm, int wn, int lane) {
            #pragma unroll
            for (int mi = 0; mi < 4; mi++) {
                int row = brow + wm * 64 + mi * 16 + (lane >> 2);
                #pragma unroll
                for (int nb = 0; nb < 4; nb++) {
                    int col = bcol + wn * 32 + nb * 8 + (lane & 3) * 2;
                    float b0 = bias[col], b1 = bias[col + 1];
                    float c00 = acc[mi][nb][0] + b0, c01 = acc[mi][nb][1] + b1;
                    float c10 = acc[mi][nb][2] + b0, c11 = acc[mi][nb][3] + b1;
                    size_t i0 = (size_t)row * N + col;
                    size_t i1 = (size_t)(row + 8) * N + col;
                    *(float2*)(C + i0) = make_float2(c00, c01);
                    *(float2*)(C + i1) = make_float2(c10, c11);
                    if (SPLIT) {
                        uint32_t hw, lw;
                        split2(c00, c01, hw, lw);
                        *(uint32_t*)(oh + i0) = hw; *(uint32_t*)(ol + i0) = lw;
                        split2(c10, c11, hw, lw);
                        *(uint32_t*)(oh + i1) = hw; *(uint32_t*)(ol + i1) = lw;
                    }
                }
            }
        });
}

// ---------------------------------------------------------------------------
// Fused QKV GEMM (N=3072, weights contiguous)
// ---------------------------------------------------------------------------
__global__ __launch_bounds__(256, 2)
void gemm_qkv(const __nv_bfloat16* __restrict__ Ah,
              const __nv_bfloat16* __restrict__ Al,
              const __nv_bfloat16* __restrict__ Wh,
              const __nv_bfloat16* __restrict__ Wl,
              const float* __restrict__ bias,   // [3072]
              __nv_bfloat16* __restrict__ qh, __nv_bfloat16* __restrict__ ql,
              __nv_bfloat16* __restrict__ kh, __nv_bfloat16* __restrict__ kl,
              float* __restrict__ vout) {
    extern __shared__ char smem[];
    const int K = D_;
    const int brow = blockIdx.y * 128;
    const int bcol = blockIdx.x * 128;
    const int mat = bcol >> 10;            // 0=q 1=k 2=v
    const int colb = bcol & 1023;
    gemm_core(Ah + (size_t)brow * K, Al + (size_t)brow * K,
              Wh + (size_t)bcol * K, Wl + (size_t)bcol * K, K, smem,
        [&](float acc[4][4][4], int wm, int wn, int lane) {
            #pragma unroll
            for (int mi = 0; mi < 4; mi++) {
                int row = brow + wm * 64 + mi * 16 + (lane >> 2);
                #pragma unroll
                for (int nb = 0; nb < 4; nb++) {
                    int col = colb + wn * 32 + nb * 8 + (lane & 3) * 2;
                    float b0 = bias[(mat << 10) + col], b1 = bias[(mat << 10) + col + 1];
                    float c00 = acc[mi][nb][0] + b0, c01 = acc[mi][nb][1] + b1;
                    float c10 = acc[mi][nb][2] + b0, c11 = acc[mi][nb][3] + b1;
                    size_t i0 = (size_t)row * D_ + col;
                    size_t i1 = (size_t)(row + 8) * D_ + col;
                    if (mat == 2) {
                        *(float2*)(vout + i0) = make_float2(c00, c01);
                        *(float2*)(vout + i1) = make_float2(c10, c11);
                    } else {
                        __nv_bfloat16* hB = (mat == 0) ? qh : kh;
                        __nv_bfloat16* lB = (mat == 0) ? ql : kl;
                        if (mat == 0) { c00 *= 0.125f; c01 *= 0.125f; c10 *= 0.125f; c11 *= 0.125f; }
                        uint32_t hw, lw;
                        split2(c00, c01, hw, lw);
                        *(uint32_t*)(hB + i0) = hw; *(uint32_t*)(lB + i0) = lw;
                        split2(c10, c11, hw, lw);
                        *(uint32_t*)(hB + i1) = hw; *(uint32_t*)(lB + i1) = lw;
                    }
                }
            }
        });
}

// ---------------------------------------------------------------------------
// Tensor-core flash attention; output as bf16 hi/lo split.
// MMA issue reordered pass-major (no back-to-back same-acc HMMA).
// ---------------------------------------------------------------------------
#define AST      36864
#define AKL      9216
#define AMASK    (3 * AST)
#define ATT_SMEM (AMASK + 3 * 256)

__global__ __launch_bounds__(256, 1)
void attn_mma(const __nv_bfloat16* __restrict__ qh, const __nv_bfloat16* __restrict__ ql,
              const __nv_bfloat16* __restrict__ kh, const __nv_bfloat16* __restrict__ kl,
              const __nv_bfloat16* __restrict__ vth, const __nv_bfloat16* __restrict__ vtl,
              const int* __restrict__ mask,
              __nv_bfloat16* __restrict__ oh, __nv_bfloat16* __restrict__ ol) {
    extern __shared__ char smem[];
    const uint32_t sb = smem_u32(smem);
    const int tid = threadIdx.x, wid = tid >> 5, lane = tid & 31;
    const int q0 = blockIdx.x * 128;
    const int bh = blockIdx.y;
    const int b = bh >> 4, h = bh & 15;
    const size_t rowbase = (size_t)b * S_;

    #pragma unroll
    for (int i = 0; i < 4; i++) {
        int t = tid + i * 256;
        int row = t >> 3, seg = t & 7;
        uint32_t dst = sb + row * 144 + seg * 16;
        size_t so = (rowbase + q0 + row) * D_ + h * HD_ + seg * 8;
        CP_ASYNC16(dst,         (const char*)(qh + so));
        CP_ASYNC16(dst + 18432, (const char*)(ql + so));
    }
    CP_COMMIT(); CP_WAIT(0);
    __syncthreads();

    uint32_t qhf[4][4], qlf[4][4];
    #pragma unroll
    for (int s = 0; s < 4; s++) {
        uint32_t a = sb + (uint32_t)((wid * 16 + (lane & 15)) * 144 + (lane >> 4) * 16 + s * 32);
        ldm_x4(qhf[s], a);
        ldm_x4(qlf[s], a + 18432);
    }
    __syncthreads();

    auto load_kv = [&](int kt, int st) {
        uint32_t buf = sb + st * AST;
        int key0 = kt * 64;
        #pragma unroll
        for (int i = 0; i < 2; i++) {
            int t = tid + i * 256;
            int row = t >> 3, seg = t & 7;
            uint32_t dst = buf + row * 144 + seg * 16;
            size_t sk = (rowbase + key0 + row) * D_ + h * HD_ + seg * 8;
            CP_ASYNC16(dst,           (const char*)(kh + sk));
            CP_ASYNC16(dst + AKL,     (const char*)(kl + sk));
            size_t sv = ((size_t)bh * HD_ + row) * S_ + key0 + seg * 8;
            CP_ASYNC16(dst + 2 * AKL, (const char*)(vth + sv));
            CP_ASYNC16(dst + 3 * AKL, (const char*)(vtl + sv));
        }
        if (tid < 16)
            CP_ASYNC16(sb + AMASK + st * 256 + tid * 16,
                       (const char*)(mask + b * S_ + key0 + tid * 4));
        CP_COMMIT();
    };

    float oacc[8][4];
    #pragma unroll
    for (int nb = 0; nb < 8; nb++)
        #pragma unroll
        for (int j = 0; j < 4; j++) oacc[nb][j] = 0.f;
    float mrow0 = -1e30f, mrow1 = -1e30f, lrow0 = 0.f, lrow1 = 0.f;

    const uint32_t bfrag_off = (uint32_t)((((lane >> 4) & 1) * 8 + (lane & 7)) * 144
                                          + ((lane >> 3) & 1) * 16);

    load_kv(0, 0);
    load_kv(1, 1);

    const int NKT = S_ / 64;
    for (int kt = 0; kt < NKT; kt++) {
        if (kt + 2 < NKT)      { load_kv(kt + 2, (kt + 2) % 3); CP_WAIT(2); }
        else if (kt + 1 < NKT) { CP_WAIT(1); }
        else                   { CP_WAIT(0); }
        __syncthreads();

        uint32_t buf = sb + (kt % 3) * AST;

        float sacc[8][4];
        #pragma unroll
        for (int nb = 0; nb < 8; nb++)
            #pragma unroll
            for (int j = 0; j < 4; j++) sacc[nb][j] = 0.f;

        #pragma unroll
        for (int s = 0; s < 4; s++) {
            uint32_t khf[4][4], klf[4][4];
            #pragma unroll
            for (int g = 0; g < 4; g++) {
                uint32_t a = buf + bfrag_off + (uint32_t)(g * 16 * 144 + s * 32);
                ldm_x4(khf[g], a);
                ldm_x4(klf[g], a + AKL);
            }
            // pass-major: 8 independent MMAs between same-acc reuse
            #pragma unroll
            for (int g = 0; g < 4; g++)
                #pragma unroll
                for (int j = 0; j < 2; j++)
                    mma16816(sacc[g * 2 + j], qhf[s], khf[g][2 * j], khf[g][2 * j + 1]);
            #pragma unroll
            for (int g = 0; g < 4; g++)
                #pragma unroll
                for (int j = 0; j < 2; j++)
                    mma16816(sacc[g * 2 + j], qhf[s], klf[g][2 * j], klf[g][2 * j + 1]);
            #pragma unroll
            for (int g = 0; g < 4; g++)
                #pragma unroll
                for (int j = 0; j < 2; j++)
                    mma16816(sacc[g * 2 + j], qlf[s], khf[g][2 * j], khf[g][2 * j + 1]);
        }

        {
            const int* smk = (const int*)(smem + AMASK + (kt % 3) * 256);
            int cb = 2 * (lane & 3);
            #pragma unroll
            for (int nb = 0; nb < 8; nb++) {
                if (smk[nb * 8 + cb] == 0)     { sacc[nb][0] = -1e9f; sacc[nb][2] = -1e9f; }
                if (smk[nb * 8 + cb + 1] == 0) { sacc[nb][1] = -1e9f; sacc[nb][3] = -1e9f; }
            }
        }

        float mx0 = -1e30f, mx1 = -1e30f;
        #pragma unroll
        for (int nb = 0; nb < 8; nb++) {
            mx0 = fmaxf(mx0, fmaxf(sacc[nb][0], sacc[nb][1]));
            mx1 = fmaxf(mx1, fmaxf(sacc[nb][2], sacc[nb][3]));
        }
        mx0 = fmaxf(mx0, __shfl_xor_sync(0xffffffffu, mx0, 1));
        mx0 = fmaxf(mx0, __shfl_xor_sync(0xffffffffu, mx0, 2));
        mx1 = fmaxf(mx1, __shfl_xor_sync(0xffffffffu, mx1, 1));
        mx1 = fmaxf(mx1, __shfl_xor_sync(0xffffffffu, mx1, 2));
        float mn0 = fmaxf(mrow0, mx0), mn1 = fmaxf(mrow1, mx1);
        float corr0 = __expf(mrow0 - mn0), corr1 = __expf(mrow1 - mn1);
        float sum0 = 0.f, sum1 = 0.f;
        #pragma unroll
        for (int nb = 0; nb < 8; nb++) {
            sacc[nb][0] = __expf(sacc[nb][0] - mn0);
            sacc[nb][1] = __expf(sacc[nb][1] - mn0);
            sacc[nb][2] = __expf(sacc[nb][2] - mn1);
            sacc[nb][3] = __expf(sacc[nb][3] - mn1);
            sum0 += sacc[nb][0] + sacc[nb][1];
            sum1 += sacc[nb][2] + sacc[nb][3];
        }
        sum0 += __shfl_xor_sync(0xffffffffu, sum0, 1);
        sum0 += __shfl_xor_sync(0xffffffffu, sum0, 2);
        sum1 += __shfl_xor_sync(0xffffffffu, sum1, 1);
        sum1 += __shfl_xor_sync(0xffffffffu, sum1, 2);
        lrow0 = lrow0 * corr0 + sum0;
        lrow1 = lrow1 * corr1 + sum1;
        mrow0 = mn0; mrow1 = mn1;
        #pragma unroll
        for (int nb = 0; nb < 8; nb++) {
            oacc[nb][0] *= corr0; oacc[nb][1] *= corr0;
            oacc[nb][2] *= corr1; oacc[nb][3] *= corr1;
        }

        // ---- O += P @ V, pass-major per c-step ----
        #pragma unroll
        for (int c = 0; c < 4; c++) {
            uint32_t pha[4], pla[4];
            #pragma unroll
            for (int half = 0; half < 2; half++) {
                int nb = 2 * c + half;
                __nv_bfloat16 b0 = __float2bfloat16(sacc[nb][0]);
                __nv_bfloat16 b1 = __float2bfloat16(sacc[nb][1]);
                __nv_bfloat16 b2 = __float2bfloat16(sacc[nb][2]);
                __nv_bfloat16 b3 = __float2bfloat16(sacc[nb][3]);
                __nv_bfloat162 t01; t01.x = b0; t01.y = b1;
                __nv_bfloat162 t23; t23.x = b2; t23.y = b3;
                pha[half * 2 + 0] = *(uint32_t*)&t01;
                pha[half * 2 + 1] = *(uint32_t*)&t23;
                pla[half * 2 + 0] = pk_bf16(sacc[nb][0] - __bfloat162float(b0),
                                            sacc[nb][1] - __bfloat162float(b1));
                pla[half * 2 + 1] = pk_bf16(sacc[nb][2] - __bfloat162float(b2),
                                            sacc[nb][3] - __bfloat162float(b3));
            }
            uint32_t vhf[4][4], vlf[4][4];
            #pragma unroll
            for (int g = 0; g < 4; g++) {
                uint32_t a = buf + 2 * AKL + bfrag_off + (uint32_t)(g * 16 * 144 + c * 32);
                ldm_x4(vhf[g], a);
                ldm_x4(vlf[g], a + AKL);
            }
            #pragma unroll
            for (int g = 0; g < 4; g++)
                #pragma unroll
                for (int j = 0; j < 2; j++)
                    mma16816(oacc[g * 2 + j], pha, vhf[g][2 * j], vhf[g][2 * j + 1]);
            #pragma unroll
            for (int g = 0; g < 4; g++)
                #pragma unroll
                for (int j = 0; j < 2; j++)
                    mma16816(oacc[g * 2 + j], pha, vlf[g][2 * j], vlf[g][2 * j + 1]);
            #pragma unroll
            for (int g = 0; g < 4; g++)
                #pragma unroll
                for (int j = 0; j < 2; j++)
                    mma16816(oacc[g * 2 + j], pla, vhf[g][2 * j], vhf[g][2 * j + 1]);
        }
        __syncthreads();
    }

    float inv0 = 1.0f / lrow0, inv1 = 1.0f / lrow1;
    int r0 = q0 + wid * 16 + (lane >> 2);
    #pragma unroll
    for (int nb = 0; nb < 8; nb++) {
        int col = h * HD_ + nb * 8 + 2 * (lane & 3);
        size_t i0 = (rowbase + r0) * D_ + col;
        size_t i1 = (rowbase + r0 + 8) * D_ + col;
        uint32_t hw, lw;
        split2(oacc[nb][0] * inv0, oacc[nb][1] * inv0, hw, lw);
        *(uint32_t*)(oh + i0) = hw; *(uint32_t*)(ol + i0) = lw;
        split2(oacc[nb][2] * inv1, oacc[nb][3] * inv1, hw, lw);
        *(uint32_t*)(oh + i1) = hw; *(uint32_t*)(ol + i1) = lw;
    }
}

// ---------------------------------------------------------------------------
// Fused residual add + LayerNorm
// ---------------------------------------------------------------------------
template <bool SPLIT>
__global__ __launch_bounds__(256)
void add_ln(const float* __restrict__ x, const float* __restrict__ y,
            const float* __restrict__ g, const float* __restrict__ bta,
            float* __restrict__ out,
            __nv_bfloat16* __restrict__ oh, __nv_bfloat16* __restrict__ ol) {
    __shared__ float red[256];
    int row = blockIdx.x, tid = threadIdx.x;
    const float* xr = x + (size_t)row * D_;
    const float* yr = y + (size_t)row * D_;

    float v[4];
    float sum = 0.f;
    #pragma unroll
    for (int i = 0; i < 4; i++) {
        int c = tid + i * 256;
        v[i] = xr[c] + yr[c];
        sum += v[i];
    }
    red[tid] = sum; __syncthreads();
    for (int s = 128; s; s >>= 1) { if (tid < s) red[tid] += red[tid + s]; __syncthreads(); }
    float mu = red[0] * (1.0f / 1024.0f);
    __syncthreads();

    float sq = 0.f;
    #pragma unroll
    for (int i = 0; i < 4; i++) { float d = v[i] - mu; sq += d * d; }
    red[tid] = sq; __syncthreads();
    for (int s = 128; s; s >>= 1) { if (tid < s) red[tid] += red[tid + s]; __syncthreads(); }
    float var  = red[0] * (1.0f / 1024.0f);
    float rstd = rsqrtf(var + 1e-5f);

    #pragma unroll
    for (int i = 0; i < 4; i++) {
        int c = tid + i * 256;
        float o = (v[i] - mu) * rstd * g[c] + bta[c];
        out[(size_t)row * D_ + c] = o;
        if (SPLIT) {
            __nv_bfloat16 h = __float2bfloat16(o);
            oh[(size_t)row * D_ + c] = h;
            ol[(size_t)row * D_ + c] = __float2bfloat16(o - __bfloat162float(h));
        }
    }
}

// ---------------------------------------------------------------------------
// Launch
// ---------------------------------------------------------------------------
extern "C" void kernel_launch(void* const* d_in, const int* in_sizes, int n_in,
                              void* d_out, int out_size) {
    const int*   seq    = (const int*)  d_in[0];
    const int*   mask   = (const int*)  d_in[1];
    const float* emb    = (const float*)d_in[2];
    const float* proj_w = (const float*)d_in[3];
    const float* proj_b = (const float*)d_in[4];
    const float* qw     = (const float*)d_in[5];
    const float* qb     = (const float*)d_in[6];
    const float* kw     = (const float*)d_in[7];
    const float* kb     = (const float*)d_in[8];
    const float* vw     = (const float*)d_in[9];
    const float* vb     = (const float*)d_in[10];
    const float* ow     = (const float*)d_in[11];
    const float* ob     = (const float*)d_in[12];
    const float* lng    = (const float*)d_in[13];
    const float* lnb    = (const float*)d_in[14];
    float* out = (float*)d_out;

    float *x, *v, *t, *bqkv;
    __nv_bfloat16 *ah, *al, *wth, *wtl, *qhp, *qlp, *khp, *klp, *vthp, *vtlp;
    cudaGetSymbolAddress((void**)&x,    g_x);
    cudaGetSymbolAddress((void**)&v,    g_v);
    cudaGetSymbolAddress((void**)&t,    g_t);
    cudaGetSymbolAddress((void**)&bqkv, g_bqkv);
    cudaGetSymbolAddress((void**)&ah,   g_ah);
    cudaGetSymbolAddress((void**)&al,   g_al);
    cudaGetSymbolAddress((void**)&wth,  g_wth);
    cudaGetSymbolAddress((void**)&wtl,  g_wtl);
    cudaGetSymbolAddress((void**)&qhp,  g_qh);
    cudaGetSymbolAddress((void**)&qlp,  g_ql);
    cudaGetSymbolAddress((void**)&khp,  g_kh);
    cudaGetSymbolAddress((void**)&klp,  g_kl);
    cudaGetSymbolAddress((void**)&vthp, g_vth);
    cudaGetSymbolAddress((void**)&vtlp, g_vtl);

    cudaFuncSetAttribute(gemm_mma<false>, cudaFuncAttributeMaxDynamicSharedMemorySize, GEMM_SMEM);
    cudaFuncSetAttribute(gemm_mma<true>,  cudaFuncAttributeMaxDynamicSharedMemorySize, GEMM_SMEM);
    cudaFuncSetAttribute(gemm_qkv, cudaFuncAttributeMaxDynamicSharedMemorySize, GEMM_SMEM);
    cudaFuncSetAttribute(attn_mma, cudaFuncAttributeMaxDynamicSharedMemorySize, ATT_SMEM);

    // ---- weight prep ----
    {
        dim3 tb(32, 8);
        tsplit_w<<<dim3(D_ / 32, SEQDIM_ / 32), tb>>>(proj_w, wth, wtl, SEQDIM_, D_);
        tsplit_all<<<dim3(D_ / 32, D_ / 32, 24), tb>>>(qw, kw, vw, ow, wth, wtl);
        bias_concat<<<(L_ * 3 * D_ + 255) / 256, 256>>>(qb, kb, vb, bqkv);
    }

    // ---- embedding (split staged in q-scratch) + input projection ----
    gather_emb<<<(ROWS_ * SEQDIM_ / 2 + 255) / 256, 256>>>(seq, emb, qhp, qlp);
    dim3 gp(D_ / 128, ROWS_ / 128);              // (8, 64)
    gemm_mma<true><<<gp, 256, GEMM_SMEM>>>(qhp, qlp, wth, wtl, proj_b, x, D_, SEQDIM_, ah, al);

    dim3 gqkv(3 * D_ / 128, ROWS_ / 128);        // (24, 64)
    dim3 ga(S_ / 128, B_ * H_);                  // (16, 64)
    dim3 vg(S_ / 32, B_ * H_);
    dim3 vb8(32, 8);
    for (int l = 0; l < L_; l++) {
        size_t off = WT_PROJ_ELEMS + (size_t)(l * 4) * WT_MAT_ELEMS;
        const __nv_bfloat16* owh = wth + off + 3 * WT_MAT_ELEMS;
        const __nv_bfloat16* owl = wtl + off + 3 * WT_MAT_ELEMS;

        gemm_qkv<<<gqkv, 256, GEMM_SMEM>>>(ah, al, wth + off, wtl + off,
                                           bqkv + l * 3 * D_,
                                           qhp, qlp, khp, klp, v);
        vtsplit<<<vg, vb8>>>(v, vthp, vtlp);
        attn_mma<<<ga, 256, ATT_SMEM>>>(qhp, qlp, khp, klp, vthp, vtlp, mask, ah, al);
        gemm_mma<false><<<gp, 256, GEMM_SMEM>>>(ah, al, owh, owl, ob + l * D_, t, D_, D_,
                                                nullptr, nullptr);
        if (l == L_ - 1)
            add_ln<false><<<ROWS_, 256>>>(x, t, lng + l * D_, lnb + l * D_, out, nullptr, nullptr);
        else
            add_ln<true><<<ROWS_, 256>>>(x, t, lng + l * D_, lnb + l * D_, x, ah, al);
    }
}

// round 10
// speedup vs baseline: 3.3704x; 1.0471x over previous
#include <cuda_runtime.h>
#include <cuda_bf16.h>
#include <math.h>
#include <stdint.h>

// Problem constants
#define B_      4
#define S_      2048
#define D_      1024
#define H_      16
#define HD_     64
#define L_      6
#define SEQDIM_ 128
#define ROWS_   (B_ * S_)   // 8192

#define WT_PROJ_ELEMS (D_ * SEQDIM_)
#define WT_MAT_ELEMS  (D_ * D_)
#define WT_ELEMS      (WT_PROJ_ELEMS + 24 * WT_MAT_ELEMS)

// ---------------------------------------------------------------------------
// Device scratch
// ---------------------------------------------------------------------------
__device__ float g_x [ROWS_ * D_];
__device__ float g_t [ROWS_ * D_];
__device__ float g_bqkv[L_ * 3 * D_];
__device__ __nv_bfloat16 g_ah[ROWS_ * D_];
__device__ __nv_bfloat16 g_al[ROWS_ * D_];
__device__ __nv_bfloat16 g_wth[WT_ELEMS];
__device__ __nv_bfloat16 g_wtl[WT_ELEMS];
__device__ __nv_bfloat16 g_qh[ROWS_ * D_];
__device__ __nv_bfloat16 g_ql[ROWS_ * D_];
__device__ __nv_bfloat16 g_kh[ROWS_ * D_];
__device__ __nv_bfloat16 g_kl[ROWS_ * D_];
__device__ __nv_bfloat16 g_vth[ROWS_ * D_];   // [bh][64][S]
__device__ __nv_bfloat16 g_vtl[ROWS_ * D_];

// ---------------------------------------------------------------------------
// Helpers
// ---------------------------------------------------------------------------
__device__ __forceinline__ uint32_t smem_u32(const void* p) {
    uint32_t a;
    asm("{ .reg .u64 t; cvta.to.shared.u64 t, %1; cvt.u32.u64 %0, t; }"
        : "=r"(a) : "l"(p));
    return a;
}

__device__ __forceinline__ void ldm_x4(uint32_t* r, uint32_t addr) {
    asm volatile("ldmatrix.sync.aligned.m8n8.x4.shared.b16 {%0,%1,%2,%3}, [%4];"
                 : "=r"(r[0]), "=r"(r[1]), "=r"(r[2]), "=r"(r[3]) : "r"(addr));
}

__device__ __forceinline__ void mma16816(float* c, const uint32_t* a,
                                         uint32_t b0, uint32_t b1) {
    asm("mma.sync.aligned.m16n8k16.row.col.f32.bf16.bf16.f32 "
        "{%0,%1,%2,%3}, {%4,%5,%6,%7}, {%8,%9}, {%0,%1,%2,%3};"
        : "+f"(c[0]), "+f"(c[1]), "+f"(c[2]), "+f"(c[3])
        : "r"(a[0]), "r"(a[1]), "r"(a[2]), "r"(a[3]), "r"(b0), "r"(b1));
}

__device__ __forceinline__ uint32_t pk_bf16(float lo, float hi) {
    uint32_t r;
    asm("cvt.rn.bf16x2.f32 %0, %1, %2;" : "=r"(r) : "f"(hi), "f"(lo));
    return r;
}

__device__ __forceinline__ void split2(float c0, float c1, uint32_t& hw, uint32_t& lw) {
    __nv_bfloat16 h0 = __float2bfloat16(c0);
    __nv_bfloat16 h1 = __float2bfloat16(c1);
    __nv_bfloat162 hp; hp.x = h0; hp.y = h1;
    hw = *(uint32_t*)&hp;
    lw = pk_bf16(c0 - __bfloat162float(h0), c1 - __bfloat162float(h1));
}

#define CP_ASYNC16(dst, src) \
    asm volatile("cp.async.cg.shared.global [%0], [%1], 16;" :: "r"(dst), "l"(src))
#define CP_COMMIT() asm volatile("cp.async.commit_group;" ::: "memory")
#define CP_WAIT(n)  asm volatile("cp.async.wait_group %0;" :: "n"(n) : "memory")

// ---------------------------------------------------------------------------
// Embedding gather -> direct bf16 hi/lo split
// ---------------------------------------------------------------------------
__global__ void gather_emb(const int* __restrict__ seq,
                           const float* __restrict__ emb,
                           __nv_bfloat16* __restrict__ xh,
                           __nv_bfloat16* __restrict__ xl) {
    int i = blockIdx.x * blockDim.x + threadIdx.x;
    if (i >= ROWS_ * SEQDIM_ / 2) return;
    int row = i >> 6;
    int c2  = (i & 63) * 2;
    const float* e = emb + seq[row] * SEQDIM_ + c2;
    uint32_t hw, lw;
    split2(e[0], e[1], hw, lw);
    ((uint32_t*)xh)[i] = hw;
    ((uint32_t*)xl)[i] = lw;
}

// ---------------------------------------------------------------------------
// bias concat
// ---------------------------------------------------------------------------
__global__ void bias_concat(const float* __restrict__ qb, const float* __restrict__ kb,
                            const float* __restrict__ vb, float* __restrict__ o) {
    int idx = blockIdx.x * blockDim.x + threadIdx.x;
    if (idx >= L_ * 3 * D_) return;
    int l = idx / (3 * D_);
    int c = idx % (3 * D_);
    float v;
    if (c < D_)           v = qb[l * D_ + c];
    else if (c < 2 * D_)  v = kb[l * D_ + c - D_];
    else                  v = vb[l * D_ + c - 2 * D_];
    o[idx] = v;
}

// ---------------------------------------------------------------------------
// Weight transpose + split: proj_w only
// ---------------------------------------------------------------------------
__global__ void tsplit_w(const float* __restrict__ W,
                         __nv_bfloat16* __restrict__ th,
                         __nv_bfloat16* __restrict__ tl, int K, int N) {
    __shared__ float t[32][33];
    int bx = blockIdx.x * 32;
    int by = blockIdx.y * 32;
    #pragma unroll
    for (int i = 0; i < 32; i += 8)
        t[threadIdx.y + i][threadIdx.x] =
            W[(size_t)(by + threadIdx.y + i) * N + bx + threadIdx.x];
    __syncthreads();
    #pragma unroll
    for (int i = 0; i < 32; i += 8) {
        float v = t[threadIdx.x][threadIdx.y + i];
        int n = bx + threadIdx.y + i;
        int k = by + threadIdx.x;
        __nv_bfloat16 h = __float2bfloat16(v);
        th[(size_t)n * K + k] = h;
        tl[(size_t)n * K + k] = __float2bfloat16(v - __bfloat162float(h));
    }
}

// ---------------------------------------------------------------------------
// Batched weight transpose + split for 24 layer matrices
// ---------------------------------------------------------------------------
__global__ void tsplit_all(const float* __restrict__ qw, const float* __restrict__ kw,
                           const float* __restrict__ vw, const float* __restrict__ ow,
                           __nv_bfloat16* __restrict__ th,
                           __nv_bfloat16* __restrict__ tl) {
    __shared__ float t[32][33];
    int z = blockIdx.z;
    int l = z >> 2, m = z & 3;
    const float* W = (m == 0 ? qw : m == 1 ? kw : m == 2 ? vw : ow) + (size_t)l * D_ * D_;
    size_t dof = WT_PROJ_ELEMS + (size_t)z * WT_MAT_ELEMS;
    int bx = blockIdx.x * 32;
    int by = blockIdx.y * 32;
    #pragma unroll
    for (int i = 0; i < 32; i += 8)
        t[threadIdx.y + i][threadIdx.x] =
            W[(size_t)(by + threadIdx.y + i) * D_ + bx + threadIdx.x];
    __syncthreads();
    #pragma unroll
    for (int i = 0; i < 32; i += 8) {
        float v = t[threadIdx.x][threadIdx.y + i];
        int n = bx + threadIdx.y + i;
        int k = by + threadIdx.x;
        __nv_bfloat16 h = __float2bfloat16(v);
        th[dof + (size_t)n * D_ + k] = h;
        tl[dof + (size_t)n * D_ + k] = __float2bfloat16(v - __bfloat162float(h));
    }
}

// ---------------------------------------------------------------------------
// GEMM core: 128x128 block tile, 8 warps of 64x32, BK=32, 2-stage cp.async,
// 3-pass bf16 split issued pass-major. 2 CTAs/SM.
// ---------------------------------------------------------------------------
#define TILEB  10240            // 128 * 80
#define CHUNKB (4 * TILEB)      // 40960
#define GEMM_SMEM (2 * CHUNKB)  // 81920

template <typename EPI>
__device__ __forceinline__
void gemm_core(const __nv_bfloat16* s0, const __nv_bfloat16* s1,
               const __nv_bfloat16* s2, const __nv_bfloat16* s3,
               int K, char* smem, EPI epilogue) {
    const uint32_t sb = smem_u32(smem);
    const int tid  = threadIdx.x;
    const int lane = tid & 31;
    const int wid  = tid >> 5;
    const int wm = wid & 1;
    const int wn = wid >> 1;

    const int nk = K >> 5;

    auto load_chunk = [&](int c, int stage) {
        const int k0 = c << 5;
        uint32_t buf = sb + stage * CHUNKB;
        #pragma unroll
        for (int i = 0; i < 2; i++) {
            int t = tid + i * 256;
            int row = t >> 2;
            int seg = t & 3;
            uint32_t dst = buf + row * 80 + seg * 16;
            size_t so = (size_t)row * K + k0 + seg * 8;
            CP_ASYNC16(dst,              (const char*)(s0 + so));
            CP_ASYNC16(dst + TILEB,      (const char*)(s1 + so));
            CP_ASYNC16(dst + 2 * TILEB,  (const char*)(s2 + so));
            CP_ASYNC16(dst + 3 * TILEB,  (const char*)(s3 + so));
        }
        CP_COMMIT();
    };

    float acc[4][4][4];
    #pragma unroll
    for (int mi = 0; mi < 4; mi++)
        #pragma unroll
        for (int nb = 0; nb < 4; nb++)
            #pragma unroll
            for (int j = 0; j < 4; j++) acc[mi][nb][j] = 0.f;

    const uint32_t a_off = (uint32_t)((wm * 64 + (lane & 15)) * 80 + (lane >> 4) * 16);
    const uint32_t b_off = (uint32_t)((wn * 32 + ((lane >> 4) & 1) * 8 + (lane & 7)) * 80
                                      + ((lane >> 3) & 1) * 16);

    load_chunk(0, 0);

    for (int c = 0; c < nk; c++) {
        if (c + 1 < nk) { load_chunk(c + 1, (c + 1) & 1); CP_WAIT(1); }
        else            { CP_WAIT(0); }
        __syncthreads();

        uint32_t buf = sb + (c & 1) * CHUNKB;
        #pragma unroll
        for (int s = 0; s < 2; s++) {
            uint32_t ah[4][4], al[4][4], wh[2][4], wl[2][4];
            #pragma unroll
            for (int g = 0; g < 4; g++) {
                uint32_t ao = buf + a_off + (uint32_t)(g * 16 * 80 + s * 32);
                ldm_x4(ah[g], ao);
                ldm_x4(al[g], ao + TILEB);
            }
            #pragma unroll
            for (int h = 0; h < 2; h++) {
                uint32_t bo = buf + 2 * TILEB + b_off + (uint32_t)(h * 16 * 80 + s * 32);
                ldm_x4(wh[h], bo);
                ldm_x4(wl[h], bo + TILEB);
            }
            #pragma unroll
            for (int mi = 0; mi < 4; mi++)
                #pragma unroll
                for (int nb = 0; nb < 4; nb++) {
                    const int h = nb >> 1, j = nb & 1;
                    mma16816(acc[mi][nb], ah[mi], wh[h][2 * j], wh[h][2 * j + 1]);
                }
            #pragma unroll
            for (int mi = 0; mi < 4; mi++)
                #pragma unroll
                for (int nb = 0; nb < 4; nb++) {
                    const int h = nb >> 1, j = nb & 1;
                    mma16816(acc[mi][nb], ah[mi], wl[h][2 * j], wl[h][2 * j + 1]);
                }
            #pragma unroll
            for (int mi = 0; mi < 4; mi++)
                #pragma unroll
                for (int nb = 0; nb < 4; nb++) {
                    const int h = nb >> 1, j = nb & 1;
                    mma16816(acc[mi][nb], al[mi], wh[h][2 * j], wh[h][2 * j + 1]);
                }
        }
        __syncthreads();
    }

    epilogue(acc, wm, wn, lane);
}

// ---------------------------------------------------------------------------
// Generic GEMM + bias -> fp32 C (optionally also emit bf16 hi/lo split)
// ---------------------------------------------------------------------------
template <bool SPLIT>
__global__ __launch_bounds__(256, 2)
void gemm_mma(const __nv_bfloat16* __restrict__ Ah,
              const __nv_bfloat16* __restrict__ Al,
              const __nv_bfloat16* __restrict__ Wh,
              const __nv_bfloat16* __restrict__ Wl,
              const float* __restrict__ bias,
              float* __restrict__ C, int N, int K,
              __nv_bfloat16* __restrict__ oh, __nv_bfloat16* __restrict__ ol) {
    extern __shared__ char smem[];
    const int brow = blockIdx.y * 128;
    const int bcol = blockIdx.x * 128;
    gemm_core(Ah + (size_t)brow * K, Al + (size_t)brow * K,
              Wh + (size_t)bcol * K, Wl + (size_t)bcol * K, K, smem,
        [&](float acc[4][4][4], int wm, int wn, int lane) {
            #pragma unroll
            for (int mi = 0; mi < 4; mi++) {
                int row = brow + wm * 64 + mi * 16 + (lane >> 2);
                #pragma unroll
                for (int nb = 0; nb < 4; nb++) {
                    int col = bcol + wn * 32 + nb * 8 + (lane & 3) * 2;
                    float b0 = bias[col], b1 = bias[col + 1];
                    float c00 = acc[mi][nb][0] + b0, c01 = acc[mi][nb][1] + b1;
                    float c10 = acc[mi][nb][2] + b0, c11 = acc[mi][nb][3] + b1;
                    size_t i0 = (size_t)row * N + col;
                    size_t i1 = (size_t)(row + 8) * N + col;
                    *(float2*)(C + i0) = make_float2(c00, c01);
                    *(float2*)(C + i1) = make_float2(c10, c11);
                    if (SPLIT) {
                        uint32_t hw, lw;
                        split2(c00, c01, hw, lw);
                        *(uint32_t*)(oh + i0) = hw; *(uint32_t*)(ol + i0) = lw;
                        split2(c10, c11, hw, lw);
                        *(uint32_t*)(oh + i1) = hw; *(uint32_t*)(ol + i1) = lw;
                    }
                }
            }
        });
}

// ---------------------------------------------------------------------------
// Fused QKV GEMM (N=3072, weights contiguous); V written TRANSPOSED+split
// directly to vth/vtl [bh][d][s] — vtsplit kernel eliminated.
// ---------------------------------------------------------------------------
__global__ __launch_bounds__(256, 2)
void gemm_qkv(const __nv_bfloat16* __restrict__ Ah,
              const __nv_bfloat16* __restrict__ Al,
              const __nv_bfloat16* __restrict__ Wh,
              const __nv_bfloat16* __restrict__ Wl,
              const float* __restrict__ bias,   // [3072]
              __nv_bfloat16* __restrict__ qh, __nv_bfloat16* __restrict__ ql,
              __nv_bfloat16* __restrict__ kh, __nv_bfloat16* __restrict__ kl,
              __nv_bfloat16* __restrict__ vth, __nv_bfloat16* __restrict__ vtl) {
    extern __shared__ char smem[];
    const int K = D_;
    const int brow = blockIdx.y * 128;
    const int bcol = blockIdx.x * 128;
    const int mat = bcol >> 10;            // 0=q 1=k 2=v
    const int colb = bcol & 1023;
    gemm_core(Ah + (size_t)brow * K, Al + (size_t)brow * K,
              Wh + (size_t)bcol * K, Wl + (size_t)bcol * K, K, smem,
        [&](float acc[4][4][4], int wm, int wn, int lane) {
            #pragma unroll
            for (int mi = 0; mi < 4; mi++) {
                int row = brow + wm * 64 + mi * 16 + (lane >> 2);
                #pragma unroll
                for (int nb = 0; nb < 4; nb++) {
                    int col = colb + wn * 32 + nb * 8 + (lane & 3) * 2;
                    float b0 = bias[(mat << 10) + col], b1 = bias[(mat << 10) + col + 1];
                    float c00 = acc[mi][nb][0] + b0, c01 = acc[mi][nb][1] + b1;
                    float c10 = acc[mi][nb][2] + b0, c11 = acc[mi][nb][3] + b1;
                    if (mat == 2) {
                        // transposed split write: vt[bh][d][s]
                        int bb = row >> 11, s = row & (S_ - 1);
                        int hh = col >> 6, dd = col & 63;
                        size_t base = (((size_t)(bb * H_ + hh) * HD_ + dd)) * S_ + s;
                        __nv_bfloat16 t;
                        t = __float2bfloat16(c00);
                        vth[base] = t;            vtl[base] = __float2bfloat16(c00 - __bfloat162float(t));
                        t = __float2bfloat16(c01);
                        vth[base + S_] = t;       vtl[base + S_] = __float2bfloat16(c01 - __bfloat162float(t));
                        t = __float2bfloat16(c10);
                        vth[base + 8] = t;        vtl[base + 8] = __float2bfloat16(c10 - __bfloat162float(t));
                        t = __float2bfloat16(c11);
                        vth[base + S_ + 8] = t;   vtl[base + S_ + 8] = __float2bfloat16(c11 - __bfloat162float(t));
                    } else {
                        size_t i0 = (size_t)row * D_ + col;
                        size_t i1 = (size_t)(row + 8) * D_ + col;
                        __nv_bfloat16* hB = (mat == 0) ? qh : kh;
                        __nv_bfloat16* lB = (mat == 0) ? ql : kl;
                        if (mat == 0) { c00 *= 0.125f; c01 *= 0.125f; c10 *= 0.125f; c11 *= 0.125f; }
                        uint32_t hw, lw;
                        split2(c00, c01, hw, lw);
                        *(uint32_t*)(hB + i0) = hw; *(uint32_t*)(lB + i0) = lw;
                        split2(c10, c11, hw, lw);
                        *(uint32_t*)(hB + i1) = hw; *(uint32_t*)(lB + i1) = lw;
                    }
                }
            }
        });
}

// ---------------------------------------------------------------------------
// Tensor-core flash attention; 2-stage KV pipeline, Q-lo parked in smem,
// 2 CTAs/SM. Output as bf16 hi/lo split.
// ---------------------------------------------------------------------------
#define AST      36864                 // bytes per KV stage
#define AKL      9216                  // one 64x144 tile
#define AMASK    (2 * AST)             // 73728
#define AQLO     (AMASK + 512)         // 74240 : Q-lo tile (128x144)
#define ATT_SMEM (AQLO + 18432)        // 92672

__global__ __launch_bounds__(256, 2)
void attn_mma(const __nv_bfloat16* __restrict__ qh, const __nv_bfloat16* __restrict__ ql,
              const __nv_bfloat16* __restrict__ kh, const __nv_bfloat16* __restrict__ kl,
              const __nv_bfloat16* __restrict__ vth, const __nv_bfloat16* __restrict__ vtl,
              const int* __restrict__ mask,
              __nv_bfloat16* __restrict__ oh, __nv_bfloat16* __restrict__ ol) {
    extern __shared__ char smem[];
    const uint32_t sb = smem_u32(smem);
    const int tid = threadIdx.x, wid = tid >> 5, lane = tid & 31;
    const int q0 = blockIdx.x * 128;
    const int bh = blockIdx.y;
    const int b = bh >> 4, h = bh & 15;
    const size_t rowbase = (size_t)b * S_;

    // Q-hi staged in stage-0 area (consumed to regs), Q-lo persistent at AQLO
    #pragma unroll
    for (int i = 0; i < 4; i++) {
        int t = tid + i * 256;
        int row = t >> 3, seg = t & 7;
        size_t so = (rowbase + q0 + row) * D_ + h * HD_ + seg * 8;
        CP_ASYNC16(sb + row * 144 + seg * 16,        (const char*)(qh + so));
        CP_ASYNC16(sb + AQLO + row * 144 + seg * 16, (const char*)(ql + so));
    }
    CP_COMMIT(); CP_WAIT(0);
    __syncthreads();

    uint32_t qhf[4][4];
    const uint32_t q_off = (uint32_t)((wid * 16 + (lane & 15)) * 144 + (lane >> 4) * 16);
    #pragma unroll
    for (int s = 0; s < 4; s++)
        ldm_x4(qhf[s], sb + q_off + s * 32);
    __syncthreads();

    auto load_kv = [&](int kt, int st) {
        uint32_t buf = sb + st * AST;
        int key0 = kt * 64;
        #pragma unroll
        for (int i = 0; i < 2; i++) {
            int t = tid + i * 256;
            int row = t >> 3, seg = t & 7;
            uint32_t dst = buf + row * 144 + seg * 16;
            size_t sk = (rowbase + key0 + row) * D_ + h * HD_ + seg * 8;
            CP_ASYNC16(dst,           (const char*)(kh + sk));
            CP_ASYNC16(dst + AKL,     (const char*)(kl + sk));
            size_t sv = ((size_t)bh * HD_ + row) * S_ + key0 + seg * 8;
            CP_ASYNC16(dst + 2 * AKL, (const char*)(vth + sv));
            CP_ASYNC16(dst + 3 * AKL, (const char*)(vtl + sv));
        }
        if (tid < 16)
            CP_ASYNC16(sb + AMASK + st * 256 + tid * 16,
                       (const char*)(mask + b * S_ + key0 + tid * 4));
        CP_COMMIT();
    };

    float oacc[8][4];
    #pragma unroll
    for (int nb = 0; nb < 8; nb++)
        #pragma unroll
        for (int j = 0; j < 4; j++) oacc[nb][j] = 0.f;
    float mrow0 = -1e30f, mrow1 = -1e30f, lrow0 = 0.f, lrow1 = 0.f;

    const uint32_t bfrag_off = (uint32_t)((((lane >> 4) & 1) * 8 + (lane & 7)) * 144
                                          + ((lane >> 3) & 1) * 16);

    const int NKT = S_ / 64;
    load_kv(0, 0);
    load_kv(1, 1);

    for (int kt = 0; kt < NKT; kt++) {
        if (kt + 1 < NKT) { CP_WAIT(1); }
        else              { CP_WAIT(0); }
        __syncthreads();

        uint32_t buf = sb + (kt & 1) * AST;

        float sacc[8][4];
        #pragma unroll
        for (int nb = 0; nb < 8; nb++)
            #pragma unroll
            for (int j = 0; j < 4; j++) sacc[nb][j] = 0.f;

        #pragma unroll
        for (int s = 0; s < 4; s++) {
            uint32_t khf[4][4], klf[4][4], qlf[4];
            ldm_x4(qlf, sb + AQLO + q_off + s * 32);
            #pragma unroll
            for (int g = 0; g < 4; g++) {
                uint32_t a = buf + bfrag_off + (uint32_t)(g * 16 * 144 + s * 32);
                ldm_x4(khf[g], a);
                ldm_x4(klf[g], a + AKL);
            }
            #pragma unroll
            for (int g = 0; g < 4; g++)
                #pragma unroll
                for (int j = 0; j < 2; j++)
                    mma16816(sacc[g * 2 + j], qhf[s], khf[g][2 * j], khf[g][2 * j + 1]);
            #pragma unroll
            for (int g = 0; g < 4; g++)
                #pragma unroll
                for (int j = 0; j < 2; j++)
                    mma16816(sacc[g * 2 + j], qhf[s], klf[g][2 * j], klf[g][2 * j + 1]);
            #pragma unroll
            for (int g = 0; g < 4; g++)
                #pragma unroll
                for (int j = 0; j < 2; j++)
                    mma16816(sacc[g * 2 + j], qlf, khf[g][2 * j], khf[g][2 * j + 1]);
        }

        {
            const int* smk = (const int*)(smem + AMASK + (kt & 1) * 256);
            int cb = 2 * (lane & 3);
            #pragma unroll
            for (int nb = 0; nb < 8; nb++) {
                if (smk[nb * 8 + cb] == 0)     { sacc[nb][0] = -1e9f; sacc[nb][2] = -1e9f; }
                if (smk[nb * 8 + cb + 1] == 0) { sacc[nb][1] = -1e9f; sacc[nb][3] = -1e9f; }
            }
        }

        float mx0 = -1e30f, mx1 = -1e30f;
        #pragma unroll
        for (int nb = 0; nb < 8; nb++) {
            mx0 = fmaxf(mx0, fmaxf(sacc[nb][0], sacc[nb][1]));
            mx1 = fmaxf(mx1, fmaxf(sacc[nb][2], sacc[nb][3]));
        }
        mx0 = fmaxf(mx0, __shfl_xor_sync(0xffffffffu, mx0, 1));
        mx0 = fmaxf(mx0, __shfl_xor_sync(0xffffffffu, mx0, 2));
        mx1 = fmaxf(mx1, __shfl_xor_sync(0xffffffffu, mx1, 1));
        mx1 = fmaxf(mx1, __shfl_xor_sync(0xffffffffu, mx1, 2));
        float mn0 = fmaxf(mrow0, mx0), mn1 = fmaxf(mrow1, mx1);
        float corr0 = __expf(mrow0 - mn0), corr1 = __expf(mrow1 - mn1);
        float sum0 = 0.f, sum1 = 0.f;
        #pragma unroll
        for (int nb = 0; nb < 8; nb++) {
            sacc[nb][0] = __expf(sacc[nb][0] - mn0);
            sacc[nb][1] = __expf(sacc[nb][1] - mn0);
            sacc[nb][2] = __expf(sacc[nb][2] - mn1);
            sacc[nb][3] = __expf(sacc[nb][3] - mn1);
            sum0 += sacc[nb][0] + sacc[nb][1];
            sum1 += sacc[nb][2] + sacc[nb][3];
        }
        sum0 += __shfl_xor_sync(0xffffffffu, sum0, 1);
        sum0 += __shfl_xor_sync(0xffffffffu, sum0, 2);
        sum1 += __shfl_xor_sync(0xffffffffu, sum1, 1);
        sum1 += __shfl_xor_sync(0xffffffffu, sum1, 2);
        lrow0 = lrow0 * corr0 + sum0;
        lrow1 = lrow1 * corr1 + sum1;
        mrow0 = mn0; mrow1 = mn1;
        #pragma unroll
        for (int nb = 0; nb < 8; nb++) {
            oacc[nb][0] *= corr0; oacc[nb][1] *= corr0;
            oacc[nb][2] *= corr1; oacc[nb][3] *= corr1;
        }

        #pragma unroll
        for (int c = 0; c < 4; c++) {
            uint32_t pha[4], pla[4];
            #pragma unroll
            for (int half = 0; half < 2; half++) {
                int nb = 2 * c + half;
                __nv_bfloat16 b0 = __float2bfloat16(sacc[nb][0]);
                __nv_bfloat16 b1 = __float2bfloat16(sacc[nb][1]);
                __nv_bfloat16 b2 = __float2bfloat16(sacc[nb][2]);
                __nv_bfloat16 b3 = __float2bfloat16(sacc[nb][3]);
                __nv_bfloat162 t01; t01.x = b0; t01.y = b1;
                __nv_bfloat162 t23; t23.x = b2; t23.y = b3;
                pha[half * 2 + 0] = *(uint32_t*)&t01;
                pha[half * 2 + 1] = *(uint32_t*)&t23;
                pla[half * 2 + 0] = pk_bf16(sacc[nb][0] - __bfloat162float(b0),
                                            sacc[nb][1] - __bfloat162float(b1));
                pla[half * 2 + 1] = pk_bf16(sacc[nb][2] - __bfloat162float(b2),
                                            sacc[nb][3] - __bfloat162float(b3));
            }
            uint32_t vhf[4][4], vlf[4][4];
            #pragma unroll
            for (int g = 0; g < 4; g++) {
                uint32_t a = buf + 2 * AKL + bfrag_off + (uint32_t)(g * 16 * 144 + c * 32);
                ldm_x4(vhf[g], a);
                ldm_x4(vlf[g], a + AKL);
            }
            #pragma unroll
            for (int g = 0; g < 4; g++)
                #pragma unroll
                for (int j = 0; j < 2; j++)
                    mma16816(oacc[g * 2 + j], pha, vhf[g][2 * j], vhf[g][2 * j + 1]);
            #pragma unroll
            for (int g = 0; g < 4; g++)
                #pragma unroll
                for (int j = 0; j < 2; j++)
                    mma16816(oacc[g * 2 + j], pha, vlf[g][2 * j], vlf[g][2 * j + 1]);
            #pragma unroll
            for (int g = 0; g < 4; g++)
                #pragma unroll
                for (int j = 0; j < 2; j++)
                    mma16816(oacc[g * 2 + j], pla, vhf[g][2 * j], vhf[g][2 * j + 1]);
        }
        __syncthreads();
        if (kt + 2 < NKT) load_kv(kt + 2, kt & 1);
    }

    float inv0 = 1.0f / lrow0, inv1 = 1.0f / lrow1;
    int r0 = q0 + wid * 16 + (lane >> 2);
    #pragma unroll
    for (int nb = 0; nb < 8; nb++) {
        int col = h * HD_ + nb * 8 + 2 * (lane & 3);
        size_t i0 = (rowbase + r0) * D_ + col;
        size_t i1 = (rowbase + r0 + 8) * D_ + col;
        uint32_t hw, lw;
        split2(oacc[nb][0] * inv0, oacc[nb][1] * inv0, hw, lw);
        *(uint32_t*)(oh + i0) = hw; *(uint32_t*)(ol + i0) = lw;
        split2(oacc[nb][2] * inv1, oacc[nb][3] * inv1, hw, lw);
        *(uint32_t*)(oh + i1) = hw; *(uint32_t*)(ol + i1) = lw;
    }
}

// ---------------------------------------------------------------------------
// Fused residual add + LayerNorm
// ---------------------------------------------------------------------------
template <bool SPLIT>
__global__ __launch_bounds__(256)
void add_ln(const float* __restrict__ x, const float* __restrict__ y,
            const float* __restrict__ g, const float* __restrict__ bta,
            float* __restrict__ out,
            __nv_bfloat16* __restrict__ oh, __nv_bfloat16* __restrict__ ol) {
    __shared__ float red[256];
    int row = blockIdx.x, tid = threadIdx.x;
    const float* xr = x + (size_t)row * D_;
    const float* yr = y + (size_t)row * D_;

    float v[4];
    float sum = 0.f;
    #pragma unroll
    for (int i = 0; i < 4; i++) {
        int c = tid + i * 256;
        v[i] = xr[c] + yr[c];
        sum += v[i];
    }
    red[tid] = sum; __syncthreads();
    for (int s = 128; s; s >>= 1) { if (tid < s) red[tid] += red[tid + s]; __syncthreads(); }
    float mu = red[0] * (1.0f / 1024.0f);
    __syncthreads();

    float sq = 0.f;
    #pragma unroll
    for (int i = 0; i < 4; i++) { float d = v[i] - mu; sq += d * d; }
    red[tid] = sq; __syncthreads();
    for (int s = 128; s; s >>= 1) { if (tid < s) red[tid] += red[tid + s]; __syncthreads(); }
    float var  = red[0] * (1.0f / 1024.0f);
    float rstd = rsqrtf(var + 1e-5f);

    #pragma unroll
    for (int i = 0; i < 4; i++) {
        int c = tid + i * 256;
        float o = (v[i] - mu) * rstd * g[c] + bta[c];
        out[(size_t)row * D_ + c] = o;
        if (SPLIT) {
            __nv_bfloat16 h = __float2bfloat16(o);
            oh[(size_t)row * D_ + c] = h;
            ol[(size_t)row * D_ + c] = __float2bfloat16(o - __bfloat162float(h));
        }
    }
}

// ---------------------------------------------------------------------------
// Launch
// ---------------------------------------------------------------------------
extern "C" void kernel_launch(void* const* d_in, const int* in_sizes, int n_in,
                              void* d_out, int out_size) {
    const int*   seq    = (const int*)  d_in[0];
    const int*   mask   = (const int*)  d_in[1];
    const float* emb    = (const float*)d_in[2];
    const float* proj_w = (const float*)d_in[3];
    const float* proj_b = (const float*)d_in[4];
    const float* qw     = (const float*)d_in[5];
    const float* qb     = (const float*)d_in[6];
    const float* kw     = (const float*)d_in[7];
    const float* kb     = (const float*)d_in[8];
    const float* vw     = (const float*)d_in[9];
    const float* vb     = (const float*)d_in[10];
    const float* ow     = (const float*)d_in[11];
    const float* ob     = (const float*)d_in[12];
    const float* lng    = (const float*)d_in[13];
    const float* lnb    = (const float*)d_in[14];
    float* out = (float*)d_out;

    float *x, *t, *bqkv;
    __nv_bfloat16 *ah, *al, *wth, *wtl, *qhp, *qlp, *khp, *klp, *vthp, *vtlp;
    cudaGetSymbolAddress((void**)&x,    g_x);
    cudaGetSymbolAddress((void**)&t,    g_t);
    cudaGetSymbolAddress((void**)&bqkv, g_bqkv);
    cudaGetSymbolAddress((void**)&ah,   g_ah);
    cudaGetSymbolAddress((void**)&al,   g_al);
    cudaGetSymbolAddress((void**)&wth,  g_wth);
    cudaGetSymbolAddress((void**)&wtl,  g_wtl);
    cudaGetSymbolAddress((void**)&qhp,  g_qh);
    cudaGetSymbolAddress((void**)&qlp,  g_ql);
    cudaGetSymbolAddress((void**)&khp,  g_kh);
    cudaGetSymbolAddress((void**)&klp,  g_kl);
    cudaGetSymbolAddress((void**)&vthp, g_vth);
    cudaGetSymbolAddress((void**)&vtlp, g_vtl);

    cudaFuncSetAttribute(gemm_mma<false>, cudaFuncAttributeMaxDynamicSharedMemorySize, GEMM_SMEM);
    cudaFuncSetAttribute(gemm_mma<true>,  cudaFuncAttributeMaxDynamicSharedMemorySize, GEMM_SMEM);
    cudaFuncSetAttribute(gemm_qkv, cudaFuncAttributeMaxDynamicSharedMemorySize, GEMM_SMEM);
    cudaFuncSetAttribute(attn_mma, cudaFuncAttributeMaxDynamicSharedMemorySize, ATT_SMEM);

    // ---- weight prep ----
    {
        dim3 tb(32, 8);
        tsplit_w<<<dim3(D_ / 32, SEQDIM_ / 32), tb>>>(proj_w, wth, wtl, SEQDIM_, D_);
        tsplit_all<<<dim3(D_ / 32, D_ / 32, 24), tb>>>(qw, kw, vw, ow, wth, wtl);
        bias_concat<<<(L_ * 3 * D_ + 255) / 256, 256>>>(qb, kb, vb, bqkv);
    }

    // ---- embedding (split staged in q-scratch) + input projection ----
    gather_emb<<<(ROWS_ * SEQDIM_ / 2 + 255) / 256, 256>>>(seq, emb, qhp, qlp);
    dim3 gp(D_ / 128, ROWS_ / 128);              // (8, 64)
    gemm_mma<true><<<gp, 256, GEMM_SMEM>>>(qhp, qlp, wth, wtl, proj_b, x, D_, SEQDIM_, ah, al);

    dim3 gqkv(3 * D_ / 128, ROWS_ / 128);        // (24, 64)
    dim3 ga(S_ / 128, B_ * H_);                  // (16, 64)
    for (int l = 0; l < L_; l++) {
        size_t off = WT_PROJ_ELEMS + (size_t)(l * 4) * WT_MAT_ELEMS;
        const __nv_bfloat16* owh = wth + off + 3 * WT_MAT_ELEMS;
        const __nv_bfloat16* owl = wtl + off + 3 * WT_MAT_ELEMS;

        gemm_qkv<<<gqkv, 256, GEMM_SMEM>>>(ah, al, wth + off, wtl + off,
                                           bqkv + l * 3 * D_,
                                           qhp, qlp, khp, klp, vthp, vtlp);
        attn_mma<<<ga, 256, ATT_SMEM>>>(qhp, qlp, khp, klp, vthp, vtlp, mask, ah, al);
        gemm_mma<false><<<gp, 256, GEMM_SMEM>>>(ah, al, owh, owl, ob + l * D_, t, D_, D_,
                                                nullptr, nullptr);
        if (l == L_ - 1)
            add_ln<false><<<ROWS_, 256>>>(x, t, lng + l * D_, lnb + l * D_, out, nullptr, nullptr);
        else
            add_ln<true><<<ROWS_, 256>>>(x, t, lng + l * D_, lnb + l * D_, x, ah, al);
    }
}

// round 11
// speedup vs baseline: 3.3777x; 1.0022x over previous
#include <cuda_runtime.h>
#include <cuda_bf16.h>
#include <math.h>
#include <stdint.h>

// Problem constants
#define B_      4
#define S_      2048
#define D_      1024
#define H_      16
#define HD_     64
#define L_      6
#define SEQDIM_ 128
#define ROWS_   (B_ * S_)   // 8192

#define WT_PROJ_ELEMS (D_ * SEQDIM_)
#define WT_MAT_ELEMS  (D_ * D_)
#define WT_ELEMS      (WT_PROJ_ELEMS + 24 * WT_MAT_ELEMS)

// ---------------------------------------------------------------------------
// Device scratch
// ---------------------------------------------------------------------------
__device__ float g_x [ROWS_ * D_];
__device__ float g_t [ROWS_ * D_];
__device__ __nv_bfloat16 g_ah[ROWS_ * D_];
__device__ __nv_bfloat16 g_al[ROWS_ * D_];
__device__ __nv_bfloat16 g_wth[WT_ELEMS];
__device__ __nv_bfloat16 g_wtl[WT_ELEMS];
__device__ __nv_bfloat16 g_qh[ROWS_ * D_];
__device__ __nv_bfloat16 g_ql[ROWS_ * D_];
__device__ __nv_bfloat16 g_kh[ROWS_ * D_];
__device__ __nv_bfloat16 g_kl[ROWS_ * D_];
__device__ __nv_bfloat16 g_vth[ROWS_ * D_];   // [bh][64][S]
__device__ __nv_bfloat16 g_vtl[ROWS_ * D_];

// ---------------------------------------------------------------------------
// Helpers
// ---------------------------------------------------------------------------
__device__ __forceinline__ uint32_t smem_u32(const void* p) {
    uint32_t a;
    asm("{ .reg .u64 t; cvta.to.shared.u64 t, %1; cvt.u32.u64 %0, t; }"
        : "=r"(a) : "l"(p));
    return a;
}

// non-volatile: output deps keep correctness; ptxas may schedule freely
__device__ __forceinline__ void ldm_x4(uint32_t* r, uint32_t addr) {
    asm("ldmatrix.sync.aligned.m8n8.x4.shared.b16 {%0,%1,%2,%3}, [%4];"
        : "=r"(r[0]), "=r"(r[1]), "=r"(r[2]), "=r"(r[3]) : "r"(addr));
}

__device__ __forceinline__ void mma16816(float* c, const uint32_t* a,
                                         uint32_t b0, uint32_t b1) {
    asm("mma.sync.aligned.m16n8k16.row.col.f32.bf16.bf16.f32 "
        "{%0,%1,%2,%3}, {%4,%5,%6,%7}, {%8,%9}, {%0,%1,%2,%3};"
        : "+f"(c[0]), "+f"(c[1]), "+f"(c[2]), "+f"(c[3])
        : "r"(a[0]), "r"(a[1]), "r"(a[2]), "r"(a[3]), "r"(b0), "r"(b1));
}

__device__ __forceinline__ uint32_t pk_bf16(float lo, float hi) {
    uint32_t r;
    asm("cvt.rn.bf16x2.f32 %0, %1, %2;" : "=r"(r) : "f"(hi), "f"(lo));
    return r;
}

__device__ __forceinline__ void split2(float c0, float c1, uint32_t& hw, uint32_t& lw) {
    __nv_bfloat16 h0 = __float2bfloat16(c0);
    __nv_bfloat16 h1 = __float2bfloat16(c1);
    __nv_bfloat162 hp; hp.x = h0; hp.y = h1;
    hw = *(uint32_t*)&hp;
    lw = pk_bf16(c0 - __bfloat162float(h0), c1 - __bfloat162float(h1));
}

#define CP_ASYNC16(dst, src) \
    asm volatile("cp.async.cg.shared.global [%0], [%1], 16;" :: "r"(dst), "l"(src))
#define CP_COMMIT() asm volatile("cp.async.commit_group;" ::: "memory")
#define CP_WAIT(n)  asm volatile("cp.async.wait_group %0;" :: "n"(n) : "memory")

// ---------------------------------------------------------------------------
// Batched weight transpose + split: z<24 layer matrices, z==24 proj_w
// ---------------------------------------------------------------------------
__global__ void tsplit_all(const float* __restrict__ qw, const float* __restrict__ kw,
                           const float* __restrict__ vw, const float* __restrict__ ow,
                           const float* __restrict__ pw,
                           __nv_bfloat16* __restrict__ th,
                           __nv_bfloat16* __restrict__ tl) {
    __shared__ float t[32][33];
    int z = blockIdx.z;
    const float* W;
    size_t dof;
    int K;
    if (z < 24) {
        int l = z >> 2, m = z & 3;
        W = (m == 0 ? qw : m == 1 ? kw : m == 2 ? vw : ow) + (size_t)l * D_ * D_;
        dof = WT_PROJ_ELEMS + (size_t)z * WT_MAT_ELEMS;
        K = D_;
    } else {
        if (blockIdx.y >= SEQDIM_ / 32) return;
        W = pw;
        dof = 0;
        K = SEQDIM_;
    }
    int bx = blockIdx.x * 32;
    int by = blockIdx.y * 32;
    #pragma unroll
    for (int i = 0; i < 32; i += 8)
        t[threadIdx.y + i][threadIdx.x] =
            W[(size_t)(by + threadIdx.y + i) * D_ + bx + threadIdx.x];
    __syncthreads();
    #pragma unroll
    for (int i = 0; i < 32; i += 8) {
        float v = t[threadIdx.x][threadIdx.y + i];
        int n = bx + threadIdx.y + i;
        int k = by + threadIdx.x;
        __nv_bfloat16 h = __float2bfloat16(v);
        th[dof + (size_t)n * K + k] = h;
        tl[dof + (size_t)n * K + k] = __float2bfloat16(v - __bfloat162float(h));
    }
}

// ---------------------------------------------------------------------------
// Embedding gather -> direct bf16 hi/lo split
// ---------------------------------------------------------------------------
__global__ void gather_emb(const int* __restrict__ seq,
                           const float* __restrict__ emb,
                           __nv_bfloat16* __restrict__ xh,
                           __nv_bfloat16* __restrict__ xl) {
    int i = blockIdx.x * blockDim.x + threadIdx.x;
    if (i >= ROWS_ * SEQDIM_ / 2) return;
    int row = i >> 6;
    int c2  = (i & 63) * 2;
    const float* e = emb + seq[row] * SEQDIM_ + c2;
    uint32_t hw, lw;
    split2(e[0], e[1], hw, lw);
    ((uint32_t*)xh)[i] = hw;
    ((uint32_t*)xl)[i] = lw;
}

// ---------------------------------------------------------------------------
// GEMM core: 128x128 block tile, 8 warps of 64x32, BK=32, 2-stage cp.async,
// 3-pass bf16 split issued pass-major. 2 CTAs/SM.
// ---------------------------------------------------------------------------
#define TILEB  10240            // 128 * 80
#define CHUNKB (4 * TILEB)      // 40960
#define GEMM_SMEM (2 * CHUNKB)  // 81920

template <typename EPI>
__device__ __forceinline__
void gemm_core(const __nv_bfloat16* s0, const __nv_bfloat16* s1,
               const __nv_bfloat16* s2, const __nv_bfloat16* s3,
               int K, char* smem, EPI epilogue) {
    const uint32_t sb = smem_u32(smem);
    const int tid  = threadIdx.x;
    const int lane = tid & 31;
    const int wid  = tid >> 5;
    const int wm = wid & 1;
    const int wn = wid >> 1;

    const int nk = K >> 5;

    auto load_chunk = [&](int c, int stage) {
        const int k0 = c << 5;
        uint32_t buf = sb + stage * CHUNKB;
        #pragma unroll
        for (int i = 0; i < 2; i++) {
            int t = tid + i * 256;
            int row = t >> 2;
            int seg = t & 3;
            uint32_t dst = buf + row * 80 + seg * 16;
            size_t so = (size_t)row * K + k0 + seg * 8;
            CP_ASYNC16(dst,              (const char*)(s0 + so));
            CP_ASYNC16(dst + TILEB,      (const char*)(s1 + so));
            CP_ASYNC16(dst + 2 * TILEB,  (const char*)(s2 + so));
            CP_ASYNC16(dst + 3 * TILEB,  (const char*)(s3 + so));
        }
        CP_COMMIT();
    };

    float acc[4][4][4];
    #pragma unroll
    for (int mi = 0; mi < 4; mi++)
        #pragma unroll
        for (int nb = 0; nb < 4; nb++)
            #pragma unroll
            for (int j = 0; j < 4; j++) acc[mi][nb][j] = 0.f;

    const uint32_t a_off = (uint32_t)((wm * 64 + (lane & 15)) * 80 + (lane >> 4) * 16);
    const uint32_t b_off = (uint32_t)((wn * 32 + ((lane >> 4) & 1) * 8 + (lane & 7)) * 80
                                      + ((lane >> 3) & 1) * 16);

    load_chunk(0, 0);

    for (int c = 0; c < nk; c++) {
        if (c + 1 < nk) { load_chunk(c + 1, (c + 1) & 1); CP_WAIT(1); }
        else            { CP_WAIT(0); }
        __syncthreads();

        uint32_t buf = sb + (c & 1) * CHUNKB;
        #pragma unroll
        for (int s = 0; s < 2; s++) {
            uint32_t ah[4][4], al[4][4], wh[2][4], wl[2][4];
            #pragma unroll
            for (int g = 0; g < 4; g++) {
                uint32_t ao = buf + a_off + (uint32_t)(g * 16 * 80 + s * 32);
                ldm_x4(ah[g], ao);
                ldm_x4(al[g], ao + TILEB);
            }
            #pragma unroll
            for (int h = 0; h < 2; h++) {
                uint32_t bo = buf + 2 * TILEB + b_off + (uint32_t)(h * 16 * 80 + s * 32);
                ldm_x4(wh[h], bo);
                ldm_x4(wl[h], bo + TILEB);
            }
            #pragma unroll
            for (int mi = 0; mi < 4; mi++)
                #pragma unroll
                for (int nb = 0; nb < 4; nb++) {
                    const int h = nb >> 1, j = nb & 1;
                    mma16816(acc[mi][nb], ah[mi], wh[h][2 * j], wh[h][2 * j + 1]);
                }
            #pragma unroll
            for (int mi = 0; mi < 4; mi++)
                #pragma unroll
                for (int nb = 0; nb < 4; nb++) {
                    const int h = nb >> 1, j = nb & 1;
                    mma16816(acc[mi][nb], ah[mi], wl[h][2 * j], wl[h][2 * j + 1]);
                }
            #pragma unroll
            for (int mi = 0; mi < 4; mi++)
                #pragma unroll
                for (int nb = 0; nb < 4; nb++) {
                    const int h = nb >> 1, j = nb & 1;
                    mma16816(acc[mi][nb], al[mi], wh[h][2 * j], wh[h][2 * j + 1]);
                }
        }
        __syncthreads();
    }

    epilogue(acc, wm, wn, lane);
}

// ---------------------------------------------------------------------------
// Generic GEMM + bias -> fp32 C (optionally also emit bf16 hi/lo split)
// ---------------------------------------------------------------------------
template <bool SPLIT>
__global__ __launch_bounds__(256, 2)
void gemm_mma(const __nv_bfloat16* __restrict__ Ah,
              const __nv_bfloat16* __restrict__ Al,
              const __nv_bfloat16* __restrict__ Wh,
              const __nv_bfloat16* __restrict__ Wl,
              const float* __restrict__ bias,
              float* __restrict__ C, int N, int K,
              __nv_bfloat16* __restrict__ oh, __nv_bfloat16* __restrict__ ol) {
    extern __shared__ char smem[];
    const int brow = blockIdx.y * 128;
    const int bcol = blockIdx.x * 128;
    gemm_core(Ah + (size_t)brow * K, Al + (size_t)brow * K,
              Wh + (size_t)bcol * K, Wl + (size_t)bcol * K, K, smem,
        [&](float acc[4][4][4], int wm, int wn, int lane) {
            #pragma unroll
            for (int mi = 0; mi < 4; mi++) {
                int row = brow + wm * 64 + mi * 16 + (lane >> 2);
                #pragma unroll
                for (int nb = 0; nb < 4; nb++) {
                    int col = bcol + wn * 32 + nb * 8 + (lane & 3) * 2;
                    float b0 = bias[col], b1 = bias[col + 1];
                    float c00 = acc[mi][nb][0] + b0, c01 = acc[mi][nb][1] + b1;
                    float c10 = acc[mi][nb][2] + b0, c11 = acc[mi][nb][3] + b1;
                    size_t i0 = (size_t)row * N + col;
                    size_t i1 = (size_t)(row + 8) * N + col;
                    *(float2*)(C + i0) = make_float2(c00, c01);
                    *(float2*)(C + i1) = make_float2(c10, c11);
                    if (SPLIT) {
                        uint32_t hw, lw;
                        split2(c00, c01, hw, lw);
                        *(uint32_t*)(oh + i0) = hw; *(uint32_t*)(ol + i0) = lw;
                        split2(c10, c11, hw, lw);
                        *(uint32_t*)(oh + i1) = hw; *(uint32_t*)(ol + i1) = lw;
                    }
                }
            }
        });
}

// ---------------------------------------------------------------------------
// Fused QKV GEMM (N=3072, weights contiguous). Bias read directly from
// qb/kb/vb (+layer offset). V emitted transposed+split via smem staging
// for coalesced stores.
// ---------------------------------------------------------------------------
__global__ __launch_bounds__(256, 2)
void gemm_qkv(const __nv_bfloat16* __restrict__ Ah,
              const __nv_bfloat16* __restrict__ Al,
              const __nv_bfloat16* __restrict__ Wh,
              const __nv_bfloat16* __restrict__ Wl,
              const float* __restrict__ qb, const float* __restrict__ kb,
              const float* __restrict__ vb, int lofs,
              __nv_bfloat16* __restrict__ qh, __nv_bfloat16* __restrict__ ql,
              __nv_bfloat16* __restrict__ kh, __nv_bfloat16* __restrict__ kl,
              __nv_bfloat16* __restrict__ vth, __nv_bfloat16* __restrict__ vtl) {
    extern __shared__ char smem[];
    const int K = D_;
    const int brow = blockIdx.y * 128;
    const int bcol = blockIdx.x * 128;
    const int mat = bcol >> 10;            // 0=q 1=k 2=v
    const int colb = bcol & 1023;
    const float* bias = (mat == 0 ? qb : mat == 1 ? kb : vb) + lofs;
    gemm_core(Ah + (size_t)brow * K, Al + (size_t)brow * K,
              Wh + (size_t)bcol * K, Wl + (size_t)bcol * K, K, smem,
        [&](float acc[4][4][4], int wm, int wn, int lane) {
            if (mat == 2) {
                // Stage transposed fp32 tile in smem: trans[d_local][s_local]
                float* trans = (float*)smem;   // 128 x 132 floats = 67.6KB
                #pragma unroll
                for (int mi = 0; mi < 4; mi++) {
                    int sl = wm * 64 + mi * 16 + (lane >> 2);
                    #pragma unroll
                    for (int nb = 0; nb < 4; nb++) {
                        int dl = wn * 32 + nb * 8 + (lane & 3) * 2;
                        float b0 = bias[colb + dl], b1 = bias[colb + dl + 1];
                        trans[dl * 132 + sl]           = acc[mi][nb][0] + b0;
                        trans[(dl + 1) * 132 + sl]     = acc[mi][nb][1] + b1;
                        trans[dl * 132 + sl + 8]       = acc[mi][nb][2] + b0;
                        trans[(dl + 1) * 132 + sl + 8] = acc[mi][nb][3] + b1;
                    }
                }
                __syncthreads();
                // Coalesced bf16 hi/lo stores along s
                int bb = brow >> 11;
                int s0 = brow & (S_ - 1);
                #pragma unroll
                for (int i = 0; i < 32; i++) {
                    int idx = (int)threadIdx.x + i * 256;   // 0..8191
                    int dl = idx >> 6;
                    int sp = idx & 63;
                    float2 v = *(float2*)&trans[dl * 132 + sp * 2];
                    int col = colb + dl;
                    int hh = col >> 6, dd = col & 63;
                    size_t o = ((size_t)(bb * H_ + hh) * HD_ + dd) * S_ + s0 + sp * 2;
                    uint32_t hw, lw;
                    split2(v.x, v.y, hw, lw);
                    *(uint32_t*)(vth + o) = hw;
                    *(uint32_t*)(vtl + o) = lw;
                }
            } else {
                #pragma unroll
                for (int mi = 0; mi < 4; mi++) {
                    int row = brow + wm * 64 + mi * 16 + (lane >> 2);
                    #pragma unroll
                    for (int nb = 0; nb < 4; nb++) {
                        int col = colb + wn * 32 + nb * 8 + (lane & 3) * 2;
                        float b0 = bias[col], b1 = bias[col + 1];
                        float c00 = acc[mi][nb][0] + b0, c01 = acc[mi][nb][1] + b1;
                        float c10 = acc[mi][nb][2] + b0, c11 = acc[mi][nb][3] + b1;
                        size_t i0 = (size_t)row * D_ + col;
                        size_t i1 = (size_t)(row + 8) * D_ + col;
                        __nv_bfloat16* hB = (mat == 0) ? qh : kh;
                        __nv_bfloat16* lB = (mat == 0) ? ql : kl;
                        if (mat == 0) { c00 *= 0.125f; c01 *= 0.125f; c10 *= 0.125f; c11 *= 0.125f; }
                        uint32_t hw, lw;
                        split2(c00, c01, hw, lw);
                        *(uint32_t*)(hB + i0) = hw; *(uint32_t*)(lB + i0) = lw;
                        split2(c10, c11, hw, lw);
                        *(uint32_t*)(hB + i1) = hw; *(uint32_t*)(lB + i1) = lw;
                    }
                }
            }
        });
}

// ---------------------------------------------------------------------------
// Tensor-core flash attention; 2-stage KV pipeline, Q-lo in smem, 2 CTAs/SM
// ---------------------------------------------------------------------------
#define AST      36864
#define AKL      9216
#define AMASK    (2 * AST)
#define AQLO     (AMASK + 512)
#define ATT_SMEM (AQLO + 18432)        // 92672

__global__ __launch_bounds__(256, 2)
void attn_mma(const __nv_bfloat16* __restrict__ qh, const __nv_bfloat16* __restrict__ ql,
              const __nv_bfloat16* __restrict__ kh, const __nv_bfloat16* __restrict__ kl,
              const __nv_bfloat16* __restrict__ vth, const __nv_bfloat16* __restrict__ vtl,
              const int* __restrict__ mask,
              __nv_bfloat16* __restrict__ oh, __nv_bfloat16* __restrict__ ol) {
    extern __shared__ char smem[];
    const uint32_t sb = smem_u32(smem);
    const int tid = threadIdx.x, wid = tid >> 5, lane = tid & 31;
    const int q0 = blockIdx.x * 128;
    const int bh = blockIdx.y;
    const int b = bh >> 4, h = bh & 15;
    const size_t rowbase = (size_t)b * S_;

    #pragma unroll
    for (int i = 0; i < 4; i++) {
        int t = tid + i * 256;
        int row = t >> 3, seg = t & 7;
        size_t so = (rowbase + q0 + row) * D_ + h * HD_ + seg * 8;
        CP_ASYNC16(sb + row * 144 + seg * 16,        (const char*)(qh + so));
        CP_ASYNC16(sb + AQLO + row * 144 + seg * 16, (const char*)(ql + so));
    }
    CP_COMMIT(); CP_WAIT(0);
    __syncthreads();

    uint32_t qhf[4][4];
    const uint32_t q_off = (uint32_t)((wid * 16 + (lane & 15)) * 144 + (lane >> 4) * 16);
    #pragma unroll
    for (int s = 0; s < 4; s++)
        ldm_x4(qhf[s], sb + q_off + s * 32);
    __syncthreads();

    auto load_kv = [&](int kt, int st) {
        uint32_t buf = sb + st * AST;
        int key0 = kt * 64;
        #pragma unroll
        for (int i = 0; i < 2; i++) {
            int t = tid + i * 256;
            int row = t >> 3, seg = t & 7;
            uint32_t dst = buf + row * 144 + seg * 16;
            size_t sk = (rowbase + key0 + row) * D_ + h * HD_ + seg * 8;
            CP_ASYNC16(dst,           (const char*)(kh + sk));
            CP_ASYNC16(dst + AKL,     (const char*)(kl + sk));
            size_t sv = ((size_t)bh * HD_ + row) * S_ + key0 + seg * 8;
            CP_ASYNC16(dst + 2 * AKL, (const char*)(vth + sv));
            CP_ASYNC16(dst + 3 * AKL, (const char*)(vtl + sv));
        }
        if (tid < 16)
            CP_ASYNC16(sb + AMASK + st * 256 + tid * 16,
                       (const char*)(mask + b * S_ + key0 + tid * 4));
        CP_COMMIT();
    };

    float oacc[8][4];
    #pragma unroll
    for (int nb = 0; nb < 8; nb++)
        #pragma unroll
        for (int j = 0; j < 4; j++) oacc[nb][j] = 0.f;
    float mrow0 = -1e30f, mrow1 = -1e30f, lrow0 = 0.f, lrow1 = 0.f;

    const uint32_t bfrag_off = (uint32_t)((((lane >> 4) & 1) * 8 + (lane & 7)) * 144
                                          + ((lane >> 3) & 1) * 16);

    const int NKT = S_ / 64;
    load_kv(0, 0);
    load_kv(1, 1);

    for (int kt = 0; kt < NKT; kt++) {
        if (kt + 1 < NKT) { CP_WAIT(1); }
        else              { CP_WAIT(0); }
        __syncthreads();

        uint32_t buf = sb + (kt & 1) * AST;

        float sacc[8][4];
        #pragma unroll
        for (int nb = 0; nb < 8; nb++)
            #pragma unroll
            for (int j = 0; j < 4; j++) sacc[nb][j] = 0.f;

        #pragma unroll
        for (int s = 0; s < 4; s++) {
            uint32_t khf[4][4], klf[4][4], qlf[4];
            ldm_x4(qlf, sb + AQLO + q_off + s * 32);
            #pragma unroll
            for (int g = 0; g < 4; g++) {
                uint32_t a = buf + bfrag_off + (uint32_t)(g * 16 * 144 + s * 32);
                ldm_x4(khf[g], a);
                ldm_x4(klf[g], a + AKL);
            }
            #pragma unroll
            for (int g = 0; g < 4; g++)
                #pragma unroll
                for (int j = 0; j < 2; j++)
                    mma16816(sacc[g * 2 + j], qhf[s], khf[g][2 * j], khf[g][2 * j + 1]);
            #pragma unroll
            for (int g = 0; g < 4; g++)
                #pragma unroll
                for (int j = 0; j < 2; j++)
                    mma16816(sacc[g * 2 + j], qhf[s], klf[g][2 * j], klf[g][2 * j + 1]);
            #pragma unroll
            for (int g = 0; g < 4; g++)
                #pragma unroll
                for (int j = 0; j < 2; j++)
                    mma16816(sacc[g * 2 + j], qlf, khf[g][2 * j], khf[g][2 * j + 1]);
        }

        {
            const int* smk = (const int*)(smem + AMASK + (kt & 1) * 256);
            int cb = 2 * (lane & 3);
            #pragma unroll
            for (int nb = 0; nb < 8; nb++) {
                if (smk[nb * 8 + cb] == 0)     { sacc[nb][0] = -1e9f; sacc[nb][2] = -1e9f; }
                if (smk[nb * 8 + cb + 1] == 0) { sacc[nb][1] = -1e9f; sacc[nb][3] = -1e9f; }
            }
        }

        float mx0 = -1e30f, mx1 = -1e30f;
        #pragma unroll
        for (int nb = 0; nb < 8; nb++) {
            mx0 = fmaxf(mx0, fmaxf(sacc[nb][0], sacc[nb][1]));
            mx1 = fmaxf(mx1, fmaxf(sacc[nb][2], sacc[nb][3]));
        }
        mx0 = fmaxf(mx0, __shfl_xor_sync(0xffffffffu, mx0, 1));
        mx0 = fmaxf(mx0, __shfl_xor_sync(0xffffffffu, mx0, 2));
        mx1 = fmaxf(mx1, __shfl_xor_sync(0xffffffffu, mx1, 1));
        mx1 = fmaxf(mx1, __shfl_xor_sync(0xffffffffu, mx1, 2));
        float mn0 = fmaxf(mrow0, mx0), mn1 = fmaxf(mrow1, mx1);
        float corr0 = __expf(mrow0 - mn0), corr1 = __expf(mrow1 - mn1);
        float sum0 = 0.f, sum1 = 0.f;
        #pragma unroll
        for (int nb = 0; nb < 8; nb++) {
            sacc[nb][0] = __expf(sacc[nb][0] - mn0);
            sacc[nb][1] = __expf(sacc[nb][1] - mn0);
            sacc[nb][2] = __expf(sacc[nb][2] - mn1);
            sacc[nb][3] = __expf(sacc[nb][3] - mn1);
            sum0 += sacc[nb][0] + sacc[nb][1];
            sum1 += sacc[nb][2] + sacc[nb][3];
        }
        sum0 += __shfl_xor_sync(0xffffffffu, sum0, 1);
        sum0 += __shfl_xor_sync(0xffffffffu, sum0, 2);
        sum1 += __shfl_xor_sync(0xffffffffu, sum1, 1);
        sum1 += __shfl_xor_sync(0xffffffffu, sum1, 2);
        lrow0 = lrow0 * corr0 + sum0;
        lrow1 = lrow1 * corr1 + sum1;
        mrow0 = mn0; mrow1 = mn1;
        #pragma unroll
        for (int nb = 0; nb < 8; nb++) {
            oacc[nb][0] *= corr0; oacc[nb][1] *= corr0;
            oacc[nb][2] *= corr1; oacc[nb][3] *= corr1;
        }

        #pragma unroll
        for (int c = 0; c < 4; c++) {
            uint32_t pha[4], pla[4];
            #pragma unroll
            for (int half = 0; half < 2; half++) {
                int nb = 2 * c + half;
                __nv_bfloat16 b0 = __float2bfloat16(sacc[nb][0]);
                __nv_bfloat16 b1 = __float2bfloat16(sacc[nb][1]);
                __nv_bfloat16 b2 = __float2bfloat16(sacc[nb][2]);
                __nv_bfloat16 b3 = __float2bfloat16(sacc[nb][3]);
                __nv_bfloat162 t01; t01.x = b0; t01.y = b1;
                __nv_bfloat162 t23; t23.x = b2; t23.y = b3;
                pha[half * 2 + 0] = *(uint32_t*)&t01;
                pha[half * 2 + 1] = *(uint32_t*)&t23;
                pla[half * 2 + 0] = pk_bf16(sacc[nb][0] - __bfloat162float(b0),
                                            sacc[nb][1] - __bfloat162float(b1));
                pla[half * 2 + 1] = pk_bf16(sacc[nb][2] - __bfloat162float(b2),
                                            sacc[nb][3] - __bfloat162float(b3));
            }
            uint32_t vhf[4][4], vlf[4][4];
            #pragma unroll
            for (int g = 0; g < 4; g++) {
                uint32_t a = buf + 2 * AKL + bfrag_off + (uint32_t)(g * 16 * 144 + c * 32);
                ldm_x4(vhf[g], a);
                ldm_x4(vlf[g], a + AKL);
            }
            #pragma unroll
            for (int g = 0; g < 4; g++)
                #pragma unroll
                for (int j = 0; j < 2; j++)
                    mma16816(oacc[g * 2 + j], pha, vhf[g][2 * j], vhf[g][2 * j + 1]);
            #pragma unroll
            for (int g = 0; g < 4; g++)
                #pragma unroll
                for (int j = 0; j < 2; j++)
                    mma16816(oacc[g * 2 + j], pha, vlf[g][2 * j], vlf[g][2 * j + 1]);
            #pragma unroll
            for (int g = 0; g < 4; g++)
                #pragma unroll
                for (int j = 0; j < 2; j++)
                    mma16816(oacc[g * 2 + j], pla, vhf[g][2 * j], vhf[g][2 * j + 1]);
        }
        __syncthreads();
        if (kt + 2 < NKT) load_kv(kt + 2, kt & 1);
    }

    float inv0 = 1.0f / lrow0, inv1 = 1.0f / lrow1;
    int r0 = q0 + wid * 16 + (lane >> 2);
    #pragma unroll
    for (int nb = 0; nb < 8; nb++) {
        int col = h * HD_ + nb * 8 + 2 * (lane & 3);
        size_t i0 = (rowbase + r0) * D_ + col;
        size_t i1 = (rowbase + r0 + 8) * D_ + col;
        uint32_t hw, lw;
        split2(oacc[nb][0] * inv0, oacc[nb][1] * inv0, hw, lw);
        *(uint32_t*)(oh + i0) = hw; *(uint32_t*)(ol + i0) = lw;
        split2(oacc[nb][2] * inv1, oacc[nb][3] * inv1, hw, lw);
        *(uint32_t*)(oh + i1) = hw; *(uint32_t*)(ol + i1) = lw;
    }
}

// ---------------------------------------------------------------------------
// Fused residual add + LayerNorm
// ---------------------------------------------------------------------------
template <bool SPLIT>
__global__ __launch_bounds__(256)
void add_ln(const float* __restrict__ x, const float* __restrict__ y,
            const float* __restrict__ g, const float* __restrict__ bta,
            float* __restrict__ out,
            __nv_bfloat16* __restrict__ oh, __nv_bfloat16* __restrict__ ol) {
    __shared__ float red[256];
    int row = blockIdx.x, tid = threadIdx.x;
    const float* xr = x + (size_t)row * D_;
    const float* yr = y + (size_t)row * D_;

    float v[4];
    float sum = 0.f;
    #pragma unroll
    for (int i = 0; i < 4; i++) {
        int c = tid + i * 256;
        v[i] = xr[c] + yr[c];
        sum += v[i];
    }
    red[tid] = sum; __syncthreads();
    for (int s = 128; s; s >>= 1) { if (tid < s) red[tid] += red[tid + s]; __syncthreads(); }
    float mu = red[0] * (1.0f / 1024.0f);
    __syncthreads();

    float sq = 0.f;
    #pragma unroll
    for (int i = 0; i < 4; i++) { float d = v[i] - mu; sq += d * d; }
    red[tid] = sq; __syncthreads();
    for (int s = 128; s; s >>= 1) { if (tid < s) red[tid] += red[tid + s]; __syncthreads(); }
    float var  = red[0] * (1.0f / 1024.0f);
    float rstd = rsqrtf(var + 1e-5f);

    #pragma unroll
    for (int i = 0; i < 4; i++) {
        int c = tid + i * 256;
        float o = (v[i] - mu) * rstd * g[c] + bta[c];
        out[(size_t)row * D_ + c] = o;
        if (SPLIT) {
            __nv_bfloat16 h = __float2bfloat16(o);
            oh[(size_t)row * D_ + c] = h;
            ol[(size_t)row * D_ + c] = __float2bfloat16(o - __bfloat162float(h));
        }
    }
}

// ---------------------------------------------------------------------------
// Launch
// ---------------------------------------------------------------------------
extern "C" void kernel_launch(void* const* d_in, const int* in_sizes, int n_in,
                              void* d_out, int out_size) {
    const int*   seq    = (const int*)  d_in[0];
    const int*   mask   = (const int*)  d_in[1];
    const float* emb    = (const float*)d_in[2];
    const float* proj_w = (const float*)d_in[3];
    const float* proj_b = (const float*)d_in[4];
    const float* qw     = (const float*)d_in[5];
    const float* qb     = (const float*)d_in[6];
    const float* kw     = (const float*)d_in[7];
    const float* kb     = (const float*)d_in[8];
    const float* vw     = (const float*)d_in[9];
    const float* vb     = (const float*)d_in[10];
    const float* ow     = (const float*)d_in[11];
    const float* ob     = (const float*)d_in[12];
    const float* lng    = (const float*)d_in[13];
    const float* lnb    = (const float*)d_in[14];
    float* out = (float*)d_out;

    float *x, *t;
    __nv_bfloat16 *ah, *al, *wth, *wtl, *qhp, *qlp, *khp, *klp, *vthp, *vtlp;
    cudaGetSymbolAddress((void**)&x,    g_x);
    cudaGetSymbolAddress((void**)&t,    g_t);
    cudaGetSymbolAddress((void**)&ah,   g_ah);
    cudaGetSymbolAddress((void**)&al,   g_al);
    cudaGetSymbolAddress((void**)&wth,  g_wth);
    cudaGetSymbolAddress((void**)&wtl,  g_wtl);
    cudaGetSymbolAddress((void**)&qhp,  g_qh);
    cudaGetSymbolAddress((void**)&qlp,  g_ql);
    cudaGetSymbolAddress((void**)&khp,  g_kh);
    cudaGetSymbolAddress((void**)&klp,  g_kl);
    cudaGetSymbolAddress((void**)&vthp, g_vth);
    cudaGetSymbolAddress((void**)&vtlp, g_vtl);

    cudaFuncSetAttribute(gemm_mma<false>, cudaFuncAttributeMaxDynamicSharedMemorySize, GEMM_SMEM);
    cudaFuncSetAttribute(gemm_mma<true>,  cudaFuncAttributeMaxDynamicSharedMemorySize, GEMM_SMEM);
    cudaFuncSetAttribute(gemm_qkv, cudaFuncAttributeMaxDynamicSharedMemorySize, GEMM_SMEM);
    cudaFuncSetAttribute(attn_mma, cudaFuncAttributeMaxDynamicSharedMemorySize, ATT_SMEM);

    // launch 0: all weight transposes (24 layer mats + proj at z=24)
    tsplit_all<<<dim3(D_ / 32, D_ / 32, 25), dim3(32, 8)>>>(qw, kw, vw, ow, proj_w, wth, wtl);
    // launch 1: embedding gather+split (staged in q-scratch)
    gather_emb<<<(ROWS_ * SEQDIM_ / 2 + 255) / 256, 256>>>(seq, emb, qhp, qlp);
    // launch 2: input projection
    dim3 gp(D_ / 128, ROWS_ / 128);
    gemm_mma<true><<<gp, 256, GEMM_SMEM>>>(qhp, qlp, wth, wtl, proj_b, x, D_, SEQDIM_, ah, al);

    dim3 gqkv(3 * D_ / 128, ROWS_ / 128);        // (24, 64)
    dim3 ga(S_ / 128, B_ * H_);                  // (16, 64)
    for (int l = 0; l < L_; l++) {
        size_t off = WT_PROJ_ELEMS + (size_t)(l * 4) * WT_MAT_ELEMS;
        const __nv_bfloat16* owh = wth + off + 3 * WT_MAT_ELEMS;
        const __nv_bfloat16* owl = wtl + off + 3 * WT_MAT_ELEMS;

        // launch 3 (layer 0) = profiled kernel
        gemm_qkv<<<gqkv, 256, GEMM_SMEM>>>(ah, al, wth + off, wtl + off,
                                           qb, kb, vb, l * D_,
                                           qhp, qlp, khp, klp, vthp, vtlp);
        attn_mma<<<ga, 256, ATT_SMEM>>>(qhp, qlp, khp, klp, vthp, vtlp, mask, ah, al);
        gemm_mma<false><<<gp, 256, GEMM_SMEM>>>(ah, al, owh, owl, ob + l * D_, t, D_, D_,
                                                nullptr, nullptr);
        if (l == L_ - 1)
            add_ln<false><<<ROWS_, 256>>>(x, t, lng + l * D_, lnb + l * D_, out, nullptr, nullptr);
        else
            add_ln<true><<<ROWS_, 256>>>(x, t, lng + l * D_, lnb + l * D_, x, ah, al);
    }
}

// round 12
// speedup vs baseline: 3.4073x; 1.0088x over previous
#include <cuda_runtime.h>
#include <cuda_bf16.h>
#include <math.h>
#include <stdint.h>

// Problem constants
#define B_      4
#define S_      2048
#define D_      1024
#define H_      16
#define HD_     64
#define L_      6
#define SEQDIM_ 128
#define ROWS_   (B_ * S_)   // 8192

#define WT_PROJ_ELEMS (D_ * SEQDIM_)
#define WT_MAT_ELEMS  (D_ * D_)
#define WT_ELEMS      (WT_PROJ_ELEMS + 24 * WT_MAT_ELEMS)

// ---------------------------------------------------------------------------
// Device scratch
// ---------------------------------------------------------------------------
__device__ float g_x [ROWS_ * D_];
__device__ float g_t [ROWS_ * D_];
__device__ __nv_bfloat16 g_ah[ROWS_ * D_];
__device__ __nv_bfloat16 g_al[ROWS_ * D_];
__device__ __nv_bfloat16 g_wth[WT_ELEMS];
__device__ __nv_bfloat16 g_wtl[WT_ELEMS];
__device__ __nv_bfloat16 g_qh[ROWS_ * D_];
__device__ __nv_bfloat16 g_ql[ROWS_ * D_];
__device__ __nv_bfloat16 g_kh[ROWS_ * D_];
__device__ __nv_bfloat16 g_kl[ROWS_ * D_];
__device__ __nv_bfloat16 g_vth[ROWS_ * D_];   // [bh][64][S]
__device__ __nv_bfloat16 g_vtl[ROWS_ * D_];

// ---------------------------------------------------------------------------
// Helpers
// ---------------------------------------------------------------------------
__device__ __forceinline__ uint32_t smem_u32(const void* p) {
    uint32_t a;
    asm("{ .reg .u64 t; cvta.to.shared.u64 t, %1; cvt.u32.u64 %0, t; }"
        : "=r"(a) : "l"(p));
    return a;
}

__device__ __forceinline__ void ldm_x4(uint32_t* r, uint32_t addr) {
    asm("ldmatrix.sync.aligned.m8n8.x4.shared.b16 {%0,%1,%2,%3}, [%4];"
        : "=r"(r[0]), "=r"(r[1]), "=r"(r[2]), "=r"(r[3]) : "r"(addr));
}

__device__ __forceinline__ void mma16816(float* c, const uint32_t* a,
                                         uint32_t b0, uint32_t b1) {
    asm("mma.sync.aligned.m16n8k16.row.col.f32.bf16.bf16.f32 "
        "{%0,%1,%2,%3}, {%4,%5,%6,%7}, {%8,%9}, {%0,%1,%2,%3};"
        : "+f"(c[0]), "+f"(c[1]), "+f"(c[2]), "+f"(c[3])
        : "r"(a[0]), "r"(a[1]), "r"(a[2]), "r"(a[3]), "r"(b0), "r"(b1));
}

__device__ __forceinline__ uint32_t pk_bf16(float lo, float hi) {
    uint32_t r;
    asm("cvt.rn.bf16x2.f32 %0, %1, %2;" : "=r"(r) : "f"(hi), "f"(lo));
    return r;
}

__device__ __forceinline__ void split2(float c0, float c1, uint32_t& hw, uint32_t& lw) {
    __nv_bfloat16 h0 = __float2bfloat16(c0);
    __nv_bfloat16 h1 = __float2bfloat16(c1);
    __nv_bfloat162 hp; hp.x = h0; hp.y = h1;
    hw = *(uint32_t*)&hp;
    lw = pk_bf16(c0 - __bfloat162float(h0), c1 - __bfloat162float(h1));
}

#define CP_ASYNC16(dst, src) \
    asm volatile("cp.async.cg.shared.global [%0], [%1], 16;" :: "r"(dst), "l"(src))
#define CP_COMMIT() asm volatile("cp.async.commit_group;" ::: "memory")
#define CP_WAIT(n)  asm volatile("cp.async.wait_group %0;" :: "n"(n) : "memory")

// ---------------------------------------------------------------------------
// Batched weight transpose + split: z<24 layer matrices, z==24 proj_w
// ---------------------------------------------------------------------------
__global__ void tsplit_all(const float* __restrict__ qw, const float* __restrict__ kw,
                           const float* __restrict__ vw, const float* __restrict__ ow,
                           const float* __restrict__ pw,
                           __nv_bfloat16* __restrict__ th,
                           __nv_bfloat16* __restrict__ tl) {
    __shared__ float t[32][33];
    int z = blockIdx.z;
    const float* W;
    size_t dof;
    int K;
    if (z < 24) {
        int l = z >> 2, m = z & 3;
        W = (m == 0 ? qw : m == 1 ? kw : m == 2 ? vw : ow) + (size_t)l * D_ * D_;
        dof = WT_PROJ_ELEMS + (size_t)z * WT_MAT_ELEMS;
        K = D_;
    } else {
        if (blockIdx.y >= SEQDIM_ / 32) return;
        W = pw;
        dof = 0;
        K = SEQDIM_;
    }
    int bx = blockIdx.x * 32;
    int by = blockIdx.y * 32;
    #pragma unroll
    for (int i = 0; i < 32; i += 8)
        t[threadIdx.y + i][threadIdx.x] =
            W[(size_t)(by + threadIdx.y + i) * D_ + bx + threadIdx.x];
    __syncthreads();
    #pragma unroll
    for (int i = 0; i < 32; i += 8) {
        float v = t[threadIdx.x][threadIdx.y + i];
        int n = bx + threadIdx.y + i;
        int k = by + threadIdx.x;
        __nv_bfloat16 h = __float2bfloat16(v);
        th[dof + (size_t)n * K + k] = h;
        tl[dof + (size_t)n * K + k] = __float2bfloat16(v - __bfloat162float(h));
    }
}

// ---------------------------------------------------------------------------
// Embedding gather -> direct bf16 hi/lo split
// ---------------------------------------------------------------------------
__global__ void gather_emb(const int* __restrict__ seq,
                           const float* __restrict__ emb,
                           __nv_bfloat16* __restrict__ xh,
                           __nv_bfloat16* __restrict__ xl) {
    int i = blockIdx.x * blockDim.x + threadIdx.x;
    if (i >= ROWS_ * SEQDIM_ / 2) return;
    int row = i >> 6;
    int c2  = (i & 63) * 2;
    const float* e = emb + seq[row] * SEQDIM_ + c2;
    uint32_t hw, lw;
    split2(e[0], e[1], hw, lw);
    ((uint32_t*)xh)[i] = hw;
    ((uint32_t*)xl)[i] = lw;
}

// ---------------------------------------------------------------------------
// GEMM core: 128x128 block tile, 8 warps of 64x32, BK=32, 2-stage cp.async,
// ONE __syncthreads per chunk (loads issued post-sync), pass-major MMAs.
// 2 CTAs/SM.
// ---------------------------------------------------------------------------
#define TILEB  10240            // 128 * 80
#define CHUNKB (4 * TILEB)      // 40960
#define GEMM_SMEM (2 * CHUNKB)  // 81920

template <typename EPI>
__device__ __forceinline__
void gemm_core(const __nv_bfloat16* s0, const __nv_bfloat16* s1,
               const __nv_bfloat16* s2, const __nv_bfloat16* s3,
               int K, char* smem, EPI epilogue) {
    const uint32_t sb = smem_u32(smem);
    const int tid  = threadIdx.x;
    const int lane = tid & 31;
    const int wid  = tid >> 5;
    const int wm = wid & 1;
    const int wn = wid >> 1;

    const int nk = K >> 5;

    auto load_chunk = [&](int c, int stage) {
        const int k0 = c << 5;
        uint32_t buf = sb + stage * CHUNKB;
        #pragma unroll
        for (int i = 0; i < 2; i++) {
            int t = tid + i * 256;
            int row = t >> 2;
            int seg = t & 3;
            uint32_t dst = buf + row * 80 + seg * 16;
            size_t so = (size_t)row * K + k0 + seg * 8;
            CP_ASYNC16(dst,              (const char*)(s0 + so));
            CP_ASYNC16(dst + TILEB,      (const char*)(s1 + so));
            CP_ASYNC16(dst + 2 * TILEB,  (const char*)(s2 + so));
            CP_ASYNC16(dst + 3 * TILEB,  (const char*)(s3 + so));
        }
        CP_COMMIT();
    };

    float acc[4][4][4];
    #pragma unroll
    for (int mi = 0; mi < 4; mi++)
        #pragma unroll
        for (int nb = 0; nb < 4; nb++)
            #pragma unroll
            for (int j = 0; j < 4; j++) acc[mi][nb][j] = 0.f;

    const uint32_t a_off = (uint32_t)((wm * 64 + (lane & 15)) * 80 + (lane >> 4) * 16);
    const uint32_t b_off = (uint32_t)((wn * 32 + ((lane >> 4) & 1) * 8 + (lane & 7)) * 80
                                      + ((lane >> 3) & 1) * 16);

    load_chunk(0, 0);

    for (int c = 0; c < nk; c++) {
        // chunk c's loads (issued last iteration, or prologue) must be done
        CP_WAIT(0);
        __syncthreads();   // all warps finished reading stage (c+1)&1 in chunk c-1
        // prefetch next chunk: overlaps this chunk's MMAs; no trailing sync needed
        if (c + 1 < nk) load_chunk(c + 1, (c + 1) & 1);

        uint32_t buf = sb + (c & 1) * CHUNKB;
        #pragma unroll
        for (int s = 0; s < 2; s++) {
            uint32_t ah[4][4], al[4][4], wh[2][4], wl[2][4];
            #pragma unroll
            for (int g = 0; g < 4; g++) {
                uint32_t ao = buf + a_off + (uint32_t)(g * 16 * 80 + s * 32);
                ldm_x4(ah[g], ao);
                ldm_x4(al[g], ao + TILEB);
            }
            #pragma unroll
            for (int h = 0; h < 2; h++) {
                uint32_t bo = buf + 2 * TILEB + b_off + (uint32_t)(h * 16 * 80 + s * 32);
                ldm_x4(wh[h], bo);
                ldm_x4(wl[h], bo + TILEB);
            }
            #pragma unroll
            for (int mi = 0; mi < 4; mi++)
                #pragma unroll
                for (int nb = 0; nb < 4; nb++) {
                    const int h = nb >> 1, j = nb & 1;
                    mma16816(acc[mi][nb], ah[mi], wh[h][2 * j], wh[h][2 * j + 1]);
                }
            #pragma unroll
            for (int mi = 0; mi < 4; mi++)
                #pragma unroll
                for (int nb = 0; nb < 4; nb++) {
                    const int h = nb >> 1, j = nb & 1;
                    mma16816(acc[mi][nb], ah[mi], wl[h][2 * j], wl[h][2 * j + 1]);
                }
            #pragma unroll
            for (int mi = 0; mi < 4; mi++)
                #pragma unroll
                for (int nb = 0; nb < 4; nb++) {
                    const int h = nb >> 1, j = nb & 1;
                    mma16816(acc[mi][nb], al[mi], wh[h][2 * j], wh[h][2 * j + 1]);
                }
        }
    }
    __syncthreads();   // protect smem before epilogue reuse (gemm_qkv V staging)

    epilogue(acc, wm, wn, lane);
}

// ---------------------------------------------------------------------------
// Generic GEMM + bias -> fp32 C (optionally also emit bf16 hi/lo split)
// ---------------------------------------------------------------------------
template <bool SPLIT>
__global__ __launch_bounds__(256, 2)
void gemm_mma(const __nv_bfloat16* __restrict__ Ah,
              const __nv_bfloat16* __restrict__ Al,
              const __nv_bfloat16* __restrict__ Wh,
              const __nv_bfloat16* __restrict__ Wl,
              const float* __restrict__ bias,
              float* __restrict__ C, int N, int K,
              __nv_bfloat16* __restrict__ oh, __nv_bfloat16* __restrict__ ol) {
    extern __shared__ char smem[];
    const int brow = blockIdx.y * 128;
    const int bcol = blockIdx.x * 128;
    gemm_core(Ah + (size_t)brow * K, Al + (size_t)brow * K,
              Wh + (size_t)bcol * K, Wl + (size_t)bcol * K, K, smem,
        [&](float acc[4][4][4], int wm, int wn, int lane) {
            #pragma unroll
            for (int mi = 0; mi < 4; mi++) {
                int row = brow + wm * 64 + mi * 16 + (lane >> 2);
                #pragma unroll
                for (int nb = 0; nb < 4; nb++) {
                    int col = bcol + wn * 32 + nb * 8 + (lane & 3) * 2;
                    float b0 = bias[col], b1 = bias[col + 1];
                    float c00 = acc[mi][nb][0] + b0, c01 = acc[mi][nb][1] + b1;
                    float c10 = acc[mi][nb][2] + b0, c11 = acc[mi][nb][3] + b1;
                    size_t i0 = (size_t)row * N + col;
                    size_t i1 = (size_t)(row + 8) * N + col;
                    *(float2*)(C + i0) = make_float2(c00, c01);
                    *(float2*)(C + i1) = make_float2(c10, c11);
                    if (SPLIT) {
                        uint32_t hw, lw;
                        split2(c00, c01, hw, lw);
                        *(uint32_t*)(oh + i0) = hw; *(uint32_t*)(ol + i0) = lw;
                        split2(c10, c11, hw, lw);
                        *(uint32_t*)(oh + i1) = hw; *(uint32_t*)(ol + i1) = lw;
                    }
                }
            }
        });
}

// ---------------------------------------------------------------------------
// Fused QKV GEMM (N=3072). V emitted transposed+split via smem staging.
// ---------------------------------------------------------------------------
__global__ __launch_bounds__(256, 2)
void gemm_qkv(const __nv_bfloat16* __restrict__ Ah,
              const __nv_bfloat16* __restrict__ Al,
              const __nv_bfloat16* __restrict__ Wh,
              const __nv_bfloat16* __restrict__ Wl,
              const float* __restrict__ qb, const float* __restrict__ kb,
              const float* __restrict__ vb, int lofs,
              __nv_bfloat16* __restrict__ qh, __nv_bfloat16* __restrict__ ql,
              __nv_bfloat16* __restrict__ kh, __nv_bfloat16* __restrict__ kl,
              __nv_bfloat16* __restrict__ vth, __nv_bfloat16* __restrict__ vtl) {
    extern __shared__ char smem[];
    const int K = D_;
    const int brow = blockIdx.y * 128;
    const int bcol = blockIdx.x * 128;
    const int mat = bcol >> 10;            // 0=q 1=k 2=v
    const int colb = bcol & 1023;
    const float* bias = (mat == 0 ? qb : mat == 1 ? kb : vb) + lofs;
    gemm_core(Ah + (size_t)brow * K, Al + (size_t)brow * K,
              Wh + (size_t)bcol * K, Wl + (size_t)bcol * K, K, smem,
        [&](float acc[4][4][4], int wm, int wn, int lane) {
            if (mat == 2) {
                float* trans = (float*)smem;   // 128 x 132 floats
                #pragma unroll
                for (int mi = 0; mi < 4; mi++) {
                    int sl = wm * 64 + mi * 16 + (lane >> 2);
                    #pragma unroll
                    for (int nb = 0; nb < 4; nb++) {
                        int dl = wn * 32 + nb * 8 + (lane & 3) * 2;
                        float b0 = bias[colb + dl], b1 = bias[colb + dl + 1];
                        trans[dl * 132 + sl]           = acc[mi][nb][0] + b0;
                        trans[(dl + 1) * 132 + sl]     = acc[mi][nb][1] + b1;
                        trans[dl * 132 + sl + 8]       = acc[mi][nb][2] + b0;
                        trans[(dl + 1) * 132 + sl + 8] = acc[mi][nb][3] + b1;
                    }
                }
                __syncthreads();
                int bb = brow >> 11;
                int s0 = brow & (S_ - 1);
                #pragma unroll
                for (int i = 0; i < 32; i++) {
                    int idx = (int)threadIdx.x + i * 256;
                    int dl = idx >> 6;
                    int sp = idx & 63;
                    float2 v = *(float2*)&trans[dl * 132 + sp * 2];
                    int col = colb + dl;
                    int hh = col >> 6, dd = col & 63;
                    size_t o = ((size_t)(bb * H_ + hh) * HD_ + dd) * S_ + s0 + sp * 2;
                    uint32_t hw, lw;
                    split2(v.x, v.y, hw, lw);
                    *(uint32_t*)(vth + o) = hw;
                    *(uint32_t*)(vtl + o) = lw;
                }
            } else {
                #pragma unroll
                for (int mi = 0; mi < 4; mi++) {
                    int row = brow + wm * 64 + mi * 16 + (lane >> 2);
                    #pragma unroll
                    for (int nb = 0; nb < 4; nb++) {
                        int col = colb + wn * 32 + nb * 8 + (lane & 3) * 2;
                        float b0 = bias[col], b1 = bias[col + 1];
                        float c00 = acc[mi][nb][0] + b0, c01 = acc[mi][nb][1] + b1;
                        float c10 = acc[mi][nb][2] + b0, c11 = acc[mi][nb][3] + b1;
                        size_t i0 = (size_t)row * D_ + col;
                        size_t i1 = (size_t)(row + 8) * D_ + col;
                        __nv_bfloat16* hB = (mat == 0) ? qh : kh;
                        __nv_bfloat16* lB = (mat == 0) ? ql : kl;
                        if (mat == 0) { c00 *= 0.125f; c01 *= 0.125f; c10 *= 0.125f; c11 *= 0.125f; }
                        uint32_t hw, lw;
                        split2(c00, c01, hw, lw);
                        *(uint32_t*)(hB + i0) = hw; *(uint32_t*)(lB + i0) = lw;
                        split2(c10, c11, hw, lw);
                        *(uint32_t*)(hB + i1) = hw; *(uint32_t*)(lB + i1) = lw;
                    }
                }
            }
        });
}

// ---------------------------------------------------------------------------
// Tensor-core flash attention; 2-stage KV pipeline, Q-lo in smem, 2 CTAs/SM
// ---------------------------------------------------------------------------
#define AST      36864
#define AKL      9216
#define AMASK    (2 * AST)
#define AQLO     (AMASK + 512)
#define ATT_SMEM (AQLO + 18432)        // 92672

__global__ __launch_bounds__(256, 2)
void attn_mma(const __nv_bfloat16* __restrict__ qh, const __nv_bfloat16* __restrict__ ql,
              const __nv_bfloat16* __restrict__ kh, const __nv_bfloat16* __restrict__ kl,
              const __nv_bfloat16* __restrict__ vth, const __nv_bfloat16* __restrict__ vtl,
              const int* __restrict__ mask,
              __nv_bfloat16* __restrict__ oh, __nv_bfloat16* __restrict__ ol) {
    extern __shared__ char smem[];
    const uint32_t sb = smem_u32(smem);
    const int tid = threadIdx.x, wid = tid >> 5, lane = tid & 31;
    const int q0 = blockIdx.x * 128;
    const int bh = blockIdx.y;
    const int b = bh >> 4, h = bh & 15;
    const size_t rowbase = (size_t)b * S_;

    #pragma unroll
    for (int i = 0; i < 4; i++) {
        int t = tid + i * 256;
        int row = t >> 3, seg = t & 7;
        size_t so = (rowbase + q0 + row) * D_ + h * HD_ + seg * 8;
        CP_ASYNC16(sb + row * 144 + seg * 16,        (const char*)(qh + so));
        CP_ASYNC16(sb + AQLO + row * 144 + seg * 16, (const char*)(ql + so));
    }
    CP_COMMIT(); CP_WAIT(0);
    __syncthreads();

    uint32_t qhf[4][4];
    const uint32_t q_off = (uint32_t)((wid * 16 + (lane & 15)) * 144 + (lane >> 4) * 16);
    #pragma unroll
    for (int s = 0; s < 4; s++)
        ldm_x4(qhf[s], sb + q_off + s * 32);
    __syncthreads();

    auto load_kv = [&](int kt, int st) {
        uint32_t buf = sb + st * AST;
        int key0 = kt * 64;
        #pragma unroll
        for (int i = 0; i < 2; i++) {
            int t = tid + i * 256;
            int row = t >> 3, seg = t & 7;
            uint32_t dst = buf + row * 144 + seg * 16;
            size_t sk = (rowbase + key0 + row) * D_ + h * HD_ + seg * 8;
            CP_ASYNC16(dst,           (const char*)(kh + sk));
            CP_ASYNC16(dst + AKL,     (const char*)(kl + sk));
            size_t sv = ((size_t)bh * HD_ + row) * S_ + key0 + seg * 8;
            CP_ASYNC16(dst + 2 * AKL, (const char*)(vth + sv));
            CP_ASYNC16(dst + 3 * AKL, (const char*)(vtl + sv));
        }
        if (tid < 16)
            CP_ASYNC16(sb + AMASK + st * 256 + tid * 16,
                       (const char*)(mask + b * S_ + key0 + tid * 4));
        CP_COMMIT();
    };

    float oacc[8][4];
    #pragma unroll
    for (int nb = 0; nb < 8; nb++)
        #pragma unroll
        for (int j = 0; j < 4; j++) oacc[nb][j] = 0.f;
    float mrow0 = -1e30f, mrow1 = -1e30f, lrow0 = 0.f, lrow1 = 0.f;

    const uint32_t bfrag_off = (uint32_t)((((lane >> 4) & 1) * 8 + (lane & 7)) * 144
                                          + ((lane >> 3) & 1) * 16);

    const int NKT = S_ / 64;
    load_kv(0, 0);
    load_kv(1, 1);

    for (int kt = 0; kt < NKT; kt++) {
        if (kt + 1 < NKT) { CP_WAIT(1); }
        else              { CP_WAIT(0); }
        __syncthreads();

        uint32_t buf = sb + (kt & 1) * AST;

        float sacc[8][4];
        #pragma unroll
        for (int nb = 0; nb < 8; nb++)
            #pragma unroll
            for (int j = 0; j < 4; j++) sacc[nb][j] = 0.f;

        #pragma unroll
        for (int s = 0; s < 4; s++) {
            uint32_t khf[4][4], klf[4][4], qlf[4];
            ldm_x4(qlf, sb + AQLO + q_off + s * 32);
            #pragma unroll
            for (int g = 0; g < 4; g++) {
                uint32_t a = buf + bfrag_off + (uint32_t)(g * 16 * 144 + s * 32);
                ldm_x4(khf[g], a);
                ldm_x4(klf[g], a + AKL);
            }
            #pragma unroll
            for (int g = 0; g < 4; g++)
                #pragma unroll
                for (int j = 0; j < 2; j++)
                    mma16816(sacc[g * 2 + j], qhf[s], khf[g][2 * j], khf[g][2 * j + 1]);
            #pragma unroll
            for (int g = 0; g < 4; g++)
                #pragma unroll
                for (int j = 0; j < 2; j++)
                    mma16816(sacc[g * 2 + j], qhf[s], klf[g][2 * j], klf[g][2 * j + 1]);
            #pragma unroll
            for (int g = 0; g < 4; g++)
                #pragma unroll
                for (int j = 0; j < 2; j++)
                    mma16816(sacc[g * 2 + j], qlf, khf[g][2 * j], khf[g][2 * j + 1]);
        }

        {
            const int* smk = (const int*)(smem + AMASK + (kt & 1) * 256);
            int cb = 2 * (lane & 3);
            #pragma unroll
            for (int nb = 0; nb < 8; nb++) {
                if (smk[nb * 8 + cb] == 0)     { sacc[nb][0] = -1e9f; sacc[nb][2] = -1e9f; }
                if (smk[nb * 8 + cb + 1] == 0) { sacc[nb][1] = -1e9f; sacc[nb][3] = -1e9f; }
            }
        }

        float mx0 = -1e30f, mx1 = -1e30f;
        #pragma unroll
        for (int nb = 0; nb < 8; nb++) {
            mx0 = fmaxf(mx0, fmaxf(sacc[nb][0], sacc[nb][1]));
            mx1 = fmaxf(mx1, fmaxf(sacc[nb][2], sacc[nb][3]));
        }
        mx0 = fmaxf(mx0, __shfl_xor_sync(0xffffffffu, mx0, 1));
        mx0 = fmaxf(mx0, __shfl_xor_sync(0xffffffffu, mx0, 2));
        mx1 = fmaxf(mx1, __shfl_xor_sync(0xffffffffu, mx1, 1));
        mx1 = fmaxf(mx1, __shfl_xor_sync(0xffffffffu, mx1, 2));
        float mn0 = fmaxf(mrow0, mx0), mn1 = fmaxf(mrow1, mx1);
        float corr0 = __expf(mrow0 - mn0), corr1 = __expf(mrow1 - mn1);
        float sum0 = 0.f, sum1 = 0.f;
        #pragma unroll
        for (int nb = 0; nb < 8; nb++) {
            sacc[nb][0] = __expf(sacc[nb][0] - mn0);
            sacc[nb][1] = __expf(sacc[nb][1] - mn0);
            sacc[nb][2] = __expf(sacc[nb][2] - mn1);
            sacc[nb][3] = __expf(sacc[nb][3] - mn1);
            sum0 += sacc[nb][0] + sacc[nb][1];
            sum1 += sacc[nb][2] + sacc[nb][3];
        }
        sum0 += __shfl_xor_sync(0xffffffffu, sum0, 1);
        sum0 += __shfl_xor_sync(0xffffffffu, sum0, 2);
        sum1 += __shfl_xor_sync(0xffffffffu, sum1, 1);
        sum1 += __shfl_xor_sync(0xffffffffu, sum1, 2);
        lrow0 = lrow0 * corr0 + sum0;
        lrow1 = lrow1 * corr1 + sum1;
        mrow0 = mn0; mrow1 = mn1;
        #pragma unroll
        for (int nb = 0; nb < 8; nb++) {
            oacc[nb][0] *= corr0; oacc[nb][1] *= corr0;
            oacc[nb][2] *= corr1; oacc[nb][3] *= corr1;
        }

        #pragma unroll
        for (int c = 0; c < 4; c++) {
            uint32_t pha[4], pla[4];
            #pragma unroll
            for (int half = 0; half < 2; half++) {
                int nb = 2 * c + half;
                __nv_bfloat16 b0 = __float2bfloat16(sacc[nb][0]);
                __nv_bfloat16 b1 = __float2bfloat16(sacc[nb][1]);
                __nv_bfloat16 b2 = __float2bfloat16(sacc[nb][2]);
                __nv_bfloat16 b3 = __float2bfloat16(sacc[nb][3]);
                __nv_bfloat162 t01; t01.x = b0; t01.y = b1;
                __nv_bfloat162 t23; t23.x = b2; t23.y = b3;
                pha[half * 2 + 0] = *(uint32_t*)&t01;
                pha[half * 2 + 1] = *(uint32_t*)&t23;
                pla[half * 2 + 0] = pk_bf16(sacc[nb][0] - __bfloat162float(b0),
                                            sacc[nb][1] - __bfloat162float(b1));
                pla[half * 2 + 1] = pk_bf16(sacc[nb][2] - __bfloat162float(b2),
                                            sacc[nb][3] - __bfloat162float(b3));
            }
            uint32_t vhf[4][4], vlf[4][4];
            #pragma unroll
            for (int g = 0; g < 4; g++) {
                uint32_t a = buf + 2 * AKL + bfrag_off + (uint32_t)(g * 16 * 144 + c * 32);
                ldm_x4(vhf[g], a);
                ldm_x4(vlf[g], a + AKL);
            }
            #pragma unroll
            for (int g = 0; g < 4; g++)
                #pragma unroll
                for (int j = 0; j < 2; j++)
                    mma16816(oacc[g * 2 + j], pha, vhf[g][2 * j], vhf[g][2 * j + 1]);
            #pragma unroll
            for (int g = 0; g < 4; g++)
                #pragma unroll
                for (int j = 0; j < 2; j++)
                    mma16816(oacc[g * 2 + j], pha, vlf[g][2 * j], vlf[g][2 * j + 1]);
            #pragma unroll
            for (int g = 0; g < 4; g++)
                #pragma unroll
                for (int j = 0; j < 2; j++)
                    mma16816(oacc[g * 2 + j], pla, vhf[g][2 * j], vhf[g][2 * j + 1]);
        }
        __syncthreads();
        if (kt + 2 < NKT) load_kv(kt + 2, kt & 1);
    }

    float inv0 = 1.0f / lrow0, inv1 = 1.0f / lrow1;
    int r0 = q0 + wid * 16 + (lane >> 2);
    #pragma unroll
    for (int nb = 0; nb < 8; nb++) {
        int col = h * HD_ + nb * 8 + 2 * (lane & 3);
        size_t i0 = (rowbase + r0) * D_ + col;
        size_t i1 = (rowbase + r0 + 8) * D_ + col;
        uint32_t hw, lw;
        split2(oacc[nb][0] * inv0, oacc[nb][1] * inv0, hw, lw);
        *(uint32_t*)(oh + i0) = hw; *(uint32_t*)(ol + i0) = lw;
        split2(oacc[nb][2] * inv1, oacc[nb][3] * inv1, hw, lw);
        *(uint32_t*)(oh + i1) = hw; *(uint32_t*)(ol + i1) = lw;
    }
}

// ---------------------------------------------------------------------------
// Fused residual add + LayerNorm
// ---------------------------------------------------------------------------
template <bool SPLIT>
__global__ __launch_bounds__(256)
void add_ln(const float* __restrict__ x, const float* __restrict__ y,
            const float* __restrict__ g, const float* __restrict__ bta,
            float* __restrict__ out,
            __nv_bfloat16* __restrict__ oh, __nv_bfloat16* __restrict__ ol) {
    __shared__ float red[256];
    int row = blockIdx.x, tid = threadIdx.x;
    const float* xr = x + (size_t)row * D_;
    const float* yr = y + (size_t)row * D_;

    float v[4];
    float sum = 0.f;
    #pragma unroll
    for (int i = 0; i < 4; i++) {
        int c = tid + i * 256;
        v[i] = xr[c] + yr[c];
        sum += v[i];
    }
    red[tid] = sum; __syncthreads();
    for (int s = 128; s; s >>= 1) { if (tid < s) red[tid] += red[tid + s]; __syncthreads(); }
    float mu = red[0] * (1.0f / 1024.0f);
    __syncthreads();

    float sq = 0.f;
    #pragma unroll
    for (int i = 0; i < 4; i++) { float d = v[i] - mu; sq += d * d; }
    red[tid] = sq; __syncthreads();
    for (int s = 128; s; s >>= 1) { if (tid < s) red[tid] += red[tid + s]; __syncthreads(); }
    float var  = red[0] * (1.0f / 1024.0f);
    float rstd = rsqrtf(var + 1e-5f);

    #pragma unroll
    for (int i = 0; i < 4; i++) {
        int c = tid + i * 256;
        float o = (v[i] - mu) * rstd * g[c] + bta[c];
        out[(size_t)row * D_ + c] = o;
        if (SPLIT) {
            __nv_bfloat16 h = __float2bfloat16(o);
            oh[(size_t)row * D_ + c] = h;
            ol[(size_t)row * D_ + c] = __float2bfloat16(o - __bfloat162float(h));
        }
    }
}

// ---------------------------------------------------------------------------
// Launch
// ---------------------------------------------------------------------------
extern "C" void kernel_launch(void* const* d_in, const int* in_sizes, int n_in,
                              void* d_out, int out_size) {
    const int*   seq    = (const int*)  d_in[0];
    const int*   mask   = (const int*)  d_in[1];
    const float* emb    = (const float*)d_in[2];
    const float* proj_w = (const float*)d_in[3];
    const float* proj_b = (const float*)d_in[4];
    const float* qw     = (const float*)d_in[5];
    const float* qb     = (const float*)d_in[6];
    const float* kw     = (const float*)d_in[7];
    const float* kb     = (const float*)d_in[8];
    const float* vw     = (const float*)d_in[9];
    const float* vb     = (const float*)d_in[10];
    const float* ow     = (const float*)d_in[11];
    const float* ob     = (const float*)d_in[12];
    const float* lng    = (const float*)d_in[13];
    const float* lnb    = (const float*)d_in[14];
    float* out = (float*)d_out;

    float *x, *t;
    __nv_bfloat16 *ah, *al, *wth, *wtl, *qhp, *qlp, *khp, *klp, *vthp, *vtlp;
    cudaGetSymbolAddress((void**)&x,    g_x);
    cudaGetSymbolAddress((void**)&t,    g_t);
    cudaGetSymbolAddress((void**)&ah,   g_ah);
    cudaGetSymbolAddress((void**)&al,   g_al);
    cudaGetSymbolAddress((void**)&wth,  g_wth);
    cudaGetSymbolAddress((void**)&wtl,  g_wtl);
    cudaGetSymbolAddress((void**)&qhp,  g_qh);
    cudaGetSymbolAddress((void**)&qlp,  g_ql);
    cudaGetSymbolAddress((void**)&khp,  g_kh);
    cudaGetSymbolAddress((void**)&klp,  g_kl);
    cudaGetSymbolAddress((void**)&vthp, g_vth);
    cudaGetSymbolAddress((void**)&vtlp, g_vtl);

    cudaFuncSetAttribute(gemm_mma<false>, cudaFuncAttributeMaxDynamicSharedMemorySize, GEMM_SMEM);
    cudaFuncSetAttribute(gemm_mma<true>,  cudaFuncAttributeMaxDynamicSharedMemorySize, GEMM_SMEM);
    cudaFuncSetAttribute(gemm_qkv, cudaFuncAttributeMaxDynamicSharedMemorySize, GEMM_SMEM);
    cudaFuncSetAttribute(attn_mma, cudaFuncAttributeMaxDynamicSharedMemorySize, ATT_SMEM);

    tsplit_all<<<dim3(D_ / 32, D_ / 32, 25), dim3(32, 8)>>>(qw, kw, vw, ow, proj_w, wth, wtl);
    gather_emb<<<(ROWS_ * SEQDIM_ / 2 + 255) / 256, 256>>>(seq, emb, qhp, qlp);
    dim3 gp(D_ / 128, ROWS_ / 128);
    gemm_mma<true><<<gp, 256, GEMM_SMEM>>>(qhp, qlp, wth, wtl, proj_b, x, D_, SEQDIM_, ah, al);

    dim3 gqkv(3 * D_ / 128, ROWS_ / 128);        // (24, 64)
    dim3 ga(S_ / 128, B_ * H_);                  // (16, 64)
    for (int l = 0; l < L_; l++) {
        size_t off = WT_PROJ_ELEMS + (size_t)(l * 4) * WT_MAT_ELEMS;
        const __nv_bfloat16* owh = wth + off + 3 * WT_MAT_ELEMS;
        const __nv_bfloat16* owl = wtl + off + 3 * WT_MAT_ELEMS;

        gemm_qkv<<<gqkv, 256, GEMM_SMEM>>>(ah, al, wth + off, wtl + off,
                                           qb, kb, vb, l * D_,
                                           qhp, qlp, khp, klp, vthp, vtlp);
        attn_mma<<<ga, 256, ATT_SMEM>>>(qhp, qlp, khp, klp, vthp, vtlp, mask, ah, al);
        gemm_mma<false><<<gp, 256, GEMM_SMEM>>>(ah, al, owh, owl, ob + l * D_, t, D_, D_,
                                                nullptr, nullptr);
        if (l == L_ - 1)
            add_ln<false><<<ROWS_, 256>>>(x, t, lng + l * D_, lnb + l * D_, out, nullptr, nullptr);
        else
            add_ln<true><<<ROWS_, 256>>>(x, t, lng + l * D_, lnb + l * D_, x, ah, al);
    }
}

// round 13
// speedup vs baseline: 3.4228x; 1.0045x over previous
#include <cuda_runtime.h>
#include <cuda_bf16.h>
#include <math.h>
#include <stdint.h>

// Problem constants
#define B_      4
#define S_      2048
#define D_      1024
#define H_      16
#define HD_     64
#define L_      6
#define SEQDIM_ 128
#define ROWS_   (B_ * S_)   // 8192

#define WT_PROJ_ELEMS (D_ * SEQDIM_)
#define WT_MAT_ELEMS  (D_ * D_)
#define WT_ELEMS      (WT_PROJ_ELEMS + 24 * WT_MAT_ELEMS)

// ---------------------------------------------------------------------------
// Device scratch
// ---------------------------------------------------------------------------
__device__ float g_x [ROWS_ * D_];
__device__ float g_t [ROWS_ * D_];
__device__ __nv_bfloat16 g_ah[ROWS_ * D_];
__device__ __nv_bfloat16 g_al[ROWS_ * D_];
__device__ __nv_bfloat16 g_wth[WT_ELEMS];
__device__ __nv_bfloat16 g_wtl[WT_ELEMS];
__device__ __nv_bfloat16 g_qh[ROWS_ * D_];
__device__ __nv_bfloat16 g_ql[ROWS_ * D_];
__device__ __nv_bfloat16 g_kh[ROWS_ * D_];
__device__ __nv_bfloat16 g_kl[ROWS_ * D_];
__device__ __nv_bfloat16 g_vth[ROWS_ * D_];   // [bh][64][S]
__device__ __nv_bfloat16 g_vtl[ROWS_ * D_];

// ---------------------------------------------------------------------------
// Helpers
// ---------------------------------------------------------------------------
__device__ __forceinline__ uint32_t smem_u32(const void* p) {
    uint32_t a;
    asm("{ .reg .u64 t; cvta.to.shared.u64 t, %1; cvt.u32.u64 %0, t; }"
        : "=r"(a) : "l"(p));
    return a;
}

__device__ __forceinline__ void ldm_x4(uint32_t* r, uint32_t addr) {
    asm("ldmatrix.sync.aligned.m8n8.x4.shared.b16 {%0,%1,%2,%3}, [%4];"
        : "=r"(r[0]), "=r"(r[1]), "=r"(r[2]), "=r"(r[3]) : "r"(addr));
}

__device__ __forceinline__ void mma16816(float* c, const uint32_t* a,
                                         uint32_t b0, uint32_t b1) {
    asm("mma.sync.aligned.m16n8k16.row.col.f32.bf16.bf16.f32 "
        "{%0,%1,%2,%3}, {%4,%5,%6,%7}, {%8,%9}, {%0,%1,%2,%3};"
        : "+f"(c[0]), "+f"(c[1]), "+f"(c[2]), "+f"(c[3])
        : "r"(a[0]), "r"(a[1]), "r"(a[2]), "r"(a[3]), "r"(b0), "r"(b1));
}

__device__ __forceinline__ uint32_t pk_bf16(float lo, float hi) {
    uint32_t r;
    asm("cvt.rn.bf16x2.f32 %0, %1, %2;" : "=r"(r) : "f"(hi), "f"(lo));
    return r;
}

__device__ __forceinline__ void split2(float c0, float c1, uint32_t& hw, uint32_t& lw) {
    __nv_bfloat16 h0 = __float2bfloat16(c0);
    __nv_bfloat16 h1 = __float2bfloat16(c1);
    __nv_bfloat162 hp; hp.x = h0; hp.y = h1;
    hw = *(uint32_t*)&hp;
    lw = pk_bf16(c0 - __bfloat162float(h0), c1 - __bfloat162float(h1));
}

#define CP_ASYNC16(dst, src) \
    asm volatile("cp.async.cg.shared.global [%0], [%1], 16;" :: "r"(dst), "l"(src))
#define CP_COMMIT() asm volatile("cp.async.commit_group;" ::: "memory")
#define CP_WAIT(n)  asm volatile("cp.async.wait_group %0;" :: "n"(n) : "memory")

// ---------------------------------------------------------------------------
// Batched weight transpose + split: z<24 layer matrices, z==24 proj_w
// ---------------------------------------------------------------------------
__global__ void tsplit_all(const float* __restrict__ qw, const float* __restrict__ kw,
                           const float* __restrict__ vw, const float* __restrict__ ow,
                           const float* __restrict__ pw,
                           __nv_bfloat16* __restrict__ th,
                           __nv_bfloat16* __restrict__ tl) {
    __shared__ float t[32][33];
    int z = blockIdx.z;
    const float* W;
    size_t dof;
    int K;
    if (z < 24) {
        int l = z >> 2, m = z & 3;
        W = (m == 0 ? qw : m == 1 ? kw : m == 2 ? vw : ow) + (size_t)l * D_ * D_;
        dof = WT_PROJ_ELEMS + (size_t)z * WT_MAT_ELEMS;
        K = D_;
    } else {
        if (blockIdx.y >= SEQDIM_ / 32) return;
        W = pw;
        dof = 0;
        K = SEQDIM_;
    }
    int bx = blockIdx.x * 32;
    int by = blockIdx.y * 32;
    #pragma unroll
    for (int i = 0; i < 32; i += 8)
        t[threadIdx.y + i][threadIdx.x] =
            W[(size_t)(by + threadIdx.y + i) * D_ + bx + threadIdx.x];
    __syncthreads();
    #pragma unroll
    for (int i = 0; i < 32; i += 8) {
        float v = t[threadIdx.x][threadIdx.y + i];
        int n = bx + threadIdx.y + i;
        int k = by + threadIdx.x;
        __nv_bfloat16 h = __float2bfloat16(v);
        th[dof + (size_t)n * K + k] = h;
        tl[dof + (size_t)n * K + k] = __float2bfloat16(v - __bfloat162float(h));
    }
}

// ---------------------------------------------------------------------------
// Embedding gather -> direct bf16 hi/lo split
// ---------------------------------------------------------------------------
__global__ void gather_emb(const int* __restrict__ seq,
                           const float* __restrict__ emb,
                           __nv_bfloat16* __restrict__ xh,
                           __nv_bfloat16* __restrict__ xl) {
    int i = blockIdx.x * blockDim.x + threadIdx.x;
    if (i >= ROWS_ * SEQDIM_ / 2) return;
    int row = i >> 6;
    int c2  = (i & 63) * 2;
    const float* e = emb + seq[row] * SEQDIM_ + c2;
    uint32_t hw, lw;
    split2(e[0], e[1], hw, lw);
    ((uint32_t*)xh)[i] = hw;
    ((uint32_t*)xl)[i] = lw;
}

// ---------------------------------------------------------------------------
// GEMM core: 128x128 block tile, 8 warps of 64x32, BK=32, 2-stage cp.async,
// single sync/chunk, fragment loads interleaved with MMA passes. 2 CTAs/SM.
// ---------------------------------------------------------------------------
#define TILEB  10240            // 128 * 80
#define CHUNKB (4 * TILEB)      // 40960
#define GEMM_SMEM (2 * CHUNKB)  // 81920

template <typename EPI>
__device__ __forceinline__
void gemm_core(const __nv_bfloat16* s0, const __nv_bfloat16* s1,
               const __nv_bfloat16* s2, const __nv_bfloat16* s3,
               int K, char* smem, EPI epilogue) {
    const uint32_t sb = smem_u32(smem);
    const int tid  = threadIdx.x;
    const int lane = tid & 31;
    const int wid  = tid >> 5;
    const int wm = wid & 1;
    const int wn = wid >> 1;

    const int nk = K >> 5;

    auto load_chunk = [&](int c, int stage) {
        const int k0 = c << 5;
        uint32_t buf = sb + stage * CHUNKB;
        #pragma unroll
        for (int i = 0; i < 2; i++) {
            int t = tid + i * 256;
            int row = t >> 2;
            int seg = t & 3;
            uint32_t dst = buf + row * 80 + seg * 16;
            size_t so = (size_t)row * K + k0 + seg * 8;
            CP_ASYNC16(dst,              (const char*)(s0 + so));
            CP_ASYNC16(dst + TILEB,      (const char*)(s1 + so));
            CP_ASYNC16(dst + 2 * TILEB,  (const char*)(s2 + so));
            CP_ASYNC16(dst + 3 * TILEB,  (const char*)(s3 + so));
        }
        CP_COMMIT();
    };

    float acc[4][4][4];
    #pragma unroll
    for (int mi = 0; mi < 4; mi++)
        #pragma unroll
        for (int nb = 0; nb < 4; nb++)
            #pragma unroll
            for (int j = 0; j < 4; j++) acc[mi][nb][j] = 0.f;

    const uint32_t a_off = (uint32_t)((wm * 64 + (lane & 15)) * 80 + (lane >> 4) * 16);
    const uint32_t b_off = (uint32_t)((wn * 32 + ((lane >> 4) & 1) * 8 + (lane & 7)) * 80
                                      + ((lane >> 3) & 1) * 16);

    load_chunk(0, 0);

    for (int c = 0; c < nk; c++) {
        CP_WAIT(0);
        __syncthreads();
        if (c + 1 < nk) load_chunk(c + 1, (c + 1) & 1);

        uint32_t buf = sb + (c & 1) * CHUNKB;
        #pragma unroll
        for (int s = 0; s < 2; s++) {
            uint32_t ah[4][4], al[4][4], wh[2][4], wl[2][4];
            // pass 1 operands
            #pragma unroll
            for (int g = 0; g < 4; g++)
                ldm_x4(ah[g], buf + a_off + (uint32_t)(g * 16 * 80 + s * 32));
            #pragma unroll
            for (int h = 0; h < 2; h++)
                ldm_x4(wh[h], buf + 2 * TILEB + b_off + (uint32_t)(h * 16 * 80 + s * 32));
            // Pass 1: Ah*Wh
            #pragma unroll
            for (int mi = 0; mi < 4; mi++)
                #pragma unroll
                for (int nb = 0; nb < 4; nb++) {
                    const int h = nb >> 1, j = nb & 1;
                    mma16816(acc[mi][nb], ah[mi], wh[h][2 * j], wh[h][2 * j + 1]);
                }
            // pass 2 operands (overlaps pass 1 tail)
            #pragma unroll
            for (int h = 0; h < 2; h++)
                ldm_x4(wl[h], buf + 3 * TILEB + b_off + (uint32_t)(h * 16 * 80 + s * 32));
            // Pass 2: Ah*Wl
            #pragma unroll
            for (int mi = 0; mi < 4; mi++)
                #pragma unroll
                for (int nb = 0; nb < 4; nb++) {
                    const int h = nb >> 1, j = nb & 1;
                    mma16816(acc[mi][nb], ah[mi], wl[h][2 * j], wl[h][2 * j + 1]);
                }
            // pass 3 operands
            #pragma unroll
            for (int g = 0; g < 4; g++)
                ldm_x4(al[g], buf + TILEB + a_off + (uint32_t)(g * 16 * 80 + s * 32));
            // Pass 3: Al*Wh
            #pragma unroll
            for (int mi = 0; mi < 4; mi++)
                #pragma unroll
                for (int nb = 0; nb < 4; nb++) {
                    const int h = nb >> 1, j = nb & 1;
                    mma16816(acc[mi][nb], al[mi], wh[h][2 * j], wh[h][2 * j + 1]);
                }
        }
    }
    __syncthreads();   // protect smem before epilogue reuse (gemm_qkv V staging)

    epilogue(acc, wm, wn, lane);
}

// ---------------------------------------------------------------------------
// Generic GEMM + bias -> fp32 C (optionally also emit bf16 hi/lo split)
// ---------------------------------------------------------------------------
template <bool SPLIT>
__global__ __launch_bounds__(256, 2)
void gemm_mma(const __nv_bfloat16* __restrict__ Ah,
              const __nv_bfloat16* __restrict__ Al,
              const __nv_bfloat16* __restrict__ Wh,
              const __nv_bfloat16* __restrict__ Wl,
              const float* __restrict__ bias,
              float* __restrict__ C, int N, int K,
              __nv_bfloat16* __restrict__ oh, __nv_bfloat16* __restrict__ ol) {
    extern __shared__ char smem[];
    const int brow = blockIdx.y * 128;
    const int bcol = blockIdx.x * 128;
    gemm_core(Ah + (size_t)brow * K, Al + (size_t)brow * K,
              Wh + (size_t)bcol * K, Wl + (size_t)bcol * K, K, smem,
        [&](float acc[4][4][4], int wm, int wn, int lane) {
            #pragma unroll
            for (int mi = 0; mi < 4; mi++) {
                int row = brow + wm * 64 + mi * 16 + (lane >> 2);
                #pragma unroll
                for (int nb = 0; nb < 4; nb++) {
                    int col = bcol + wn * 32 + nb * 8 + (lane & 3) * 2;
                    float b0 = bias[col], b1 = bias[col + 1];
                    float c00 = acc[mi][nb][0] + b0, c01 = acc[mi][nb][1] + b1;
                    float c10 = acc[mi][nb][2] + b0, c11 = acc[mi][nb][3] + b1;
                    size_t i0 = (size_t)row * N + col;
                    size_t i1 = (size_t)(row + 8) * N + col;
                    *(float2*)(C + i0) = make_float2(c00, c01);
                    *(float2*)(C + i1) = make_float2(c10, c11);
                    if (SPLIT) {
                        uint32_t hw, lw;
                        split2(c00, c01, hw, lw);
                        *(uint32_t*)(oh + i0) = hw; *(uint32_t*)(ol + i0) = lw;
                        split2(c10, c11, hw, lw);
                        *(uint32_t*)(oh + i1) = hw; *(uint32_t*)(ol + i1) = lw;
                    }
                }
            }
        });
}

// ---------------------------------------------------------------------------
// Fused QKV GEMM (N=3072). V emitted transposed+split via smem staging.
// ---------------------------------------------------------------------------
__global__ __launch_bounds__(256, 2)
void gemm_qkv(const __nv_bfloat16* __restrict__ Ah,
              const __nv_bfloat16* __restrict__ Al,
              const __nv_bfloat16* __restrict__ Wh,
              const __nv_bfloat16* __restrict__ Wl,
              const float* __restrict__ qb, const float* __restrict__ kb,
              const float* __restrict__ vb, int lofs,
              __nv_bfloat16* __restrict__ qh, __nv_bfloat16* __restrict__ ql,
              __nv_bfloat16* __restrict__ kh, __nv_bfloat16* __restrict__ kl,
              __nv_bfloat16* __restrict__ vth, __nv_bfloat16* __restrict__ vtl) {
    extern __shared__ char smem[];
    const int K = D_;
    const int brow = blockIdx.y * 128;
    const int bcol = blockIdx.x * 128;
    const int mat = bcol >> 10;            // 0=q 1=k 2=v
    const int colb = bcol & 1023;
    const float* bias = (mat == 0 ? qb : mat == 1 ? kb : vb) + lofs;
    gemm_core(Ah + (size_t)brow * K, Al + (size_t)brow * K,
              Wh + (size_t)bcol * K, Wl + (size_t)bcol * K, K, smem,
        [&](float acc[4][4][4], int wm, int wn, int lane) {
            if (mat == 2) {
                float* trans = (float*)smem;   // 128 x 132 floats
                #pragma unroll
                for (int mi = 0; mi < 4; mi++) {
                    int sl = wm * 64 + mi * 16 + (lane >> 2);
                    #pragma unroll
                    for (int nb = 0; nb < 4; nb++) {
                        int dl = wn * 32 + nb * 8 + (lane & 3) * 2;
                        float b0 = bias[colb + dl], b1 = bias[colb + dl + 1];
                        trans[dl * 132 + sl]           = acc[mi][nb][0] + b0;
                        trans[(dl + 1) * 132 + sl]     = acc[mi][nb][1] + b1;
                        trans[dl * 132 + sl + 8]       = acc[mi][nb][2] + b0;
                        trans[(dl + 1) * 132 + sl + 8] = acc[mi][nb][3] + b1;
                    }
                }
                __syncthreads();
                int bb = brow >> 11;
                int s0 = brow & (S_ - 1);
                #pragma unroll
                for (int i = 0; i < 32; i++) {
                    int idx = (int)threadIdx.x + i * 256;
                    int dl = idx >> 6;
                    int sp = idx & 63;
                    float2 v = *(float2*)&trans[dl * 132 + sp * 2];
                    int col = colb + dl;
                    int hh = col >> 6, dd = col & 63;
                    size_t o = ((size_t)(bb * H_ + hh) * HD_ + dd) * S_ + s0 + sp * 2;
                    uint32_t hw, lw;
                    split2(v.x, v.y, hw, lw);
                    *(uint32_t*)(vth + o) = hw;
                    *(uint32_t*)(vtl + o) = lw;
                }
            } else {
                #pragma unroll
                for (int mi = 0; mi < 4; mi++) {
                    int row = brow + wm * 64 + mi * 16 + (lane >> 2);
                    #pragma unroll
                    for (int nb = 0; nb < 4; nb++) {
                        int col = colb + wn * 32 + nb * 8 + (lane & 3) * 2;
                        float b0 = bias[col], b1 = bias[col + 1];
                        float c00 = acc[mi][nb][0] + b0, c01 = acc[mi][nb][1] + b1;
                        float c10 = acc[mi][nb][2] + b0, c11 = acc[mi][nb][3] + b1;
                        size_t i0 = (size_t)row * D_ + col;
                        size_t i1 = (size_t)(row + 8) * D_ + col;
                        __nv_bfloat16* hB = (mat == 0) ? qh : kh;
                        __nv_bfloat16* lB = (mat == 0) ? ql : kl;
                        if (mat == 0) { c00 *= 0.125f; c01 *= 0.125f; c10 *= 0.125f; c11 *= 0.125f; }
                        uint32_t hw, lw;
                        split2(c00, c01, hw, lw);
                        *(uint32_t*)(hB + i0) = hw; *(uint32_t*)(lB + i0) = lw;
                        split2(c10, c11, hw, lw);
                        *(uint32_t*)(hB + i1) = hw; *(uint32_t*)(lB + i1) = lw;
                    }
                }
            }
        });
}

// ---------------------------------------------------------------------------
// Tensor-core flash attention; 2-stage KV pipeline, SINGLE sync per kt
// (distance-1 prefetch), Q-lo in smem, fragment loads interleaved with MMA
// passes. 2 CTAs/SM.
// ---------------------------------------------------------------------------
#define AST      36864
#define AKL      9216
#define AMASK    (2 * AST)
#define AQLO     (AMASK + 512)
#define ATT_SMEM (AQLO + 18432)        // 92672

__global__ __launch_bounds__(256, 2)
void attn_mma(const __nv_bfloat16* __restrict__ qh, const __nv_bfloat16* __restrict__ ql,
              const __nv_bfloat16* __restrict__ kh, const __nv_bfloat16* __restrict__ kl,
              const __nv_bfloat16* __restrict__ vth, const __nv_bfloat16* __restrict__ vtl,
              const int* __restrict__ mask,
              __nv_bfloat16* __restrict__ oh, __nv_bfloat16* __restrict__ ol) {
    extern __shared__ char smem[];
    const uint32_t sb = smem_u32(smem);
    const int tid = threadIdx.x, wid = tid >> 5, lane = tid & 31;
    const int q0 = blockIdx.x * 128;
    const int bh = blockIdx.y;
    const int b = bh >> 4, h = bh & 15;
    const size_t rowbase = (size_t)b * S_;

    #pragma unroll
    for (int i = 0; i < 4; i++) {
        int t = tid + i * 256;
        int row = t >> 3, seg = t & 7;
        size_t so = (rowbase + q0 + row) * D_ + h * HD_ + seg * 8;
        CP_ASYNC16(sb + row * 144 + seg * 16,        (const char*)(qh + so));
        CP_ASYNC16(sb + AQLO + row * 144 + seg * 16, (const char*)(ql + so));
    }
    CP_COMMIT(); CP_WAIT(0);
    __syncthreads();

    uint32_t qhf[4][4];
    const uint32_t q_off = (uint32_t)((wid * 16 + (lane & 15)) * 144 + (lane >> 4) * 16);
    #pragma unroll
    for (int s = 0; s < 4; s++)
        ldm_x4(qhf[s], sb + q_off + s * 32);
    __syncthreads();

    auto load_kv = [&](int kt, int st) {
        uint32_t buf = sb + st * AST;
        int key0 = kt * 64;
        #pragma unroll
        for (int i = 0; i < 2; i++) {
            int t = tid + i * 256;
            int row = t >> 3, seg = t & 7;
            uint32_t dst = buf + row * 144 + seg * 16;
            size_t sk = (rowbase + key0 + row) * D_ + h * HD_ + seg * 8;
            CP_ASYNC16(dst,           (const char*)(kh + sk));
            CP_ASYNC16(dst + AKL,     (const char*)(kl + sk));
            size_t sv = ((size_t)bh * HD_ + row) * S_ + key0 + seg * 8;
            CP_ASYNC16(dst + 2 * AKL, (const char*)(vth + sv));
            CP_ASYNC16(dst + 3 * AKL, (const char*)(vtl + sv));
        }
        if (tid < 16)
            CP_ASYNC16(sb + AMASK + st * 256 + tid * 16,
                       (const char*)(mask + b * S_ + key0 + tid * 4));
        CP_COMMIT();
    };

    float oacc[8][4];
    #pragma unroll
    for (int nb = 0; nb < 8; nb++)
        #pragma unroll
        for (int j = 0; j < 4; j++) oacc[nb][j] = 0.f;
    float mrow0 = -1e30f, mrow1 = -1e30f, lrow0 = 0.f, lrow1 = 0.f;

    const uint32_t bfrag_off = (uint32_t)((((lane >> 4) & 1) * 8 + (lane & 7)) * 144
                                          + ((lane >> 3) & 1) * 16);

    const int NKT = S_ / 64;
    load_kv(0, 0);

    for (int kt = 0; kt < NKT; kt++) {
        CP_WAIT(0);
        __syncthreads();   // all warps finished reading stage (kt+1)&1 in kt-1
        if (kt + 1 < NKT) load_kv(kt + 1, (kt + 1) & 1);

        uint32_t buf = sb + (kt & 1) * AST;

        float sacc[8][4];
        #pragma unroll
        for (int nb = 0; nb < 8; nb++)
            #pragma unroll
            for (int j = 0; j < 4; j++) sacc[nb][j] = 0.f;

        #pragma unroll
        for (int s = 0; s < 4; s++) {
            uint32_t khf[4][4], klf[4][4], qlf[4];
            #pragma unroll
            for (int g = 0; g < 4; g++)
                ldm_x4(khf[g], buf + bfrag_off + (uint32_t)(g * 16 * 144 + s * 32));
            #pragma unroll
            for (int g = 0; g < 4; g++)
                #pragma unroll
                for (int j = 0; j < 2; j++)
                    mma16816(sacc[g * 2 + j], qhf[s], khf[g][2 * j], khf[g][2 * j + 1]);
            #pragma unroll
            for (int g = 0; g < 4; g++)
                ldm_x4(klf[g], buf + AKL + bfrag_off + (uint32_t)(g * 16 * 144 + s * 32));
            #pragma unroll
            for (int g = 0; g < 4; g++)
                #pragma unroll
                for (int j = 0; j < 2; j++)
                    mma16816(sacc[g * 2 + j], qhf[s], klf[g][2 * j], klf[g][2 * j + 1]);
            ldm_x4(qlf, sb + AQLO + q_off + s * 32);
            #pragma unroll
            for (int g = 0; g < 4; g++)
                #pragma unroll
                for (int j = 0; j < 2; j++)
                    mma16816(sacc[g * 2 + j], qlf, khf[g][2 * j], khf[g][2 * j + 1]);
        }

        {
            const int* smk = (const int*)(smem + AMASK + (kt & 1) * 256);
            int cb = 2 * (lane & 3);
            #pragma unroll
            for (int nb = 0; nb < 8; nb++) {
                if (smk[nb * 8 + cb] == 0)     { sacc[nb][0] = -1e9f; sacc[nb][2] = -1e9f; }
                if (smk[nb * 8 + cb + 1] == 0) { sacc[nb][1] = -1e9f; sacc[nb][3] = -1e9f; }
            }
        }

        float mx0 = -1e30f, mx1 = -1e30f;
        #pragma unroll
        for (int nb = 0; nb < 8; nb++) {
            mx0 = fmaxf(mx0, fmaxf(sacc[nb][0], sacc[nb][1]));
            mx1 = fmaxf(mx1, fmaxf(sacc[nb][2], sacc[nb][3]));
        }
        mx0 = fmaxf(mx0, __shfl_xor_sync(0xffffffffu, mx0, 1));
        mx0 = fmaxf(mx0, __shfl_xor_sync(0xffffffffu, mx0, 2));
        mx1 = fmaxf(mx1, __shfl_xor_sync(0xffffffffu, mx1, 1));
        mx1 = fmaxf(mx1, __shfl_xor_sync(0xffffffffu, mx1, 2));
        float mn0 = fmaxf(mrow0, mx0), mn1 = fmaxf(mrow1, mx1);
        float corr0 = __expf(mrow0 - mn0), corr1 = __expf(mrow1 - mn1);
        float sum0 = 0.f, sum1 = 0.f;
        #pragma unroll
        for (int nb = 0; nb < 8; nb++) {
            sacc[nb][0] = __expf(sacc[nb][0] - mn0);
            sacc[nb][1] = __expf(sacc[nb][1] - mn0);
            sacc[nb][2] = __expf(sacc[nb][2] - mn1);
            sacc[nb][3] = __expf(sacc[nb][3] - mn1);
            sum0 += sacc[nb][0] + sacc[nb][1];
            sum1 += sacc[nb][2] + sacc[nb][3];
        }
        sum0 += __shfl_xor_sync(0xffffffffu, sum0, 1);
        sum0 += __shfl_xor_sync(0xffffffffu, sum0, 2);
        sum1 += __shfl_xor_sync(0xffffffffu, sum1, 1);
        sum1 += __shfl_xor_sync(0xffffffffu, sum1, 2);
        lrow0 = lrow0 * corr0 + sum0;
        lrow1 = lrow1 * corr1 + sum1;
        mrow0 = mn0; mrow1 = mn1;
        #pragma unroll
        for (int nb = 0; nb < 8; nb++) {
            oacc[nb][0] *= corr0; oacc[nb][1] *= corr0;
            oacc[nb][2] *= corr1; oacc[nb][3] *= corr1;
        }

        #pragma unroll
        for (int c = 0; c < 4; c++) {
            uint32_t pha[4], pla[4];
            #pragma unroll
            for (int half = 0; half < 2; half++) {
                int nb = 2 * c + half;
                __nv_bfloat16 b0 = __float2bfloat16(sacc[nb][0]);
                __nv_bfloat16 b1 = __float2bfloat16(sacc[nb][1]);
                __nv_bfloat16 b2 = __float2bfloat16(sacc[nb][2]);
                __nv_bfloat16 b3 = __float2bfloat16(sacc[nb][3]);
                __nv_bfloat162 t01; t01.x = b0; t01.y = b1;
                __nv_bfloat162 t23; t23.x = b2; t23.y = b3;
                pha[half * 2 + 0] = *(uint32_t*)&t01;
                pha[half * 2 + 1] = *(uint32_t*)&t23;
                pla[half * 2 + 0] = pk_bf16(sacc[nb][0] - __bfloat162float(b0),
                                            sacc[nb][1] - __bfloat162float(b1));
                pla[half * 2 + 1] = pk_bf16(sacc[nb][2] - __bfloat162float(b2),
                                            sacc[nb][3] - __bfloat162float(b3));
            }
            uint32_t vhf[4][4], vlf[4][4];
            #pragma unroll
            for (int g = 0; g < 4; g++)
                ldm_x4(vhf[g], buf + 2 * AKL + bfrag_off + (uint32_t)(g * 16 * 144 + c * 32));
            #pragma unroll
            for (int g = 0; g < 4; g++)
                #pragma unroll
                for (int j = 0; j < 2; j++)
                    mma16816(oacc[g * 2 + j], pha, vhf[g][2 * j], vhf[g][2 * j + 1]);
            #pragma unroll
            for (int g = 0; g < 4; g++)
                ldm_x4(vlf[g], buf + 3 * AKL + bfrag_off + (uint32_t)(g * 16 * 144 + c * 32));
            #pragma unroll
            for (int g = 0; g < 4; g++)
                #pragma unroll
                for (int j = 0; j < 2; j++)
                    mma16816(oacc[g * 2 + j], pha, vlf[g][2 * j], vlf[g][2 * j + 1]);
            #pragma unroll
            for (int g = 0; g < 4; g++)
                #pragma unroll
                for (int j = 0; j < 2; j++)
                    mma16816(oacc[g * 2 + j], pla, vhf[g][2 * j], vhf[g][2 * j + 1]);
        }
    }

    float inv0 = 1.0f / lrow0, inv1 = 1.0f / lrow1;
    int r0 = q0 + wid * 16 + (lane >> 2);
    #pragma unroll
    for (int nb = 0; nb < 8; nb++) {
        int col = h * HD_ + nb * 8 + 2 * (lane & 3);
        size_t i0 = (rowbase + r0) * D_ + col;
        size_t i1 = (rowbase + r0 + 8) * D_ + col;
        uint32_t hw, lw;
        split2(oacc[nb][0] * inv0, oacc[nb][1] * inv0, hw, lw);
        *(uint32_t*)(oh + i0) = hw; *(uint32_t*)(ol + i0) = lw;
        split2(oacc[nb][2] * inv1, oacc[nb][3] * inv1, hw, lw);
        *(uint32_t*)(oh + i1) = hw; *(uint32_t*)(ol + i1) = lw;
    }
}

// ---------------------------------------------------------------------------
// Fused residual add + LayerNorm
// ---------------------------------------------------------------------------
template <bool SPLIT>
__global__ __launch_bounds__(256)
void add_ln(const float* __restrict__ x, const float* __restrict__ y,
            const float* __restrict__ g, const float* __restrict__ bta,
            float* __restrict__ out,
            __nv_bfloat16* __restrict__ oh, __nv_bfloat16* __restrict__ ol) {
    __shared__ float red[256];
    int row = blockIdx.x, tid = threadIdx.x;
    const float* xr = x + (size_t)row * D_;
    const float* yr = y + (size_t)row * D_;

    float v[4];
    float sum = 0.f;
    #pragma unroll
    for (int i = 0; i < 4; i++) {
        int c = tid + i * 256;
        v[i] = xr[c] + yr[c];
        sum += v[i];
    }
    red[tid] = sum; __syncthreads();
    for (int s = 128; s; s >>= 1) { if (tid < s) red[tid] += red[tid + s]; __syncthreads(); }
    float mu = red[0] * (1.0f / 1024.0f);
    __syncthreads();

    float sq = 0.f;
    #pragma unroll
    for (int i = 0; i < 4; i++) { float d = v[i] - mu; sq += d * d; }
    red[tid] = sq; __syncthreads();
    for (int s = 128; s; s >>= 1) { if (tid < s) red[tid] += red[tid + s]; __syncthreads(); }
    float var  = red[0] * (1.0f / 1024.0f);
    float rstd = rsqrtf(var + 1e-5f);

    #pragma unroll
    for (int i = 0; i < 4; i++) {
        int c = tid + i * 256;
        float o = (v[i] - mu) * rstd * g[c] + bta[c];
        out[(size_t)row * D_ + c] = o;
        if (SPLIT) {
            __nv_bfloat16 h = __float2bfloat16(o);
            oh[(size_t)row * D_ + c] = h;
            ol[(size_t)row * D_ + c] = __float2bfloat16(o - __bfloat162float(h));
        }
    }
}

// ---------------------------------------------------------------------------
// Launch
// ---------------------------------------------------------------------------
extern "C" void kernel_launch(void* const* d_in, const int* in_sizes, int n_in,
                              void* d_out, int out_size) {
    const int*   seq    = (const int*)  d_in[0];
    const int*   mask   = (const int*)  d_in[1];
    const float* emb    = (const float*)d_in[2];
    const float* proj_w = (const float*)d_in[3];
    const float* proj_b = (const float*)d_in[4];
    const float* qw     = (const float*)d_in[5];
    const float* qb     = (const float*)d_in[6];
    const float* kw     = (const float*)d_in[7];
    const float* kb     = (const float*)d_in[8];
    const float* vw     = (const float*)d_in[9];
    const float* vb     = (const float*)d_in[10];
    const float* ow     = (const float*)d_in[11];
    const float* ob     = (const float*)d_in[12];
    const float* lng    = (const float*)d_in[13];
    const float* lnb    = (const float*)d_in[14];
    float* out = (float*)d_out;

    float *x, *t;
    __nv_bfloat16 *ah, *al, *wth, *wtl, *qhp, *qlp, *khp, *klp, *vthp, *vtlp;
    cudaGetSymbolAddress((void**)&x,    g_x);
    cudaGetSymbolAddress((void**)&t,    g_t);
    cudaGetSymbolAddress((void**)&ah,   g_ah);
    cudaGetSymbolAddress((void**)&al,   g_al);
    cudaGetSymbolAddress((void**)&wth,  g_wth);
    cudaGetSymbolAddress((void**)&wtl,  g_wtl);
    cudaGetSymbolAddress((void**)&qhp,  g_qh);
    cudaGetSymbolAddress((void**)&qlp,  g_ql);
    cudaGetSymbolAddress((void**)&khp,  g_kh);
    cudaGetSymbolAddress((void**)&klp,  g_kl);
    cudaGetSymbolAddress((void**)&vthp, g_vth);
    cudaGetSymbolAddress((void**)&vtlp, g_vtl);

    cudaFuncSetAttribute(gemm_mma<false>, cudaFuncAttributeMaxDynamicSharedMemorySize, GEMM_SMEM);
    cudaFuncSetAttribute(gemm_mma<true>,  cudaFuncAttributeMaxDynamicSharedMemorySize, GEMM_SMEM);
    cudaFuncSetAttribute(gemm_qkv, cudaFuncAttributeMaxDynamicSharedMemorySize, GEMM_SMEM);
    cudaFuncSetAttribute(attn_mma, cudaFuncAttributeMaxDynamicSharedMemorySize, ATT_SMEM);

    tsplit_all<<<dim3(D_ / 32, D_ / 32, 25), dim3(32, 8)>>>(qw, kw, vw, ow, proj_w, wth, wtl);
    gather_emb<<<(ROWS_ * SEQDIM_ / 2 + 255) / 256, 256>>>(seq, emb, qhp, qlp);
    dim3 gp(D_ / 128, ROWS_ / 128);
    gemm_mma<true><<<gp, 256, GEMM_SMEM>>>(qhp, qlp, wth, wtl, proj_b, x, D_, SEQDIM_, ah, al);

    dim3 gqkv(3 * D_ / 128, ROWS_ / 128);        // (24, 64)
    dim3 ga(S_ / 128, B_ * H_);                  // (16, 64)
    for (int l = 0; l < L_; l++) {
        size_t off = WT_PROJ_ELEMS + (size_t)(l * 4) * WT_MAT_ELEMS;
        const __nv_bfloat16* owh = wth + off + 3 * WT_MAT_ELEMS;
        const __nv_bfloat16* owl = wtl + off + 3 * WT_MAT_ELEMS;

        gemm_qkv<<<gqkv, 256, GEMM_SMEM>>>(ah, al, wth + off, wtl + off,
                                           qb, kb, vb, l * D_,
                                           qhp, qlp, khp, klp, vthp, vtlp);
        attn_mma<<<ga, 256, ATT_SMEM>>>(qhp, qlp, khp, klp, vthp, vtlp, mask, ah, al);
        gemm_mma<false><<<gp, 256, GEMM_SMEM>>>(ah, al, owh, owl, ob + l * D_, t, D_, D_,
                                                nullptr, nullptr);
        if (l == L_ - 1)
            add_ln<false><<<ROWS_, 256>>>(x, t, lng + l * D_, lnb + l * D_, out, nullptr, nullptr);
        else
            add_ln<true><<<ROWS_, 256>>>(x, t, lng + l * D_, lnb + l * D_, x, ah, al);
    }
}

// round 14
// speedup vs baseline: 3.4419x; 1.0056x over previous
#include <cuda_runtime.h>
#include <cuda_bf16.h>
#include <math.h>
#include <stdint.h>

// Problem constants
#define B_      4
#define S_      2048
#define D_      1024
#define H_      16
#define HD_     64
#define L_      6
#define SEQDIM_ 128
#define ROWS_   (B_ * S_)   // 8192

#define WT_PROJ_ELEMS (D_ * SEQDIM_)
#define WT_MAT_ELEMS  (D_ * D_)
#define WT_ELEMS      (WT_PROJ_ELEMS + 24 * WT_MAT_ELEMS)

// ---------------------------------------------------------------------------
// Device scratch
// ---------------------------------------------------------------------------
__device__ float g_x [ROWS_ * D_];
__device__ float g_t [ROWS_ * D_];
__device__ __nv_bfloat16 g_ah[ROWS_ * D_];
__device__ __nv_bfloat16 g_al[ROWS_ * D_];
__device__ __nv_bfloat16 g_wth[WT_ELEMS];
__device__ __nv_bfloat16 g_wtl[WT_ELEMS];
__device__ __nv_bfloat16 g_qh[ROWS_ * D_];
__device__ __nv_bfloat16 g_ql[ROWS_ * D_];
__device__ __nv_bfloat16 g_kh[ROWS_ * D_];
__device__ __nv_bfloat16 g_kl[ROWS_ * D_];
__device__ __nv_bfloat16 g_vth[ROWS_ * D_];   // [bh][64][S]
__device__ __nv_bfloat16 g_vtl[ROWS_ * D_];

// ---------------------------------------------------------------------------
// Helpers
// ---------------------------------------------------------------------------
__device__ __forceinline__ uint32_t smem_u32(const void* p) {
    uint32_t a;
    asm("{ .reg .u64 t; cvta.to.shared.u64 t, %1; cvt.u32.u64 %0, t; }"
        : "=r"(a) : "l"(p));
    return a;
}

__device__ __forceinline__ void ldm_x4(uint32_t* r, uint32_t addr) {
    asm("ldmatrix.sync.aligned.m8n8.x4.shared.b16 {%0,%1,%2,%3}, [%4];"
        : "=r"(r[0]), "=r"(r[1]), "=r"(r[2]), "=r"(r[3]) : "r"(addr));
}

__device__ __forceinline__ void mma16816(float* c, const uint32_t* a,
                                         uint32_t b0, uint32_t b1) {
    asm("mma.sync.aligned.m16n8k16.row.col.f32.bf16.bf16.f32 "
        "{%0,%1,%2,%3}, {%4,%5,%6,%7}, {%8,%9}, {%0,%1,%2,%3};"
        : "+f"(c[0]), "+f"(c[1]), "+f"(c[2]), "+f"(c[3])
        : "r"(a[0]), "r"(a[1]), "r"(a[2]), "r"(a[3]), "r"(b0), "r"(b1));
}

__device__ __forceinline__ uint32_t pk_bf16(float lo, float hi) {
    uint32_t r;
    asm("cvt.rn.bf16x2.f32 %0, %1, %2;" : "=r"(r) : "f"(hi), "f"(lo));
    return r;
}

__device__ __forceinline__ void split2(float c0, float c1, uint32_t& hw, uint32_t& lw) {
    __nv_bfloat16 h0 = __float2bfloat16(c0);
    __nv_bfloat16 h1 = __float2bfloat16(c1);
    __nv_bfloat162 hp; hp.x = h0; hp.y = h1;
    hw = *(uint32_t*)&hp;
    lw = pk_bf16(c0 - __bfloat162float(h0), c1 - __bfloat162float(h1));
}

#define CP_ASYNC16(dst, src) \
    asm volatile("cp.async.cg.shared.global [%0], [%1], 16;" :: "r"(dst), "l"(src))
#define CP_COMMIT() asm volatile("cp.async.commit_group;" ::: "memory")
#define CP_WAIT(n)  asm volatile("cp.async.wait_group %0;" :: "n"(n) : "memory")

// ---------------------------------------------------------------------------
// Unified prep: z<24 layer weight transpose+split; z==24 proj_w; z>=25 gather
// ---------------------------------------------------------------------------
__global__ void prep_all(const float* __restrict__ qw, const float* __restrict__ kw,
                         const float* __restrict__ vw, const float* __restrict__ ow,
                         const float* __restrict__ pw,
                         const int* __restrict__ seq, const float* __restrict__ emb,
                         __nv_bfloat16* __restrict__ th,
                         __nv_bfloat16* __restrict__ tl,
                         __nv_bfloat16* __restrict__ xh,
                         __nv_bfloat16* __restrict__ xl) {
    int z = blockIdx.z;
    if (z >= 25) {
        // gather: slices z=25,26 each 1024 blocks x 256 threads
        int tid = threadIdx.y * 32 + threadIdx.x;
        int i = (((z - 25) * 1024 + blockIdx.y * 32 + blockIdx.x) << 8) + tid;
        if (i >= ROWS_ * SEQDIM_ / 2) return;
        int row = i >> 6;
        int c2  = (i & 63) * 2;
        const float* e = emb + seq[row] * SEQDIM_ + c2;
        uint32_t hw, lw;
        split2(e[0], e[1], hw, lw);
        ((uint32_t*)xh)[i] = hw;
        ((uint32_t*)xl)[i] = lw;
        return;
    }
    __shared__ float t[32][33];
    const float* W;
    size_t dof;
    int K;
    if (z < 24) {
        int l = z >> 2, m = z & 3;
        W = (m == 0 ? qw : m == 1 ? kw : m == 2 ? vw : ow) + (size_t)l * D_ * D_;
        dof = WT_PROJ_ELEMS + (size_t)z * WT_MAT_ELEMS;
        K = D_;
    } else {
        if (blockIdx.y >= SEQDIM_ / 32) return;
        W = pw;
        dof = 0;
        K = SEQDIM_;
    }
    int bx = blockIdx.x * 32;
    int by = blockIdx.y * 32;
    #pragma unroll
    for (int i = 0; i < 32; i += 8)
        t[threadIdx.y + i][threadIdx.x] =
            W[(size_t)(by + threadIdx.y + i) * D_ + bx + threadIdx.x];
    __syncthreads();
    #pragma unroll
    for (int i = 0; i < 32; i += 8) {
        float v = t[threadIdx.x][threadIdx.y + i];
        int n = bx + threadIdx.y + i;
        int k = by + threadIdx.x;
        __nv_bfloat16 h = __float2bfloat16(v);
        th[dof + (size_t)n * K + k] = h;
        tl[dof + (size_t)n * K + k] = __float2bfloat16(v - __bfloat162float(h));
    }
}

// ---------------------------------------------------------------------------
// GEMM core: 128x128 block tile, 8 warps of 64x32, BK=32, 2-stage cp.async,
// single sync/chunk, fragment loads interleaved with MMA passes. 2 CTAs/SM.
// ---------------------------------------------------------------------------
#define TILEB  10240            // 128 * 80
#define CHUNKB (4 * TILEB)      // 40960
#define GEMM_SMEM (2 * CHUNKB)  // 81920

template <typename EPI>
__device__ __forceinline__
void gemm_core(const __nv_bfloat16* s0, const __nv_bfloat16* s1,
               const __nv_bfloat16* s2, const __nv_bfloat16* s3,
               int K, char* smem, EPI epilogue) {
    const uint32_t sb = smem_u32(smem);
    const int tid  = threadIdx.x;
    const int lane = tid & 31;
    const int wid  = tid >> 5;
    const int wm = wid & 1;
    const int wn = wid >> 1;

    const int nk = K >> 5;

    auto load_chunk = [&](int c, int stage) {
        const int k0 = c << 5;
        uint32_t buf = sb + stage * CHUNKB;
        #pragma unroll
        for (int i = 0; i < 2; i++) {
            int t = tid + i * 256;
            int row = t >> 2;
            int seg = t & 3;
            uint32_t dst = buf + row * 80 + seg * 16;
            size_t so = (size_t)row * K + k0 + seg * 8;
            CP_ASYNC16(dst,              (const char*)(s0 + so));
            CP_ASYNC16(dst + TILEB,      (const char*)(s1 + so));
            CP_ASYNC16(dst + 2 * TILEB,  (const char*)(s2 + so));
            CP_ASYNC16(dst + 3 * TILEB,  (const char*)(s3 + so));
        }
        CP_COMMIT();
    };

    float acc[4][4][4];
    #pragma unroll
    for (int mi = 0; mi < 4; mi++)
        #pragma unroll
        for (int nb = 0; nb < 4; nb++)
            #pragma unroll
            for (int j = 0; j < 4; j++) acc[mi][nb][j] = 0.f;

    const uint32_t a_off = (uint32_t)((wm * 64 + (lane & 15)) * 80 + (lane >> 4) * 16);
    const uint32_t b_off = (uint32_t)((wn * 32 + ((lane >> 4) & 1) * 8 + (lane & 7)) * 80
                                      + ((lane >> 3) & 1) * 16);

    load_chunk(0, 0);

    for (int c = 0; c < nk; c++) {
        CP_WAIT(0);
        __syncthreads();
        if (c + 1 < nk) load_chunk(c + 1, (c + 1) & 1);

        uint32_t buf = sb + (c & 1) * CHUNKB;
        #pragma unroll
        for (int s = 0; s < 2; s++) {
            uint32_t ah[4][4], al[4][4], wh[2][4], wl[2][4];
            #pragma unroll
            for (int g = 0; g < 4; g++)
                ldm_x4(ah[g], buf + a_off + (uint32_t)(g * 16 * 80 + s * 32));
            #pragma unroll
            for (int h = 0; h < 2; h++)
                ldm_x4(wh[h], buf + 2 * TILEB + b_off + (uint32_t)(h * 16 * 80 + s * 32));
            #pragma unroll
            for (int mi = 0; mi < 4; mi++)
                #pragma unroll
                for (int nb = 0; nb < 4; nb++) {
                    const int h = nb >> 1, j = nb & 1;
                    mma16816(acc[mi][nb], ah[mi], wh[h][2 * j], wh[h][2 * j + 1]);
                }
            #pragma unroll
            for (int h = 0; h < 2; h++)
                ldm_x4(wl[h], buf + 3 * TILEB + b_off + (uint32_t)(h * 16 * 80 + s * 32));
            #pragma unroll
            for (int mi = 0; mi < 4; mi++)
                #pragma unroll
                for (int nb = 0; nb < 4; nb++) {
                    const int h = nb >> 1, j = nb & 1;
                    mma16816(acc[mi][nb], ah[mi], wl[h][2 * j], wl[h][2 * j + 1]);
                }
            #pragma unroll
            for (int g = 0; g < 4; g++)
                ldm_x4(al[g], buf + TILEB + a_off + (uint32_t)(g * 16 * 80 + s * 32));
            #pragma unroll
            for (int mi = 0; mi < 4; mi++)
                #pragma unroll
                for (int nb = 0; nb < 4; nb++) {
                    const int h = nb >> 1, j = nb & 1;
                    mma16816(acc[mi][nb], al[mi], wh[h][2 * j], wh[h][2 * j + 1]);
                }
        }
    }
    __syncthreads();

    epilogue(acc, wm, wn, lane);
}

// ---------------------------------------------------------------------------
// Generic GEMM + bias -> fp32 C (optionally also emit bf16 hi/lo split)
// ---------------------------------------------------------------------------
template <bool SPLIT>
__global__ __launch_bounds__(256, 2)
void gemm_mma(const __nv_bfloat16* __restrict__ Ah,
              const __nv_bfloat16* __restrict__ Al,
              const __nv_bfloat16* __restrict__ Wh,
              const __nv_bfloat16* __restrict__ Wl,
              const float* __restrict__ bias,
              float* __restrict__ C, int N, int K,
              __nv_bfloat16* __restrict__ oh, __nv_bfloat16* __restrict__ ol) {
    extern __shared__ char smem[];
    const int brow = blockIdx.y * 128;
    const int bcol = blockIdx.x * 128;
    gemm_core(Ah + (size_t)brow * K, Al + (size_t)brow * K,
              Wh + (size_t)bcol * K, Wl + (size_t)bcol * K, K, smem,
        [&](float acc[4][4][4], int wm, int wn, int lane) {
            #pragma unroll
            for (int mi = 0; mi < 4; mi++) {
                int row = brow + wm * 64 + mi * 16 + (lane >> 2);
                #pragma unroll
                for (int nb = 0; nb < 4; nb++) {
                    int col = bcol + wn * 32 + nb * 8 + (lane & 3) * 2;
                    float b0 = bias[col], b1 = bias[col + 1];
                    float c00 = acc[mi][nb][0] + b0, c01 = acc[mi][nb][1] + b1;
                    float c10 = acc[mi][nb][2] + b0, c11 = acc[mi][nb][3] + b1;
                    size_t i0 = (size_t)row * N + col;
                    size_t i1 = (size_t)(row + 8) * N + col;
                    *(float2*)(C + i0) = make_float2(c00, c01);
                    *(float2*)(C + i1) = make_float2(c10, c11);
                    if (SPLIT) {
                        uint32_t hw, lw;
                        split2(c00, c01, hw, lw);
                        *(uint32_t*)(oh + i0) = hw; *(uint32_t*)(ol + i0) = lw;
                        split2(c10, c11, hw, lw);
                        *(uint32_t*)(oh + i1) = hw; *(uint32_t*)(ol + i1) = lw;
                    }
                }
            }
        });
}

// ---------------------------------------------------------------------------
// Fused QKV GEMM (N=3072). V emitted transposed+split via smem staging.
// ---------------------------------------------------------------------------
__global__ __launch_bounds__(256, 2)
void gemm_qkv(const __nv_bfloat16* __restrict__ Ah,
              const __nv_bfloat16* __restrict__ Al,
              const __nv_bfloat16* __restrict__ Wh,
              const __nv_bfloat16* __restrict__ Wl,
              const float* __restrict__ qb, const float* __restrict__ kb,
              const float* __restrict__ vb, int lofs,
              __nv_bfloat16* __restrict__ qh, __nv_bfloat16* __restrict__ ql,
              __nv_bfloat16* __restrict__ kh, __nv_bfloat16* __restrict__ kl,
              __nv_bfloat16* __restrict__ vth, __nv_bfloat16* __restrict__ vtl) {
    extern __shared__ char smem[];
    const int K = D_;
    const int brow = blockIdx.y * 128;
    const int bcol = blockIdx.x * 128;
    const int mat = bcol >> 10;            // 0=q 1=k 2=v
    const int colb = bcol & 1023;
    const float* bias = (mat == 0 ? qb : mat == 1 ? kb : vb) + lofs;
    gemm_core(Ah + (size_t)brow * K, Al + (size_t)brow * K,
              Wh + (size_t)bcol * K, Wl + (size_t)bcol * K, K, smem,
        [&](float acc[4][4][4], int wm, int wn, int lane) {
            if (mat == 2) {
                float* trans = (float*)smem;   // 128 x 132 floats
                #pragma unroll
                for (int mi = 0; mi < 4; mi++) {
                    int sl = wm * 64 + mi * 16 + (lane >> 2);
                    #pragma unroll
                    for (int nb = 0; nb < 4; nb++) {
                        int dl = wn * 32 + nb * 8 + (lane & 3) * 2;
                        float b0 = bias[colb + dl], b1 = bias[colb + dl + 1];
                        trans[dl * 132 + sl]           = acc[mi][nb][0] + b0;
                        trans[(dl + 1) * 132 + sl]     = acc[mi][nb][1] + b1;
                        trans[dl * 132 + sl + 8]       = acc[mi][nb][2] + b0;
                        trans[(dl + 1) * 132 + sl + 8] = acc[mi][nb][3] + b1;
                    }
                }
                __syncthreads();
                int bb = brow >> 11;
                int s0 = brow & (S_ - 1);
                #pragma unroll
                for (int i = 0; i < 32; i++) {
                    int idx = (int)threadIdx.x + i * 256;
                    int dl = idx >> 6;
                    int sp = idx & 63;
                    float2 v = *(float2*)&trans[dl * 132 + sp * 2];
                    int col = colb + dl;
                    int hh = col >> 6, dd = col & 63;
                    size_t o = ((size_t)(bb * H_ + hh) * HD_ + dd) * S_ + s0 + sp * 2;
                    uint32_t hw, lw;
                    split2(v.x, v.y, hw, lw);
                    *(uint32_t*)(vth + o) = hw;
                    *(uint32_t*)(vtl + o) = lw;
                }
            } else {
                #pragma unroll
                for (int mi = 0; mi < 4; mi++) {
                    int row = brow + wm * 64 + mi * 16 + (lane >> 2);
                    #pragma unroll
                    for (int nb = 0; nb < 4; nb++) {
                        int col = colb + wn * 32 + nb * 8 + (lane & 3) * 2;
                        float b0 = bias[col], b1 = bias[col + 1];
                        float c00 = acc[mi][nb][0] + b0, c01 = acc[mi][nb][1] + b1;
                        float c10 = acc[mi][nb][2] + b0, c11 = acc[mi][nb][3] + b1;
                        size_t i0 = (size_t)row * D_ + col;
                        size_t i1 = (size_t)(row + 8) * D_ + col;
                        __nv_bfloat16* hB = (mat == 0) ? qh : kh;
                        __nv_bfloat16* lB = (mat == 0) ? ql : kl;
                        if (mat == 0) { c00 *= 0.125f; c01 *= 0.125f; c10 *= 0.125f; c11 *= 0.125f; }
                        uint32_t hw, lw;
                        split2(c00, c01, hw, lw);
                        *(uint32_t*)(hB + i0) = hw; *(uint32_t*)(lB + i0) = lw;
                        split2(c10, c11, hw, lw);
                        *(uint32_t*)(hB + i1) = hw; *(uint32_t*)(lB + i1) = lw;
                    }
                }
            }
        });
}

// ---------------------------------------------------------------------------
// Tensor-core flash attention; 2-stage KV pipeline, single sync per kt,
// Q-lo in smem, interleaved fragment loads. 2 CTAs/SM.
// ---------------------------------------------------------------------------
#define AST      36864
#define AKL      9216
#define AMASK    (2 * AST)
#define AQLO     (AMASK + 512)
#define ATT_SMEM (AQLO + 18432)        // 92672

__global__ __launch_bounds__(256, 2)
void attn_mma(const __nv_bfloat16* __restrict__ qh, const __nv_bfloat16* __restrict__ ql,
              const __nv_bfloat16* __restrict__ kh, const __nv_bfloat16* __restrict__ kl,
              const __nv_bfloat16* __restrict__ vth, const __nv_bfloat16* __restrict__ vtl,
              const int* __restrict__ mask,
              __nv_bfloat16* __restrict__ oh, __nv_bfloat16* __restrict__ ol) {
    extern __shared__ char smem[];
    const uint32_t sb = smem_u32(smem);
    const int tid = threadIdx.x, wid = tid >> 5, lane = tid & 31;
    const int q0 = blockIdx.x * 128;
    const int bh = blockIdx.y;
    const int b = bh >> 4, h = bh & 15;
    const size_t rowbase = (size_t)b * S_;

    #pragma unroll
    for (int i = 0; i < 4; i++) {
        int t = tid + i * 256;
        int row = t >> 3, seg = t & 7;
        size_t so = (rowbase + q0 + row) * D_ + h * HD_ + seg * 8;
        CP_ASYNC16(sb + row * 144 + seg * 16,        (const char*)(qh + so));
        CP_ASYNC16(sb + AQLO + row * 144 + seg * 16, (const char*)(ql + so));
    }
    CP_COMMIT(); CP_WAIT(0);
    __syncthreads();

    uint32_t qhf[4][4];
    const uint32_t q_off = (uint32_t)((wid * 16 + (lane & 15)) * 144 + (lane >> 4) * 16);
    #pragma unroll
    for (int s = 0; s < 4; s++)
        ldm_x4(qhf[s], sb + q_off + s * 32);
    __syncthreads();

    auto load_kv = [&](int kt, int st) {
        uint32_t buf = sb + st * AST;
        int key0 = kt * 64;
        #pragma unroll
        for (int i = 0; i < 2; i++) {
            int t = tid + i * 256;
            int row = t >> 3, seg = t & 7;
            uint32_t dst = buf + row * 144 + seg * 16;
            size_t sk = (rowbase + key0 + row) * D_ + h * HD_ + seg * 8;
            CP_ASYNC16(dst,           (const char*)(kh + sk));
            CP_ASYNC16(dst + AKL,     (const char*)(kl + sk));
            size_t sv = ((size_t)bh * HD_ + row) * S_ + key0 + seg * 8;
            CP_ASYNC16(dst + 2 * AKL, (const char*)(vth + sv));
            CP_ASYNC16(dst + 3 * AKL, (const char*)(vtl + sv));
        }
        if (tid < 16)
            CP_ASYNC16(sb + AMASK + st * 256 + tid * 16,
                       (const char*)(mask + b * S_ + key0 + tid * 4));
        CP_COMMIT();
    };

    float oacc[8][4];
    #pragma unroll
    for (int nb = 0; nb < 8; nb++)
        #pragma unroll
        for (int j = 0; j < 4; j++) oacc[nb][j] = 0.f;
    float mrow0 = -1e30f, mrow1 = -1e30f, lrow0 = 0.f, lrow1 = 0.f;

    const uint32_t bfrag_off = (uint32_t)((((lane >> 4) & 1) * 8 + (lane & 7)) * 144
                                          + ((lane >> 3) & 1) * 16);

    const int NKT = S_ / 64;
    load_kv(0, 0);

    for (int kt = 0; kt < NKT; kt++) {
        CP_WAIT(0);
        __syncthreads();
        if (kt + 1 < NKT) load_kv(kt + 1, (kt + 1) & 1);

        uint32_t buf = sb + (kt & 1) * AST;

        float sacc[8][4];
        #pragma unroll
        for (int nb = 0; nb < 8; nb++)
            #pragma unroll
            for (int j = 0; j < 4; j++) sacc[nb][j] = 0.f;

        #pragma unroll
        for (int s = 0; s < 4; s++) {
            uint32_t khf[4][4], klf[4][4], qlf[4];
            #pragma unroll
            for (int g = 0; g < 4; g++)
                ldm_x4(khf[g], buf + bfrag_off + (uint32_t)(g * 16 * 144 + s * 32));
            #pragma unroll
            for (int g = 0; g < 4; g++)
                #pragma unroll
                for (int j = 0; j < 2; j++)
                    mma16816(sacc[g * 2 + j], qhf[s], khf[g][2 * j], khf[g][2 * j + 1]);
            #pragma unroll
            for (int g = 0; g < 4; g++)
                ldm_x4(klf[g], buf + AKL + bfrag_off + (uint32_t)(g * 16 * 144 + s * 32));
            #pragma unroll
            for (int g = 0; g < 4; g++)
                #pragma unroll
                for (int j = 0; j < 2; j++)
                    mma16816(sacc[g * 2 + j], qhf[s], klf[g][2 * j], klf[g][2 * j + 1]);
            ldm_x4(qlf, sb + AQLO + q_off + s * 32);
            #pragma unroll
            for (int g = 0; g < 4; g++)
                #pragma unroll
                for (int j = 0; j < 2; j++)
                    mma16816(sacc[g * 2 + j], qlf, khf[g][2 * j], khf[g][2 * j + 1]);
        }

        {
            const int* smk = (const int*)(smem + AMASK + (kt & 1) * 256);
            int cb = 2 * (lane & 3);
            #pragma unroll
            for (int nb = 0; nb < 8; nb++) {
                if (smk[nb * 8 + cb] == 0)     { sacc[nb][0] = -1e9f; sacc[nb][2] = -1e9f; }
                if (smk[nb * 8 + cb + 1] == 0) { sacc[nb][1] = -1e9f; sacc[nb][3] = -1e9f; }
            }
        }

        float mx0 = -1e30f, mx1 = -1e30f;
        #pragma unroll
        for (int nb = 0; nb < 8; nb++) {
            mx0 = fmaxf(mx0, fmaxf(sacc[nb][0], sacc[nb][1]));
            mx1 = fmaxf(mx1, fmaxf(sacc[nb][2], sacc[nb][3]));
        }
        mx0 = fmaxf(mx0, __shfl_xor_sync(0xffffffffu, mx0, 1));
        mx0 = fmaxf(mx0, __shfl_xor_sync(0xffffffffu, mx0, 2));
        mx1 = fmaxf(mx1, __shfl_xor_sync(0xffffffffu, mx1, 1));
        mx1 = fmaxf(mx1, __shfl_xor_sync(0xffffffffu, mx1, 2));
        float mn0 = fmaxf(mrow0, mx0), mn1 = fmaxf(mrow1, mx1);
        float corr0 = __expf(mrow0 - mn0), corr1 = __expf(mrow1 - mn1);
        float sum0 = 0.f, sum1 = 0.f;
        #pragma unroll
        for (int nb = 0; nb < 8; nb++) {
            sacc[nb][0] = __expf(sacc[nb][0] - mn0);
            sacc[nb][1] = __expf(sacc[nb][1] - mn0);
            sacc[nb][2] = __expf(sacc[nb][2] - mn1);
            sacc[nb][3] = __expf(sacc[nb][3] - mn1);
            sum0 += sacc[nb][0] + sacc[nb][1];
            sum1 += sacc[nb][2] + sacc[nb][3];
        }
        sum0 += __shfl_xor_sync(0xffffffffu, sum0, 1);
        sum0 += __shfl_xor_sync(0xffffffffu, sum0, 2);
        sum1 += __shfl_xor_sync(0xffffffffu, sum1, 1);
        sum1 += __shfl_xor_sync(0xffffffffu, sum1, 2);
        lrow0 = lrow0 * corr0 + sum0;
        lrow1 = lrow1 * corr1 + sum1;
        mrow0 = mn0; mrow1 = mn1;
        #pragma unroll
        for (int nb = 0; nb < 8; nb++) {
            oacc[nb][0] *= corr0; oacc[nb][1] *= corr0;
            oacc[nb][2] *= corr1; oacc[nb][3] *= corr1;
        }

        #pragma unroll
        for (int c = 0; c < 4; c++) {
            uint32_t pha[4], pla[4];
            #pragma unroll
            for (int half = 0; half < 2; half++) {
                int nb = 2 * c + half;
                __nv_bfloat16 b0 = __float2bfloat16(sacc[nb][0]);
                __nv_bfloat16 b1 = __float2bfloat16(sacc[nb][1]);
                __nv_bfloat16 b2 = __float2bfloat16(sacc[nb][2]);
                __nv_bfloat16 b3 = __float2bfloat16(sacc[nb][3]);
                __nv_bfloat162 t01; t01.x = b0; t01.y = b1;
                __nv_bfloat162 t23; t23.x = b2; t23.y = b3;
                pha[half * 2 + 0] = *(uint32_t*)&t01;
                pha[half * 2 + 1] = *(uint32_t*)&t23;
                pla[half * 2 + 0] = pk_bf16(sacc[nb][0] - __bfloat162float(b0),
                                            sacc[nb][1] - __bfloat162float(b1));
                pla[half * 2 + 1] = pk_bf16(sacc[nb][2] - __bfloat162float(b2),
                                            sacc[nb][3] - __bfloat162float(b3));
            }
            uint32_t vhf[4][4], vlf[4][4];
            #pragma unroll
            for (int g = 0; g < 4; g++)
                ldm_x4(vhf[g], buf + 2 * AKL + bfrag_off + (uint32_t)(g * 16 * 144 + c * 32));
            #pragma unroll
            for (int g = 0; g < 4; g++)
                #pragma unroll
                for (int j = 0; j < 2; j++)
                    mma16816(oacc[g * 2 + j], pha, vhf[g][2 * j], vhf[g][2 * j + 1]);
            #pragma unroll
            for (int g = 0; g < 4; g++)
                ldm_x4(vlf[g], buf + 3 * AKL + bfrag_off + (uint32_t)(g * 16 * 144 + c * 32));
            #pragma unroll
            for (int g = 0; g < 4; g++)
                #pragma unroll
                for (int j = 0; j < 2; j++)
                    mma16816(oacc[g * 2 + j], pha, vlf[g][2 * j], vlf[g][2 * j + 1]);
            #pragma unroll
            for (int g = 0; g < 4; g++)
                #pragma unroll
                for (int j = 0; j < 2; j++)
                    mma16816(oacc[g * 2 + j], pla, vhf[g][2 * j], vhf[g][2 * j + 1]);
        }
    }

    float inv0 = 1.0f / lrow0, inv1 = 1.0f / lrow1;
    int r0 = q0 + wid * 16 + (lane >> 2);
    #pragma unroll
    for (int nb = 0; nb < 8; nb++) {
        int col = h * HD_ + nb * 8 + 2 * (lane & 3);
        size_t i0 = (rowbase + r0) * D_ + col;
        size_t i1 = (rowbase + r0 + 8) * D_ + col;
        uint32_t hw, lw;
        split2(oacc[nb][0] * inv0, oacc[nb][1] * inv0, hw, lw);
        *(uint32_t*)(oh + i0) = hw; *(uint32_t*)(ol + i0) = lw;
        split2(oacc[nb][2] * inv1, oacc[nb][3] * inv1, hw, lw);
        *(uint32_t*)(oh + i1) = hw; *(uint32_t*)(ol + i1) = lw;
    }
}

// ---------------------------------------------------------------------------
// Fused residual add + LayerNorm (warp-shuffle reductions)
// ---------------------------------------------------------------------------
template <bool SPLIT>
__global__ __launch_bounds__(256)
void add_ln(const float* __restrict__ x, const float* __restrict__ y,
            const float* __restrict__ g, const float* __restrict__ bta,
            float* __restrict__ out,
            __nv_bfloat16* __restrict__ oh, __nv_bfloat16* __restrict__ ol) {
    __shared__ float red[16];
    int row = blockIdx.x, tid = threadIdx.x;
    int wid = tid >> 5, lane = tid & 31;
    const float* xr = x + (size_t)row * D_;
    const float* yr = y + (size_t)row * D_;

    float v[4];
    float sum = 0.f, sq = 0.f;
    #pragma unroll
    for (int i = 0; i < 4; i++) {
        int c = tid + i * 256;
        v[i] = xr[c] + yr[c];
        sum += v[i];
        sq  += v[i] * v[i];
    }
    // warp reduce sum & sum-of-squares together
    #pragma unroll
    for (int off = 16; off; off >>= 1) {
        sum += __shfl_xor_sync(0xffffffffu, sum, off);
        sq  += __shfl_xor_sync(0xffffffffu, sq,  off);
    }
    if (lane == 0) { red[wid] = sum; red[8 + wid] = sq; }
    __syncthreads();
    float ts = red[lane & 7], tq = red[8 + (lane & 7)];
    #pragma unroll
    for (int off = 4; off; off >>= 1) {
        ts += __shfl_xor_sync(0xffffffffu, ts, off);
        tq += __shfl_xor_sync(0xffffffffu, tq, off);
    }
    ts = __shfl_sync(0xffffffffu, ts, 0);
    tq = __shfl_sync(0xffffffffu, tq, 0);
    float mu   = ts * (1.0f / 1024.0f);
    float var  = tq * (1.0f / 1024.0f) - mu * mu;
    float rstd = rsqrtf(var + 1e-5f);

    #pragma unroll
    for (int i = 0; i < 4; i++) {
        int c = tid + i * 256;
        float o = (v[i] - mu) * rstd * g[c] + bta[c];
        out[(size_t)row * D_ + c] = o;
        if (SPLIT) {
            __nv_bfloat16 h = __float2bfloat16(o);
            oh[(size_t)row * D_ + c] = h;
            ol[(size_t)row * D_ + c] = __float2bfloat16(o - __bfloat162float(h));
        }
    }
}

// ---------------------------------------------------------------------------
// Launch
// ---------------------------------------------------------------------------
extern "C" void kernel_launch(void* const* d_in, const int* in_sizes, int n_in,
                              void* d_out, int out_size) {
    const int*   seq    = (const int*)  d_in[0];
    const int*   mask   = (const int*)  d_in[1];
    const float* emb    = (const float*)d_in[2];
    const float* proj_w = (const float*)d_in[3];
    const float* proj_b = (const float*)d_in[4];
    const float* qw     = (const float*)d_in[5];
    const float* qb     = (const float*)d_in[6];
    const float* kw     = (const float*)d_in[7];
    const float* kb     = (const float*)d_in[8];
    const float* vw     = (const float*)d_in[9];
    const float* vb     = (const float*)d_in[10];
    const float* ow     = (const float*)d_in[11];
    const float* ob     = (const float*)d_in[12];
    const float* lng    = (const float*)d_in[13];
    const float* lnb    = (const float*)d_in[14];
    float* out = (float*)d_out;

    float *x, *t;
    __nv_bfloat16 *ah, *al, *wth, *wtl, *qhp, *qlp, *khp, *klp, *vthp, *vtlp;
    cudaGetSymbolAddress((void**)&x,    g_x);
    cudaGetSymbolAddress((void**)&t,    g_t);
    cudaGetSymbolAddress((void**)&ah,   g_ah);
    cudaGetSymbolAddress((void**)&al,   g_al);
    cudaGetSymbolAddress((void**)&wth,  g_wth);
    cudaGetSymbolAddress((void**)&wtl,  g_wtl);
    cudaGetSymbolAddress((void**)&qhp,  g_qh);
    cudaGetSymbolAddress((void**)&qlp,  g_ql);
    cudaGetSymbolAddress((void**)&khp,  g_kh);
    cudaGetSymbolAddress((void**)&klp,  g_kl);
    cudaGetSymbolAddress((void**)&vthp, g_vth);
    cudaGetSymbolAddress((void**)&vtlp, g_vtl);

    cudaFuncSetAttribute(gemm_mma<false>, cudaFuncAttributeMaxDynamicSharedMemorySize, GEMM_SMEM);
    cudaFuncSetAttribute(gemm_mma<true>,  cudaFuncAttributeMaxDynamicSharedMemorySize, GEMM_SMEM);
    cudaFuncSetAttribute(gemm_qkv, cudaFuncAttributeMaxDynamicSharedMemorySize, GEMM_SMEM);
    cudaFuncSetAttribute(attn_mma, cudaFuncAttributeMaxDynamicSharedMemorySize, ATT_SMEM);

    // launch 0: unified prep (weights z<25, gather z=25..26)
    prep_all<<<dim3(D_ / 32, D_ / 32, 27), dim3(32, 8)>>>(qw, kw, vw, ow, proj_w,
                                                          seq, emb, wth, wtl, qhp, qlp);
    // launch 1: input projection
    dim3 gp(D_ / 128, ROWS_ / 128);
    gemm_mma<true><<<gp, 256, GEMM_SMEM>>>(qhp, qlp, wth, wtl, proj_b, x, D_, SEQDIM_, ah, al);

    dim3 gqkv(3 * D_ / 128, ROWS_ / 128);        // (24, 64)
    dim3 ga(S_ / 128, B_ * H_);                  // (16, 64)
    for (int l = 0; l < L_; l++) {
        size_t off = WT_PROJ_ELEMS + (size_t)(l * 4) * WT_MAT_ELEMS;
        const __nv_bfloat16* owh = wth + off + 3 * WT_MAT_ELEMS;
        const __nv_bfloat16* owl = wtl + off + 3 * WT_MAT_ELEMS;

        // launch 2 (layer 0): gemm_qkv; launch 3 (layer 0): attn -> profiled
        gemm_qkv<<<gqkv, 256, GEMM_SMEM>>>(ah, al, wth + off, wtl + off,
                                           qb, kb, vb, l * D_,
                                           qhp, qlp, khp, klp, vthp, vtlp);
        attn_mma<<<ga, 256, ATT_SMEM>>>(qhp, qlp, khp, klp, vthp, vtlp, mask, ah, al);
        gemm_mma<false><<<gp, 256, GEMM_SMEM>>>(ah, al, owh, owl, ob + l * D_, t, D_, D_,
                                                nullptr, nullptr);
        if (l == L_ - 1)
            add_ln<false><<<ROWS_, 256>>>(x, t, lng + l * D_, lnb + l * D_, out, nullptr, nullptr);
        else
            add_ln<true><<<ROWS_, 256>>>(x, t, lng + l * D_, lnb + l * D_, x, ah, al);
    }
}